// round 4
// baseline (speedup 1.0000x reference)
#include <cuda_runtime.h>
#include <cuda_bf16.h>

// ---------------- problem constants ----------------
#define N_NODES 26240      // B * N_PER = 128 * 205
#define HDIM    200
#define NEDGE   209920
#define BATCH   128
#define NPER    205
#define EMBD    768
#define SEQ     512
#define NLAYERS 6

// ---------------- static device scratch ----------------
__device__ float g_h0[N_NODES * HDIM];
__device__ float g_h1[N_NODES * HDIM];
__device__ float g_m [N_NODES * HDIM];
__device__ float g_agg[N_NODES * HDIM];
__device__ float g_gi[N_NODES * 3 * HDIM];
__device__ float g_gh[N_NODES * 3 * HDIM];
__device__ float g_etm[(size_t)BATCH * SEQ * EMBD];     // time-major embeddings [b][t][c]
__device__ float g_hp [BATCH * 207 * HDIM];             // zero-padded conv0 input [b][t+1][c]
__device__ float g_w0t[200 * 600];
__device__ float g_w1t[200 * 2304];
__device__ float g_w2t[200 * 3072];
__device__ float g_w3t[200 * 3840];
__device__ float g_feats[BATCH * 800];
__device__ int   g_deg[N_NODES];
__device__ int   g_rs [N_NODES + 1];
__device__ int   g_cur[N_NODES];
__device__ int   g_csrc[NEDGE];

// ---------------- packed fp32x2 helpers (sm_100+) ----------------
#define FMA2(d, a, b) asm("fma.rn.f32x2 %0, %1, %2, %0;" : "+l"(d) : "l"(a), "l"(b))

__device__ __forceinline__ unsigned long long pack2(float x, float y) {
    unsigned long long r;
    asm("mov.b64 %0, {%1, %2};" : "=l"(r) : "r"(__float_as_uint(x)), "r"(__float_as_uint(y)));
    return r;
}

// ---------------- GEMM ----------------
// C[M,N] = A[M,K] * B  (+bias)
//   TB = false: B is [K,N] row-major   (C = A @ B)
//   TB = true : B is [N,K] row-major   (C = A @ B^T)
// A rows may overlap (lda < K) -> conv-as-GEMM.
// EPI = 0: store C (row stride ldc), optional bias.
// EPI = 1: per-column max over rows of ReLU(acc + bias), atomicMax into
//          C[z*featLd + featOff + col]  (values >= 0 so uint compare is valid).
// blockIdx.z selects batch: A += z * aStride.
template<bool TB, int EPI>
__global__ void __launch_bounds__(256, 2) sgemm_k(
    const float* __restrict__ A, int lda, long long aStride,
    const float* __restrict__ B,
    const float* __restrict__ bias,
    float* __restrict__ C,
    int M, int N, int K,
    int ldc, int featLd, int featOff)
{
    constexpr int BM = 128, BN = 64, BK = 8;
    __shared__ __align__(16) float As[2][BK][132];
    __shared__ __align__(16) float Bs[2][BK][68];
    __shared__ float red[16][68];

    const int tid = threadIdx.x;
    const int tx = tid & 15, ty = tid >> 4;
    const int m0 = blockIdx.y * BM;
    const int n0 = blockIdx.x * BN;
    const float* Ab = A + (long long)blockIdx.z * aStride;

    // global-load lane mapping
    const int arow = tid >> 1, akq = (tid & 1) * 4;      // A: 128 rows x 8k, float4 each
    const int bk   = tid >> 5, bn2 = (tid & 31) * 2;     // B normal: 8k x 64n, float2
    const int bn   = tid >> 2, bkq = (tid & 3) * 2;      // B trans : 64n x 8k, float2

    unsigned long long acc[4][4];
#pragma unroll
    for (int i = 0; i < 4; i++)
#pragma unroll
        for (int j = 0; j < 4; j++) acc[i][j] = 0ULL;

    const int KT = K / BK;   // all K used are multiples of 8

    // ---- prologue: tile 0 ----
    float4 aR = make_float4(0.f, 0.f, 0.f, 0.f);
    float2 bR = make_float2(0.f, 0.f);
    {
        int row = m0 + arow;
        if (row < M) aR = *(const float4*)(Ab + (long long)row * lda + akq);
        if (!TB) { if (n0 + bn2 < N) bR = *(const float2*)(B + (long long)bk * N + n0 + bn2); }
        else     { if (n0 + bn  < N) bR = *(const float2*)(B + (long long)(n0 + bn) * K + bkq); }
    }
    As[0][akq + 0][arow] = aR.x; As[0][akq + 1][arow] = aR.y;
    As[0][akq + 2][arow] = aR.z; As[0][akq + 3][arow] = aR.w;
    if (!TB) { Bs[0][bk][bn2] = bR.x; Bs[0][bk][bn2 + 1] = bR.y; }
    else     { Bs[0][bkq][bn] = bR.x; Bs[0][bkq + 1][bn] = bR.y; }
    __syncthreads();

    for (int kt = 0; kt < KT; kt++) {
        const int cur = kt & 1;
        const int k0n = (kt + 1) * BK;
        if (kt + 1 < KT) {
            int row = m0 + arow;
            aR = make_float4(0.f, 0.f, 0.f, 0.f);
            bR = make_float2(0.f, 0.f);
            if (row < M) aR = *(const float4*)(Ab + (long long)row * lda + k0n + akq);
            if (!TB) { if (n0 + bn2 < N) bR = *(const float2*)(B + (long long)(k0n + bk) * N + n0 + bn2); }
            else     { if (n0 + bn  < N) bR = *(const float2*)(B + (long long)(n0 + bn) * K + k0n + bkq); }
        }
#pragma unroll
        for (int k = 0; k < BK; k++) {
            const float* ap_ = &As[cur][k][ty * 8];
            ulonglong2 a0 = *(const ulonglong2*)ap_;         // rows r0..r3 packed as pairs
            ulonglong2 a1 = *(const ulonglong2*)(ap_ + 4);   // rows r4..r7
            float4 bv = *(const float4*)&Bs[cur][k][tx * 4];
            unsigned long long ap[4] = { a0.x, a0.y, a1.x, a1.y };
            unsigned long long bb[4] = { pack2(bv.x, bv.x), pack2(bv.y, bv.y),
                                         pack2(bv.z, bv.z), pack2(bv.w, bv.w) };
#pragma unroll
            for (int mp = 0; mp < 4; mp++)
#pragma unroll
                for (int j = 0; j < 4; j++)
                    FMA2(acc[mp][j], ap[mp], bb[j]);
        }
        if (kt + 1 < KT) {
            const int nb = cur ^ 1;
            As[nb][akq + 0][arow] = aR.x; As[nb][akq + 1][arow] = aR.y;
            As[nb][akq + 2][arow] = aR.z; As[nb][akq + 3][arow] = aR.w;
            if (!TB) { Bs[nb][bk][bn2] = bR.x; Bs[nb][bk][bn2 + 1] = bR.y; }
            else     { Bs[nb][bkq][bn] = bR.x; Bs[nb][bkq + 1][bn] = bR.y; }
        }
        __syncthreads();
    }

    // ---- epilogue ----
    if (EPI == 0) {
#pragma unroll
        for (int j = 0; j < 4; j++) {
            int col = n0 + tx * 4 + j;
            if (col >= N) continue;
            float bv = bias ? bias[col] : 0.f;
#pragma unroll
            for (int mp = 0; mp < 4; mp++) {
                union { unsigned long long u; float2 f; } cv; cv.u = acc[mp][j];
                int r = m0 + ty * 8 + mp * 2;
                if (r     < M) C[(long long)r * ldc + col]       = cv.f.x + bv;
                if (r + 1 < M) C[(long long)(r + 1) * ldc + col] = cv.f.y + bv;
            }
        }
    } else {
        float cmax[4] = { 0.f, 0.f, 0.f, 0.f };   // 0 == ReLU floor, valid identity
#pragma unroll
        for (int j = 0; j < 4; j++) {
            int col = n0 + tx * 4 + j;
            float bv = (col < N) ? bias[col] : 0.f;
#pragma unroll
            for (int mp = 0; mp < 4; mp++) {
                union { unsigned long long u; float2 f; } cv; cv.u = acc[mp][j];
                int r = m0 + ty * 8 + mp * 2;
                if (r     < M) cmax[j] = fmaxf(cmax[j], cv.f.x + bv);
                if (r + 1 < M) cmax[j] = fmaxf(cmax[j], cv.f.y + bv);
            }
        }
#pragma unroll
        for (int j = 0; j < 4; j++) red[ty][tx * 4 + j] = cmax[j];
        __syncthreads();
        if (ty == 0) {
#pragma unroll
            for (int j = 0; j < 4; j++) {
                int col = n0 + tx * 4 + j;
                if (col >= N) continue;
                float mx = 0.f;
                for (int t2 = 0; t2 < 16; t2++) mx = fmaxf(mx, red[t2][tx * 4 + j]);
                atomicMax((unsigned int*)&C[(long long)blockIdx.z * featLd + featOff + col],
                          __float_as_uint(mx));
            }
        }
    }
}

// ---------------- CSR build ----------------
__global__ void k_hist(const int* __restrict__ ei, int* __restrict__ deg) {
    int i = blockIdx.x * blockDim.x + threadIdx.x;
    if (i < NEDGE) atomicAdd(&deg[ei[NEDGE + i]], 1);
}

__global__ void k_scan(const int* __restrict__ deg, int* __restrict__ rs,
                       int* __restrict__ cur, int n) {
    __shared__ int s[1024];
    __shared__ int carry;
    int t = threadIdx.x;
    if (t == 0) carry = 0;
    __syncthreads();
    for (int base = 0; base < n; base += 1024) {
        int v = (base + t < n) ? deg[base + t] : 0;
        s[t] = v;
        __syncthreads();
        for (int off = 1; off < 1024; off <<= 1) {
            int add = (t >= off) ? s[t - off] : 0;
            __syncthreads();
            s[t] += add;
            __syncthreads();
        }
        int c0 = carry;
        int ex = c0 + s[t] - v;   // exclusive
        if (base + t < n) { rs[base + t] = ex; cur[base + t] = ex; }
        __syncthreads();
        if (t == 0) carry = c0 + s[1023];
        __syncthreads();
    }
    if (t == 0) rs[n] = carry;
}

__global__ void k_fill(const int* __restrict__ ei, int* __restrict__ cur,
                       int* __restrict__ cs) {
    int i = blockIdx.x * blockDim.x + threadIdx.x;
    if (i < NEDGE) {
        int d = ei[NEDGE + i];
        int p = atomicAdd(&cur[d], 1);
        cs[p] = ei[i];
    }
}

// ---------------- segment-sum: warp per destination node ----------------
__global__ void k_agg(const float* __restrict__ m, const int* __restrict__ rs,
                      const int* __restrict__ cs, float* __restrict__ agg) {
    int w = (blockIdx.x * blockDim.x + threadIdx.x) >> 5;
    int lane = threadIdx.x & 31;
    if (w >= N_NODES) return;
    int s = rs[w], e = rs[w + 1];
    float a0 = 0, a1 = 0, a2 = 0, a3 = 0, a4 = 0, a5 = 0, a6 = 0;
    int i = s;
    for (; i + 1 < e; i += 2) {
        const float* r0 = m + (long long)cs[i]     * HDIM;
        const float* r1 = m + (long long)cs[i + 1] * HDIM;
        a0 += r0[lane]       + r1[lane];
        a1 += r0[lane +  32] + r1[lane +  32];
        a2 += r0[lane +  64] + r1[lane +  64];
        a3 += r0[lane +  96] + r1[lane +  96];
        a4 += r0[lane + 128] + r1[lane + 128];
        a5 += r0[lane + 160] + r1[lane + 160];
        if (lane < 8) a6 += r0[lane + 192] + r1[lane + 192];
    }
    if (i < e) {
        const float* r0 = m + (long long)cs[i] * HDIM;
        a0 += r0[lane];       a1 += r0[lane + 32];  a2 += r0[lane + 64];
        a3 += r0[lane + 96];  a4 += r0[lane + 128]; a5 += r0[lane + 160];
        if (lane < 8) a6 += r0[lane + 192];
    }
    float* o = agg + (long long)w * HDIM;
    o[lane] = a0;       o[lane + 32] = a1;  o[lane + 64] = a2;
    o[lane + 96] = a3;  o[lane + 128] = a4; o[lane + 160] = a5;
    if (lane < 8) o[lane + 192] = a6;
}

// ---------------- GRU gates ----------------
__global__ void k_gates(const float* __restrict__ gi, const float* __restrict__ gh,
                        const float* __restrict__ hsrc, float* __restrict__ hdst) {
    int idx = blockIdx.x * blockDim.x + threadIdx.x;
    if (idx >= N_NODES * HDIM) return;
    int n = idx / HDIM, c = idx - n * HDIM;
    const float* giN = gi + (long long)n * 600;
    const float* ghN = gh + (long long)n * 600;
    float r  = 1.f / (1.f + expf(-(giN[c]       + ghN[c])));
    float z  = 1.f / (1.f + expf(-(giN[200 + c] + ghN[200 + c])));
    float nn = tanhf(giN[400 + c] + r * ghN[400 + c]);
    hdst[idx] = (1.f - z) * nn + z * hsrc[idx];
}

// ---------------- misc data movement ----------------
__global__ void k_embed(const int* __restrict__ ids, const float* __restrict__ tbl,
                        float* __restrict__ etm) {
    int row = blockIdx.x;          // b * SEQ + t
    int t = threadIdx.x;           // 192 threads * float4 = 768 floats
    long long id = ids[row];
    const float4* src = (const float4*)(tbl + id * EMBD);
    float4* dst = (float4*)(etm + (long long)row * EMBD);
    dst[t] = src[t];
}

__global__ void k_hp(const float* __restrict__ h, float* __restrict__ hp) {
    int idx = blockIdx.x * blockDim.x + threadIdx.x;
    if (idx >= BATCH * 207 * HDIM) return;
    int b = idx / (207 * HDIM);
    int rem = idx - b * 207 * HDIM;
    int r = rem / HDIM, c = rem - r * HDIM;
    hp[idx] = (r == 0 || r == 206) ? 0.f
              : h[((long long)b * NPER + (r - 1)) * HDIM + c];
}

// w[co][ci][k] -> wt[co][k*CI + ci]
__global__ void k_wt(const float* __restrict__ w, float* __restrict__ wt,
                     int CO, int CI, int KK) {
    int idx = blockIdx.x * blockDim.x + threadIdx.x;
    if (idx >= CO * CI * KK) return;
    int co = idx / (CI * KK);
    int rem = idx - co * CI * KK;
    int ci = rem / KK, k = rem - ci * KK;
    wt[(long long)co * CI * KK + k * CI + ci] = w[idx];
}

// ---------------- fused FC head ----------------
__global__ void k_fc(const float* __restrict__ feats,
                     const float* __restrict__ w1, const float* __restrict__ b1,
                     const float* __restrict__ w2, const float* __restrict__ b2,
                     const float* __restrict__ w3, const float* __restrict__ b3,
                     float* __restrict__ out) {
    int b = blockIdx.x;
    int tid = threadIdx.x;
    int lane = tid & 31, wrp = tid >> 5;     // 8 warps
    __shared__ float sf[800];
    __shared__ float s1[256];
    __shared__ float s2[128];
    for (int i = tid; i < 800; i += 256) sf[i] = feats[b * 800 + i];
    __syncthreads();
    for (int jj = 0; jj < 32; jj++) {        // fc1: warp-cooperative, coalesced weights
        int j = wrp * 32 + jj;
        float a = 0.f;
        for (int i = lane; i < 800; i += 32) a += sf[i] * w1[(long long)j * 800 + i];
        for (int o = 16; o; o >>= 1) a += __shfl_down_sync(0xffffffffu, a, o);
        if (lane == 0) s1[j] = fmaxf(a + b1[j], 0.f);
    }
    __syncthreads();
    if (tid < 128) {
        float a = b2[tid];
        for (int i = 0; i < 256; i++) a += s1[i] * w2[tid * 256 + i];
        s2[tid] = fmaxf(a, 0.f);
    }
    __syncthreads();
    if (tid < 2) {
        float a = b3[tid];
        for (int i = 0; i < 128; i++) a += s2[i] * w3[tid * 128 + i];
        out[b * 2 + tid] = a;
    }
}

// ---------------- launcher ----------------
extern "C" void kernel_launch(void* const* d_in, const int* in_sizes, int n_in,
                              void* d_out, int out_size) {
    const float* x     = (const float*)d_in[0];
    const int*   ei    = (const int*)  d_in[1];
    const int*   ids   = (const int*)  d_in[2];
    const float* etab  = (const float*)d_in[3];
    const float* ggcw  = (const float*)d_in[4];
    const float* wih   = (const float*)d_in[5];
    const float* whh   = (const float*)d_in[6];
    const float* bih   = (const float*)d_in[7];
    const float* bhh   = (const float*)d_in[8];
    const float* c0w   = (const float*)d_in[9];
    const float* c0b   = (const float*)d_in[10];
    const float* c1w   = (const float*)d_in[11];
    const float* c1b   = (const float*)d_in[12];
    const float* c2w   = (const float*)d_in[13];
    const float* c2b   = (const float*)d_in[14];
    const float* c3w   = (const float*)d_in[15];
    const float* c3b   = (const float*)d_in[16];
    const float* f1w   = (const float*)d_in[17];
    const float* f1b   = (const float*)d_in[18];
    const float* f2w   = (const float*)d_in[19];
    const float* f2b   = (const float*)d_in[20];
    const float* f3w   = (const float*)d_in[21];
    const float* f3b   = (const float*)d_in[22];
    float* out = (float*)d_out;

    float *h0, *h1, *mm, *agg, *gi, *gh, *etm, *hp;
    float *w0t, *w1t, *w2t, *w3t, *feats;
    int *deg, *rs, *cur, *cs;
    cudaGetSymbolAddress((void**)&h0,   g_h0);
    cudaGetSymbolAddress((void**)&h1,   g_h1);
    cudaGetSymbolAddress((void**)&mm,   g_m);
    cudaGetSymbolAddress((void**)&agg,  g_agg);
    cudaGetSymbolAddress((void**)&gi,   g_gi);
    cudaGetSymbolAddress((void**)&gh,   g_gh);
    cudaGetSymbolAddress((void**)&etm,  g_etm);
    cudaGetSymbolAddress((void**)&hp,   g_hp);
    cudaGetSymbolAddress((void**)&w0t,  g_w0t);
    cudaGetSymbolAddress((void**)&w1t,  g_w1t);
    cudaGetSymbolAddress((void**)&w2t,  g_w2t);
    cudaGetSymbolAddress((void**)&w3t,  g_w3t);
    cudaGetSymbolAddress((void**)&feats,g_feats);
    cudaGetSymbolAddress((void**)&deg,  g_deg);
    cudaGetSymbolAddress((void**)&rs,   g_rs);
    cudaGetSymbolAddress((void**)&cur,  g_cur);
    cudaGetSymbolAddress((void**)&cs,   g_csrc);

    // ---- CSR build ----
    cudaMemsetAsync(deg, 0, N_NODES * sizeof(int));
    k_hist<<<(NEDGE + 255) / 256, 256>>>(ei, deg);
    k_scan<<<1, 1024>>>(deg, rs, cur, N_NODES);
    k_fill<<<(NEDGE + 255) / 256, 256>>>(ei, cur, cs);

    // ---- independent prep ----
    cudaMemcpyAsync(h0, x, (size_t)N_NODES * HDIM * sizeof(float),
                    cudaMemcpyDeviceToDevice);
    k_embed<<<BATCH * SEQ, 192>>>(ids, etab, etm);
    k_wt<<<(200 * 200 * 3 + 255) / 256, 256>>>(c0w, w0t, 200, 200, 3);
    k_wt<<<(200 * 768 * 3 + 255) / 256, 256>>>(c1w, w1t, 200, 768, 3);
    k_wt<<<(200 * 768 * 4 + 255) / 256, 256>>>(c2w, w2t, 200, 768, 4);
    k_wt<<<(200 * 768 * 5 + 255) / 256, 256>>>(c3w, w3t, 200, 768, 5);
    cudaMemsetAsync(feats, 0, BATCH * 800 * sizeof(float));

    // ---- gated graph conv: 6 layers ----
    float* hc = h0;
    float* hn = h1;
    dim3 gM((HDIM + 63) / 64, (N_NODES + 127) / 128, 1);         // 4 x 205
    dim3 gG((3 * HDIM + 63) / 64, (N_NODES + 127) / 128, 1);     // 10 x 205
    for (int l = 0; l < NLAYERS; l++) {
        sgemm_k<false, 0><<<gM, 256>>>(hc, HDIM, 0,
                                       ggcw + (long long)l * HDIM * HDIM, nullptr, mm,
                                       N_NODES, HDIM, HDIM, HDIM, 0, 0);
        k_agg<<<(N_NODES + 7) / 8, 256>>>(mm, rs, cs, agg);
        sgemm_k<true, 0><<<gG, 256>>>(agg, HDIM, 0, wih, bih, gi,
                                      N_NODES, 3 * HDIM, HDIM, 3 * HDIM, 0, 0);
        sgemm_k<true, 0><<<gG, 256>>>(hc, HDIM, 0, whh, bhh, gh,
                                      N_NODES, 3 * HDIM, HDIM, 3 * HDIM, 0, 0);
        k_gates<<<(N_NODES * HDIM + 255) / 256, 256>>>(gi, gh, hc, hn);
        float* t = hc; hc = hn; hn = t;
    }

    // ---- conv0 padded input ----
    k_hp<<<(BATCH * 207 * HDIM + 255) / 256, 256>>>(hc, hp);

    // ---- convs as GEMMs with fused bias+ReLU+max epilogue ----
    // conv0: M=205, K=600, A = hp[b], lda=200
    sgemm_k<true, 1><<<dim3(4, 2, BATCH), 256>>>(hp, 200, 207LL * 200, w0t, c0b, feats,
                                                 205, 200, 600, 0, 800, 0);
    // conv1: M=510, K=2304, A = e_tm[b], lda=768 (overlapping rows)
    sgemm_k<true, 1><<<dim3(4, 4, BATCH), 256>>>(etm, 768, (long long)SEQ * EMBD, w1t, c1b, feats,
                                                 510, 200, 2304, 0, 800, 200);
    // conv2: M=509, K=3072
    sgemm_k<true, 1><<<dim3(4, 4, BATCH), 256>>>(etm, 768, (long long)SEQ * EMBD, w2t, c2b, feats,
                                                 509, 200, 3072, 0, 800, 400);
    // conv3: M=508, K=3840
    sgemm_k<true, 1><<<dim3(4, 4, BATCH), 256>>>(etm, 768, (long long)SEQ * EMBD, w3t, c3b, feats,
                                                 508, 200, 3840, 0, 800, 600);

    // ---- FC head ----
    k_fc<<<BATCH, 256>>>(feats, f1w, f1b, f2w, f2b, f3w, f3b, out);
}

// round 6
// speedup vs baseline: 1.7127x; 1.7127x over previous
#include <cuda_runtime.h>
#include <cuda_bf16.h>
#include <cstdint>

// ---------------- problem constants ----------------
#define N_NODES 26240      // B * N_PER = 128 * 205
#define HDIM    200
#define NEDGE   209920
#define BATCH   128
#define NPER    205
#define EMBD    768
#define SEQ     512
#define NLAYERS 6

// ---------------- static device scratch ----------------
__device__ float g_h0[N_NODES * HDIM];
__device__ float g_h1[N_NODES * HDIM];
__device__ float g_m [N_NODES * HDIM];
__device__ float g_agg[N_NODES * HDIM];
__device__ float g_gi[N_NODES * 3 * HDIM];
__device__ float g_gh[N_NODES * 3 * HDIM];
__device__ float g_hp [BATCH * 207 * HDIM];             // zero-padded conv0 input
__device__ float g_w0t[200 * 600];
__device__ float g_feats[BATCH * 800];
__device__ int   g_deg[N_NODES];
__device__ int   g_rs [N_NODES + 1];
__device__ int   g_cur[N_NODES];
__device__ int   g_csrc[NEDGE];

// bf16 hi/lo embeddings, time-major [b][t][c], +8 zero rows for tap overrun
__device__ __align__(16) __nv_bfloat16 g_ehi[((size_t)BATCH * SEQ + 8) * EMBD];
__device__ __align__(16) __nv_bfloat16 g_elo[((size_t)BATCH * SEQ + 8) * EMBD];
// expanded conv weights: [200][3K] = [Whi | Wlo | Whi], K-major per tap
__device__ __align__(16) __nv_bfloat16 g_w1b[200 * 3 * 2304];
__device__ __align__(16) __nv_bfloat16 g_w2b[200 * 3 * 3072];
__device__ __align__(16) __nv_bfloat16 g_w3b[200 * 3 * 3840];

// ---------------- packed fp32x2 helpers (sm_100+) ----------------
#define FMA2(d, a, b) asm("fma.rn.f32x2 %0, %1, %2, %0;" : "+l"(d) : "l"(a), "l"(b))

__device__ __forceinline__ unsigned long long pack2(float x, float y) {
    unsigned long long r;
    asm("mov.b64 %0, {%1, %2};" : "=l"(r) : "r"(__float_as_uint(x)), "r"(__float_as_uint(y)));
    return r;
}

// ---------------- warp-level bf16 MMA (compute_100-safe PTX) ----------------
#define MMA_BF16(d, a, b0, b1) asm volatile(                           \
    "mma.sync.aligned.m16n8k16.row.col.f32.bf16.bf16.f32 "             \
    "{%0,%1,%2,%3}, {%4,%5,%6,%7}, {%8,%9}, {%0,%1,%2,%3};"            \
    : "+f"((d)[0]), "+f"((d)[1]), "+f"((d)[2]), "+f"((d)[3])           \
    : "r"((a)[0]), "r"((a)[1]), "r"((a)[2]), "r"((a)[3]),              \
      "r"(b0), "r"(b1))

// ---------------- conv1/2/3: HMMA bf16x3 conv-as-GEMM ----------------
// grid (1, m-tiles, 128 batches), 256 threads = 8 warps (4m x 2n).
// Block computes 128 rows x 208 cols (200 real). K3 = 3*K.
// K tiled by 64, double-buffered smem, register-staged global loads.
__global__ void __launch_bounds__(256, 1) conv_hmma_k(
    const __nv_bfloat16* __restrict__ ehi,
    const __nv_bfloat16* __restrict__ elo,
    const __nv_bfloat16* __restrict__ wb,
    const float* __restrict__ bias,
    float* __restrict__ feats,
    int M, int K3, int featOff)
{
    extern __shared__ __align__(16) char dsm[];
    // As[2][128][72] bf16 (36864 B), Bs[2][208][72] bf16 (59904 B),
    // smax[208] f32 (832 B), sbias[208] f32 (832 B)
    constexpr int ASTR = 72, BSTR = 72;
    __nv_bfloat16* As = (__nv_bfloat16*)dsm;
    __nv_bfloat16* Bs = (__nv_bfloat16*)(dsm + 36864);
    float* smax  = (float*)(dsm + 36864 + 59904);
    float* sbias = smax + 208;

    const int tid = threadIdx.x;
    const int lane = tid & 31, wid = tid >> 5;
    const int wm = wid & 3, wn = wid >> 2;
    const int g = lane >> 2, t2 = (lane & 3) * 2;
    const int b = blockIdx.z, m0 = blockIdx.y * 128;
    const int TK = K3 / 192;          // 64-tiles per pass (K/64)
    const int T  = K3 / 64;           // total 64-tiles

    // init bias + shared max
    if (tid < 208) { smax[tid] = 0.f; sbias[tid] = (tid < 200) ? bias[tid] : 0.f; }

    // global-load staging
    uint4 ra[4], rb[7];
    auto ldg_tile = [&](int kt) {
        int p = kt / TK;
        int rem = kt - p * TK;
        int kk = rem / 12;
        int c0 = (rem - kk * 12) * 64;
        const __nv_bfloat16* src = (p < 2) ? ehi : elo;
        long long abase = ((long long)(b * SEQ + m0 + kk)) * EMBD + c0;
#pragma unroll
        for (int i = 0; i < 4; i++) {
            int u = tid + i * 256;                 // 1024 x 16B
            int row = u >> 3, ch = u & 7;
            ra[i] = *(const uint4*)(src + abase + (long long)row * EMBD + ch * 8);
        }
        int kg = kt * 64;
#pragma unroll
        for (int i = 0; i < 7; i++) {
            int u = tid + i * 256;                 // 1600 x 16B (200 rows)
            if (u < 1600) {
                int row = u >> 3, ch = u & 7;
                rb[i] = *(const uint4*)(wb + (long long)row * K3 + kg + ch * 8);
            }
        }
    };
    auto sts_tile = [&](int buf) {
        __nv_bfloat16* A = As + buf * 128 * ASTR;
        __nv_bfloat16* B = Bs + buf * 208 * BSTR;
#pragma unroll
        for (int i = 0; i < 4; i++) {
            int u = tid + i * 256;
            int row = u >> 3, ch = u & 7;
            *(uint4*)(A + row * ASTR + ch * 8) = ra[i];
        }
#pragma unroll
        for (int i = 0; i < 7; i++) {
            int u = tid + i * 256;
            if (u < 1600) {
                int row = u >> 3, ch = u & 7;
                *(uint4*)(B + row * BSTR + ch * 8) = rb[i];
            }
        }
    };

    float acc[2][13][4];
#pragma unroll
    for (int i = 0; i < 2; i++)
#pragma unroll
        for (int j = 0; j < 13; j++)
#pragma unroll
            for (int q = 0; q < 4; q++) acc[i][j][q] = 0.f;

    // prologue
    ldg_tile(0);
    sts_tile(0);
    __syncthreads();

    for (int kt = 0; kt < T; kt++) {
        const int buf = kt & 1;
        const bool more = (kt + 1 < T);
        if (more) ldg_tile(kt + 1);                  // overlap with compute

        const __nv_bfloat16* Ab = As + buf * 128 * ASTR;
        const __nv_bfloat16* Bb = Bs + buf * 208 * BSTR;
#pragma unroll
        for (int ks = 0; ks < 4; ks++) {
            const int ko = ks * 16;
            uint32_t a[2][4];
#pragma unroll
            for (int i = 0; i < 2; i++) {
                const int r = wm * 32 + i * 16 + g;
                a[i][0] = *(const uint32_t*)(Ab + (r)     * ASTR + ko + t2);
                a[i][1] = *(const uint32_t*)(Ab + (r + 8) * ASTR + ko + t2);
                a[i][2] = *(const uint32_t*)(Ab + (r)     * ASTR + ko + t2 + 8);
                a[i][3] = *(const uint32_t*)(Ab + (r + 8) * ASTR + ko + t2 + 8);
            }
#pragma unroll
            for (int j = 0; j < 13; j++) {
                const int n = wn * 104 + j * 8 + g;
                uint32_t b0 = *(const uint32_t*)(Bb + n * BSTR + ko + t2);
                uint32_t b1 = *(const uint32_t*)(Bb + n * BSTR + ko + t2 + 8);
                MMA_BF16(acc[0][j], a[0], b0, b1);
                MMA_BF16(acc[1][j], a[1], b0, b1);
            }
        }
        if (more) sts_tile(buf ^ 1);
        __syncthreads();
    }

    // ---- epilogue: masked max over rows, +bias, ReLU, column max ----
    const int valid = (M - m0 < 128) ? (M - m0) : 128;
#pragma unroll
    for (int j = 0; j < 13; j++) {
        float v0 = -1e30f, v1 = -1e30f;
#pragma unroll
        for (int i = 0; i < 2; i++) {
            const int r0 = wm * 32 + i * 16 + g;
            if (r0 < valid)     { v0 = fmaxf(v0, acc[i][j][0]); v1 = fmaxf(v1, acc[i][j][1]); }
            if (r0 + 8 < valid) { v0 = fmaxf(v0, acc[i][j][2]); v1 = fmaxf(v1, acc[i][j][3]); }
        }
#pragma unroll
        for (int o = 4; o <= 16; o <<= 1) {
            v0 = fmaxf(v0, __shfl_xor_sync(~0u, v0, o));
            v1 = fmaxf(v1, __shfl_xor_sync(~0u, v1, o));
        }
        if (g == 0) {
            const int col = wn * 104 + j * 8 + t2;
            if (col < 200) {
                float r = fmaxf(v0 + sbias[col], 0.f);
                atomicMax((unsigned int*)&smax[col], __float_as_uint(r));
            }
            if (col + 1 < 200) {
                float r = fmaxf(v1 + sbias[col + 1], 0.f);
                atomicMax((unsigned int*)&smax[col + 1], __float_as_uint(r));
            }
        }
    }
    __syncthreads();
    if (tid < 200)
        atomicMax((unsigned int*)&feats[(long long)b * 800 + featOff + tid],
                  __float_as_uint(smax[tid]));
}

// ---------------- bf16 split precompute ----------------
__global__ void k_embed2(const int* __restrict__ ids, const float* __restrict__ tbl,
                         __nv_bfloat16* __restrict__ hi, __nv_bfloat16* __restrict__ lo) {
    int row = blockIdx.x;                  // b * SEQ + t, plus 8 pad rows
    long long o = (long long)row * EMBD;
    if (row >= BATCH * SEQ) {
        for (int c = threadIdx.x; c < EMBD; c += 256) {
            hi[o + c] = __float2bfloat16(0.f);
            lo[o + c] = __float2bfloat16(0.f);
        }
        return;
    }
    long long id = ids[row];
    const float* s = tbl + id * EMBD;
    for (int c = threadIdx.x; c < EMBD; c += 256) {
        float x = s[c];
        __nv_bfloat16 h = __float2bfloat16(x);
        hi[o + c] = h;
        lo[o + c] = __float2bfloat16(x - __bfloat162float(h));
    }
}

// w: [200][768][KK] fp32  ->  wb: [200][3K] bf16, [Whi | Wlo | Whi], tap-major K
__global__ void k_wsplit(const float* __restrict__ w, __nv_bfloat16* __restrict__ wb, int KK) {
    int K = 768 * KK;
    int idx = blockIdx.x * blockDim.x + threadIdx.x;
    if (idx >= 200 * K) return;
    int co = idx / K, r = idx - co * K;
    int kk = r / 768, ci = r - kk * 768;
    float x = w[(co * 768 + ci) * KK + kk];
    __nv_bfloat16 h = __float2bfloat16(x);
    __nv_bfloat16 l = __float2bfloat16(x - __bfloat162float(h));
    long long base = (long long)co * 3 * K + r;
    wb[base] = h; wb[base + K] = l; wb[base + 2 * K] = h;
}

// ---------------- fp32 SIMT GEMM (GGC + conv0) ----------------
template<bool TB, int EPI>
__global__ void __launch_bounds__(256, 2) sgemm_k(
    const float* __restrict__ A, int lda, long long aStride,
    const float* __restrict__ B,
    const float* __restrict__ bias,
    float* __restrict__ C,
    int M, int N, int K,
    int ldc, int featLd, int featOff)
{
    constexpr int BM = 128, BN = 64, BK = 8;
    __shared__ __align__(16) float As[2][BK][132];
    __shared__ __align__(16) float Bs[2][BK][68];
    __shared__ float red[16][68];

    const int tid = threadIdx.x;
    const int tx = tid & 15, ty = tid >> 4;
    const int m0 = blockIdx.y * BM;
    const int n0 = blockIdx.x * BN;
    const float* Ab = A + (long long)blockIdx.z * aStride;

    const int arow = tid >> 1, akq = (tid & 1) * 4;
    const int bk   = tid >> 5, bn2 = (tid & 31) * 2;
    const int bn   = tid >> 2, bkq = (tid & 3) * 2;

    unsigned long long acc[4][4];
#pragma unroll
    for (int i = 0; i < 4; i++)
#pragma unroll
        for (int j = 0; j < 4; j++) acc[i][j] = 0ULL;

    const int KT = K / BK;

    float4 aR = make_float4(0.f, 0.f, 0.f, 0.f);
    float2 bR = make_float2(0.f, 0.f);
    {
        int row = m0 + arow;
        if (row < M) aR = *(const float4*)(Ab + (long long)row * lda + akq);
        if (!TB) { if (n0 + bn2 < N) bR = *(const float2*)(B + (long long)bk * N + n0 + bn2); }
        else     { if (n0 + bn  < N) bR = *(const float2*)(B + (long long)(n0 + bn) * K + bkq); }
    }
    As[0][akq + 0][arow] = aR.x; As[0][akq + 1][arow] = aR.y;
    As[0][akq + 2][arow] = aR.z; As[0][akq + 3][arow] = aR.w;
    if (!TB) { Bs[0][bk][bn2] = bR.x; Bs[0][bk][bn2 + 1] = bR.y; }
    else     { Bs[0][bkq][bn] = bR.x; Bs[0][bkq + 1][bn] = bR.y; }
    __syncthreads();

    for (int kt = 0; kt < KT; kt++) {
        const int cur = kt & 1;
        const int k0n = (kt + 1) * BK;
        if (kt + 1 < KT) {
            int row = m0 + arow;
            aR = make_float4(0.f, 0.f, 0.f, 0.f);
            bR = make_float2(0.f, 0.f);
            if (row < M) aR = *(const float4*)(Ab + (long long)row * lda + k0n + akq);
            if (!TB) { if (n0 + bn2 < N) bR = *(const float2*)(B + (long long)(k0n + bk) * N + n0 + bn2); }
            else     { if (n0 + bn  < N) bR = *(const float2*)(B + (long long)(n0 + bn) * K + k0n + bkq); }
        }
#pragma unroll
        for (int k = 0; k < BK; k++) {
            const float* ap_ = &As[cur][k][ty * 8];
            ulonglong2 a0 = *(const ulonglong2*)ap_;
            ulonglong2 a1 = *(const ulonglong2*)(ap_ + 4);
            float4 bv = *(const float4*)&Bs[cur][k][tx * 4];
            unsigned long long ap[4] = { a0.x, a0.y, a1.x, a1.y };
            unsigned long long bb[4] = { pack2(bv.x, bv.x), pack2(bv.y, bv.y),
                                         pack2(bv.z, bv.z), pack2(bv.w, bv.w) };
#pragma unroll
            for (int mp = 0; mp < 4; mp++)
#pragma unroll
                for (int j = 0; j < 4; j++)
                    FMA2(acc[mp][j], ap[mp], bb[j]);
        }
        if (kt + 1 < KT) {
            const int nb = cur ^ 1;
            As[nb][akq + 0][arow] = aR.x; As[nb][akq + 1][arow] = aR.y;
            As[nb][akq + 2][arow] = aR.z; As[nb][akq + 3][arow] = aR.w;
            if (!TB) { Bs[nb][bk][bn2] = bR.x; Bs[nb][bk][bn2 + 1] = bR.y; }
            else     { Bs[nb][bkq][bn] = bR.x; Bs[nb][bkq + 1][bn] = bR.y; }
        }
        __syncthreads();
    }

    if (EPI == 0) {
#pragma unroll
        for (int j = 0; j < 4; j++) {
            int col = n0 + tx * 4 + j;
            if (col >= N) continue;
            float bv = bias ? bias[col] : 0.f;
#pragma unroll
            for (int mp = 0; mp < 4; mp++) {
                union { unsigned long long u; float2 f; } cv; cv.u = acc[mp][j];
                int r = m0 + ty * 8 + mp * 2;
                if (r     < M) C[(long long)r * ldc + col]       = cv.f.x + bv;
                if (r + 1 < M) C[(long long)(r + 1) * ldc + col] = cv.f.y + bv;
            }
        }
    } else {
        float cmax[4] = { 0.f, 0.f, 0.f, 0.f };
#pragma unroll
        for (int j = 0; j < 4; j++) {
            int col = n0 + tx * 4 + j;
            float bv = (col < N) ? bias[col] : 0.f;
#pragma unroll
            for (int mp = 0; mp < 4; mp++) {
                union { unsigned long long u; float2 f; } cv; cv.u = acc[mp][j];
                int r = m0 + ty * 8 + mp * 2;
                if (r     < M) cmax[j] = fmaxf(cmax[j], cv.f.x + bv);
                if (r + 1 < M) cmax[j] = fmaxf(cmax[j], cv.f.y + bv);
            }
        }
#pragma unroll
        for (int j = 0; j < 4; j++) red[ty][tx * 4 + j] = cmax[j];
        __syncthreads();
        if (ty == 0) {
#pragma unroll
            for (int j = 0; j < 4; j++) {
                int col = n0 + tx * 4 + j;
                if (col >= N) continue;
                float mx = 0.f;
                for (int t2 = 0; t2 < 16; t2++) mx = fmaxf(mx, red[t2][tx * 4 + j]);
                atomicMax((unsigned int*)&C[(long long)blockIdx.z * featLd + featOff + col],
                          __float_as_uint(mx));
            }
        }
    }
}

// ---------------- CSR build ----------------
__global__ void k_hist(const int* __restrict__ ei, int* __restrict__ deg) {
    int i = blockIdx.x * blockDim.x + threadIdx.x;
    if (i < NEDGE) atomicAdd(&deg[ei[NEDGE + i]], 1);
}

__global__ void k_scan(const int* __restrict__ deg, int* __restrict__ rs,
                       int* __restrict__ cur, int n) {
    __shared__ int s[1024];
    __shared__ int carry;
    int t = threadIdx.x;
    if (t == 0) carry = 0;
    __syncthreads();
    for (int base = 0; base < n; base += 1024) {
        int v = (base + t < n) ? deg[base + t] : 0;
        s[t] = v;
        __syncthreads();
        for (int off = 1; off < 1024; off <<= 1) {
            int add = (t >= off) ? s[t - off] : 0;
            __syncthreads();
            s[t] += add;
            __syncthreads();
        }
        int c0 = carry;
        int ex = c0 + s[t] - v;
        if (base + t < n) { rs[base + t] = ex; cur[base + t] = ex; }
        __syncthreads();
        if (t == 0) carry = c0 + s[1023];
        __syncthreads();
    }
    if (t == 0) rs[n] = carry;
}

__global__ void k_fill(const int* __restrict__ ei, int* __restrict__ cur,
                       int* __restrict__ cs) {
    int i = blockIdx.x * blockDim.x + threadIdx.x;
    if (i < NEDGE) {
        int d = ei[NEDGE + i];
        int p = atomicAdd(&cur[d], 1);
        cs[p] = ei[i];
    }
}

// ---------------- segment-sum ----------------
__global__ void k_agg(const float* __restrict__ m, const int* __restrict__ rs,
                      const int* __restrict__ cs, float* __restrict__ agg) {
    int w = (blockIdx.x * blockDim.x + threadIdx.x) >> 5;
    int lane = threadIdx.x & 31;
    if (w >= N_NODES) return;
    int s = rs[w], e = rs[w + 1];
    float a0 = 0, a1 = 0, a2 = 0, a3 = 0, a4 = 0, a5 = 0, a6 = 0;
    int i = s;
    for (; i + 1 < e; i += 2) {
        const float* r0 = m + (long long)cs[i]     * HDIM;
        const float* r1 = m + (long long)cs[i + 1] * HDIM;
        a0 += r0[lane]       + r1[lane];
        a1 += r0[lane +  32] + r1[lane +  32];
        a2 += r0[lane +  64] + r1[lane +  64];
        a3 += r0[lane +  96] + r1[lane +  96];
        a4 += r0[lane + 128] + r1[lane + 128];
        a5 += r0[lane + 160] + r1[lane + 160];
        if (lane < 8) a6 += r0[lane + 192] + r1[lane + 192];
    }
    if (i < e) {
        const float* r0 = m + (long long)cs[i] * HDIM;
        a0 += r0[lane];       a1 += r0[lane + 32];  a2 += r0[lane + 64];
        a3 += r0[lane + 96];  a4 += r0[lane + 128]; a5 += r0[lane + 160];
        if (lane < 8) a6 += r0[lane + 192];
    }
    float* o = agg + (long long)w * HDIM;
    o[lane] = a0;       o[lane + 32] = a1;  o[lane + 64] = a2;
    o[lane + 96] = a3;  o[lane + 128] = a4; o[lane + 160] = a5;
    if (lane < 8) o[lane + 192] = a6;
}

// ---------------- GRU gates ----------------
__global__ void k_gates(const float* __restrict__ gi, const float* __restrict__ gh,
                        const float* __restrict__ hsrc, float* __restrict__ hdst) {
    int idx = blockIdx.x * blockDim.x + threadIdx.x;
    if (idx >= N_NODES * HDIM) return;
    int n = idx / HDIM, c = idx - n * HDIM;
    const float* giN = gi + (long long)n * 600;
    const float* ghN = gh + (long long)n * 600;
    float r  = 1.f / (1.f + expf(-(giN[c]       + ghN[c])));
    float z  = 1.f / (1.f + expf(-(giN[200 + c] + ghN[200 + c])));
    float nn = tanhf(giN[400 + c] + r * ghN[400 + c]);
    hdst[idx] = (1.f - z) * nn + z * hsrc[idx];
}

// ---------------- misc data movement ----------------
__global__ void k_hp(const float* __restrict__ h, float* __restrict__ hp) {
    int idx = blockIdx.x * blockDim.x + threadIdx.x;
    if (idx >= BATCH * 207 * HDIM) return;
    int b = idx / (207 * HDIM);
    int rem = idx - b * 207 * HDIM;
    int r = rem / HDIM, c = rem - r * HDIM;
    hp[idx] = (r == 0 || r == 206) ? 0.f
              : h[((long long)b * NPER + (r - 1)) * HDIM + c];
}

__global__ void k_wt(const float* __restrict__ w, float* __restrict__ wt,
                     int CO, int CI, int KK) {
    int idx = blockIdx.x * blockDim.x + threadIdx.x;
    if (idx >= CO * CI * KK) return;
    int co = idx / (CI * KK);
    int rem = idx - co * CI * KK;
    int ci = rem / KK, k = rem - ci * KK;
    wt[(long long)co * CI * KK + k * CI + ci] = w[idx];
}

// ---------------- fused FC head ----------------
__global__ void k_fc(const float* __restrict__ feats,
                     const float* __restrict__ w1, const float* __restrict__ b1,
                     const float* __restrict__ w2, const float* __restrict__ b2,
                     const float* __restrict__ w3, const float* __restrict__ b3,
                     float* __restrict__ out) {
    int b = blockIdx.x;
    int tid = threadIdx.x;
    int lane = tid & 31, wrp = tid >> 5;
    __shared__ float sf[800];
    __shared__ float s1[256];
    __shared__ float s2[128];
    for (int i = tid; i < 800; i += 256) sf[i] = feats[b * 800 + i];
    __syncthreads();
    for (int jj = 0; jj < 32; jj++) {
        int j = wrp * 32 + jj;
        float a = 0.f;
        for (int i = lane; i < 800; i += 32) a += sf[i] * w1[(long long)j * 800 + i];
        for (int o = 16; o; o >>= 1) a += __shfl_down_sync(0xffffffffu, a, o);
        if (lane == 0) s1[j] = fmaxf(a + b1[j], 0.f);
    }
    __syncthreads();
    if (tid < 128) {
        float a = b2[tid];
        for (int i = 0; i < 256; i++) a += s1[i] * w2[tid * 256 + i];
        s2[tid] = fmaxf(a, 0.f);
    }
    __syncthreads();
    if (tid < 2) {
        float a = b3[tid];
        for (int i = 0; i < 128; i++) a += s2[i] * w3[tid * 128 + i];
        out[b * 2 + tid] = a;
    }
}

// ---------------- launcher ----------------
extern "C" void kernel_launch(void* const* d_in, const int* in_sizes, int n_in,
                              void* d_out, int out_size) {
    const float* x     = (const float*)d_in[0];
    const int*   ei    = (const int*)  d_in[1];
    const int*   ids   = (const int*)  d_in[2];
    const float* etab  = (const float*)d_in[3];
    const float* ggcw  = (const float*)d_in[4];
    const float* wih   = (const float*)d_in[5];
    const float* whh   = (const float*)d_in[6];
    const float* bih   = (const float*)d_in[7];
    const float* bhh   = (const float*)d_in[8];
    const float* c0w   = (const float*)d_in[9];
    const float* c0b   = (const float*)d_in[10];
    const float* c1w   = (const float*)d_in[11];
    const float* c1b   = (const float*)d_in[12];
    const float* c2w   = (const float*)d_in[13];
    const float* c2b   = (const float*)d_in[14];
    const float* c3w   = (const float*)d_in[15];
    const float* c3b   = (const float*)d_in[16];
    const float* f1w   = (const float*)d_in[17];
    const float* f1b   = (const float*)d_in[18];
    const float* f2w   = (const float*)d_in[19];
    const float* f2b   = (const float*)d_in[20];
    const float* f3w   = (const float*)d_in[21];
    const float* f3b   = (const float*)d_in[22];
    float* out = (float*)d_out;

    float *h0, *h1, *mm, *agg, *gi, *gh, *hp, *w0t, *feats;
    int *deg, *rs, *cur, *cs;
    __nv_bfloat16 *ehi, *elo, *w1b, *w2b, *w3b;
    cudaGetSymbolAddress((void**)&h0,   g_h0);
    cudaGetSymbolAddress((void**)&h1,   g_h1);
    cudaGetSymbolAddress((void**)&mm,   g_m);
    cudaGetSymbolAddress((void**)&agg,  g_agg);
    cudaGetSymbolAddress((void**)&gi,   g_gi);
    cudaGetSymbolAddress((void**)&gh,   g_gh);
    cudaGetSymbolAddress((void**)&hp,   g_hp);
    cudaGetSymbolAddress((void**)&w0t,  g_w0t);
    cudaGetSymbolAddress((void**)&feats,g_feats);
    cudaGetSymbolAddress((void**)&deg,  g_deg);
    cudaGetSymbolAddress((void**)&rs,   g_rs);
    cudaGetSymbolAddress((void**)&cur,  g_cur);
    cudaGetSymbolAddress((void**)&cs,   g_csrc);
    cudaGetSymbolAddress((void**)&ehi,  g_ehi);
    cudaGetSymbolAddress((void**)&elo,  g_elo);
    cudaGetSymbolAddress((void**)&w1b,  g_w1b);
    cudaGetSymbolAddress((void**)&w2b,  g_w2b);
    cudaGetSymbolAddress((void**)&w3b,  g_w3b);

    const int CONV_SMEM = 36864 + 59904 + 832 + 832;   // 98432 B
    cudaFuncSetAttribute(conv_hmma_k, cudaFuncAttributeMaxDynamicSharedMemorySize, CONV_SMEM);

    // ---- CSR build ----
    cudaMemsetAsync(deg, 0, N_NODES * sizeof(int));
    k_hist<<<(NEDGE + 255) / 256, 256>>>(ei, deg);
    k_scan<<<1, 1024>>>(deg, rs, cur, N_NODES);
    k_fill<<<(NEDGE + 255) / 256, 256>>>(ei, cur, cs);

    // ---- independent prep ----
    cudaMemcpyAsync(h0, x, (size_t)N_NODES * HDIM * sizeof(float),
                    cudaMemcpyDeviceToDevice);
    k_embed2<<<BATCH * SEQ + 8, 256>>>(ids, etab, ehi, elo);
    k_wt<<<(200 * 200 * 3 + 255) / 256, 256>>>(c0w, w0t, 200, 200, 3);
    k_wsplit<<<(200 * 768 * 3 + 255) / 256, 256>>>(c1w, w1b, 3);
    k_wsplit<<<(200 * 768 * 4 + 255) / 256, 256>>>(c2w, w2b, 4);
    k_wsplit<<<(200 * 768 * 5 + 255) / 256, 256>>>(c3w, w3b, 5);
    cudaMemsetAsync(feats, 0, BATCH * 800 * sizeof(float));

    // ---- gated graph conv: 6 layers (fp32 SIMT) ----
    float* hc = h0;
    float* hn = h1;
    dim3 gM((HDIM + 63) / 64, (N_NODES + 127) / 128, 1);
    dim3 gG((3 * HDIM + 63) / 64, (N_NODES + 127) / 128, 1);
    for (int l = 0; l < NLAYERS; l++) {
        sgemm_k<false, 0><<<gM, 256>>>(hc, HDIM, 0,
                                       ggcw + (long long)l * HDIM * HDIM, nullptr, mm,
                                       N_NODES, HDIM, HDIM, HDIM, 0, 0);
        k_agg<<<(N_NODES + 7) / 8, 256>>>(mm, rs, cs, agg);
        sgemm_k<true, 0><<<gG, 256>>>(agg, HDIM, 0, wih, bih, gi,
                                      N_NODES, 3 * HDIM, HDIM, 3 * HDIM, 0, 0);
        sgemm_k<true, 0><<<gG, 256>>>(hc, HDIM, 0, whh, bhh, gh,
                                      N_NODES, 3 * HDIM, HDIM, 3 * HDIM, 0, 0);
        k_gates<<<(N_NODES * HDIM + 255) / 256, 256>>>(gi, gh, hc, hn);
        float* t = hc; hc = hn; hn = t;
    }

    // ---- conv0 (fp32 SIMT, fused bias+ReLU+max) ----
    k_hp<<<(BATCH * 207 * HDIM + 255) / 256, 256>>>(hc, hp);
    sgemm_k<true, 1><<<dim3(4, 2, BATCH), 256>>>(hp, 200, 207LL * 200, w0t, c0b, feats,
                                                 205, 200, 600, 0, 800, 0);

    // ---- conv1/2/3: HMMA bf16x3 ----
    dim3 gc(1, 4, BATCH);
    conv_hmma_k<<<gc, 256, CONV_SMEM>>>(ehi, elo, w1b, c1b, feats, 510, 3 * 2304, 200);
    conv_hmma_k<<<gc, 256, CONV_SMEM>>>(ehi, elo, w2b, c2b, feats, 509, 3 * 3072, 400);
    conv_hmma_k<<<gc, 256, CONV_SMEM>>>(ehi, elo, w3b, c3b, feats, 508, 3 * 3840, 600);

    // ---- FC head ----
    k_fc<<<BATCH, 256>>>(feats, f1w, f1b, f2w, f2b, f3w, f3b, out);
}

// round 7
// speedup vs baseline: 2.0538x; 1.1991x over previous
#include <cuda_runtime.h>
#include <cuda_bf16.h>
#include <cstdint>

// ---------------- problem constants ----------------
#define N_NODES 26240      // B * N_PER = 128 * 205 (exactly 205 blocks of 128)
#define HDIM    200
#define NEDGE   209920
#define BATCH   128
#define NPER    205
#define EMBD    768
#define SEQ     512
#define NLAYERS 6
#define KPAD    256        // padded K per bf16x3 pass (GGC)

// ---------------- static device scratch ----------------
__device__ float g_h0[N_NODES * HDIM];
__device__ float g_h1[N_NODES * HDIM];
__device__ float g_m [N_NODES * HDIM];
__device__ float g_gi[N_NODES * 3 * HDIM];
__device__ float g_gh[N_NODES * 3 * HDIM];
__device__ float g_hp [BATCH * 207 * HDIM];             // zero-padded conv0 input
__device__ float g_w0t[200 * 600];
__device__ float g_feats[BATCH * 800];
__device__ int   g_deg[N_NODES];
__device__ int   g_rs [N_NODES + 1];
__device__ int   g_cur[N_NODES];
__device__ int   g_csrc[NEDGE];

// GGC bf16 split operands, K-padded to 256 (pads stay zero after init)
__device__ __align__(16) __nv_bfloat16 g_hhi[(size_t)N_NODES * KPAD];
__device__ __align__(16) __nv_bfloat16 g_hlo[(size_t)N_NODES * KPAD];
__device__ __align__(16) __nv_bfloat16 g_ahi[(size_t)N_NODES * KPAD];
__device__ __align__(16) __nv_bfloat16 g_alo[(size_t)N_NODES * KPAD];
// GGC weights expanded: [Npad][768] = [Whi(0:256) | Wlo(256:512) | Whi(512:768)]
__device__ __align__(16) __nv_bfloat16 g_wg[NLAYERS * 208 * 768];   // ggc_w[l]^T
__device__ __align__(16) __nv_bfloat16 g_wi[624 * 768];             // wih
__device__ __align__(16) __nv_bfloat16 g_wh[624 * 768];             // whh

// bf16 hi/lo embeddings, time-major [b][t][c], +8 zero rows for tap overrun
__device__ __align__(16) __nv_bfloat16 g_ehi[((size_t)BATCH * SEQ + 8) * EMBD];
__device__ __align__(16) __nv_bfloat16 g_elo[((size_t)BATCH * SEQ + 8) * EMBD];
// expanded conv weights: [200][3K] = [Whi | Wlo | Whi], K-major per tap
__device__ __align__(16) __nv_bfloat16 g_w1b[200 * 3 * 2304];
__device__ __align__(16) __nv_bfloat16 g_w2b[200 * 3 * 3072];
__device__ __align__(16) __nv_bfloat16 g_w3b[200 * 3 * 3840];

// ---------------- packed fp32x2 helpers (sm_100+) ----------------
#define FMA2(d, a, b) asm("fma.rn.f32x2 %0, %1, %2, %0;" : "+l"(d) : "l"(a), "l"(b))

__device__ __forceinline__ unsigned long long pack2(float x, float y) {
    unsigned long long r;
    asm("mov.b64 %0, {%1, %2};" : "=l"(r) : "r"(__float_as_uint(x)), "r"(__float_as_uint(y)));
    return r;
}

// ---------------- warp-level bf16 MMA (compute_100-safe PTX) ----------------
#define MMA_BF16(d, a, b0, b1) asm volatile(                           \
    "mma.sync.aligned.m16n8k16.row.col.f32.bf16.bf16.f32 "             \
    "{%0,%1,%2,%3}, {%4,%5,%6,%7}, {%8,%9}, {%0,%1,%2,%3};"            \
    : "+f"((d)[0]), "+f"((d)[1]), "+f"((d)[2]), "+f"((d)[3])           \
    : "r"((a)[0]), "r"((a)[1]), "r"((a)[2]), "r"((a)[3]),              \
      "r"(b0), "r"(b1))

// ---------------- GGC GEMM: HMMA bf16x3, plain fp32 store ----------------
// C[M, N] = A @ B^T with A = hi+lo split [M][KPAD], B expanded [Ntiles*208][768].
// grid (n-tiles, m-tiles). 256 threads = 8 warps (4m x 2n). K3 = 768, 12 tiles of 64.
__global__ void __launch_bounds__(256, 1) ggc_hmma_k(
    const __nv_bfloat16* __restrict__ Ahi,
    const __nv_bfloat16* __restrict__ Alo,
    const __nv_bfloat16* __restrict__ B,
    float* __restrict__ C, int N, int ldc)
{
    extern __shared__ __align__(16) char dsm[];
    constexpr int ASTR = 72, BSTR = 72;
    __nv_bfloat16* As = (__nv_bfloat16*)dsm;                 // [2][128][72]
    __nv_bfloat16* Bs = (__nv_bfloat16*)(dsm + 36864);       // [2][208][72]

    const int tid = threadIdx.x;
    const int lane = tid & 31, wid = tid >> 5;
    const int wm = wid & 3, wn = wid >> 2;
    const int g = lane >> 2, t2 = (lane & 3) * 2;
    const int m0 = blockIdx.y * 128;
    const int n0 = blockIdx.x * 208;

    uint4 ra[4], rb[7];
    auto ldg_tile = [&](int kt) {
        const int p = kt >> 2;                    // pass 0,1 -> hi, 2 -> lo
        const int koff = (kt & 3) * 64;
        const __nv_bfloat16* src = (p < 2) ? Ahi : Alo;
#pragma unroll
        for (int i = 0; i < 4; i++) {
            int u = tid + i * 256;                // 1024 x 16B
            int row = u >> 3, ch = u & 7;
            ra[i] = *(const uint4*)(src + (long long)(m0 + row) * KPAD + koff + ch * 8);
        }
        const int kg = kt * 64;
#pragma unroll
        for (int i = 0; i < 7; i++) {
            int u = tid + i * 256;                // 1664 x 16B (208 rows)
            if (u < 1664) {
                int row = u >> 3, ch = u & 7;
                rb[i] = *(const uint4*)(B + (long long)(n0 + row) * 768 + kg + ch * 8);
            }
        }
    };
    auto sts_tile = [&](int buf) {
        __nv_bfloat16* A = As + buf * 128 * ASTR;
        __nv_bfloat16* Bb = Bs + buf * 208 * BSTR;
#pragma unroll
        for (int i = 0; i < 4; i++) {
            int u = tid + i * 256;
            int row = u >> 3, ch = u & 7;
            *(uint4*)(A + row * ASTR + ch * 8) = ra[i];
        }
#pragma unroll
        for (int i = 0; i < 7; i++) {
            int u = tid + i * 256;
            if (u < 1664) {
                int row = u >> 3, ch = u & 7;
                *(uint4*)(Bb + row * BSTR + ch * 8) = rb[i];
            }
        }
    };

    float acc[2][13][4];
#pragma unroll
    for (int i = 0; i < 2; i++)
#pragma unroll
        for (int j = 0; j < 13; j++)
#pragma unroll
            for (int q = 0; q < 4; q++) acc[i][j][q] = 0.f;

    ldg_tile(0);
    sts_tile(0);
    __syncthreads();

#pragma unroll 1
    for (int kt = 0; kt < 12; kt++) {
        const int buf = kt & 1;
        const bool more = (kt + 1 < 12);
        if (more) ldg_tile(kt + 1);

        const __nv_bfloat16* Ab = As + buf * 128 * ASTR;
        const __nv_bfloat16* Bb = Bs + buf * 208 * BSTR;
#pragma unroll
        for (int ks = 0; ks < 4; ks++) {
            const int ko = ks * 16;
            uint32_t a[2][4];
#pragma unroll
            for (int i = 0; i < 2; i++) {
                const int r = wm * 32 + i * 16 + g;
                a[i][0] = *(const uint32_t*)(Ab + (r)     * ASTR + ko + t2);
                a[i][1] = *(const uint32_t*)(Ab + (r + 8) * ASTR + ko + t2);
                a[i][2] = *(const uint32_t*)(Ab + (r)     * ASTR + ko + t2 + 8);
                a[i][3] = *(const uint32_t*)(Ab + (r + 8) * ASTR + ko + t2 + 8);
            }
#pragma unroll
            for (int j = 0; j < 13; j++) {
                const int n = wn * 104 + j * 8 + g;
                uint32_t b0 = *(const uint32_t*)(Bb + n * BSTR + ko + t2);
                uint32_t b1 = *(const uint32_t*)(Bb + n * BSTR + ko + t2 + 8);
                MMA_BF16(acc[0][j], a[0], b0, b1);
                MMA_BF16(acc[1][j], a[1], b0, b1);
            }
        }
        if (more) sts_tile(buf ^ 1);
        __syncthreads();
    }

    // store epilogue (M is always a multiple of 128; guard columns only)
#pragma unroll
    for (int i = 0; i < 2; i++) {
        const int r = m0 + wm * 32 + i * 16 + g;
#pragma unroll
        for (int j = 0; j < 13; j++) {
            const int col = n0 + wn * 104 + j * 8 + t2;
            if (col < N) {
                C[(long long)r * ldc + col]       = acc[i][j][0];
                C[(long long)(r + 8) * ldc + col] = acc[i][j][2];
            }
            if (col + 1 < N) {
                C[(long long)r * ldc + col + 1]       = acc[i][j][1];
                C[(long long)(r + 8) * ldc + col + 1] = acc[i][j][3];
            }
        }
    }
}

// ---------------- conv1/2/3: HMMA bf16x3 conv-as-GEMM ----------------
__global__ void __launch_bounds__(256, 1) conv_hmma_k(
    const __nv_bfloat16* __restrict__ ehi,
    const __nv_bfloat16* __restrict__ elo,
    const __nv_bfloat16* __restrict__ wb,
    const float* __restrict__ bias,
    float* __restrict__ feats,
    int M, int K3, int featOff)
{
    extern __shared__ __align__(16) char dsm[];
    constexpr int ASTR = 72, BSTR = 72;
    __nv_bfloat16* As = (__nv_bfloat16*)dsm;
    __nv_bfloat16* Bs = (__nv_bfloat16*)(dsm + 36864);
    float* smax  = (float*)(dsm + 36864 + 59904);
    float* sbias = smax + 208;

    const int tid = threadIdx.x;
    const int lane = tid & 31, wid = tid >> 5;
    const int wm = wid & 3, wn = wid >> 2;
    const int g = lane >> 2, t2 = (lane & 3) * 2;
    const int b = blockIdx.z, m0 = blockIdx.y * 128;
    const int TK = K3 / 192;
    const int T  = K3 / 64;

    if (tid < 208) { smax[tid] = 0.f; sbias[tid] = (tid < 200) ? bias[tid] : 0.f; }

    uint4 ra[4], rb[7];
    auto ldg_tile = [&](int kt) {
        int p = kt / TK;
        int rem = kt - p * TK;
        int kk = rem / 12;
        int c0 = (rem - kk * 12) * 64;
        const __nv_bfloat16* src = (p < 2) ? ehi : elo;
        long long abase = ((long long)(b * SEQ + m0 + kk)) * EMBD + c0;
#pragma unroll
        for (int i = 0; i < 4; i++) {
            int u = tid + i * 256;
            int row = u >> 3, ch = u & 7;
            ra[i] = *(const uint4*)(src + abase + (long long)row * EMBD + ch * 8);
        }
        int kg = kt * 64;
#pragma unroll
        for (int i = 0; i < 7; i++) {
            int u = tid + i * 256;
            if (u < 1600) {
                int row = u >> 3, ch = u & 7;
                rb[i] = *(const uint4*)(wb + (long long)row * K3 + kg + ch * 8);
            }
        }
    };
    auto sts_tile = [&](int buf) {
        __nv_bfloat16* A = As + buf * 128 * ASTR;
        __nv_bfloat16* B = Bs + buf * 208 * BSTR;
#pragma unroll
        for (int i = 0; i < 4; i++) {
            int u = tid + i * 256;
            int row = u >> 3, ch = u & 7;
            *(uint4*)(A + row * ASTR + ch * 8) = ra[i];
        }
#pragma unroll
        for (int i = 0; i < 7; i++) {
            int u = tid + i * 256;
            if (u < 1600) {
                int row = u >> 3, ch = u & 7;
                *(uint4*)(B + row * BSTR + ch * 8) = rb[i];
            }
        }
    };

    float acc[2][13][4];
#pragma unroll
    for (int i = 0; i < 2; i++)
#pragma unroll
        for (int j = 0; j < 13; j++)
#pragma unroll
            for (int q = 0; q < 4; q++) acc[i][j][q] = 0.f;

    ldg_tile(0);
    sts_tile(0);
    __syncthreads();

#pragma unroll 1
    for (int kt = 0; kt < T; kt++) {
        const int buf = kt & 1;
        const bool more = (kt + 1 < T);
        if (more) ldg_tile(kt + 1);

        const __nv_bfloat16* Ab = As + buf * 128 * ASTR;
        const __nv_bfloat16* Bb = Bs + buf * 208 * BSTR;
#pragma unroll
        for (int ks = 0; ks < 4; ks++) {
            const int ko = ks * 16;
            uint32_t a[2][4];
#pragma unroll
            for (int i = 0; i < 2; i++) {
                const int r = wm * 32 + i * 16 + g;
                a[i][0] = *(const uint32_t*)(Ab + (r)     * ASTR + ko + t2);
                a[i][1] = *(const uint32_t*)(Ab + (r + 8) * ASTR + ko + t2);
                a[i][2] = *(const uint32_t*)(Ab + (r)     * ASTR + ko + t2 + 8);
                a[i][3] = *(const uint32_t*)(Ab + (r + 8) * ASTR + ko + t2 + 8);
            }
#pragma unroll
            for (int j = 0; j < 13; j++) {
                const int n = wn * 104 + j * 8 + g;
                uint32_t b0 = *(const uint32_t*)(Bb + n * BSTR + ko + t2);
                uint32_t b1 = *(const uint32_t*)(Bb + n * BSTR + ko + t2 + 8);
                MMA_BF16(acc[0][j], a[0], b0, b1);
                MMA_BF16(acc[1][j], a[1], b0, b1);
            }
        }
        if (more) sts_tile(buf ^ 1);
        __syncthreads();
    }

    const int valid = (M - m0 < 128) ? (M - m0) : 128;
#pragma unroll
    for (int j = 0; j < 13; j++) {
        float v0 = -1e30f, v1 = -1e30f;
#pragma unroll
        for (int i = 0; i < 2; i++) {
            const int r0 = wm * 32 + i * 16 + g;
            if (r0 < valid)     { v0 = fmaxf(v0, acc[i][j][0]); v1 = fmaxf(v1, acc[i][j][1]); }
            if (r0 + 8 < valid) { v0 = fmaxf(v0, acc[i][j][2]); v1 = fmaxf(v1, acc[i][j][3]); }
        }
#pragma unroll
        for (int o = 4; o <= 16; o <<= 1) {
            v0 = fmaxf(v0, __shfl_xor_sync(~0u, v0, o));
            v1 = fmaxf(v1, __shfl_xor_sync(~0u, v1, o));
        }
        if (g == 0) {
            const int col = wn * 104 + j * 8 + t2;
            if (col < 200) {
                float r = fmaxf(v0 + sbias[col], 0.f);
                atomicMax((unsigned int*)&smax[col], __float_as_uint(r));
            }
            if (col + 1 < 200) {
                float r = fmaxf(v1 + sbias[col + 1], 0.f);
                atomicMax((unsigned int*)&smax[col + 1], __float_as_uint(r));
            }
        }
    }
    __syncthreads();
    if (tid < 200)
        atomicMax((unsigned int*)&feats[(long long)b * 800 + featOff + tid],
                  __float_as_uint(smax[tid]));
}

// ---------------- bf16 split precompute ----------------
__global__ void k_embed2(const int* __restrict__ ids, const float* __restrict__ tbl,
                         __nv_bfloat16* __restrict__ hi, __nv_bfloat16* __restrict__ lo) {
    int row = blockIdx.x;
    long long o = (long long)row * EMBD;
    if (row >= BATCH * SEQ) {
        for (int c = threadIdx.x; c < EMBD; c += 256) {
            hi[o + c] = __float2bfloat16(0.f);
            lo[o + c] = __float2bfloat16(0.f);
        }
        return;
    }
    long long id = ids[row];
    const float* s = tbl + id * EMBD;
    for (int c = threadIdx.x; c < EMBD; c += 256) {
        float x = s[c];
        __nv_bfloat16 h = __float2bfloat16(x);
        hi[o + c] = h;
        lo[o + c] = __float2bfloat16(x - __bfloat162float(h));
    }
}

// w: [200][768][KK] fp32 -> wb: [200][3K] bf16, [Whi | Wlo | Whi], tap-major K
__global__ void k_wsplit(const float* __restrict__ w, __nv_bfloat16* __restrict__ wb, int KK) {
    int K = 768 * KK;
    int idx = blockIdx.x * blockDim.x + threadIdx.x;
    if (idx >= 200 * K) return;
    int co = idx / K, r = idx - co * K;
    int kk = r / 768, ci = r - kk * 768;
    float x = w[(co * 768 + ci) * KK + kk];
    __nv_bfloat16 h = __float2bfloat16(x);
    __nv_bfloat16 l = __float2bfloat16(x - __bfloat162float(h));
    long long base = (long long)co * 3 * K + r;
    wb[base] = h; wb[base + K] = l; wb[base + 2 * K] = h;
}

// ggc_w[l][k][n] -> g_wg[l][208 rows (n)][768 cols]: [Whi|Wlo|Whi] with zero pad
__global__ void k_wggc(const float* __restrict__ w, __nv_bfloat16* __restrict__ out) {
    int idx = blockIdx.x * blockDim.x + threadIdx.x;
    if (idx >= NLAYERS * 208 * 768) return;
    int l = idx / (208 * 768);
    int rem = idx - l * 208 * 768;
    int n = rem / 768, col = rem - n * 768;
    int p = col >> 8, kk = col & 255;
    float x = (n < 200 && kk < 200) ? w[(long long)l * 40000 + kk * 200 + n] : 0.f;
    __nv_bfloat16 h = __float2bfloat16(x);
    out[idx] = (p == 1) ? __float2bfloat16(x - __bfloat162float(h)) : h;
}

// wih/whh [600][200] -> [624][768]: [Whi|Wlo|Whi] with zero pad
__global__ void k_wgru(const float* __restrict__ w, __nv_bfloat16* __restrict__ out) {
    int idx = blockIdx.x * blockDim.x + threadIdx.x;
    if (idx >= 624 * 768) return;
    int n = idx / 768, col = idx - n * 768;
    int p = col >> 8, kk = col & 255;
    float x = (n < 600 && kk < 200) ? w[n * 200 + kk] : 0.f;
    __nv_bfloat16 h = __float2bfloat16(x);
    out[idx] = (p == 1) ? __float2bfloat16(x - __bfloat162float(h)) : h;
}

// x [26240][200] fp32 -> hi/lo [26240][256] bf16 (pads zeroed here, forever)
__global__ void k_xsplit(const float* __restrict__ xin,
                         __nv_bfloat16* __restrict__ hi, __nv_bfloat16* __restrict__ lo) {
    int idx = blockIdx.x * blockDim.x + threadIdx.x;
    if (idx >= N_NODES * KPAD) return;
    int n = idx >> 8, c = idx & 255;
    float x = (c < 200) ? xin[n * HDIM + c] : 0.f;
    __nv_bfloat16 h = __float2bfloat16(x);
    hi[idx] = h;
    lo[idx] = __float2bfloat16(x - __bfloat162float(h));
}

// ---------------- fp32 SIMT GEMM (conv0 only) ----------------
template<bool TB, int EPI>
__global__ void __launch_bounds__(256, 2) sgemm_k(
    const float* __restrict__ A, int lda, long long aStride,
    const float* __restrict__ B,
    const float* __restrict__ bias,
    float* __restrict__ C,
    int M, int N, int K,
    int ldc, int featLd, int featOff)
{
    constexpr int BM = 128, BN = 64, BK = 8;
    __shared__ __align__(16) float As[2][BK][132];
    __shared__ __align__(16) float Bs[2][BK][68];
    __shared__ float red[16][68];

    const int tid = threadIdx.x;
    const int tx = tid & 15, ty = tid >> 4;
    const int m0 = blockIdx.y * BM;
    const int n0 = blockIdx.x * BN;
    const float* Ab = A + (long long)blockIdx.z * aStride;

    const int arow = tid >> 1, akq = (tid & 1) * 4;
    const int bk   = tid >> 5, bn2 = (tid & 31) * 2;
    const int bn   = tid >> 2, bkq = (tid & 3) * 2;

    unsigned long long acc[4][4];
#pragma unroll
    for (int i = 0; i < 4; i++)
#pragma unroll
        for (int j = 0; j < 4; j++) acc[i][j] = 0ULL;

    const int KT = K / BK;

    float4 aR = make_float4(0.f, 0.f, 0.f, 0.f);
    float2 bR = make_float2(0.f, 0.f);
    {
        int row = m0 + arow;
        if (row < M) aR = *(const float4*)(Ab + (long long)row * lda + akq);
        if (!TB) { if (n0 + bn2 < N) bR = *(const float2*)(B + (long long)bk * N + n0 + bn2); }
        else     { if (n0 + bn  < N) bR = *(const float2*)(B + (long long)(n0 + bn) * K + bkq); }
    }
    As[0][akq + 0][arow] = aR.x; As[0][akq + 1][arow] = aR.y;
    As[0][akq + 2][arow] = aR.z; As[0][akq + 3][arow] = aR.w;
    if (!TB) { Bs[0][bk][bn2] = bR.x; Bs[0][bk][bn2 + 1] = bR.y; }
    else     { Bs[0][bkq][bn] = bR.x; Bs[0][bkq + 1][bn] = bR.y; }
    __syncthreads();

    for (int kt = 0; kt < KT; kt++) {
        const int cur = kt & 1;
        const int k0n = (kt + 1) * BK;
        if (kt + 1 < KT) {
            int row = m0 + arow;
            aR = make_float4(0.f, 0.f, 0.f, 0.f);
            bR = make_float2(0.f, 0.f);
            if (row < M) aR = *(const float4*)(Ab + (long long)row * lda + k0n + akq);
            if (!TB) { if (n0 + bn2 < N) bR = *(const float2*)(B + (long long)(k0n + bk) * N + n0 + bn2); }
            else     { if (n0 + bn  < N) bR = *(const float2*)(B + (long long)(n0 + bn) * K + k0n + bkq); }
        }
#pragma unroll
        for (int k = 0; k < BK; k++) {
            const float* ap_ = &As[cur][k][ty * 8];
            ulonglong2 a0 = *(const ulonglong2*)ap_;
            ulonglong2 a1 = *(const ulonglong2*)(ap_ + 4);
            float4 bv = *(const float4*)&Bs[cur][k][tx * 4];
            unsigned long long ap[4] = { a0.x, a0.y, a1.x, a1.y };
            unsigned long long bb[4] = { pack2(bv.x, bv.x), pack2(bv.y, bv.y),
                                         pack2(bv.z, bv.z), pack2(bv.w, bv.w) };
#pragma unroll
            for (int mp = 0; mp < 4; mp++)
#pragma unroll
                for (int j = 0; j < 4; j++)
                    FMA2(acc[mp][j], ap[mp], bb[j]);
        }
        if (kt + 1 < KT) {
            const int nb = cur ^ 1;
            As[nb][akq + 0][arow] = aR.x; As[nb][akq + 1][arow] = aR.y;
            As[nb][akq + 2][arow] = aR.z; As[nb][akq + 3][arow] = aR.w;
            if (!TB) { Bs[nb][bk][bn2] = bR.x; Bs[nb][bk][bn2 + 1] = bR.y; }
            else     { Bs[nb][bkq][bn] = bR.x; Bs[nb][bkq + 1][bn] = bR.y; }
        }
        __syncthreads();
    }

    if (EPI == 0) {
#pragma unroll
        for (int j = 0; j < 4; j++) {
            int col = n0 + tx * 4 + j;
            if (col >= N) continue;
            float bv = bias ? bias[col] : 0.f;
#pragma unroll
            for (int mp = 0; mp < 4; mp++) {
                union { unsigned long long u; float2 f; } cv; cv.u = acc[mp][j];
                int r = m0 + ty * 8 + mp * 2;
                if (r     < M) C[(long long)r * ldc + col]       = cv.f.x + bv;
                if (r + 1 < M) C[(long long)(r + 1) * ldc + col] = cv.f.y + bv;
            }
        }
    } else {
        float cmax[4] = { 0.f, 0.f, 0.f, 0.f };
#pragma unroll
        for (int j = 0; j < 4; j++) {
            int col = n0 + tx * 4 + j;
            float bv = (col < N) ? bias[col] : 0.f;
#pragma unroll
            for (int mp = 0; mp < 4; mp++) {
                union { unsigned long long u; float2 f; } cv; cv.u = acc[mp][j];
                int r = m0 + ty * 8 + mp * 2;
                if (r     < M) cmax[j] = fmaxf(cmax[j], cv.f.x + bv);
                if (r + 1 < M) cmax[j] = fmaxf(cmax[j], cv.f.y + bv);
            }
        }
#pragma unroll
        for (int j = 0; j < 4; j++) red[ty][tx * 4 + j] = cmax[j];
        __syncthreads();
        if (ty == 0) {
#pragma unroll
            for (int j = 0; j < 4; j++) {
                int col = n0 + tx * 4 + j;
                if (col >= N) continue;
                float mx = 0.f;
                for (int t2 = 0; t2 < 16; t2++) mx = fmaxf(mx, red[t2][tx * 4 + j]);
                atomicMax((unsigned int*)&C[(long long)blockIdx.z * featLd + featOff + col],
                          __float_as_uint(mx));
            }
        }
    }
}

// ---------------- CSR build ----------------
__global__ void k_hist(const int* __restrict__ ei, int* __restrict__ deg) {
    int i = blockIdx.x * blockDim.x + threadIdx.x;
    if (i < NEDGE) atomicAdd(&deg[ei[NEDGE + i]], 1);
}

__global__ void k_scan(const int* __restrict__ deg, int* __restrict__ rs,
                       int* __restrict__ cur, int n) {
    __shared__ int s[1024];
    __shared__ int carry;
    int t = threadIdx.x;
    if (t == 0) carry = 0;
    __syncthreads();
    for (int base = 0; base < n; base += 1024) {
        int v = (base + t < n) ? deg[base + t] : 0;
        s[t] = v;
        __syncthreads();
        for (int off = 1; off < 1024; off <<= 1) {
            int add = (t >= off) ? s[t - off] : 0;
            __syncthreads();
            s[t] += add;
            __syncthreads();
        }
        int c0 = carry;
        int ex = c0 + s[t] - v;
        if (base + t < n) { rs[base + t] = ex; cur[base + t] = ex; }
        __syncthreads();
        if (t == 0) carry = c0 + s[1023];
        __syncthreads();
    }
    if (t == 0) rs[n] = carry;
}

__global__ void k_fill(const int* __restrict__ ei, int* __restrict__ cur,
                       int* __restrict__ cs) {
    int i = blockIdx.x * blockDim.x + threadIdx.x;
    if (i < NEDGE) {
        int d = ei[NEDGE + i];
        int p = atomicAdd(&cur[d], 1);
        cs[p] = ei[i];
    }
}

// ---------------- segment-sum + bf16 split of agg ----------------
__global__ void k_agg(const float* __restrict__ m, const int* __restrict__ rs,
                      const int* __restrict__ cs,
                      __nv_bfloat16* __restrict__ ahi, __nv_bfloat16* __restrict__ alo) {
    int w = (blockIdx.x * blockDim.x + threadIdx.x) >> 5;
    int lane = threadIdx.x & 31;
    if (w >= N_NODES) return;
    int s = rs[w], e = rs[w + 1];
    float a[7] = {0, 0, 0, 0, 0, 0, 0};
    int i = s;
    for (; i + 1 < e; i += 2) {
        const float* r0 = m + (long long)cs[i]     * HDIM;
        const float* r1 = m + (long long)cs[i + 1] * HDIM;
        a[0] += r0[lane]       + r1[lane];
        a[1] += r0[lane +  32] + r1[lane +  32];
        a[2] += r0[lane +  64] + r1[lane +  64];
        a[3] += r0[lane +  96] + r1[lane +  96];
        a[4] += r0[lane + 128] + r1[lane + 128];
        a[5] += r0[lane + 160] + r1[lane + 160];
        if (lane < 8) a[6] += r0[lane + 192] + r1[lane + 192];
    }
    if (i < e) {
        const float* r0 = m + (long long)cs[i] * HDIM;
        a[0] += r0[lane];       a[1] += r0[lane + 32];  a[2] += r0[lane + 64];
        a[3] += r0[lane + 96];  a[4] += r0[lane + 128]; a[5] += r0[lane + 160];
        if (lane < 8) a[6] += r0[lane + 192];
    }
    long long o = (long long)w * KPAD + lane;
#pragma unroll
    for (int q = 0; q < 6; q++) {
        __nv_bfloat16 h = __float2bfloat16(a[q]);
        ahi[o + q * 32] = h;
        alo[o + q * 32] = __float2bfloat16(a[q] - __bfloat162float(h));
    }
    if (lane < 8) {
        __nv_bfloat16 h = __float2bfloat16(a[6]);
        ahi[o + 192] = h;
        alo[o + 192] = __float2bfloat16(a[6] - __bfloat162float(h));
    }
}

// ---------------- GRU gates (+ bias fold + bf16 split of new h) ----------------
__global__ void k_gates(const float* __restrict__ gi, const float* __restrict__ gh,
                        const float* __restrict__ bih, const float* __restrict__ bhh,
                        const float* __restrict__ hsrc, float* __restrict__ hdst,
                        __nv_bfloat16* __restrict__ hhi, __nv_bfloat16* __restrict__ hlo) {
    int idx = blockIdx.x * blockDim.x + threadIdx.x;
    if (idx >= N_NODES * HDIM) return;
    int n = idx / HDIM, c = idx - n * HDIM;
    const float* giN = gi + (long long)n * 600;
    const float* ghN = gh + (long long)n * 600;
    float r  = 1.f / (1.f + expf(-(giN[c] + bih[c] + ghN[c] + bhh[c])));
    float z  = 1.f / (1.f + expf(-(giN[200 + c] + bih[200 + c] + ghN[200 + c] + bhh[200 + c])));
    float nn = tanhf(giN[400 + c] + bih[400 + c] + r * (ghN[400 + c] + bhh[400 + c]));
    float h = (1.f - z) * nn + z * hsrc[idx];
    hdst[idx] = h;
    __nv_bfloat16 hb = __float2bfloat16(h);
    long long o = (long long)n * KPAD + c;
    hhi[o] = hb;
    hlo[o] = __float2bfloat16(h - __bfloat162float(hb));
}

// ---------------- misc data movement ----------------
__global__ void k_hp(const float* __restrict__ h, float* __restrict__ hp) {
    int idx = blockIdx.x * blockDim.x + threadIdx.x;
    if (idx >= BATCH * 207 * HDIM) return;
    int b = idx / (207 * HDIM);
    int rem = idx - b * 207 * HDIM;
    int r = rem / HDIM, c = rem - r * HDIM;
    hp[idx] = (r == 0 || r == 206) ? 0.f
              : h[((long long)b * NPER + (r - 1)) * HDIM + c];
}

__global__ void k_wt(const float* __restrict__ w, float* __restrict__ wt,
                     int CO, int CI, int KK) {
    int idx = blockIdx.x * blockDim.x + threadIdx.x;
    if (idx >= CO * CI * KK) return;
    int co = idx / (CI * KK);
    int rem = idx - co * CI * KK;
    int ci = rem / KK, k = rem - ci * KK;
    wt[(long long)co * CI * KK + k * CI + ci] = w[idx];
}

// ---------------- fused FC head ----------------
__global__ void k_fc(const float* __restrict__ feats,
                     const float* __restrict__ w1, const float* __restrict__ b1,
                     const float* __restrict__ w2, const float* __restrict__ b2,
                     const float* __restrict__ w3, const float* __restrict__ b3,
                     float* __restrict__ out) {
    int b = blockIdx.x;
    int tid = threadIdx.x;
    int lane = tid & 31, wrp = tid >> 5;
    __shared__ float sf[800];
    __shared__ float s1[256];
    __shared__ float s2[128];
    for (int i = tid; i < 800; i += 256) sf[i] = feats[b * 800 + i];
    __syncthreads();
    for (int jj = 0; jj < 32; jj++) {
        int j = wrp * 32 + jj;
        float a = 0.f;
        for (int i = lane; i < 800; i += 32) a += sf[i] * w1[(long long)j * 800 + i];
        for (int o = 16; o; o >>= 1) a += __shfl_down_sync(0xffffffffu, a, o);
        if (lane == 0) s1[j] = fmaxf(a + b1[j], 0.f);
    }
    __syncthreads();
    if (tid < 128) {
        float a = b2[tid];
        for (int i = 0; i < 256; i++) a += s1[i] * w2[tid * 256 + i];
        s2[tid] = fmaxf(a, 0.f);
    }
    __syncthreads();
    if (tid < 2) {
        float a = b3[tid];
        for (int i = 0; i < 128; i++) a += s2[i] * w3[tid * 128 + i];
        out[b * 2 + tid] = a;
    }
}

// ---------------- launcher ----------------
extern "C" void kernel_launch(void* const* d_in, const int* in_sizes, int n_in,
                              void* d_out, int out_size) {
    const float* x     = (const float*)d_in[0];
    const int*   ei    = (const int*)  d_in[1];
    const int*   ids   = (const int*)  d_in[2];
    const float* etab  = (const float*)d_in[3];
    const float* ggcw  = (const float*)d_in[4];
    const float* wih   = (const float*)d_in[5];
    const float* whh   = (const float*)d_in[6];
    const float* bih   = (const float*)d_in[7];
    const float* bhh   = (const float*)d_in[8];
    const float* c0w   = (const float*)d_in[9];
    const float* c0b   = (const float*)d_in[10];
    const float* c1w   = (const float*)d_in[11];
    const float* c1b   = (const float*)d_in[12];
    const float* c2w   = (const float*)d_in[13];
    const float* c2b   = (const float*)d_in[14];
    const float* c3w   = (const float*)d_in[15];
    const float* c3b   = (const float*)d_in[16];
    const float* f1w   = (const float*)d_in[17];
    const float* f1b   = (const float*)d_in[18];
    const float* f2w   = (const float*)d_in[19];
    const float* f2b   = (const float*)d_in[20];
    const float* f3w   = (const float*)d_in[21];
    const float* f3b   = (const float*)d_in[22];
    float* out = (float*)d_out;

    float *h0, *h1, *mm, *gi, *gh, *hp, *w0t, *feats;
    int *deg, *rs, *cur, *cs;
    __nv_bfloat16 *ehi, *elo, *w1b, *w2b, *w3b;
    __nv_bfloat16 *hhi, *hlo, *ahi, *alo, *wg, *wi, *wh;
    cudaGetSymbolAddress((void**)&h0,   g_h0);
    cudaGetSymbolAddress((void**)&h1,   g_h1);
    cudaGetSymbolAddress((void**)&mm,   g_m);
    cudaGetSymbolAddress((void**)&gi,   g_gi);
    cudaGetSymbolAddress((void**)&gh,   g_gh);
    cudaGetSymbolAddress((void**)&hp,   g_hp);
    cudaGetSymbolAddress((void**)&w0t,  g_w0t);
    cudaGetSymbolAddress((void**)&feats,g_feats);
    cudaGetSymbolAddress((void**)&deg,  g_deg);
    cudaGetSymbolAddress((void**)&rs,   g_rs);
    cudaGetSymbolAddress((void**)&cur,  g_cur);
    cudaGetSymbolAddress((void**)&cs,   g_csrc);
    cudaGetSymbolAddress((void**)&ehi,  g_ehi);
    cudaGetSymbolAddress((void**)&elo,  g_elo);
    cudaGetSymbolAddress((void**)&w1b,  g_w1b);
    cudaGetSymbolAddress((void**)&w2b,  g_w2b);
    cudaGetSymbolAddress((void**)&w3b,  g_w3b);
    cudaGetSymbolAddress((void**)&hhi,  g_hhi);
    cudaGetSymbolAddress((void**)&hlo,  g_hlo);
    cudaGetSymbolAddress((void**)&ahi,  g_ahi);
    cudaGetSymbolAddress((void**)&alo,  g_alo);
    cudaGetSymbolAddress((void**)&wg,   g_wg);
    cudaGetSymbolAddress((void**)&wi,   g_wi);
    cudaGetSymbolAddress((void**)&wh,   g_wh);

    const int CONV_SMEM = 36864 + 59904 + 832 + 832;   // 98432 B
    const int GGC_SMEM  = 36864 + 59904;               // 96768 B
    cudaFuncSetAttribute(conv_hmma_k, cudaFuncAttributeMaxDynamicSharedMemorySize, CONV_SMEM);
    cudaFuncSetAttribute(ggc_hmma_k,  cudaFuncAttributeMaxDynamicSharedMemorySize, GGC_SMEM);

    // ---- CSR build ----
    cudaMemsetAsync(deg, 0, N_NODES * sizeof(int));
    k_hist<<<(NEDGE + 255) / 256, 256>>>(ei, deg);
    k_scan<<<1, 1024>>>(deg, rs, cur, N_NODES);
    k_fill<<<(NEDGE + 255) / 256, 256>>>(ei, cur, cs);

    // ---- independent prep ----
    cudaMemcpyAsync(h0, x, (size_t)N_NODES * HDIM * sizeof(float),
                    cudaMemcpyDeviceToDevice);
    k_xsplit<<<(N_NODES * KPAD + 255) / 256, 256>>>(x, hhi, hlo);
    k_wggc<<<(NLAYERS * 208 * 768 + 255) / 256, 256>>>(ggcw, wg);
    k_wgru<<<(624 * 768 + 255) / 256, 256>>>(wih, wi);
    k_wgru<<<(624 * 768 + 255) / 256, 256>>>(whh, wh);
    k_embed2<<<BATCH * SEQ + 8, 256>>>(ids, etab, ehi, elo);
    k_wt<<<(200 * 200 * 3 + 255) / 256, 256>>>(c0w, w0t, 200, 200, 3);
    k_wsplit<<<(200 * 768 * 3 + 255) / 256, 256>>>(c1w, w1b, 3);
    k_wsplit<<<(200 * 768 * 4 + 255) / 256, 256>>>(c2w, w2b, 4);
    k_wsplit<<<(200 * 768 * 5 + 255) / 256, 256>>>(c3w, w3b, 5);
    cudaMemsetAsync(feats, 0, BATCH * 800 * sizeof(float));

    // ---- gated graph conv: 6 layers (HMMA bf16x3) ----
    float* hc = h0;
    float* hn = h1;
    for (int l = 0; l < NLAYERS; l++) {
        // m = h @ ggc_w[l]
        ggc_hmma_k<<<dim3(1, NPER), 256, GGC_SMEM>>>(hhi, hlo, wg + (long long)l * 208 * 768,
                                                     mm, HDIM, HDIM);
        // agg = segment_sum(m[src], dst), split to bf16
        k_agg<<<(N_NODES + 7) / 8, 256>>>(mm, rs, cs, ahi, alo);
        // gi = agg @ wih^T ; gh = h @ whh^T
        ggc_hmma_k<<<dim3(3, NPER), 256, GGC_SMEM>>>(ahi, alo, wi, gi, 600, 600);
        ggc_hmma_k<<<dim3(3, NPER), 256, GGC_SMEM>>>(hhi, hlo, wh, gh, 600, 600);
        // GRU update (+bias fold) and re-split h
        k_gates<<<(N_NODES * HDIM + 255) / 256, 256>>>(gi, gh, bih, bhh, hc, hn, hhi, hlo);
        float* t = hc; hc = hn; hn = t;
    }

    // ---- conv0 (fp32 SIMT, fused bias+ReLU+max) ----
    k_hp<<<(BATCH * 207 * HDIM + 255) / 256, 256>>>(hc, hp);
    sgemm_k<true, 1><<<dim3(4, 2, BATCH), 256>>>(hp, 200, 207LL * 200, w0t, c0b, feats,
                                                 205, 200, 600, 0, 800, 0);

    // ---- conv1/2/3: HMMA bf16x3 ----
    dim3 gc(1, 4, BATCH);
    conv_hmma_k<<<gc, 256, CONV_SMEM>>>(ehi, elo, w1b, c1b, feats, 510, 3 * 2304, 200);
    conv_hmma_k<<<gc, 256, CONV_SMEM>>>(ehi, elo, w2b, c2b, feats, 509, 3 * 3072, 400);
    conv_hmma_k<<<gc, 256, CONV_SMEM>>>(ehi, elo, w3b, c3b, feats, 508, 3 * 3840, 600);

    // ---- FC head ----
    k_fc<<<BATCH, 256>>>(feats, f1w, f1b, f2w, f2b, f3w, f3b, out);
}

// round 8
// speedup vs baseline: 2.3400x; 1.1394x over previous
#include <cuda_runtime.h>
#include <cuda_bf16.h>
#include <cstdint>

// ---------------- problem constants ----------------
#define N_NODES 26240      // B * N_PER = 128 * 205 (exactly 205 blocks of 128)
#define HDIM    200
#define NEDGE   209920
#define BATCH   128
#define NPER    205
#define EMBD    768
#define SEQ     512
#define NLAYERS 6
#define KPAD    256        // padded K per bf16x3 pass (GGC)

// ---------------- static device scratch ----------------
__device__ float g_h0[N_NODES * HDIM];
__device__ float g_h1[N_NODES * HDIM];
__device__ float g_m [N_NODES * HDIM];
__device__ float g_gi[N_NODES * 3 * HDIM];
__device__ float g_gh[N_NODES * 3 * HDIM];
__device__ float g_hp [BATCH * 207 * HDIM];             // zero-padded conv0 input
__device__ float g_w0t[200 * 600];
__device__ float g_feats[BATCH * 800];
__device__ int   g_deg[N_NODES];
__device__ int   g_rs [N_NODES + 1];
__device__ int   g_cur[N_NODES];
__device__ int   g_csrc[NEDGE];

// GGC bf16 split operands, K-padded to 256 (pads stay zero after init)
__device__ __align__(16) __nv_bfloat16 g_hhi[(size_t)N_NODES * KPAD];
__device__ __align__(16) __nv_bfloat16 g_hlo[(size_t)N_NODES * KPAD];
__device__ __align__(16) __nv_bfloat16 g_ahi[(size_t)N_NODES * KPAD];
__device__ __align__(16) __nv_bfloat16 g_alo[(size_t)N_NODES * KPAD];
// GGC weights expanded: [Npad][768] = [Whi(0:256) | Wlo(256:512) | Whi(512:768)]
__device__ __align__(16) __nv_bfloat16 g_wg[NLAYERS * 208 * 768];   // ggc_w[l]^T
__device__ __align__(16) __nv_bfloat16 g_wi[624 * 768];             // wih
__device__ __align__(16) __nv_bfloat16 g_wh[624 * 768];             // whh

// bf16 hi/lo embeddings, time-major [b][t][c], +8 zero rows for tap overrun
__device__ __align__(16) __nv_bfloat16 g_ehi[((size_t)BATCH * SEQ + 8) * EMBD];
__device__ __align__(16) __nv_bfloat16 g_elo[((size_t)BATCH * SEQ + 8) * EMBD];
// expanded conv weights: [200][3K] = [Whi | Wlo | Whi], K-major per tap
__device__ __align__(16) __nv_bfloat16 g_w1b[200 * 3 * 2304];
__device__ __align__(16) __nv_bfloat16 g_w2b[200 * 3 * 3072];
__device__ __align__(16) __nv_bfloat16 g_w3b[200 * 3 * 3840];

// ---------------- packed fp32x2 helpers (sm_100+) ----------------
#define FMA2(d, a, b) asm("fma.rn.f32x2 %0, %1, %2, %0;" : "+l"(d) : "l"(a), "l"(b))

__device__ __forceinline__ unsigned long long pack2(float x, float y) {
    unsigned long long r;
    asm("mov.b64 %0, {%1, %2};" : "=l"(r) : "r"(__float_as_uint(x)), "r"(__float_as_uint(y)));
    return r;
}

// ---------------- warp-level bf16 MMA (compute_100-safe PTX) ----------------
#define MMA_BF16(d, a, b0, b1) asm volatile(                           \
    "mma.sync.aligned.m16n8k16.row.col.f32.bf16.bf16.f32 "             \
    "{%0,%1,%2,%3}, {%4,%5,%6,%7}, {%8,%9}, {%0,%1,%2,%3};"            \
    : "+f"((d)[0]), "+f"((d)[1]), "+f"((d)[2]), "+f"((d)[3])           \
    : "r"((a)[0]), "r"((a)[1]), "r"((a)[2]), "r"((a)[3]),              \
      "r"(b0), "r"(b1))

// ---------------- shared HMMA mainloop body (macro-free via inline fn) ----------
// Computes acc += A_tile @ B_tile^T over 12*passes K-tiles with double buffering.
// ldg/sts are provided by the caller through lambdas.

// ---------------- GGC GEMM: gi = agg @ wih^T ----------------
// grid (3 n-tiles, 205 m-tiles). 256 threads = 8 warps (4m x 2n). K3 = 768.
__global__ void __launch_bounds__(256, 1) ggc_hmma_k(
    const __nv_bfloat16* __restrict__ Ahi,
    const __nv_bfloat16* __restrict__ Alo,
    const __nv_bfloat16* __restrict__ B,
    float* __restrict__ C, int N, int ldc)
{
    extern __shared__ __align__(16) char dsm[];
    constexpr int ASTR = 72, BSTR = 72;
    __nv_bfloat16* As = (__nv_bfloat16*)dsm;                 // [2][128][72]
    __nv_bfloat16* Bs = (__nv_bfloat16*)(dsm + 36864);       // [2][208][72]

    const int tid = threadIdx.x;
    const int lane = tid & 31, wid = tid >> 5;
    const int wm = wid & 3, wn = wid >> 2;
    const int g = lane >> 2, t2 = (lane & 3) * 2;
    const int m0 = blockIdx.y * 128;
    const int n0 = blockIdx.x * 208;

    uint4 ra[4], rb[7];
    auto ldg_tile = [&](int kt) {
        const int p = kt >> 2;
        const int koff = (kt & 3) * 64;
        const __nv_bfloat16* src = (p < 2) ? Ahi : Alo;
#pragma unroll
        for (int i = 0; i < 4; i++) {
            int u = tid + i * 256;
            int row = u >> 3, ch = u & 7;
            ra[i] = *(const uint4*)(src + (long long)(m0 + row) * KPAD + koff + ch * 8);
        }
        const int kg = kt * 64;
#pragma unroll
        for (int i = 0; i < 7; i++) {
            int u = tid + i * 256;
            if (u < 1664) {
                int row = u >> 3, ch = u & 7;
                rb[i] = *(const uint4*)(B + (long long)(n0 + row) * 768 + kg + ch * 8);
            }
        }
    };
    auto sts_tile = [&](int buf) {
        __nv_bfloat16* A = As + buf * 128 * ASTR;
        __nv_bfloat16* Bb = Bs + buf * 208 * BSTR;
#pragma unroll
        for (int i = 0; i < 4; i++) {
            int u = tid + i * 256;
            int row = u >> 3, ch = u & 7;
            *(uint4*)(A + row * ASTR + ch * 8) = ra[i];
        }
#pragma unroll
        for (int i = 0; i < 7; i++) {
            int u = tid + i * 256;
            if (u < 1664) {
                int row = u >> 3, ch = u & 7;
                *(uint4*)(Bb + row * BSTR + ch * 8) = rb[i];
            }
        }
    };

    float acc[2][13][4];
#pragma unroll
    for (int i = 0; i < 2; i++)
#pragma unroll
        for (int j = 0; j < 13; j++)
#pragma unroll
            for (int q = 0; q < 4; q++) acc[i][j][q] = 0.f;

    ldg_tile(0);
    sts_tile(0);
    __syncthreads();

#pragma unroll 1
    for (int kt = 0; kt < 12; kt++) {
        const int buf = kt & 1;
        const bool more = (kt + 1 < 12);
        if (more) ldg_tile(kt + 1);

        const __nv_bfloat16* Ab = As + buf * 128 * ASTR;
        const __nv_bfloat16* Bb = Bs + buf * 208 * BSTR;
#pragma unroll
        for (int ks = 0; ks < 4; ks++) {
            const int ko = ks * 16;
            uint32_t a[2][4];
#pragma unroll
            for (int i = 0; i < 2; i++) {
                const int r = wm * 32 + i * 16 + g;
                a[i][0] = *(const uint32_t*)(Ab + (r)     * ASTR + ko + t2);
                a[i][1] = *(const uint32_t*)(Ab + (r + 8) * ASTR + ko + t2);
                a[i][2] = *(const uint32_t*)(Ab + (r)     * ASTR + ko + t2 + 8);
                a[i][3] = *(const uint32_t*)(Ab + (r + 8) * ASTR + ko + t2 + 8);
            }
#pragma unroll
            for (int j = 0; j < 13; j++) {
                const int n = wn * 104 + j * 8 + g;
                uint32_t b0 = *(const uint32_t*)(Bb + n * BSTR + ko + t2);
                uint32_t b1 = *(const uint32_t*)(Bb + n * BSTR + ko + t2 + 8);
                MMA_BF16(acc[0][j], a[0], b0, b1);
                MMA_BF16(acc[1][j], a[1], b0, b1);
            }
        }
        if (more) sts_tile(buf ^ 1);
        __syncthreads();
    }

#pragma unroll
    for (int i = 0; i < 2; i++) {
        const int r = m0 + wm * 32 + i * 16 + g;
#pragma unroll
        for (int j = 0; j < 13; j++) {
            const int col = n0 + wn * 104 + j * 8 + t2;
            if (col < N) {
                C[(long long)r * ldc + col]       = acc[i][j][0];
                C[(long long)(r + 8) * ldc + col] = acc[i][j][2];
            }
            if (col + 1 < N) {
                C[(long long)r * ldc + col + 1]       = acc[i][j][1];
                C[(long long)(r + 8) * ldc + col + 1] = acc[i][j][3];
            }
        }
    }
}

// ---------------- fused m + gh GEMM (same A = h) ----------------
// grid (4, 205): bx==0 -> m = h @ ggc_w[l] (N=200); bx in 1..3 -> gh slice.
__global__ void __launch_bounds__(256, 1) ggc_mh_k(
    const __nv_bfloat16* __restrict__ Ahi,
    const __nv_bfloat16* __restrict__ Alo,
    const __nv_bfloat16* __restrict__ wgl,    // [208][768] layer slice
    const __nv_bfloat16* __restrict__ wh,     // [624][768]
    float* __restrict__ Cm,
    float* __restrict__ Cg)
{
    extern __shared__ __align__(16) char dsm[];
    constexpr int ASTR = 72, BSTR = 72;
    __nv_bfloat16* As = (__nv_bfloat16*)dsm;
    __nv_bfloat16* Bs = (__nv_bfloat16*)(dsm + 36864);

    const int tid = threadIdx.x;
    const int lane = tid & 31, wid = tid >> 5;
    const int wm = wid & 3, wn = wid >> 2;
    const int g = lane >> 2, t2 = (lane & 3) * 2;
    const int m0 = blockIdx.y * 128;
    const int bx = blockIdx.x;

    const __nv_bfloat16* B = (bx == 0) ? wgl : (wh + (long long)(bx - 1) * 208 * 768);
    float* C      = (bx == 0) ? Cm  : Cg;
    const int ldc = (bx == 0) ? 200 : 600;
    const int N   = (bx == 0) ? 200 : 600;
    const int cb  = (bx == 0) ? 0   : (bx - 1) * 208;

    uint4 ra[4], rb[7];
    auto ldg_tile = [&](int kt) {
        const int p = kt >> 2;
        const int koff = (kt & 3) * 64;
        const __nv_bfloat16* src = (p < 2) ? Ahi : Alo;
#pragma unroll
        for (int i = 0; i < 4; i++) {
            int u = tid + i * 256;
            int row = u >> 3, ch = u & 7;
            ra[i] = *(const uint4*)(src + (long long)(m0 + row) * KPAD + koff + ch * 8);
        }
        const int kg = kt * 64;
#pragma unroll
        for (int i = 0; i < 7; i++) {
            int u = tid + i * 256;
            if (u < 1664) {
                int row = u >> 3, ch = u & 7;
                rb[i] = *(const uint4*)(B + (long long)row * 768 + kg + ch * 8);
            }
        }
    };
    auto sts_tile = [&](int buf) {
        __nv_bfloat16* A = As + buf * 128 * ASTR;
        __nv_bfloat16* Bb = Bs + buf * 208 * BSTR;
#pragma unroll
        for (int i = 0; i < 4; i++) {
            int u = tid + i * 256;
            int row = u >> 3, ch = u & 7;
            *(uint4*)(A + row * ASTR + ch * 8) = ra[i];
        }
#pragma unroll
        for (int i = 0; i < 7; i++) {
            int u = tid + i * 256;
            if (u < 1664) {
                int row = u >> 3, ch = u & 7;
                *(uint4*)(Bb + row * BSTR + ch * 8) = rb[i];
            }
        }
    };

    float acc[2][13][4];
#pragma unroll
    for (int i = 0; i < 2; i++)
#pragma unroll
        for (int j = 0; j < 13; j++)
#pragma unroll
            for (int q = 0; q < 4; q++) acc[i][j][q] = 0.f;

    ldg_tile(0);
    sts_tile(0);
    __syncthreads();

#pragma unroll 1
    for (int kt = 0; kt < 12; kt++) {
        const int buf = kt & 1;
        const bool more = (kt + 1 < 12);
        if (more) ldg_tile(kt + 1);

        const __nv_bfloat16* Ab = As + buf * 128 * ASTR;
        const __nv_bfloat16* Bb = Bs + buf * 208 * BSTR;
#pragma unroll
        for (int ks = 0; ks < 4; ks++) {
            const int ko = ks * 16;
            uint32_t a[2][4];
#pragma unroll
            for (int i = 0; i < 2; i++) {
                const int r = wm * 32 + i * 16 + g;
                a[i][0] = *(const uint32_t*)(Ab + (r)     * ASTR + ko + t2);
                a[i][1] = *(const uint32_t*)(Ab + (r + 8) * ASTR + ko + t2);
                a[i][2] = *(const uint32_t*)(Ab + (r)     * ASTR + ko + t2 + 8);
                a[i][3] = *(const uint32_t*)(Ab + (r + 8) * ASTR + ko + t2 + 8);
            }
#pragma unroll
            for (int j = 0; j < 13; j++) {
                const int n = wn * 104 + j * 8 + g;
                uint32_t b0 = *(const uint32_t*)(Bb + n * BSTR + ko + t2);
                uint32_t b1 = *(const uint32_t*)(Bb + n * BSTR + ko + t2 + 8);
                MMA_BF16(acc[0][j], a[0], b0, b1);
                MMA_BF16(acc[1][j], a[1], b0, b1);
            }
        }
        if (more) sts_tile(buf ^ 1);
        __syncthreads();
    }

#pragma unroll
    for (int i = 0; i < 2; i++) {
        const int r = m0 + wm * 32 + i * 16 + g;
#pragma unroll
        for (int j = 0; j < 13; j++) {
            const int col = cb + wn * 104 + j * 8 + t2;
            if (col < N) {
                C[(long long)r * ldc + col]       = acc[i][j][0];
                C[(long long)(r + 8) * ldc + col] = acc[i][j][2];
            }
            if (col + 1 < N) {
                C[(long long)r * ldc + col + 1]       = acc[i][j][1];
                C[(long long)(r + 8) * ldc + col + 1] = acc[i][j][3];
            }
        }
    }
}

// ---------------- fused conv1/2/3: HMMA bf16x3 conv-as-GEMM ----------------
struct Conv3Args {
    const __nv_bfloat16* wb[3];
    const float* bias[3];
};
// grid (3 convs, 4 m-tiles, 128 batches)
__global__ void __launch_bounds__(256, 1) conv3x_hmma_k(
    const __nv_bfloat16* __restrict__ ehi,
    const __nv_bfloat16* __restrict__ elo,
    Conv3Args args,
    float* __restrict__ feats)
{
    extern __shared__ __align__(16) char dsm[];
    constexpr int ASTR = 72, BSTR = 72;
    __nv_bfloat16* As = (__nv_bfloat16*)dsm;
    __nv_bfloat16* Bs = (__nv_bfloat16*)(dsm + 36864);
    float* smax  = (float*)(dsm + 36864 + 59904);
    float* sbias = smax + 208;

    const int cid = blockIdx.x;
    const int M   = (cid == 0) ? 510 : (cid == 1) ? 509 : 508;
    const int K3  = (cid == 0) ? 6912 : (cid == 1) ? 9216 : 11520;
    const int featOff = 200 + cid * 200;
    const __nv_bfloat16* wb = args.wb[cid];
    const float* bias = args.bias[cid];

    const int tid = threadIdx.x;
    const int lane = tid & 31, wid = tid >> 5;
    const int wm = wid & 3, wn = wid >> 2;
    const int g = lane >> 2, t2 = (lane & 3) * 2;
    const int b = blockIdx.z, m0 = blockIdx.y * 128;
    const int TK = K3 / 192;
    const int T  = K3 / 64;

    if (tid < 208) { smax[tid] = 0.f; sbias[tid] = (tid < 200) ? bias[tid] : 0.f; }

    uint4 ra[4], rb[7];
    auto ldg_tile = [&](int kt) {
        int p = kt / TK;
        int rem = kt - p * TK;
        int kk = rem / 12;
        int c0 = (rem - kk * 12) * 64;
        const __nv_bfloat16* src = (p < 2) ? ehi : elo;
        long long abase = ((long long)(b * SEQ + m0 + kk)) * EMBD + c0;
#pragma unroll
        for (int i = 0; i < 4; i++) {
            int u = tid + i * 256;
            int row = u >> 3, ch = u & 7;
            ra[i] = *(const uint4*)(src + abase + (long long)row * EMBD + ch * 8);
        }
        int kg = kt * 64;
#pragma unroll
        for (int i = 0; i < 7; i++) {
            int u = tid + i * 256;
            if (u < 1600) {
                int row = u >> 3, ch = u & 7;
                rb[i] = *(const uint4*)(wb + (long long)row * K3 + kg + ch * 8);
            }
        }
    };
    auto sts_tile = [&](int buf) {
        __nv_bfloat16* A = As + buf * 128 * ASTR;
        __nv_bfloat16* B = Bs + buf * 208 * BSTR;
#pragma unroll
        for (int i = 0; i < 4; i++) {
            int u = tid + i * 256;
            int row = u >> 3, ch = u & 7;
            *(uint4*)(A + row * ASTR + ch * 8) = ra[i];
        }
#pragma unroll
        for (int i = 0; i < 7; i++) {
            int u = tid + i * 256;
            if (u < 1600) {
                int row = u >> 3, ch = u & 7;
                *(uint4*)(B + row * BSTR + ch * 8) = rb[i];
            }
        }
    };

    float acc[2][13][4];
#pragma unroll
    for (int i = 0; i < 2; i++)
#pragma unroll
        for (int j = 0; j < 13; j++)
#pragma unroll
            for (int q = 0; q < 4; q++) acc[i][j][q] = 0.f;

    ldg_tile(0);
    sts_tile(0);
    __syncthreads();

#pragma unroll 1
    for (int kt = 0; kt < T; kt++) {
        const int buf = kt & 1;
        const bool more = (kt + 1 < T);
        if (more) ldg_tile(kt + 1);

        const __nv_bfloat16* Ab = As + buf * 128 * ASTR;
        const __nv_bfloat16* Bb = Bs + buf * 208 * BSTR;
#pragma unroll
        for (int ks = 0; ks < 4; ks++) {
            const int ko = ks * 16;
            uint32_t a[2][4];
#pragma unroll
            for (int i = 0; i < 2; i++) {
                const int r = wm * 32 + i * 16 + g;
                a[i][0] = *(const uint32_t*)(Ab + (r)     * ASTR + ko + t2);
                a[i][1] = *(const uint32_t*)(Ab + (r + 8) * ASTR + ko + t2);
                a[i][2] = *(const uint32_t*)(Ab + (r)     * ASTR + ko + t2 + 8);
                a[i][3] = *(const uint32_t*)(Ab + (r + 8) * ASTR + ko + t2 + 8);
            }
#pragma unroll
            for (int j = 0; j < 13; j++) {
                const int n = wn * 104 + j * 8 + g;
                uint32_t b0 = *(const uint32_t*)(Bb + n * BSTR + ko + t2);
                uint32_t b1 = *(const uint32_t*)(Bb + n * BSTR + ko + t2 + 8);
                MMA_BF16(acc[0][j], a[0], b0, b1);
                MMA_BF16(acc[1][j], a[1], b0, b1);
            }
        }
        if (more) sts_tile(buf ^ 1);
        __syncthreads();
    }

    const int valid = (M - m0 < 128) ? (M - m0) : 128;
#pragma unroll
    for (int j = 0; j < 13; j++) {
        float v0 = -1e30f, v1 = -1e30f;
#pragma unroll
        for (int i = 0; i < 2; i++) {
            const int r0 = wm * 32 + i * 16 + g;
            if (r0 < valid)     { v0 = fmaxf(v0, acc[i][j][0]); v1 = fmaxf(v1, acc[i][j][1]); }
            if (r0 + 8 < valid) { v0 = fmaxf(v0, acc[i][j][2]); v1 = fmaxf(v1, acc[i][j][3]); }
        }
#pragma unroll
        for (int o = 4; o <= 16; o <<= 1) {
            v0 = fmaxf(v0, __shfl_xor_sync(~0u, v0, o));
            v1 = fmaxf(v1, __shfl_xor_sync(~0u, v1, o));
        }
        if (g == 0) {
            const int col = wn * 104 + j * 8 + t2;
            if (col < 200) {
                float r = fmaxf(v0 + sbias[col], 0.f);
                atomicMax((unsigned int*)&smax[col], __float_as_uint(r));
            }
            if (col + 1 < 200) {
                float r = fmaxf(v1 + sbias[col + 1], 0.f);
                atomicMax((unsigned int*)&smax[col + 1], __float_as_uint(r));
            }
        }
    }
    __syncthreads();
    if (tid < 200)
        atomicMax((unsigned int*)&feats[(long long)b * 800 + featOff + tid],
                  __float_as_uint(smax[tid]));
}

// ---------------- bf16 split precompute ----------------
__global__ void k_embed2(const int* __restrict__ ids, const float* __restrict__ tbl,
                         __nv_bfloat16* __restrict__ hi, __nv_bfloat16* __restrict__ lo) {
    int row = blockIdx.x;
    long long o = (long long)row * EMBD;
    if (row >= BATCH * SEQ) {
        for (int c = threadIdx.x; c < EMBD; c += 256) {
            hi[o + c] = __float2bfloat16(0.f);
            lo[o + c] = __float2bfloat16(0.f);
        }
        return;
    }
    long long id = ids[row];
    const float* s = tbl + id * EMBD;
    for (int c = threadIdx.x; c < EMBD; c += 256) {
        float x = s[c];
        __nv_bfloat16 h = __float2bfloat16(x);
        hi[o + c] = h;
        lo[o + c] = __float2bfloat16(x - __bfloat162float(h));
    }
}

__global__ void k_wsplit(const float* __restrict__ w, __nv_bfloat16* __restrict__ wb, int KK) {
    int K = 768 * KK;
    int idx = blockIdx.x * blockDim.x + threadIdx.x;
    if (idx >= 200 * K) return;
    int co = idx / K, r = idx - co * K;
    int kk = r / 768, ci = r - kk * 768;
    float x = w[(co * 768 + ci) * KK + kk];
    __nv_bfloat16 h = __float2bfloat16(x);
    __nv_bfloat16 l = __float2bfloat16(x - __bfloat162float(h));
    long long base = (long long)co * 3 * K + r;
    wb[base] = h; wb[base + K] = l; wb[base + 2 * K] = h;
}

__global__ void k_wggc(const float* __restrict__ w, __nv_bfloat16* __restrict__ out) {
    int idx = blockIdx.x * blockDim.x + threadIdx.x;
    if (idx >= NLAYERS * 208 * 768) return;
    int l = idx / (208 * 768);
    int rem = idx - l * 208 * 768;
    int n = rem / 768, col = rem - n * 768;
    int p = col >> 8, kk = col & 255;
    float x = (n < 200 && kk < 200) ? w[(long long)l * 40000 + kk * 200 + n] : 0.f;
    __nv_bfloat16 h = __float2bfloat16(x);
    out[idx] = (p == 1) ? __float2bfloat16(x - __bfloat162float(h)) : h;
}

__global__ void k_wgru(const float* __restrict__ w, __nv_bfloat16* __restrict__ out) {
    int idx = blockIdx.x * blockDim.x + threadIdx.x;
    if (idx >= 624 * 768) return;
    int n = idx / 768, col = idx - n * 768;
    int p = col >> 8, kk = col & 255;
    float x = (n < 600 && kk < 200) ? w[n * 200 + kk] : 0.f;
    __nv_bfloat16 h = __float2bfloat16(x);
    out[idx] = (p == 1) ? __float2bfloat16(x - __bfloat162float(h)) : h;
}

__global__ void k_xsplit(const float* __restrict__ xin,
                         __nv_bfloat16* __restrict__ hi, __nv_bfloat16* __restrict__ lo) {
    int idx = blockIdx.x * blockDim.x + threadIdx.x;
    if (idx >= N_NODES * KPAD) return;
    int n = idx >> 8, c = idx & 255;
    float x = (c < 200) ? xin[n * HDIM + c] : 0.f;
    __nv_bfloat16 h = __float2bfloat16(x);
    hi[idx] = h;
    lo[idx] = __float2bfloat16(x - __bfloat162float(h));
}

// ---------------- fp32 SIMT GEMM (conv0 only) ----------------
template<bool TB, int EPI>
__global__ void __launch_bounds__(256, 2) sgemm_k(
    const float* __restrict__ A, int lda, long long aStride,
    const float* __restrict__ B,
    const float* __restrict__ bias,
    float* __restrict__ C,
    int M, int N, int K,
    int ldc, int featLd, int featOff)
{
    constexpr int BM = 128, BN = 64, BK = 8;
    __shared__ __align__(16) float As[2][BK][132];
    __shared__ __align__(16) float Bs[2][BK][68];
    __shared__ float red[16][68];

    const int tid = threadIdx.x;
    const int tx = tid & 15, ty = tid >> 4;
    const int m0 = blockIdx.y * BM;
    const int n0 = blockIdx.x * BN;
    const float* Ab = A + (long long)blockIdx.z * aStride;

    const int arow = tid >> 1, akq = (tid & 1) * 4;
    const int bk   = tid >> 5, bn2 = (tid & 31) * 2;
    const int bn   = tid >> 2, bkq = (tid & 3) * 2;

    unsigned long long acc[4][4];
#pragma unroll
    for (int i = 0; i < 4; i++)
#pragma unroll
        for (int j = 0; j < 4; j++) acc[i][j] = 0ULL;

    const int KT = K / BK;

    float4 aR = make_float4(0.f, 0.f, 0.f, 0.f);
    float2 bR = make_float2(0.f, 0.f);
    {
        int row = m0 + arow;
        if (row < M) aR = *(const float4*)(Ab + (long long)row * lda + akq);
        if (!TB) { if (n0 + bn2 < N) bR = *(const float2*)(B + (long long)bk * N + n0 + bn2); }
        else     { if (n0 + bn  < N) bR = *(const float2*)(B + (long long)(n0 + bn) * K + bkq); }
    }
    As[0][akq + 0][arow] = aR.x; As[0][akq + 1][arow] = aR.y;
    As[0][akq + 2][arow] = aR.z; As[0][akq + 3][arow] = aR.w;
    if (!TB) { Bs[0][bk][bn2] = bR.x; Bs[0][bk][bn2 + 1] = bR.y; }
    else     { Bs[0][bkq][bn] = bR.x; Bs[0][bkq + 1][bn] = bR.y; }
    __syncthreads();

    for (int kt = 0; kt < KT; kt++) {
        const int cur = kt & 1;
        const int k0n = (kt + 1) * BK;
        if (kt + 1 < KT) {
            int row = m0 + arow;
            aR = make_float4(0.f, 0.f, 0.f, 0.f);
            bR = make_float2(0.f, 0.f);
            if (row < M) aR = *(const float4*)(Ab + (long long)row * lda + k0n + akq);
            if (!TB) { if (n0 + bn2 < N) bR = *(const float2*)(B + (long long)(k0n + bk) * N + n0 + bn2); }
            else     { if (n0 + bn  < N) bR = *(const float2*)(B + (long long)(n0 + bn) * K + k0n + bkq); }
        }
#pragma unroll
        for (int k = 0; k < BK; k++) {
            const float* ap_ = &As[cur][k][ty * 8];
            ulonglong2 a0 = *(const ulonglong2*)ap_;
            ulonglong2 a1 = *(const ulonglong2*)(ap_ + 4);
            float4 bv = *(const float4*)&Bs[cur][k][tx * 4];
            unsigned long long ap[4] = { a0.x, a0.y, a1.x, a1.y };
            unsigned long long bb[4] = { pack2(bv.x, bv.x), pack2(bv.y, bv.y),
                                         pack2(bv.z, bv.z), pack2(bv.w, bv.w) };
#pragma unroll
            for (int mp = 0; mp < 4; mp++)
#pragma unroll
                for (int j = 0; j < 4; j++)
                    FMA2(acc[mp][j], ap[mp], bb[j]);
        }
        if (kt + 1 < KT) {
            const int nb = cur ^ 1;
            As[nb][akq + 0][arow] = aR.x; As[nb][akq + 1][arow] = aR.y;
            As[nb][akq + 2][arow] = aR.z; As[nb][akq + 3][arow] = aR.w;
            if (!TB) { Bs[nb][bk][bn2] = bR.x; Bs[nb][bk][bn2 + 1] = bR.y; }
            else     { Bs[nb][bkq][bn] = bR.x; Bs[nb][bkq + 1][bn] = bR.y; }
        }
        __syncthreads();
    }

    if (EPI == 0) {
#pragma unroll
        for (int j = 0; j < 4; j++) {
            int col = n0 + tx * 4 + j;
            if (col >= N) continue;
            float bv = bias ? bias[col] : 0.f;
#pragma unroll
            for (int mp = 0; mp < 4; mp++) {
                union { unsigned long long u; float2 f; } cv; cv.u = acc[mp][j];
                int r = m0 + ty * 8 + mp * 2;
                if (r     < M) C[(long long)r * ldc + col]       = cv.f.x + bv;
                if (r + 1 < M) C[(long long)(r + 1) * ldc + col] = cv.f.y + bv;
            }
        }
    } else {
        float cmax[4] = { 0.f, 0.f, 0.f, 0.f };
#pragma unroll
        for (int j = 0; j < 4; j++) {
            int col = n0 + tx * 4 + j;
            float bv = (col < N) ? bias[col] : 0.f;
#pragma unroll
            for (int mp = 0; mp < 4; mp++) {
                union { unsigned long long u; float2 f; } cv; cv.u = acc[mp][j];
                int r = m0 + ty * 8 + mp * 2;
                if (r     < M) cmax[j] = fmaxf(cmax[j], cv.f.x + bv);
                if (r + 1 < M) cmax[j] = fmaxf(cmax[j], cv.f.y + bv);
            }
        }
#pragma unroll
        for (int j = 0; j < 4; j++) red[ty][tx * 4 + j] = cmax[j];
        __syncthreads();
        if (ty == 0) {
#pragma unroll
            for (int j = 0; j < 4; j++) {
                int col = n0 + tx * 4 + j;
                if (col >= N) continue;
                float mx = 0.f;
                for (int t2 = 0; t2 < 16; t2++) mx = fmaxf(mx, red[t2][tx * 4 + j]);
                atomicMax((unsigned int*)&C[(long long)blockIdx.z * featLd + featOff + col],
                          __float_as_uint(mx));
            }
        }
    }
}

// ---------------- CSR build ----------------
__global__ void k_hist(const int* __restrict__ ei, int* __restrict__ deg) {
    int i = blockIdx.x * blockDim.x + threadIdx.x;
    if (i < NEDGE) atomicAdd(&deg[ei[NEDGE + i]], 1);
}

__global__ void k_scan(const int* __restrict__ deg, int* __restrict__ rs,
                       int* __restrict__ cur, int n) {
    __shared__ int s[1024];
    __shared__ int carry;
    int t = threadIdx.x;
    if (t == 0) carry = 0;
    __syncthreads();
    for (int base = 0; base < n; base += 1024) {
        int v = (base + t < n) ? deg[base + t] : 0;
        s[t] = v;
        __syncthreads();
        for (int off = 1; off < 1024; off <<= 1) {
            int add = (t >= off) ? s[t - off] : 0;
            __syncthreads();
            s[t] += add;
            __syncthreads();
        }
        int c0 = carry;
        int ex = c0 + s[t] - v;
        if (base + t < n) { rs[base + t] = ex; cur[base + t] = ex; }
        __syncthreads();
        if (t == 0) carry = c0 + s[1023];
        __syncthreads();
    }
    if (t == 0) rs[n] = carry;
}

__global__ void k_fill(const int* __restrict__ ei, int* __restrict__ cur,
                       int* __restrict__ cs) {
    int i = blockIdx.x * blockDim.x + threadIdx.x;
    if (i < NEDGE) {
        int d = ei[NEDGE + i];
        int p = atomicAdd(&cur[d], 1);
        cs[p] = ei[i];
    }
}

// ---------------- segment-sum + bf16 split of agg ----------------
__global__ void k_agg(const float* __restrict__ m, const int* __restrict__ rs,
                      const int* __restrict__ cs,
                      __nv_bfloat16* __restrict__ ahi, __nv_bfloat16* __restrict__ alo) {
    int w = (blockIdx.x * blockDim.x + threadIdx.x) >> 5;
    int lane = threadIdx.x & 31;
    if (w >= N_NODES) return;
    int s = rs[w], e = rs[w + 1];
    float a[7] = {0, 0, 0, 0, 0, 0, 0};
    int i = s;
    for (; i + 1 < e; i += 2) {
        const float* r0 = m + (long long)cs[i]     * HDIM;
        const float* r1 = m + (long long)cs[i + 1] * HDIM;
        a[0] += r0[lane]       + r1[lane];
        a[1] += r0[lane +  32] + r1[lane +  32];
        a[2] += r0[lane +  64] + r1[lane +  64];
        a[3] += r0[lane +  96] + r1[lane +  96];
        a[4] += r0[lane + 128] + r1[lane + 128];
        a[5] += r0[lane + 160] + r1[lane + 160];
        if (lane < 8) a[6] += r0[lane + 192] + r1[lane + 192];
    }
    if (i < e) {
        const float* r0 = m + (long long)cs[i] * HDIM;
        a[0] += r0[lane];       a[1] += r0[lane + 32];  a[2] += r0[lane + 64];
        a[3] += r0[lane + 96];  a[4] += r0[lane + 128]; a[5] += r0[lane + 160];
        if (lane < 8) a[6] += r0[lane + 192];
    }
    long long o = (long long)w * KPAD + lane;
#pragma unroll
    for (int q = 0; q < 6; q++) {
        __nv_bfloat16 h = __float2bfloat16(a[q]);
        ahi[o + q * 32] = h;
        alo[o + q * 32] = __float2bfloat16(a[q] - __bfloat162float(h));
    }
    if (lane < 8) {
        __nv_bfloat16 h = __float2bfloat16(a[6]);
        ahi[o + 192] = h;
        alo[o + 192] = __float2bfloat16(a[6] - __bfloat162float(h));
    }
}

// ---------------- GRU gates (+ bias fold + bf16 split of new h) ----------------
__global__ void k_gates(const float* __restrict__ gi, const float* __restrict__ gh,
                        const float* __restrict__ bih, const float* __restrict__ bhh,
                        const float* __restrict__ hsrc, float* __restrict__ hdst,
                        __nv_bfloat16* __restrict__ hhi, __nv_bfloat16* __restrict__ hlo) {
    int idx = blockIdx.x * blockDim.x + threadIdx.x;
    if (idx >= N_NODES * HDIM) return;
    int n = idx / HDIM, c = idx - n * HDIM;
    const float* giN = gi + (long long)n * 600;
    const float* ghN = gh + (long long)n * 600;
    float r  = 1.f / (1.f + expf(-(giN[c] + bih[c] + ghN[c] + bhh[c])));
    float z  = 1.f / (1.f + expf(-(giN[200 + c] + bih[200 + c] + ghN[200 + c] + bhh[200 + c])));
    float nn = tanhf(giN[400 + c] + bih[400 + c] + r * (ghN[400 + c] + bhh[400 + c]));
    float h = (1.f - z) * nn + z * hsrc[idx];
    hdst[idx] = h;
    __nv_bfloat16 hb = __float2bfloat16(h);
    long long o = (long long)n * KPAD + c;
    hhi[o] = hb;
    hlo[o] = __float2bfloat16(h - __bfloat162float(hb));
}

// ---------------- misc data movement ----------------
__global__ void k_hp(const float* __restrict__ h, float* __restrict__ hp) {
    int idx = blockIdx.x * blockDim.x + threadIdx.x;
    if (idx >= BATCH * 207 * HDIM) return;
    int b = idx / (207 * HDIM);
    int rem = idx - b * 207 * HDIM;
    int r = rem / HDIM, c = rem - r * HDIM;
    hp[idx] = (r == 0 || r == 206) ? 0.f
              : h[((long long)b * NPER + (r - 1)) * HDIM + c];
}

__global__ void k_wt(const float* __restrict__ w, float* __restrict__ wt,
                     int CO, int CI, int KK) {
    int idx = blockIdx.x * blockDim.x + threadIdx.x;
    if (idx >= CO * CI * KK) return;
    int co = idx / (CI * KK);
    int rem = idx - co * CI * KK;
    int ci = rem / KK, k = rem - ci * KK;
    wt[(long long)co * CI * KK + k * CI + ci] = w[idx];
}

// ---------------- fused FC head ----------------
__global__ void k_fc(const float* __restrict__ feats,
                     const float* __restrict__ w1, const float* __restrict__ b1,
                     const float* __restrict__ w2, const float* __restrict__ b2,
                     const float* __restrict__ w3, const float* __restrict__ b3,
                     float* __restrict__ out) {
    int b = blockIdx.x;
    int tid = threadIdx.x;
    int lane = tid & 31, wrp = tid >> 5;
    __shared__ float sf[800];
    __shared__ float s1[256];
    __shared__ float s2[128];
    for (int i = tid; i < 800; i += 256) sf[i] = feats[b * 800 + i];
    __syncthreads();
    for (int jj = 0; jj < 32; jj++) {
        int j = wrp * 32 + jj;
        float a = 0.f;
        for (int i = lane; i < 800; i += 32) a += sf[i] * w1[(long long)j * 800 + i];
        for (int o = 16; o; o >>= 1) a += __shfl_down_sync(0xffffffffu, a, o);
        if (lane == 0) s1[j] = fmaxf(a + b1[j], 0.f);
    }
    __syncthreads();
    if (tid < 128) {
        float a = b2[tid];
        for (int i = 0; i < 256; i++) a += s1[i] * w2[tid * 256 + i];
        s2[tid] = fmaxf(a, 0.f);
    }
    __syncthreads();
    if (tid < 2) {
        float a = b3[tid];
        for (int i = 0; i < 128; i++) a += s2[i] * w3[tid * 128 + i];
        out[b * 2 + tid] = a;
    }
}

// ---------------- launcher ----------------
extern "C" void kernel_launch(void* const* d_in, const int* in_sizes, int n_in,
                              void* d_out, int out_size) {
    const float* x     = (const float*)d_in[0];
    const int*   ei    = (const int*)  d_in[1];
    const int*   ids   = (const int*)  d_in[2];
    const float* etab  = (const float*)d_in[3];
    const float* ggcw  = (const float*)d_in[4];
    const float* wih   = (const float*)d_in[5];
    const float* whh   = (const float*)d_in[6];
    const float* bih   = (const float*)d_in[7];
    const float* bhh   = (const float*)d_in[8];
    const float* c0w   = (const float*)d_in[9];
    const float* c0b   = (const float*)d_in[10];
    const float* c1w   = (const float*)d_in[11];
    const float* c1b   = (const float*)d_in[12];
    const float* c2w   = (const float*)d_in[13];
    const float* c2b   = (const float*)d_in[14];
    const float* c3w   = (const float*)d_in[15];
    const float* c3b   = (const float*)d_in[16];
    const float* f1w   = (const float*)d_in[17];
    const float* f1b   = (const float*)d_in[18];
    const float* f2w   = (const float*)d_in[19];
    const float* f2b   = (const float*)d_in[20];
    const float* f3w   = (const float*)d_in[21];
    const float* f3b   = (const float*)d_in[22];
    float* out = (float*)d_out;

    float *h0, *h1, *mm, *gi, *gh, *hp, *w0t, *feats;
    int *deg, *rs, *cur, *cs;
    __nv_bfloat16 *ehi, *elo, *w1b, *w2b, *w3b;
    __nv_bfloat16 *hhi, *hlo, *ahi, *alo, *wg, *wi, *wh;
    cudaGetSymbolAddress((void**)&h0,   g_h0);
    cudaGetSymbolAddress((void**)&h1,   g_h1);
    cudaGetSymbolAddress((void**)&mm,   g_m);
    cudaGetSymbolAddress((void**)&gi,   g_gi);
    cudaGetSymbolAddress((void**)&gh,   g_gh);
    cudaGetSymbolAddress((void**)&hp,   g_hp);
    cudaGetSymbolAddress((void**)&w0t,  g_w0t);
    cudaGetSymbolAddress((void**)&feats,g_feats);
    cudaGetSymbolAddress((void**)&deg,  g_deg);
    cudaGetSymbolAddress((void**)&rs,   g_rs);
    cudaGetSymbolAddress((void**)&cur,  g_cur);
    cudaGetSymbolAddress((void**)&cs,   g_csrc);
    cudaGetSymbolAddress((void**)&ehi,  g_ehi);
    cudaGetSymbolAddress((void**)&elo,  g_elo);
    cudaGetSymbolAddress((void**)&w1b,  g_w1b);
    cudaGetSymbolAddress((void**)&w2b,  g_w2b);
    cudaGetSymbolAddress((void**)&w3b,  g_w3b);
    cudaGetSymbolAddress((void**)&hhi,  g_hhi);
    cudaGetSymbolAddress((void**)&hlo,  g_hlo);
    cudaGetSymbolAddress((void**)&ahi,  g_ahi);
    cudaGetSymbolAddress((void**)&alo,  g_alo);
    cudaGetSymbolAddress((void**)&wg,   g_wg);
    cudaGetSymbolAddress((void**)&wi,   g_wi);
    cudaGetSymbolAddress((void**)&wh,   g_wh);

    const int CONV_SMEM = 36864 + 59904 + 832 + 832;   // 98432 B
    const int GGC_SMEM  = 36864 + 59904;               // 96768 B
    cudaFuncSetAttribute(conv3x_hmma_k, cudaFuncAttributeMaxDynamicSharedMemorySize, CONV_SMEM);
    cudaFuncSetAttribute(ggc_hmma_k,    cudaFuncAttributeMaxDynamicSharedMemorySize, GGC_SMEM);
    cudaFuncSetAttribute(ggc_mh_k,      cudaFuncAttributeMaxDynamicSharedMemorySize, GGC_SMEM);

    // side stream + events (created once; host resources, no device allocs)
    static cudaStream_t s2 = nullptr;
    static cudaEvent_t ev1 = nullptr, ev2 = nullptr;
    if (!s2) {
        cudaStreamCreateWithFlags(&s2, cudaStreamNonBlocking);
        cudaEventCreateWithFlags(&ev1, cudaEventDisableTiming);
        cudaEventCreateWithFlags(&ev2, cudaEventDisableTiming);
    }

    // ---- default stream: feats zero, then fork conv branch ----
    cudaMemsetAsync(feats, 0, BATCH * 800 * sizeof(float));
    cudaEventRecord(ev1, 0);
    cudaStreamWaitEvent(s2, ev1, 0);

    // ---- side stream: conv1/2/3 branch (independent of GGC) ----
    k_embed2<<<BATCH * SEQ + 8, 256, 0, s2>>>(ids, etab, ehi, elo);
    k_wsplit<<<(200 * 768 * 3 + 255) / 256, 256, 0, s2>>>(c1w, w1b, 3);
    k_wsplit<<<(200 * 768 * 4 + 255) / 256, 256, 0, s2>>>(c2w, w2b, 4);
    k_wsplit<<<(200 * 768 * 5 + 255) / 256, 256, 0, s2>>>(c3w, w3b, 5);
    {
        Conv3Args ca;
        ca.wb[0] = w1b; ca.wb[1] = w2b; ca.wb[2] = w3b;
        ca.bias[0] = c1b; ca.bias[1] = c2b; ca.bias[2] = c3b;
        conv3x_hmma_k<<<dim3(3, 4, BATCH), 256, CONV_SMEM, s2>>>(ehi, elo, ca, feats);
    }
    cudaEventRecord(ev2, s2);

    // ---- default stream: CSR + GGC prep ----
    cudaMemsetAsync(deg, 0, N_NODES * sizeof(int));
    k_hist<<<(NEDGE + 255) / 256, 256>>>(ei, deg);
    k_scan<<<1, 1024>>>(deg, rs, cur, N_NODES);
    k_fill<<<(NEDGE + 255) / 256, 256>>>(ei, cur, cs);
    cudaMemcpyAsync(h0, x, (size_t)N_NODES * HDIM * sizeof(float),
                    cudaMemcpyDeviceToDevice);
    k_xsplit<<<(N_NODES * KPAD + 255) / 256, 256>>>(x, hhi, hlo);
    k_wggc<<<(NLAYERS * 208 * 768 + 255) / 256, 256>>>(ggcw, wg);
    k_wgru<<<(624 * 768 + 255) / 256, 256>>>(wih, wi);
    k_wgru<<<(624 * 768 + 255) / 256, 256>>>(whh, wh);
    k_wt<<<(200 * 200 * 3 + 255) / 256, 256>>>(c0w, w0t, 200, 200, 3);

    // ---- gated graph conv: 6 layers (HMMA bf16x3) ----
    float* hc = h0;
    float* hn = h1;
    for (int l = 0; l < NLAYERS; l++) {
        // fused: m = h @ ggc_w[l]  and  gh = h @ whh^T  (same A)
        ggc_mh_k<<<dim3(4, NPER), 256, GGC_SMEM>>>(hhi, hlo,
                                                   wg + (long long)l * 208 * 768, wh,
                                                   mm, gh);
        // agg = segment_sum(m[src], dst), split to bf16
        k_agg<<<(N_NODES + 7) / 8, 256>>>(mm, rs, cs, ahi, alo);
        // gi = agg @ wih^T
        ggc_hmma_k<<<dim3(3, NPER), 256, GGC_SMEM>>>(ahi, alo, wi, gi, 600, 600);
        // GRU update (+bias fold) and re-split h
        k_gates<<<(N_NODES * HDIM + 255) / 256, 256>>>(gi, gh, bih, bhh, hc, hn, hhi, hlo);
        float* t = hc; hc = hn; hn = t;
    }

    // ---- conv0 (fp32 SIMT, fused bias+ReLU+max; feats cols 0..199) ----
    k_hp<<<(BATCH * 207 * HDIM + 255) / 256, 256>>>(hc, hp);
    sgemm_k<true, 1><<<dim3(4, 2, BATCH), 256>>>(hp, 200, 207LL * 200, w0t, c0b, feats,
                                                 205, 200, 600, 0, 800, 0);

    // ---- join conv branch, then FC head ----
    cudaStreamWaitEvent(0, ev2, 0);
    k_fc<<<BATCH, 256>>>(feats, f1w, f1b, f2w, f2b, f3w, f3b, out);
}

// round 9
// speedup vs baseline: 2.3721x; 1.0137x over previous
#include <cuda_runtime.h>
#include <cuda_bf16.h>
#include <cstdint>

// ---------------- problem constants ----------------
#define N_NODES 26240      // B * N_PER = 128 * 205 (exactly 205 blocks of 128)
#define HDIM    200
#define NEDGE   209920
#define BATCH   128
#define NPER    205
#define EMBD    768
#define SEQ     512
#define NLAYERS 6
#define KPAD    256        // padded K per bf16x3 pass (GGC)

// ---------------- static device scratch ----------------
__device__ float g_h0[N_NODES * HDIM];
__device__ float g_h1[N_NODES * HDIM];
__device__ float g_m [N_NODES * HDIM];
__device__ float g_gi[N_NODES * 3 * HDIM];
__device__ float g_gh[N_NODES * 3 * HDIM];
__device__ float g_hp [BATCH * 207 * HDIM];             // zero-padded conv0 input
__device__ float g_w0t[200 * 600];
__device__ float g_feats[BATCH * 800];
__device__ int   g_deg[N_NODES];
__device__ int   g_rs [N_NODES + 1];
__device__ int   g_cur[N_NODES];
__device__ int   g_csrc[NEDGE];

// GGC bf16 split operands, K-padded to 256 (pads stay zero after init)
__device__ __align__(16) __nv_bfloat16 g_hhi[(size_t)N_NODES * KPAD];
__device__ __align__(16) __nv_bfloat16 g_hlo[(size_t)N_NODES * KPAD];
__device__ __align__(16) __nv_bfloat16 g_ahi[(size_t)N_NODES * KPAD];
__device__ __align__(16) __nv_bfloat16 g_alo[(size_t)N_NODES * KPAD];
// GGC weights expanded: [Npad][768] = [Whi(0:256) | Wlo(256:512) | Whi(512:768)]
__device__ __align__(16) __nv_bfloat16 g_wg[NLAYERS * 208 * 768];   // ggc_w[l]^T
__device__ __align__(16) __nv_bfloat16 g_wi[624 * 768];             // wih
__device__ __align__(16) __nv_bfloat16 g_wh[624 * 768];             // whh

// bf16 hi/lo embeddings, time-major [b][t][c], +8 zero rows for tap overrun
__device__ __align__(16) __nv_bfloat16 g_ehi[((size_t)BATCH * SEQ + 8) * EMBD];
__device__ __align__(16) __nv_bfloat16 g_elo[((size_t)BATCH * SEQ + 8) * EMBD];
// expanded conv weights: [200][3K] = [Whi | Wlo | Whi], K-major per tap
__device__ __align__(16) __nv_bfloat16 g_w1b[200 * 3 * 2304];
__device__ __align__(16) __nv_bfloat16 g_w2b[200 * 3 * 3072];
__device__ __align__(16) __nv_bfloat16 g_w3b[200 * 3 * 3840];

// ---------------- packed fp32x2 helpers (sm_100+) ----------------
#define FMA2(d, a, b) asm("fma.rn.f32x2 %0, %1, %2, %0;" : "+l"(d) : "l"(a), "l"(b))

__device__ __forceinline__ unsigned long long pack2(float x, float y) {
    unsigned long long r;
    asm("mov.b64 %0, {%1, %2};" : "=l"(r) : "r"(__float_as_uint(x)), "r"(__float_as_uint(y)));
    return r;
}

// ---------------- warp-level bf16 MMA (compute_100-safe PTX) ----------------
#define MMA_BF16(d, a, b0, b1) asm volatile(                           \
    "mma.sync.aligned.m16n8k16.row.col.f32.bf16.bf16.f32 "             \
    "{%0,%1,%2,%3}, {%4,%5,%6,%7}, {%8,%9}, {%0,%1,%2,%3};"            \
    : "+f"((d)[0]), "+f"((d)[1]), "+f"((d)[2]), "+f"((d)[3])           \
    : "r"((a)[0]), "r"((a)[1]), "r"((a)[2]), "r"((a)[3]),              \
      "r"(b0), "r"(b1))

// ---------------- cp.async helpers (sm_80+ PTX, compute_100-safe) ----------------
#define CP16(dst, src) asm volatile("cp.async.ca.shared.global [%0], [%1], 16;" \
                                    :: "r"(dst), "l"(src))
#define CP_COMMIT() asm volatile("cp.async.commit_group;" ::: "memory")
#define CP_WAIT0()  asm volatile("cp.async.wait_group 0;" ::: "memory")

__device__ __forceinline__ uint32_t s2u(const void* p) {
    return (uint32_t)__cvta_generic_to_shared(p);
}

// ---------------- GGC GEMM: gi = agg @ wih^T ----------------
// grid (3 n-tiles, 205 m-tiles). 256 threads = 8 warps (4m x 2n). K3 = 768.
__global__ void __launch_bounds__(256, 1) ggc_hmma_k(
    const __nv_bfloat16* __restrict__ Ahi,
    const __nv_bfloat16* __restrict__ Alo,
    const __nv_bfloat16* __restrict__ B,
    float* __restrict__ C, int N, int ldc)
{
    extern __shared__ __align__(16) char dsm[];
    constexpr int ASTR = 72, BSTR = 72;
    __nv_bfloat16* As = (__nv_bfloat16*)dsm;                 // [2][128][72]
    __nv_bfloat16* Bs = (__nv_bfloat16*)(dsm + 36864);       // [2][208][72]

    const int tid = threadIdx.x;
    const int lane = tid & 31, wid = tid >> 5;
    const int wm = wid & 3, wn = wid >> 2;
    const int g = lane >> 2, t2 = (lane & 3) * 2;
    const int m0 = blockIdx.y * 128;
    const int n0 = blockIdx.x * 208;
    const uint32_t asb = s2u(As), bsb = s2u(Bs);

    auto copy_tile = [&](int kt, int buf) {
        const int p = kt >> 2;
        const int koff = (kt & 3) * 64;
        const __nv_bfloat16* src = (p < 2) ? Ahi : Alo;
        const uint32_t ab = asb + buf * 128 * ASTR * 2;
        const uint32_t bb = bsb + buf * 208 * BSTR * 2;
#pragma unroll
        for (int i = 0; i < 4; i++) {
            int u = tid + i * 256;
            int row = u >> 3, ch = u & 7;
            CP16(ab + (row * ASTR + ch * 8) * 2,
                 src + (long long)(m0 + row) * KPAD + koff + ch * 8);
        }
        const int kg = kt * 64;
#pragma unroll
        for (int i = 0; i < 7; i++) {
            int u = tid + i * 256;
            if (u < 1664) {
                int row = u >> 3, ch = u & 7;
                CP16(bb + (row * BSTR + ch * 8) * 2,
                     B + (long long)(n0 + row) * 768 + kg + ch * 8);
            }
        }
    };

    float acc[2][13][4];
#pragma unroll
    for (int i = 0; i < 2; i++)
#pragma unroll
        for (int j = 0; j < 13; j++)
#pragma unroll
            for (int q = 0; q < 4; q++) acc[i][j][q] = 0.f;

    copy_tile(0, 0); CP_COMMIT(); CP_WAIT0();
    __syncthreads();

#pragma unroll 1
    for (int kt = 0; kt < 12; kt++) {
        const int buf = kt & 1;
        const bool more = (kt + 1 < 12);
        if (more) { copy_tile(kt + 1, buf ^ 1); CP_COMMIT(); }

        const __nv_bfloat16* Ab = As + buf * 128 * ASTR;
        const __nv_bfloat16* Bb = Bs + buf * 208 * BSTR;
#pragma unroll
        for (int ks = 0; ks < 4; ks++) {
            const int ko = ks * 16;
            uint32_t a[2][4];
#pragma unroll
            for (int i = 0; i < 2; i++) {
                const int r = wm * 32 + i * 16 + g;
                a[i][0] = *(const uint32_t*)(Ab + (r)     * ASTR + ko + t2);
                a[i][1] = *(const uint32_t*)(Ab + (r + 8) * ASTR + ko + t2);
                a[i][2] = *(const uint32_t*)(Ab + (r)     * ASTR + ko + t2 + 8);
                a[i][3] = *(const uint32_t*)(Ab + (r + 8) * ASTR + ko + t2 + 8);
            }
            uint32_t bf[13][2];
#pragma unroll
            for (int j = 0; j < 13; j++) {
                const int n = wn * 104 + j * 8 + g;
                bf[j][0] = *(const uint32_t*)(Bb + n * BSTR + ko + t2);
                bf[j][1] = *(const uint32_t*)(Bb + n * BSTR + ko + t2 + 8);
            }
#pragma unroll
            for (int j = 0; j < 13; j++) {
                MMA_BF16(acc[0][j], a[0], bf[j][0], bf[j][1]);
                MMA_BF16(acc[1][j], a[1], bf[j][0], bf[j][1]);
            }
        }
        if (more) CP_WAIT0();
        __syncthreads();
    }

#pragma unroll
    for (int i = 0; i < 2; i++) {
        const int r = m0 + wm * 32 + i * 16 + g;
#pragma unroll
        for (int j = 0; j < 13; j++) {
            const int col = n0 + wn * 104 + j * 8 + t2;
            if (col < N) {
                C[(long long)r * ldc + col]       = acc[i][j][0];
                C[(long long)(r + 8) * ldc + col] = acc[i][j][2];
            }
            if (col + 1 < N) {
                C[(long long)r * ldc + col + 1]       = acc[i][j][1];
                C[(long long)(r + 8) * ldc + col + 1] = acc[i][j][3];
            }
        }
    }
}

// ---------------- fused m + gh GEMM (same A = h) ----------------
// grid (4, 205): bx==0 -> m = h @ ggc_w[l] (N=200); bx in 1..3 -> gh slice.
__global__ void __launch_bounds__(256, 1) ggc_mh_k(
    const __nv_bfloat16* __restrict__ Ahi,
    const __nv_bfloat16* __restrict__ Alo,
    const __nv_bfloat16* __restrict__ wgl,    // [208][768] layer slice
    const __nv_bfloat16* __restrict__ wh,     // [624][768]
    float* __restrict__ Cm,
    float* __restrict__ Cg)
{
    extern __shared__ __align__(16) char dsm[];
    constexpr int ASTR = 72, BSTR = 72;
    __nv_bfloat16* As = (__nv_bfloat16*)dsm;
    __nv_bfloat16* Bs = (__nv_bfloat16*)(dsm + 36864);

    const int tid = threadIdx.x;
    const int lane = tid & 31, wid = tid >> 5;
    const int wm = wid & 3, wn = wid >> 2;
    const int g = lane >> 2, t2 = (lane & 3) * 2;
    const int m0 = blockIdx.y * 128;
    const int bx = blockIdx.x;
    const uint32_t asb = s2u(As), bsb = s2u(Bs);

    const __nv_bfloat16* B = (bx == 0) ? wgl : (wh + (long long)(bx - 1) * 208 * 768);
    float* C      = (bx == 0) ? Cm  : Cg;
    const int ldc = (bx == 0) ? 200 : 600;
    const int N   = (bx == 0) ? 200 : 600;
    const int cb  = (bx == 0) ? 0   : (bx - 1) * 208;

    auto copy_tile = [&](int kt, int buf) {
        const int p = kt >> 2;
        const int koff = (kt & 3) * 64;
        const __nv_bfloat16* src = (p < 2) ? Ahi : Alo;
        const uint32_t ab = asb + buf * 128 * ASTR * 2;
        const uint32_t bb = bsb + buf * 208 * BSTR * 2;
#pragma unroll
        for (int i = 0; i < 4; i++) {
            int u = tid + i * 256;
            int row = u >> 3, ch = u & 7;
            CP16(ab + (row * ASTR + ch * 8) * 2,
                 src + (long long)(m0 + row) * KPAD + koff + ch * 8);
        }
        const int kg = kt * 64;
#pragma unroll
        for (int i = 0; i < 7; i++) {
            int u = tid + i * 256;
            if (u < 1664) {
                int row = u >> 3, ch = u & 7;
                CP16(bb + (row * BSTR + ch * 8) * 2,
                     B + (long long)row * 768 + kg + ch * 8);
            }
        }
    };

    float acc[2][13][4];
#pragma unroll
    for (int i = 0; i < 2; i++)
#pragma unroll
        for (int j = 0; j < 13; j++)
#pragma unroll
            for (int q = 0; q < 4; q++) acc[i][j][q] = 0.f;

    copy_tile(0, 0); CP_COMMIT(); CP_WAIT0();
    __syncthreads();

#pragma unroll 1
    for (int kt = 0; kt < 12; kt++) {
        const int buf = kt & 1;
        const bool more = (kt + 1 < 12);
        if (more) { copy_tile(kt + 1, buf ^ 1); CP_COMMIT(); }

        const __nv_bfloat16* Ab = As + buf * 128 * ASTR;
        const __nv_bfloat16* Bb = Bs + buf * 208 * BSTR;
#pragma unroll
        for (int ks = 0; ks < 4; ks++) {
            const int ko = ks * 16;
            uint32_t a[2][4];
#pragma unroll
            for (int i = 0; i < 2; i++) {
                const int r = wm * 32 + i * 16 + g;
                a[i][0] = *(const uint32_t*)(Ab + (r)     * ASTR + ko + t2);
                a[i][1] = *(const uint32_t*)(Ab + (r + 8) * ASTR + ko + t2);
                a[i][2] = *(const uint32_t*)(Ab + (r)     * ASTR + ko + t2 + 8);
                a[i][3] = *(const uint32_t*)(Ab + (r + 8) * ASTR + ko + t2 + 8);
            }
            uint32_t bf[13][2];
#pragma unroll
            for (int j = 0; j < 13; j++) {
                const int n = wn * 104 + j * 8 + g;
                bf[j][0] = *(const uint32_t*)(Bb + n * BSTR + ko + t2);
                bf[j][1] = *(const uint32_t*)(Bb + n * BSTR + ko + t2 + 8);
            }
#pragma unroll
            for (int j = 0; j < 13; j++) {
                MMA_BF16(acc[0][j], a[0], bf[j][0], bf[j][1]);
                MMA_BF16(acc[1][j], a[1], bf[j][0], bf[j][1]);
            }
        }
        if (more) CP_WAIT0();
        __syncthreads();
    }

#pragma unroll
    for (int i = 0; i < 2; i++) {
        const int r = m0 + wm * 32 + i * 16 + g;
#pragma unroll
        for (int j = 0; j < 13; j++) {
            const int col = cb + wn * 104 + j * 8 + t2;
            if (col < N) {
                C[(long long)r * ldc + col]       = acc[i][j][0];
                C[(long long)(r + 8) * ldc + col] = acc[i][j][2];
            }
            if (col + 1 < N) {
                C[(long long)r * ldc + col + 1]       = acc[i][j][1];
                C[(long long)(r + 8) * ldc + col + 1] = acc[i][j][3];
            }
        }
    }
}

// ---------------- fused conv1/2/3: HMMA bf16x3 conv-as-GEMM ----------------
struct Conv3Args {
    const __nv_bfloat16* wb[3];
    const float* bias[3];
};
// grid (3 convs, 4 m-tiles, 128 batches)
__global__ void __launch_bounds__(256, 1) conv3x_hmma_k(
    const __nv_bfloat16* __restrict__ ehi,
    const __nv_bfloat16* __restrict__ elo,
    Conv3Args args,
    float* __restrict__ feats)
{
    extern __shared__ __align__(16) char dsm[];
    constexpr int ASTR = 72, BSTR = 72;
    __nv_bfloat16* As = (__nv_bfloat16*)dsm;
    __nv_bfloat16* Bs = (__nv_bfloat16*)(dsm + 36864);
    float* smax  = (float*)(dsm + 36864 + 59904);
    float* sbias = smax + 208;

    const int cid = blockIdx.x;
    const int M   = (cid == 0) ? 510 : (cid == 1) ? 509 : 508;
    const int K3  = (cid == 0) ? 6912 : (cid == 1) ? 9216 : 11520;
    const int featOff = 200 + cid * 200;
    const __nv_bfloat16* wb = args.wb[cid];
    const float* bias = args.bias[cid];

    const int tid = threadIdx.x;
    const int lane = tid & 31, wid = tid >> 5;
    const int wm = wid & 3, wn = wid >> 2;
    const int g = lane >> 2, t2 = (lane & 3) * 2;
    const int b = blockIdx.z, m0 = blockIdx.y * 128;
    const int TK = K3 / 192;
    const int T  = K3 / 64;
    const uint32_t asb = s2u(As), bsb = s2u(Bs);

    if (tid < 208) { smax[tid] = 0.f; sbias[tid] = (tid < 200) ? bias[tid] : 0.f; }

    auto copy_tile = [&](int kt, int buf) {
        int p = kt / TK;
        int rem = kt - p * TK;
        int kk = rem / 12;
        int c0 = (rem - kk * 12) * 64;
        const __nv_bfloat16* src = (p < 2) ? ehi : elo;
        long long abase = ((long long)(b * SEQ + m0 + kk)) * EMBD + c0;
        const uint32_t ab = asb + buf * 128 * ASTR * 2;
        const uint32_t bb = bsb + buf * 208 * BSTR * 2;
#pragma unroll
        for (int i = 0; i < 4; i++) {
            int u = tid + i * 256;
            int row = u >> 3, ch = u & 7;
            CP16(ab + (row * ASTR + ch * 8) * 2,
                 src + abase + (long long)row * EMBD + ch * 8);
        }
        int kg = kt * 64;
#pragma unroll
        for (int i = 0; i < 7; i++) {
            int u = tid + i * 256;
            if (u < 1600) {
                int row = u >> 3, ch = u & 7;
                CP16(bb + (row * BSTR + ch * 8) * 2,
                     wb + (long long)row * K3 + kg + ch * 8);
            }
        }
    };

    float acc[2][13][4];
#pragma unroll
    for (int i = 0; i < 2; i++)
#pragma unroll
        for (int j = 0; j < 13; j++)
#pragma unroll
            for (int q = 0; q < 4; q++) acc[i][j][q] = 0.f;

    copy_tile(0, 0); CP_COMMIT(); CP_WAIT0();
    __syncthreads();

#pragma unroll 1
    for (int kt = 0; kt < T; kt++) {
        const int buf = kt & 1;
        const bool more = (kt + 1 < T);
        if (more) { copy_tile(kt + 1, buf ^ 1); CP_COMMIT(); }

        const __nv_bfloat16* Ab = As + buf * 128 * ASTR;
        const __nv_bfloat16* Bb = Bs + buf * 208 * BSTR;
#pragma unroll
        for (int ks = 0; ks < 4; ks++) {
            const int ko = ks * 16;
            uint32_t a[2][4];
#pragma unroll
            for (int i = 0; i < 2; i++) {
                const int r = wm * 32 + i * 16 + g;
                a[i][0] = *(const uint32_t*)(Ab + (r)     * ASTR + ko + t2);
                a[i][1] = *(const uint32_t*)(Ab + (r + 8) * ASTR + ko + t2);
                a[i][2] = *(const uint32_t*)(Ab + (r)     * ASTR + ko + t2 + 8);
                a[i][3] = *(const uint32_t*)(Ab + (r + 8) * ASTR + ko + t2 + 8);
            }
            uint32_t bf[13][2];
#pragma unroll
            for (int j = 0; j < 13; j++) {
                const int n = wn * 104 + j * 8 + g;
                bf[j][0] = *(const uint32_t*)(Bb + n * BSTR + ko + t2);
                bf[j][1] = *(const uint32_t*)(Bb + n * BSTR + ko + t2 + 8);
            }
#pragma unroll
            for (int j = 0; j < 13; j++) {
                MMA_BF16(acc[0][j], a[0], bf[j][0], bf[j][1]);
                MMA_BF16(acc[1][j], a[1], bf[j][0], bf[j][1]);
            }
        }
        if (more) CP_WAIT0();
        __syncthreads();
    }

    const int valid = (M - m0 < 128) ? (M - m0) : 128;
#pragma unroll
    for (int j = 0; j < 13; j++) {
        float v0 = -1e30f, v1 = -1e30f;
#pragma unroll
        for (int i = 0; i < 2; i++) {
            const int r0 = wm * 32 + i * 16 + g;
            if (r0 < valid)     { v0 = fmaxf(v0, acc[i][j][0]); v1 = fmaxf(v1, acc[i][j][1]); }
            if (r0 + 8 < valid) { v0 = fmaxf(v0, acc[i][j][2]); v1 = fmaxf(v1, acc[i][j][3]); }
        }
#pragma unroll
        for (int o = 4; o <= 16; o <<= 1) {
            v0 = fmaxf(v0, __shfl_xor_sync(~0u, v0, o));
            v1 = fmaxf(v1, __shfl_xor_sync(~0u, v1, o));
        }
        if (g == 0) {
            const int col = wn * 104 + j * 8 + t2;
            if (col < 200) {
                float r = fmaxf(v0 + sbias[col], 0.f);
                atomicMax((unsigned int*)&smax[col], __float_as_uint(r));
            }
            if (col + 1 < 200) {
                float r = fmaxf(v1 + sbias[col + 1], 0.f);
                atomicMax((unsigned int*)&smax[col + 1], __float_as_uint(r));
            }
        }
    }
    __syncthreads();
    if (tid < 200)
        atomicMax((unsigned int*)&feats[(long long)b * 800 + featOff + tid],
                  __float_as_uint(smax[tid]));
}

// ---------------- bf16 split precompute ----------------
__global__ void k_embed2(const int* __restrict__ ids, const float* __restrict__ tbl,
                         __nv_bfloat16* __restrict__ hi, __nv_bfloat16* __restrict__ lo) {
    int row = blockIdx.x;
    int t = threadIdx.x;                   // 192 threads, one float4 each
    long long o = (long long)row * EMBD;
    if (row >= BATCH * SEQ) {
        if (t < 96) {
            uint4 z = make_uint4(0, 0, 0, 0);
            ((uint4*)(hi + o))[t] = z;
            ((uint4*)(lo + o))[t] = z;
        }
        return;
    }
    long long id = ids[row];
    float4 v = ((const float4*)(tbl + id * EMBD))[t];
    __nv_bfloat162 h01 = __floats2bfloat162_rn(v.x, v.y);
    __nv_bfloat162 h23 = __floats2bfloat162_rn(v.z, v.w);
    float r0 = v.x - __bfloat162float(__low2bfloat16(h01));
    float r1 = v.y - __bfloat162float(__high2bfloat16(h01));
    float r2 = v.z - __bfloat162float(__low2bfloat16(h23));
    float r3 = v.w - __bfloat162float(__high2bfloat16(h23));
    __nv_bfloat162 l01 = __floats2bfloat162_rn(r0, r1);
    __nv_bfloat162 l23 = __floats2bfloat162_rn(r2, r3);
    uint2 hv, lv;
    hv.x = *(uint32_t*)&h01; hv.y = *(uint32_t*)&h23;
    lv.x = *(uint32_t*)&l01; lv.y = *(uint32_t*)&l23;
    ((uint2*)(hi + o))[t] = hv;
    ((uint2*)(lo + o))[t] = lv;
}

__global__ void k_wsplit(const float* __restrict__ w, __nv_bfloat16* __restrict__ wb, int KK) {
    int K = 768 * KK;
    int idx = blockIdx.x * blockDim.x + threadIdx.x;
    if (idx >= 200 * K) return;
    int co = idx / K, r = idx - co * K;
    int kk = r / 768, ci = r - kk * 768;
    float x = w[(co * 768 + ci) * KK + kk];
    __nv_bfloat16 h = __float2bfloat16(x);
    __nv_bfloat16 l = __float2bfloat16(x - __bfloat162float(h));
    long long base = (long long)co * 3 * K + r;
    wb[base] = h; wb[base + K] = l; wb[base + 2 * K] = h;
}

__global__ void k_wggc(const float* __restrict__ w, __nv_bfloat16* __restrict__ out) {
    int idx = blockIdx.x * blockDim.x + threadIdx.x;
    if (idx >= NLAYERS * 208 * 768) return;
    int l = idx / (208 * 768);
    int rem = idx - l * 208 * 768;
    int n = rem / 768, col = rem - n * 768;
    int p = col >> 8, kk = col & 255;
    float x = (n < 200 && kk < 200) ? w[(long long)l * 40000 + kk * 200 + n] : 0.f;
    __nv_bfloat16 h = __float2bfloat16(x);
    out[idx] = (p == 1) ? __float2bfloat16(x - __bfloat162float(h)) : h;
}

__global__ void k_wgru(const float* __restrict__ w, __nv_bfloat16* __restrict__ out) {
    int idx = blockIdx.x * blockDim.x + threadIdx.x;
    if (idx >= 624 * 768) return;
    int n = idx / 768, col = idx - n * 768;
    int p = col >> 8, kk = col & 255;
    float x = (n < 600 && kk < 200) ? w[n * 200 + kk] : 0.f;
    __nv_bfloat16 h = __float2bfloat16(x);
    out[idx] = (p == 1) ? __float2bfloat16(x - __bfloat162float(h)) : h;
}

__global__ void k_xsplit(const float* __restrict__ xin,
                         __nv_bfloat16* __restrict__ hi, __nv_bfloat16* __restrict__ lo) {
    int idx = blockIdx.x * blockDim.x + threadIdx.x;
    if (idx >= N_NODES * KPAD) return;
    int n = idx >> 8, c = idx & 255;
    float x = (c < 200) ? xin[n * HDIM + c] : 0.f;
    __nv_bfloat16 h = __float2bfloat16(x);
    hi[idx] = h;
    lo[idx] = __float2bfloat16(x - __bfloat162float(h));
}

// ---------------- fp32 SIMT GEMM (conv0 only) ----------------
template<bool TB, int EPI>
__global__ void __launch_bounds__(256, 2) sgemm_k(
    const float* __restrict__ A, int lda, long long aStride,
    const float* __restrict__ B,
    const float* __restrict__ bias,
    float* __restrict__ C,
    int M, int N, int K,
    int ldc, int featLd, int featOff)
{
    constexpr int BM = 128, BN = 64, BK = 8;
    __shared__ __align__(16) float As[2][BK][132];
    __shared__ __align__(16) float Bs[2][BK][68];
    __shared__ float red[16][68];

    const int tid = threadIdx.x;
    const int tx = tid & 15, ty = tid >> 4;
    const int m0 = blockIdx.y * BM;
    const int n0 = blockIdx.x * BN;
    const float* Ab = A + (long long)blockIdx.z * aStride;

    const int arow = tid >> 1, akq = (tid & 1) * 4;
    const int bk   = tid >> 5, bn2 = (tid & 31) * 2;
    const int bn   = tid >> 2, bkq = (tid & 3) * 2;

    unsigned long long acc[4][4];
#pragma unroll
    for (int i = 0; i < 4; i++)
#pragma unroll
        for (int j = 0; j < 4; j++) acc[i][j] = 0ULL;

    const int KT = K / BK;

    float4 aR = make_float4(0.f, 0.f, 0.f, 0.f);
    float2 bR = make_float2(0.f, 0.f);
    {
        int row = m0 + arow;
        if (row < M) aR = *(const float4*)(Ab + (long long)row * lda + akq);
        if (!TB) { if (n0 + bn2 < N) bR = *(const float2*)(B + (long long)bk * N + n0 + bn2); }
        else     { if (n0 + bn  < N) bR = *(const float2*)(B + (long long)(n0 + bn) * K + bkq); }
    }
    As[0][akq + 0][arow] = aR.x; As[0][akq + 1][arow] = aR.y;
    As[0][akq + 2][arow] = aR.z; As[0][akq + 3][arow] = aR.w;
    if (!TB) { Bs[0][bk][bn2] = bR.x; Bs[0][bk][bn2 + 1] = bR.y; }
    else     { Bs[0][bkq][bn] = bR.x; Bs[0][bkq + 1][bn] = bR.y; }
    __syncthreads();

    for (int kt = 0; kt < KT; kt++) {
        const int cur = kt & 1;
        const int k0n = (kt + 1) * BK;
        if (kt + 1 < KT) {
            int row = m0 + arow;
            aR = make_float4(0.f, 0.f, 0.f, 0.f);
            bR = make_float2(0.f, 0.f);
            if (row < M) aR = *(const float4*)(Ab + (long long)row * lda + k0n + akq);
            if (!TB) { if (n0 + bn2 < N) bR = *(const float2*)(B + (long long)(k0n + bk) * N + n0 + bn2); }
            else     { if (n0 + bn  < N) bR = *(const float2*)(B + (long long)(n0 + bn) * K + k0n + bkq); }
        }
#pragma unroll
        for (int k = 0; k < BK; k++) {
            const float* ap_ = &As[cur][k][ty * 8];
            ulonglong2 a0 = *(const ulonglong2*)ap_;
            ulonglong2 a1 = *(const ulonglong2*)(ap_ + 4);
            float4 bv = *(const float4*)&Bs[cur][k][tx * 4];
            unsigned long long ap[4] = { a0.x, a0.y, a1.x, a1.y };
            unsigned long long bb[4] = { pack2(bv.x, bv.x), pack2(bv.y, bv.y),
                                         pack2(bv.z, bv.z), pack2(bv.w, bv.w) };
#pragma unroll
            for (int mp = 0; mp < 4; mp++)
#pragma unroll
                for (int j = 0; j < 4; j++)
                    FMA2(acc[mp][j], ap[mp], bb[j]);
        }
        if (kt + 1 < KT) {
            const int nb = cur ^ 1;
            As[nb][akq + 0][arow] = aR.x; As[nb][akq + 1][arow] = aR.y;
            As[nb][akq + 2][arow] = aR.z; As[nb][akq + 3][arow] = aR.w;
            if (!TB) { Bs[nb][bk][bn2] = bR.x; Bs[nb][bk][bn2 + 1] = bR.y; }
            else     { Bs[nb][bkq][bn] = bR.x; Bs[nb][bkq + 1][bn] = bR.y; }
        }
        __syncthreads();
    }

    if (EPI == 0) {
#pragma unroll
        for (int j = 0; j < 4; j++) {
            int col = n0 + tx * 4 + j;
            if (col >= N) continue;
            float bv = bias ? bias[col] : 0.f;
#pragma unroll
            for (int mp = 0; mp < 4; mp++) {
                union { unsigned long long u; float2 f; } cv; cv.u = acc[mp][j];
                int r = m0 + ty * 8 + mp * 2;
                if (r     < M) C[(long long)r * ldc + col]       = cv.f.x + bv;
                if (r + 1 < M) C[(long long)(r + 1) * ldc + col] = cv.f.y + bv;
            }
        }
    } else {
        float cmax[4] = { 0.f, 0.f, 0.f, 0.f };
#pragma unroll
        for (int j = 0; j < 4; j++) {
            int col = n0 + tx * 4 + j;
            float bv = (col < N) ? bias[col] : 0.f;
#pragma unroll
            for (int mp = 0; mp < 4; mp++) {
                union { unsigned long long u; float2 f; } cv; cv.u = acc[mp][j];
                int r = m0 + ty * 8 + mp * 2;
                if (r     < M) cmax[j] = fmaxf(cmax[j], cv.f.x + bv);
                if (r + 1 < M) cmax[j] = fmaxf(cmax[j], cv.f.y + bv);
            }
        }
#pragma unroll
        for (int j = 0; j < 4; j++) red[ty][tx * 4 + j] = cmax[j];
        __syncthreads();
        if (ty == 0) {
#pragma unroll
            for (int j = 0; j < 4; j++) {
                int col = n0 + tx * 4 + j;
                if (col >= N) continue;
                float mx = 0.f;
                for (int t2 = 0; t2 < 16; t2++) mx = fmaxf(mx, red[t2][tx * 4 + j]);
                atomicMax((unsigned int*)&C[(long long)blockIdx.z * featLd + featOff + col],
                          __float_as_uint(mx));
            }
        }
    }
}

// ---------------- CSR build ----------------
__global__ void k_hist(const int* __restrict__ ei, int* __restrict__ deg) {
    int i = blockIdx.x * blockDim.x + threadIdx.x;
    if (i < NEDGE) atomicAdd(&deg[ei[NEDGE + i]], 1);
}

__global__ void k_scan(const int* __restrict__ deg, int* __restrict__ rs,
                       int* __restrict__ cur, int n) {
    __shared__ int s[1024];
    __shared__ int carry;
    int t = threadIdx.x;
    if (t == 0) carry = 0;
    __syncthreads();
    for (int base = 0; base < n; base += 1024) {
        int v = (base + t < n) ? deg[base + t] : 0;
        s[t] = v;
        __syncthreads();
        for (int off = 1; off < 1024; off <<= 1) {
            int add = (t >= off) ? s[t - off] : 0;
            __syncthreads();
            s[t] += add;
            __syncthreads();
        }
        int c0 = carry;
        int ex = c0 + s[t] - v;
        if (base + t < n) { rs[base + t] = ex; cur[base + t] = ex; }
        __syncthreads();
        if (t == 0) carry = c0 + s[1023];
        __syncthreads();
    }
    if (t == 0) rs[n] = carry;
}

__global__ void k_fill(const int* __restrict__ ei, int* __restrict__ cur,
                       int* __restrict__ cs) {
    int i = blockIdx.x * blockDim.x + threadIdx.x;
    if (i < NEDGE) {
        int d = ei[NEDGE + i];
        int p = atomicAdd(&cur[d], 1);
        cs[p] = ei[i];
    }
}

// ---------------- segment-sum + bf16 split of agg ----------------
__global__ void k_agg(const float* __restrict__ m, const int* __restrict__ rs,
                      const int* __restrict__ cs,
                      __nv_bfloat16* __restrict__ ahi, __nv_bfloat16* __restrict__ alo) {
    int w = (blockIdx.x * blockDim.x + threadIdx.x) >> 5;
    int lane = threadIdx.x & 31;
    if (w >= N_NODES) return;
    int s = rs[w], e = rs[w + 1];
    float a[7] = {0, 0, 0, 0, 0, 0, 0};
    int i = s;
    for (; i + 1 < e; i += 2) {
        const float* r0 = m + (long long)cs[i]     * HDIM;
        const float* r1 = m + (long long)cs[i + 1] * HDIM;
        a[0] += r0[lane]       + r1[lane];
        a[1] += r0[lane +  32] + r1[lane +  32];
        a[2] += r0[lane +  64] + r1[lane +  64];
        a[3] += r0[lane +  96] + r1[lane +  96];
        a[4] += r0[lane + 128] + r1[lane + 128];
        a[5] += r0[lane + 160] + r1[lane + 160];
        if (lane < 8) a[6] += r0[lane + 192] + r1[lane + 192];
    }
    if (i < e) {
        const float* r0 = m + (long long)cs[i] * HDIM;
        a[0] += r0[lane];       a[1] += r0[lane + 32];  a[2] += r0[lane + 64];
        a[3] += r0[lane + 96];  a[4] += r0[lane + 128]; a[5] += r0[lane + 160];
        if (lane < 8) a[6] += r0[lane + 192];
    }
    long long o = (long long)w * KPAD + lane;
#pragma unroll
    for (int q = 0; q < 6; q++) {
        __nv_bfloat16 h = __float2bfloat16(a[q]);
        ahi[o + q * 32] = h;
        alo[o + q * 32] = __float2bfloat16(a[q] - __bfloat162float(h));
    }
    if (lane < 8) {
        __nv_bfloat16 h = __float2bfloat16(a[6]);
        ahi[o + 192] = h;
        alo[o + 192] = __float2bfloat16(a[6] - __bfloat162float(h));
    }
}

// ---------------- GRU gates (+ bias fold + bf16 split of new h) ----------------
__global__ void k_gates(const float* __restrict__ gi, const float* __restrict__ gh,
                        const float* __restrict__ bih, const float* __restrict__ bhh,
                        const float* __restrict__ hsrc, float* __restrict__ hdst,
                        __nv_bfloat16* __restrict__ hhi, __nv_bfloat16* __restrict__ hlo) {
    int idx = blockIdx.x * blockDim.x + threadIdx.x;
    if (idx >= N_NODES * HDIM) return;
    int n = idx / HDIM, c = idx - n * HDIM;
    const float* giN = gi + (long long)n * 600;
    const float* ghN = gh + (long long)n * 600;
    float r  = 1.f / (1.f + expf(-(giN[c] + bih[c] + ghN[c] + bhh[c])));
    float z  = 1.f / (1.f + expf(-(giN[200 + c] + bih[200 + c] + ghN[200 + c] + bhh[200 + c])));
    float nn = tanhf(giN[400 + c] + bih[400 + c] + r * (ghN[400 + c] + bhh[400 + c]));
    float h = (1.f - z) * nn + z * hsrc[idx];
    hdst[idx] = h;
    __nv_bfloat16 hb = __float2bfloat16(h);
    long long o = (long long)n * KPAD + c;
    hhi[o] = hb;
    hlo[o] = __float2bfloat16(h - __bfloat162float(hb));
}

// ---------------- misc data movement ----------------
__global__ void k_hp(const float* __restrict__ h, float* __restrict__ hp) {
    int idx = blockIdx.x * blockDim.x + threadIdx.x;
    if (idx >= BATCH * 207 * HDIM) return;
    int b = idx / (207 * HDIM);
    int rem = idx - b * 207 * HDIM;
    int r = rem / HDIM, c = rem - r * HDIM;
    hp[idx] = (r == 0 || r == 206) ? 0.f
              : h[((long long)b * NPER + (r - 1)) * HDIM + c];
}

__global__ void k_wt(const float* __restrict__ w, float* __restrict__ wt,
                     int CO, int CI, int KK) {
    int idx = blockIdx.x * blockDim.x + threadIdx.x;
    if (idx >= CO * CI * KK) return;
    int co = idx / (CI * KK);
    int rem = idx - co * CI * KK;
    int ci = rem / KK, k = rem - ci * KK;
    wt[(long long)co * CI * KK + k * CI + ci] = w[idx];
}

// ---------------- fused FC head ----------------
__global__ void k_fc(const float* __restrict__ feats,
                     const float* __restrict__ w1, const float* __restrict__ b1,
                     const float* __restrict__ w2, const float* __restrict__ b2,
                     const float* __restrict__ w3, const float* __restrict__ b3,
                     float* __restrict__ out) {
    int b = blockIdx.x;
    int tid = threadIdx.x;
    int lane = tid & 31, wrp = tid >> 5;
    __shared__ float sf[800];
    __shared__ float s1[256];
    __shared__ float s2[128];
    for (int i = tid; i < 800; i += 256) sf[i] = feats[b * 800 + i];
    __syncthreads();
    for (int jj = 0; jj < 32; jj++) {
        int j = wrp * 32 + jj;
        float a = 0.f;
        for (int i = lane; i < 800; i += 32) a += sf[i] * w1[(long long)j * 800 + i];
        for (int o = 16; o; o >>= 1) a += __shfl_down_sync(0xffffffffu, a, o);
        if (lane == 0) s1[j] = fmaxf(a + b1[j], 0.f);
    }
    __syncthreads();
    if (tid < 128) {
        float a = b2[tid];
        for (int i = 0; i < 256; i++) a += s1[i] * w2[tid * 256 + i];
        s2[tid] = fmaxf(a, 0.f);
    }
    __syncthreads();
    if (tid < 2) {
        float a = b3[tid];
        for (int i = 0; i < 128; i++) a += s2[i] * w3[tid * 128 + i];
        out[b * 2 + tid] = a;
    }
}

// ---------------- launcher ----------------
extern "C" void kernel_launch(void* const* d_in, const int* in_sizes, int n_in,
                              void* d_out, int out_size) {
    const float* x     = (const float*)d_in[0];
    const int*   ei    = (const int*)  d_in[1];
    const int*   ids   = (const int*)  d_in[2];
    const float* etab  = (const float*)d_in[3];
    const float* ggcw  = (const float*)d_in[4];
    const float* wih   = (const float*)d_in[5];
    const float* whh   = (const float*)d_in[6];
    const float* bih   = (const float*)d_in[7];
    const float* bhh   = (const float*)d_in[8];
    const float* c0w   = (const float*)d_in[9];
    const float* c0b   = (const float*)d_in[10];
    const float* c1w   = (const float*)d_in[11];
    const float* c1b   = (const float*)d_in[12];
    const float* c2w   = (const float*)d_in[13];
    const float* c2b   = (const float*)d_in[14];
    const float* c3w   = (const float*)d_in[15];
    const float* c3b   = (const float*)d_in[16];
    const float* f1w   = (const float*)d_in[17];
    const float* f1b   = (const float*)d_in[18];
    const float* f2w   = (const float*)d_in[19];
    const float* f2b   = (const float*)d_in[20];
    const float* f3w   = (const float*)d_in[21];
    const float* f3b   = (const float*)d_in[22];
    float* out = (float*)d_out;

    float *h0, *h1, *mm, *gi, *gh, *hp, *w0t, *feats;
    int *deg, *rs, *cur, *cs;
    __nv_bfloat16 *ehi, *elo, *w1b, *w2b, *w3b;
    __nv_bfloat16 *hhi, *hlo, *ahi, *alo, *wg, *wi, *wh;
    cudaGetSymbolAddress((void**)&h0,   g_h0);
    cudaGetSymbolAddress((void**)&h1,   g_h1);
    cudaGetSymbolAddress((void**)&mm,   g_m);
    cudaGetSymbolAddress((void**)&gi,   g_gi);
    cudaGetSymbolAddress((void**)&gh,   g_gh);
    cudaGetSymbolAddress((void**)&hp,   g_hp);
    cudaGetSymbolAddress((void**)&w0t,  g_w0t);
    cudaGetSymbolAddress((void**)&feats,g_feats);
    cudaGetSymbolAddress((void**)&deg,  g_deg);
    cudaGetSymbolAddress((void**)&rs,   g_rs);
    cudaGetSymbolAddress((void**)&cur,  g_cur);
    cudaGetSymbolAddress((void**)&cs,   g_csrc);
    cudaGetSymbolAddress((void**)&ehi,  g_ehi);
    cudaGetSymbolAddress((void**)&elo,  g_elo);
    cudaGetSymbolAddress((void**)&w1b,  g_w1b);
    cudaGetSymbolAddress((void**)&w2b,  g_w2b);
    cudaGetSymbolAddress((void**)&w3b,  g_w3b);
    cudaGetSymbolAddress((void**)&hhi,  g_hhi);
    cudaGetSymbolAddress((void**)&hlo,  g_hlo);
    cudaGetSymbolAddress((void**)&ahi,  g_ahi);
    cudaGetSymbolAddress((void**)&alo,  g_alo);
    cudaGetSymbolAddress((void**)&wg,   g_wg);
    cudaGetSymbolAddress((void**)&wi,   g_wi);
    cudaGetSymbolAddress((void**)&wh,   g_wh);

    const int CONV_SMEM = 36864 + 59904 + 832 + 832;   // 98432 B
    const int GGC_SMEM  = 36864 + 59904;               // 96768 B
    cudaFuncSetAttribute(conv3x_hmma_k, cudaFuncAttributeMaxDynamicSharedMemorySize, CONV_SMEM);
    cudaFuncSetAttribute(ggc_hmma_k,    cudaFuncAttributeMaxDynamicSharedMemorySize, GGC_SMEM);
    cudaFuncSetAttribute(ggc_mh_k,      cudaFuncAttributeMaxDynamicSharedMemorySize, GGC_SMEM);

    // side stream + events (created once; host resources, no device allocs)
    static cudaStream_t s2 = nullptr;
    static cudaEvent_t ev1 = nullptr, ev2 = nullptr;
    if (!s2) {
        cudaStreamCreateWithFlags(&s2, cudaStreamNonBlocking);
        cudaEventCreateWithFlags(&ev1, cudaEventDisableTiming);
        cudaEventCreateWithFlags(&ev2, cudaEventDisableTiming);
    }

    // ---- default stream: feats zero, then fork conv branch ----
    cudaMemsetAsync(feats, 0, BATCH * 800 * sizeof(float));
    cudaEventRecord(ev1, 0);
    cudaStreamWaitEvent(s2, ev1, 0);

    // ---- side stream: conv1/2/3 branch (independent of GGC) ----
    k_embed2<<<BATCH * SEQ + 8, 192, 0, s2>>>(ids, etab, ehi, elo);
    k_wsplit<<<(200 * 768 * 3 + 255) / 256, 256, 0, s2>>>(c1w, w1b, 3);
    k_wsplit<<<(200 * 768 * 4 + 255) / 256, 256, 0, s2>>>(c2w, w2b, 4);
    k_wsplit<<<(200 * 768 * 5 + 255) / 256, 256, 0, s2>>>(c3w, w3b, 5);
    {
        Conv3Args ca;
        ca.wb[0] = w1b; ca.wb[1] = w2b; ca.wb[2] = w3b;
        ca.bias[0] = c1b; ca.bias[1] = c2b; ca.bias[2] = c3b;
        conv3x_hmma_k<<<dim3(3, 4, BATCH), 256, CONV_SMEM, s2>>>(ehi, elo, ca, feats);
    }
    cudaEventRecord(ev2, s2);

    // ---- default stream: CSR + GGC prep ----
    cudaMemsetAsync(deg, 0, N_NODES * sizeof(int));
    k_hist<<<(NEDGE + 255) / 256, 256>>>(ei, deg);
    k_scan<<<1, 1024>>>(deg, rs, cur, N_NODES);
    k_fill<<<(NEDGE + 255) / 256, 256>>>(ei, cur, cs);
    cudaMemcpyAsync(h0, x, (size_t)N_NODES * HDIM * sizeof(float),
                    cudaMemcpyDeviceToDevice);
    k_xsplit<<<(N_NODES * KPAD + 255) / 256, 256>>>(x, hhi, hlo);
    k_wggc<<<(NLAYERS * 208 * 768 + 255) / 256, 256>>>(ggcw, wg);
    k_wgru<<<(624 * 768 + 255) / 256, 256>>>(wih, wi);
    k_wgru<<<(624 * 768 + 255) / 256, 256>>>(whh, wh);
    k_wt<<<(200 * 200 * 3 + 255) / 256, 256>>>(c0w, w0t, 200, 200, 3);

    // ---- gated graph conv: 6 layers (HMMA bf16x3) ----
    float* hc = h0;
    float* hn = h1;
    for (int l = 0; l < NLAYERS; l++) {
        // fused: m = h @ ggc_w[l]  and  gh = h @ whh^T  (same A)
        ggc_mh_k<<<dim3(4, NPER), 256, GGC_SMEM>>>(hhi, hlo,
                                                   wg + (long long)l * 208 * 768, wh,
                                                   mm, gh);
        // agg = segment_sum(m[src], dst), split to bf16
        k_agg<<<(N_NODES + 7) / 8, 256>>>(mm, rs, cs, ahi, alo);
        // gi = agg @ wih^T
        ggc_hmma_k<<<dim3(3, NPER), 256, GGC_SMEM>>>(ahi, alo, wi, gi, 600, 600);
        // GRU update (+bias fold) and re-split h
        k_gates<<<(N_NODES * HDIM + 255) / 256, 256>>>(gi, gh, bih, bhh, hc, hn, hhi, hlo);
        float* t = hc; hc = hn; hn = t;
    }

    // ---- conv0 (fp32 SIMT, fused bias+ReLU+max; feats cols 0..199) ----
    k_hp<<<(BATCH * 207 * HDIM + 255) / 256, 256>>>(hc, hp);
    sgemm_k<true, 1><<<dim3(4, 2, BATCH), 256>>>(hp, 200, 207LL * 200, w0t, c0b, feats,
                                                 205, 200, 600, 0, 800, 0);

    // ---- join conv branch, then FC head ----
    cudaStreamWaitEvent(0, ev2, 0);
    k_fc<<<BATCH, 256>>>(feats, f1w, f1b, f2w, f2b, f3w, f3b, out);
}

// round 11
// speedup vs baseline: 2.8464x; 1.2000x over previous
#include <cuda_runtime.h>
#include <cuda_bf16.h>
#include <cuda_fp16.h>
#include <cstdint>

// ---------------- problem constants ----------------
#define N_NODES 26240      // B * N_PER = 128 * 205 (exactly 205 blocks of 128)
#define HDIM    200
#define NEDGE   209920
#define BATCH   128
#define NPER    205
#define EMBD    768
#define SEQ     512
#define NLAYERS 6
#define KPAD    256        // padded K per bf16x3 pass (GGC)

// ---------------- static device scratch ----------------
__device__ float g_h0[N_NODES * HDIM];
__device__ float g_h1[N_NODES * HDIM];
__device__ float g_m [N_NODES * HDIM];
__device__ float g_gi[N_NODES * 3 * HDIM];
__device__ float g_gh[N_NODES * 3 * HDIM];
__device__ float g_hp [BATCH * 207 * HDIM];             // zero-padded conv0 input
__device__ float g_w0t[200 * 600];
__device__ float g_feats[BATCH * 800];
__device__ int   g_deg[N_NODES];
__device__ int   g_rs [N_NODES + 1];
__device__ int   g_cur[N_NODES];
__device__ int   g_csrc[NEDGE];

// GGC bf16 split operands, K-padded to 256 (pads stay zero after init)
__device__ __align__(16) __nv_bfloat16 g_hhi[(size_t)N_NODES * KPAD];
__device__ __align__(16) __nv_bfloat16 g_hlo[(size_t)N_NODES * KPAD];
__device__ __align__(16) __nv_bfloat16 g_ahi[(size_t)N_NODES * KPAD];
__device__ __align__(16) __nv_bfloat16 g_alo[(size_t)N_NODES * KPAD];
// GGC weights expanded: [Npad][768] = [Whi(0:256) | Wlo(256:512) | Whi(512:768)]
__device__ __align__(16) __nv_bfloat16 g_wg[NLAYERS * 208 * 768];   // ggc_w[l]^T
__device__ __align__(16) __nv_bfloat16 g_wi[624 * 768];             // wih
__device__ __align__(16) __nv_bfloat16 g_wh[624 * 768];             // whh

// fp16 embeddings, time-major [b][t][c], +8 zero rows for tap overrun
__device__ __align__(16) __half g_e16[((size_t)BATCH * SEQ + 8) * EMBD];
// fp16 conv weights: [200][2K] = [Wh | Wl], tap-major K per pass
__device__ __align__(16) __half g_w1h[200 * 2 * 2304];
__device__ __align__(16) __half g_w2h[200 * 2 * 3072];
__device__ __align__(16) __half g_w3h[200 * 2 * 3840];

// ---------------- packed fp32x2 helpers (sm_100+) ----------------
#define FMA2(d, a, b) asm("fma.rn.f32x2 %0, %1, %2, %0;" : "+l"(d) : "l"(a), "l"(b))

__device__ __forceinline__ unsigned long long pack2(float x, float y) {
    unsigned long long r;
    asm("mov.b64 %0, {%1, %2};" : "=l"(r) : "r"(__float_as_uint(x)), "r"(__float_as_uint(y)));
    return r;
}

// ---------------- warp-level MMAs (compute_100-safe PTX) ----------------
#define MMA_BF16(d, a, b0, b1) asm volatile(                           \
    "mma.sync.aligned.m16n8k16.row.col.f32.bf16.bf16.f32 "             \
    "{%0,%1,%2,%3}, {%4,%5,%6,%7}, {%8,%9}, {%0,%1,%2,%3};"            \
    : "+f"((d)[0]), "+f"((d)[1]), "+f"((d)[2]), "+f"((d)[3])           \
    : "r"((a)[0]), "r"((a)[1]), "r"((a)[2]), "r"((a)[3]),              \
      "r"(b0), "r"(b1))

#define MMA_F16(d, a, b0, b1) asm volatile(                            \
    "mma.sync.aligned.m16n8k16.row.col.f32.f16.f16.f32 "               \
    "{%0,%1,%2,%3}, {%4,%5,%6,%7}, {%8,%9}, {%0,%1,%2,%3};"            \
    : "+f"((d)[0]), "+f"((d)[1]), "+f"((d)[2]), "+f"((d)[3])           \
    : "r"((a)[0]), "r"((a)[1]), "r"((a)[2]), "r"((a)[3]),              \
      "r"(b0), "r"(b1))

// ---------------- cp.async helpers (sm_80+ PTX) ----------------
#define CP16(dst, src) asm volatile("cp.async.ca.shared.global [%0], [%1], 16;" \
                                    :: "r"(dst), "l"(src))
#define CP_COMMIT() asm volatile("cp.async.commit_group;" ::: "memory")
#define CP_WAIT0()  asm volatile("cp.async.wait_group 0;" ::: "memory")

__device__ __forceinline__ uint32_t s2u(const void* p) {
    return (uint32_t)__cvta_generic_to_shared(p);
}

// ---------------- GGC GEMM: gi = agg @ wih^T (bf16x3) ----------------
// grid (3 n-tiles, 205 m-tiles). 256 threads = 8 warps (4m x 2n). K3 = 768.
__global__ void __launch_bounds__(256, 1) ggc_hmma_k(
    const __nv_bfloat16* __restrict__ Ahi,
    const __nv_bfloat16* __restrict__ Alo,
    const __nv_bfloat16* __restrict__ B,
    float* __restrict__ C, int N, int ldc)
{
    extern __shared__ __align__(16) char dsm[];
    constexpr int ASTR = 72, BSTR = 72;
    __nv_bfloat16* As = (__nv_bfloat16*)dsm;                 // [2][128][72]
    __nv_bfloat16* Bs = (__nv_bfloat16*)(dsm + 36864);       // [2][208][72]

    const int tid = threadIdx.x;
    const int lane = tid & 31, wid = tid >> 5;
    const int wm = wid & 3, wn = wid >> 2;
    const int g = lane >> 2, t2 = (lane & 3) * 2;
    const int m0 = blockIdx.y * 128;
    const int n0 = blockIdx.x * 208;
    const uint32_t asb = s2u(As), bsb = s2u(Bs);

    auto copy_tile = [&](int kt, int buf) {
        const int p = kt >> 2;
        const int koff = (kt & 3) * 64;
        const __nv_bfloat16* src = (p < 2) ? Ahi : Alo;
        const uint32_t ab = asb + buf * 128 * ASTR * 2;
        const uint32_t bb = bsb + buf * 208 * BSTR * 2;
#pragma unroll
        for (int i = 0; i < 4; i++) {
            int u = tid + i * 256;
            int row = u >> 3, ch = u & 7;
            CP16(ab + (row * ASTR + ch * 8) * 2,
                 src + (long long)(m0 + row) * KPAD + koff + ch * 8);
        }
        const int kg = kt * 64;
#pragma unroll
        for (int i = 0; i < 7; i++) {
            int u = tid + i * 256;
            if (u < 1664) {
                int row = u >> 3, ch = u & 7;
                CP16(bb + (row * BSTR + ch * 8) * 2,
                     B + (long long)(n0 + row) * 768 + kg + ch * 8);
            }
        }
    };

    float acc[2][13][4];
#pragma unroll
    for (int i = 0; i < 2; i++)
#pragma unroll
        for (int j = 0; j < 13; j++)
#pragma unroll
            for (int q = 0; q < 4; q++) acc[i][j][q] = 0.f;

    copy_tile(0, 0); CP_COMMIT(); CP_WAIT0();
    __syncthreads();

#pragma unroll 1
    for (int kt = 0; kt < 12; kt++) {
        const int buf = kt & 1;
        const bool more = (kt + 1 < 12);
        if (more) { copy_tile(kt + 1, buf ^ 1); CP_COMMIT(); }

        const __nv_bfloat16* Ab = As + buf * 128 * ASTR;
        const __nv_bfloat16* Bb = Bs + buf * 208 * BSTR;
#pragma unroll
        for (int ks = 0; ks < 4; ks++) {
            const int ko = ks * 16;
            uint32_t a[2][4];
#pragma unroll
            for (int i = 0; i < 2; i++) {
                const int r = wm * 32 + i * 16 + g;
                a[i][0] = *(const uint32_t*)(Ab + (r)     * ASTR + ko + t2);
                a[i][1] = *(const uint32_t*)(Ab + (r + 8) * ASTR + ko + t2);
                a[i][2] = *(const uint32_t*)(Ab + (r)     * ASTR + ko + t2 + 8);
                a[i][3] = *(const uint32_t*)(Ab + (r + 8) * ASTR + ko + t2 + 8);
            }
            uint32_t bf[13][2];
#pragma unroll
            for (int j = 0; j < 13; j++) {
                const int n = wn * 104 + j * 8 + g;
                bf[j][0] = *(const uint32_t*)(Bb + n * BSTR + ko + t2);
                bf[j][1] = *(const uint32_t*)(Bb + n * BSTR + ko + t2 + 8);
            }
#pragma unroll
            for (int j = 0; j < 13; j++) {
                MMA_BF16(acc[0][j], a[0], bf[j][0], bf[j][1]);
                MMA_BF16(acc[1][j], a[1], bf[j][0], bf[j][1]);
            }
        }
        if (more) CP_WAIT0();
        __syncthreads();
    }

#pragma unroll
    for (int i = 0; i < 2; i++) {
        const int r = m0 + wm * 32 + i * 16 + g;
#pragma unroll
        for (int j = 0; j < 13; j++) {
            const int col = n0 + wn * 104 + j * 8 + t2;
            if (col < N) {
                C[(long long)r * ldc + col]       = acc[i][j][0];
                C[(long long)(r + 8) * ldc + col] = acc[i][j][2];
            }
            if (col + 1 < N) {
                C[(long long)r * ldc + col + 1]       = acc[i][j][1];
                C[(long long)(r + 8) * ldc + col + 1] = acc[i][j][3];
            }
        }
    }
}

// ---------------- fused m + gh GEMM (same A = h, bf16x3) ----------------
// grid (4, 205): bx==0 -> m = h @ ggc_w[l] (N=200); bx in 1..3 -> gh slice.
__global__ void __launch_bounds__(256, 1) ggc_mh_k(
    const __nv_bfloat16* __restrict__ Ahi,
    const __nv_bfloat16* __restrict__ Alo,
    const __nv_bfloat16* __restrict__ wgl,    // [208][768] layer slice
    const __nv_bfloat16* __restrict__ wh,     // [624][768]
    float* __restrict__ Cm,
    float* __restrict__ Cg)
{
    extern __shared__ __align__(16) char dsm[];
    constexpr int ASTR = 72, BSTR = 72;
    __nv_bfloat16* As = (__nv_bfloat16*)dsm;
    __nv_bfloat16* Bs = (__nv_bfloat16*)(dsm + 36864);

    const int tid = threadIdx.x;
    const int lane = tid & 31, wid = tid >> 5;
    const int wm = wid & 3, wn = wid >> 2;
    const int g = lane >> 2, t2 = (lane & 3) * 2;
    const int m0 = blockIdx.y * 128;
    const int bx = blockIdx.x;
    const uint32_t asb = s2u(As), bsb = s2u(Bs);

    const __nv_bfloat16* B = (bx == 0) ? wgl : (wh + (long long)(bx - 1) * 208 * 768);
    float* C      = (bx == 0) ? Cm  : Cg;
    const int ldc = (bx == 0) ? 200 : 600;
    const int N   = (bx == 0) ? 200 : 600;
    const int cb  = (bx == 0) ? 0   : (bx - 1) * 208;

    auto copy_tile = [&](int kt, int buf) {
        const int p = kt >> 2;
        const int koff = (kt & 3) * 64;
        const __nv_bfloat16* src = (p < 2) ? Ahi : Alo;
        const uint32_t ab = asb + buf * 128 * ASTR * 2;
        const uint32_t bb = bsb + buf * 208 * BSTR * 2;
#pragma unroll
        for (int i = 0; i < 4; i++) {
            int u = tid + i * 256;
            int row = u >> 3, ch = u & 7;
            CP16(ab + (row * ASTR + ch * 8) * 2,
                 src + (long long)(m0 + row) * KPAD + koff + ch * 8);
        }
        const int kg = kt * 64;
#pragma unroll
        for (int i = 0; i < 7; i++) {
            int u = tid + i * 256;
            if (u < 1664) {
                int row = u >> 3, ch = u & 7;
                CP16(bb + (row * BSTR + ch * 8) * 2,
                     B + (long long)row * 768 + kg + ch * 8);
            }
        }
    };

    float acc[2][13][4];
#pragma unroll
    for (int i = 0; i < 2; i++)
#pragma unroll
        for (int j = 0; j < 13; j++)
#pragma unroll
            for (int q = 0; q < 4; q++) acc[i][j][q] = 0.f;

    copy_tile(0, 0); CP_COMMIT(); CP_WAIT0();
    __syncthreads();

#pragma unroll 1
    for (int kt = 0; kt < 12; kt++) {
        const int buf = kt & 1;
        const bool more = (kt + 1 < 12);
        if (more) { copy_tile(kt + 1, buf ^ 1); CP_COMMIT(); }

        const __nv_bfloat16* Ab = As + buf * 128 * ASTR;
        const __nv_bfloat16* Bb = Bs + buf * 208 * BSTR;
#pragma unroll
        for (int ks = 0; ks < 4; ks++) {
            const int ko = ks * 16;
            uint32_t a[2][4];
#pragma unroll
            for (int i = 0; i < 2; i++) {
                const int r = wm * 32 + i * 16 + g;
                a[i][0] = *(const uint32_t*)(Ab + (r)     * ASTR + ko + t2);
                a[i][1] = *(const uint32_t*)(Ab + (r + 8) * ASTR + ko + t2);
                a[i][2] = *(const uint32_t*)(Ab + (r)     * ASTR + ko + t2 + 8);
                a[i][3] = *(const uint32_t*)(Ab + (r + 8) * ASTR + ko + t2 + 8);
            }
            uint32_t bf[13][2];
#pragma unroll
            for (int j = 0; j < 13; j++) {
                const int n = wn * 104 + j * 8 + g;
                bf[j][0] = *(const uint32_t*)(Bb + n * BSTR + ko + t2);
                bf[j][1] = *(const uint32_t*)(Bb + n * BSTR + ko + t2 + 8);
            }
#pragma unroll
            for (int j = 0; j < 13; j++) {
                MMA_BF16(acc[0][j], a[0], bf[j][0], bf[j][1]);
                MMA_BF16(acc[1][j], a[1], bf[j][0], bf[j][1]);
            }
        }
        if (more) CP_WAIT0();
        __syncthreads();
    }

#pragma unroll
    for (int i = 0; i < 2; i++) {
        const int r = m0 + wm * 32 + i * 16 + g;
#pragma unroll
        for (int j = 0; j < 13; j++) {
            const int col = cb + wn * 104 + j * 8 + t2;
            if (col < N) {
                C[(long long)r * ldc + col]       = acc[i][j][0];
                C[(long long)(r + 8) * ldc + col] = acc[i][j][2];
            }
            if (col + 1 < N) {
                C[(long long)r * ldc + col + 1]       = acc[i][j][1];
                C[(long long)(r + 8) * ldc + col + 1] = acc[i][j][3];
            }
        }
    }
}

// ---------------- fused conv1/2/3: fp16 hi/lo x2 conv-as-GEMM ----------------
// A = fp16(E) (single array, both passes); B = [Wh | Wl].
struct Conv3Args {
    const __half* wb[3];
    const float* bias[3];
};
// grid (3 convs, 4 m-tiles, 128 batches)
__global__ void __launch_bounds__(256, 1) conv3h_k(
    const __half* __restrict__ e16,
    Conv3Args args,
    float* __restrict__ feats)
{
    extern __shared__ __align__(16) char dsm[];
    constexpr int ASTR = 72, BSTR = 72;
    __half* As = (__half*)dsm;
    __half* Bs = (__half*)(dsm + 36864);
    float* smax  = (float*)(dsm + 36864 + 59904);
    float* sbias = smax + 208;

    const int cid = blockIdx.x;
    const int M   = (cid == 0) ? 510 : (cid == 1) ? 509 : 508;
    const int K2  = (cid == 0) ? 4608 : (cid == 1) ? 6144 : 7680;   // 2 * 768 * taps
    const int featOff = 200 + cid * 200;
    const __half* wb = args.wb[cid];
    const float* bias = args.bias[cid];

    const int tid = threadIdx.x;
    const int lane = tid & 31, wid = tid >> 5;
    const int wm = wid & 3, wn = wid >> 2;
    const int g = lane >> 2, t2 = (lane & 3) * 2;
    const int b = blockIdx.z, m0 = blockIdx.y * 128;
    const int TKp = K2 / 128;          // 64-tiles per pass (= taps*12)
    const int T   = K2 / 64;           // total tiles
    const uint32_t asb = s2u(As), bsb = s2u(Bs);

    if (tid < 208) { smax[tid] = 0.f; sbias[tid] = (tid < 200) ? bias[tid] : 0.f; }

    auto copy_tile = [&](int kt, int buf) {
        int p = kt / TKp;
        int rem = kt - p * TKp;           // A depends only on rem (A = Ah both passes)
        int kk = rem / 12;
        int c0 = (rem - kk * 12) * 64;
        long long abase = ((long long)(b * SEQ + m0 + kk)) * EMBD + c0;
        const uint32_t ab = asb + buf * 128 * ASTR * 2;
        const uint32_t bb = bsb + buf * 208 * BSTR * 2;
#pragma unroll
        for (int i = 0; i < 4; i++) {
            int u = tid + i * 256;
            int row = u >> 3, ch = u & 7;
            CP16(ab + (row * ASTR + ch * 8) * 2,
                 e16 + abase + (long long)row * EMBD + ch * 8);
        }
        int kg = kt * 64;
#pragma unroll
        for (int i = 0; i < 7; i++) {
            int u = tid + i * 256;
            if (u < 1600) {
                int row = u >> 3, ch = u & 7;
                CP16(bb + (row * BSTR + ch * 8) * 2,
                     wb + (long long)row * K2 + kg + ch * 8);
            }
        }
    };

    float acc[2][13][4];
#pragma unroll
    for (int i = 0; i < 2; i++)
#pragma unroll
        for (int j = 0; j < 13; j++)
#pragma unroll
            for (int q = 0; q < 4; q++) acc[i][j][q] = 0.f;

    copy_tile(0, 0); CP_COMMIT(); CP_WAIT0();
    __syncthreads();

#pragma unroll 1
    for (int kt = 0; kt < T; kt++) {
        const int buf = kt & 1;
        const bool more = (kt + 1 < T);
        if (more) { copy_tile(kt + 1, buf ^ 1); CP_COMMIT(); }

        const __half* Ab = As + buf * 128 * ASTR;
        const __half* Bb = Bs + buf * 208 * BSTR;
#pragma unroll
        for (int ks = 0; ks < 4; ks++) {
            const int ko = ks * 16;
            uint32_t a[2][4];
#pragma unroll
            for (int i = 0; i < 2; i++) {
                const int r = wm * 32 + i * 16 + g;
                a[i][0] = *(const uint32_t*)(Ab + (r)     * ASTR + ko + t2);
                a[i][1] = *(const uint32_t*)(Ab + (r + 8) * ASTR + ko + t2);
                a[i][2] = *(const uint32_t*)(Ab + (r)     * ASTR + ko + t2 + 8);
                a[i][3] = *(const uint32_t*)(Ab + (r + 8) * ASTR + ko + t2 + 8);
            }
            uint32_t bf[13][2];
#pragma unroll
            for (int j = 0; j < 13; j++) {
                const int n = wn * 104 + j * 8 + g;
                bf[j][0] = *(const uint32_t*)(Bb + n * BSTR + ko + t2);
                bf[j][1] = *(const uint32_t*)(Bb + n * BSTR + ko + t2 + 8);
            }
#pragma unroll
            for (int j = 0; j < 13; j++) {
                MMA_F16(acc[0][j], a[0], bf[j][0], bf[j][1]);
                MMA_F16(acc[1][j], a[1], bf[j][0], bf[j][1]);
            }
        }
        if (more) CP_WAIT0();
        __syncthreads();
    }

    const int valid = (M - m0 < 128) ? (M - m0) : 128;
#pragma unroll
    for (int j = 0; j < 13; j++) {
        float v0 = -1e30f, v1 = -1e30f;
#pragma unroll
        for (int i = 0; i < 2; i++) {
            const int r0 = wm * 32 + i * 16 + g;
            if (r0 < valid)     { v0 = fmaxf(v0, acc[i][j][0]); v1 = fmaxf(v1, acc[i][j][1]); }
            if (r0 + 8 < valid) { v0 = fmaxf(v0, acc[i][j][2]); v1 = fmaxf(v1, acc[i][j][3]); }
        }
#pragma unroll
        for (int o = 4; o <= 16; o <<= 1) {
            v0 = fmaxf(v0, __shfl_xor_sync(~0u, v0, o));
            v1 = fmaxf(v1, __shfl_xor_sync(~0u, v1, o));
        }
        if (g == 0) {
            const int col = wn * 104 + j * 8 + t2;
            if (col < 200) {
                float r = fmaxf(v0 + sbias[col], 0.f);
                atomicMax((unsigned int*)&smax[col], __float_as_uint(r));
            }
            if (col + 1 < 200) {
                float r = fmaxf(v1 + sbias[col + 1], 0.f);
                atomicMax((unsigned int*)&smax[col + 1], __float_as_uint(r));
            }
        }
    }
    __syncthreads();
    if (tid < 200)
        atomicMax((unsigned int*)&feats[(long long)b * 800 + featOff + tid],
                  __float_as_uint(smax[tid]));
}

// ---------------- fp16 embed (single array) ----------------
__global__ void k_embed16(const int* __restrict__ ids, const float* __restrict__ tbl,
                          __half* __restrict__ e16) {
    int row = blockIdx.x;
    int t = threadIdx.x;                   // 192 threads, one float4 each
    long long o = (long long)row * EMBD;
    if (row >= BATCH * SEQ) {
        if (t < 96) {
            ((uint2*)(e16 + o))[t * 2]     = make_uint2(0, 0);
            ((uint2*)(e16 + o))[t * 2 + 1] = make_uint2(0, 0);
        }
        return;
    }
    long long id = ids[row];
    float4 v = ((const float4*)(tbl + id * EMBD))[t];
    __half2 h01 = __floats2half2_rn(v.x, v.y);
    __half2 h23 = __floats2half2_rn(v.z, v.w);
    uint2 hv;
    hv.x = *(uint32_t*)&h01; hv.y = *(uint32_t*)&h23;
    ((uint2*)(e16 + o))[t] = hv;
}

// w: [200][768][KK] fp32 -> wb: [200][2K] fp16, [Wh | Wl], tap-major K
__global__ void k_wsplit16(const float* __restrict__ w, __half* __restrict__ wb, int KK) {
    int K = 768 * KK;
    int idx = blockIdx.x * blockDim.x + threadIdx.x;
    if (idx >= 200 * K) return;
    int co = idx / K, r = idx - co * K;
    int kk = r / 768, ci = r - kk * 768;
    float x = w[(co * 768 + ci) * KK + kk];
    __half h = __float2half(x);
    __half l = __float2half(x - __half2float(h));
    long long base = (long long)co * 2 * K + r;
    wb[base] = h; wb[base + K] = l;
}

// ---------------- GGC bf16 split precompute ----------------
__global__ void k_wggc(const float* __restrict__ w, __nv_bfloat16* __restrict__ out) {
    int idx = blockIdx.x * blockDim.x + threadIdx.x;
    if (idx >= NLAYERS * 208 * 768) return;
    int l = idx / (208 * 768);
    int rem = idx - l * 208 * 768;
    int n = rem / 768, col = rem - n * 768;
    int p = col >> 8, kk = col & 255;
    float x = (n < 200 && kk < 200) ? w[(long long)l * 40000 + kk * 200 + n] : 0.f;
    __nv_bfloat16 h = __float2bfloat16(x);
    out[idx] = (p == 1) ? __float2bfloat16(x - __bfloat162float(h)) : h;
}

__global__ void k_wgru(const float* __restrict__ w, __nv_bfloat16* __restrict__ out) {
    int idx = blockIdx.x * blockDim.x + threadIdx.x;
    if (idx >= 624 * 768) return;
    int n = idx / 768, col = idx - n * 768;
    int p = col >> 8, kk = col & 255;
    float x = (n < 600 && kk < 200) ? w[n * 200 + kk] : 0.f;
    __nv_bfloat16 h = __float2bfloat16(x);
    out[idx] = (p == 1) ? __float2bfloat16(x - __bfloat162float(h)) : h;
}

__global__ void k_xsplit(const float* __restrict__ xin,
                         __nv_bfloat16* __restrict__ hi, __nv_bfloat16* __restrict__ lo) {
    int idx = blockIdx.x * blockDim.x + threadIdx.x;
    if (idx >= N_NODES * KPAD) return;
    int n = idx >> 8, c = idx & 255;
    float x = (c < 200) ? xin[n * HDIM + c] : 0.f;
    __nv_bfloat16 h = __float2bfloat16(x);
    hi[idx] = h;
    lo[idx] = __float2bfloat16(x - __bfloat162float(h));
}

// ---------------- fp32 SIMT GEMM (conv0 only) ----------------
template<bool TB, int EPI>
__global__ void __launch_bounds__(256, 2) sgemm_k(
    const float* __restrict__ A, int lda, long long aStride,
    const float* __restrict__ B,
    const float* __restrict__ bias,
    float* __restrict__ C,
    int M, int N, int K,
    int ldc, int featLd, int featOff)
{
    constexpr int BM = 128, BN = 64, BK = 8;
    __shared__ __align__(16) float As[2][BK][132];
    __shared__ __align__(16) float Bs[2][BK][68];
    __shared__ float red[16][68];

    const int tid = threadIdx.x;
    const int tx = tid & 15, ty = tid >> 4;
    const int m0 = blockIdx.y * BM;
    const int n0 = blockIdx.x * BN;
    const float* Ab = A + (long long)blockIdx.z * aStride;

    const int arow = tid >> 1, akq = (tid & 1) * 4;
    const int bk   = tid >> 5, bn2 = (tid & 31) * 2;
    const int bn   = tid >> 2, bkq = (tid & 3) * 2;

    unsigned long long acc[4][4];
#pragma unroll
    for (int i = 0; i < 4; i++)
#pragma unroll
        for (int j = 0; j < 4; j++) acc[i][j] = 0ULL;

    const int KT = K / BK;

    float4 aR = make_float4(0.f, 0.f, 0.f, 0.f);
    float2 bR = make_float2(0.f, 0.f);
    {
        int row = m0 + arow;
        if (row < M) aR = *(const float4*)(Ab + (long long)row * lda + akq);
        if (!TB) { if (n0 + bn2 < N) bR = *(const float2*)(B + (long long)bk * N + n0 + bn2); }
        else     { if (n0 + bn  < N) bR = *(const float2*)(B + (long long)(n0 + bn) * K + bkq); }
    }
    As[0][akq + 0][arow] = aR.x; As[0][akq + 1][arow] = aR.y;
    As[0][akq + 2][arow] = aR.z; As[0][akq + 3][arow] = aR.w;
    if (!TB) { Bs[0][bk][bn2] = bR.x; Bs[0][bk][bn2 + 1] = bR.y; }
    else     { Bs[0][bkq][bn] = bR.x; Bs[0][bkq + 1][bn] = bR.y; }
    __syncthreads();

    for (int kt = 0; kt < KT; kt++) {
        const int cur = kt & 1;
        const int k0n = (kt + 1) * BK;
        if (kt + 1 < KT) {
            int row = m0 + arow;
            aR = make_float4(0.f, 0.f, 0.f, 0.f);
            bR = make_float2(0.f, 0.f);
            if (row < M) aR = *(const float4*)(Ab + (long long)row * lda + k0n + akq);
            if (!TB) { if (n0 + bn2 < N) bR = *(const float2*)(B + (long long)(k0n + bk) * N + n0 + bn2); }
            else     { if (n0 + bn  < N) bR = *(const float2*)(B + (long long)(n0 + bn) * K + k0n + bkq); }
        }
#pragma unroll
        for (int k = 0; k < BK; k++) {
            const float* ap_ = &As[cur][k][ty * 8];
            ulonglong2 a0 = *(const ulonglong2*)ap_;
            ulonglong2 a1 = *(const ulonglong2*)(ap_ + 4);
            float4 bv = *(const float4*)&Bs[cur][k][tx * 4];
            unsigned long long ap[4] = { a0.x, a0.y, a1.x, a1.y };
            unsigned long long bb[4] = { pack2(bv.x, bv.x), pack2(bv.y, bv.y),
                                         pack2(bv.z, bv.z), pack2(bv.w, bv.w) };
#pragma unroll
            for (int mp = 0; mp < 4; mp++)
#pragma unroll
                for (int j = 0; j < 4; j++)
                    FMA2(acc[mp][j], ap[mp], bb[j]);
        }
        if (kt + 1 < KT) {
            const int nb = cur ^ 1;
            As[nb][akq + 0][arow] = aR.x; As[nb][akq + 1][arow] = aR.y;
            As[nb][akq + 2][arow] = aR.z; As[nb][akq + 3][arow] = aR.w;
            if (!TB) { Bs[nb][bk][bn2] = bR.x; Bs[nb][bk][bn2 + 1] = bR.y; }
            else     { Bs[nb][bkq][bn] = bR.x; Bs[nb][bkq + 1][bn] = bR.y; }
        }
        __syncthreads();
    }

    if (EPI == 0) {
#pragma unroll
        for (int j = 0; j < 4; j++) {
            int col = n0 + tx * 4 + j;
            if (col >= N) continue;
            float bv = bias ? bias[col] : 0.f;
#pragma unroll
            for (int mp = 0; mp < 4; mp++) {
                union { unsigned long long u; float2 f; } cv; cv.u = acc[mp][j];
                int r = m0 + ty * 8 + mp * 2;
                if (r     < M) C[(long long)r * ldc + col]       = cv.f.x + bv;
                if (r + 1 < M) C[(long long)(r + 1) * ldc + col] = cv.f.y + bv;
            }
        }
    } else {
        float cmax[4] = { 0.f, 0.f, 0.f, 0.f };
#pragma unroll
        for (int j = 0; j < 4; j++) {
            int col = n0 + tx * 4 + j;
            float bv = (col < N) ? bias[col] : 0.f;
#pragma unroll
            for (int mp = 0; mp < 4; mp++) {
                union { unsigned long long u; float2 f; } cv; cv.u = acc[mp][j];
                int r = m0 + ty * 8 + mp * 2;
                if (r     < M) cmax[j] = fmaxf(cmax[j], cv.f.x + bv);
                if (r + 1 < M) cmax[j] = fmaxf(cmax[j], cv.f.y + bv);
            }
        }
#pragma unroll
        for (int j = 0; j < 4; j++) red[ty][tx * 4 + j] = cmax[j];
        __syncthreads();
        if (ty == 0) {
#pragma unroll
            for (int j = 0; j < 4; j++) {
                int col = n0 + tx * 4 + j;
                if (col >= N) continue;
                float mx = 0.f;
                for (int t2 = 0; t2 < 16; t2++) mx = fmaxf(mx, red[t2][tx * 4 + j]);
                atomicMax((unsigned int*)&C[(long long)blockIdx.z * featLd + featOff + col],
                          __float_as_uint(mx));
            }
        }
    }
}

// ---------------- CSR build ----------------
__global__ void k_hist(const int* __restrict__ ei, int* __restrict__ deg) {
    int i = blockIdx.x * blockDim.x + threadIdx.x;
    if (i < NEDGE) atomicAdd(&deg[ei[NEDGE + i]], 1);
}

__global__ void k_scan(const int* __restrict__ deg, int* __restrict__ rs,
                       int* __restrict__ cur, int n) {
    __shared__ int s[1024];
    __shared__ int carry;
    int t = threadIdx.x;
    if (t == 0) carry = 0;
    __syncthreads();
    for (int base = 0; base < n; base += 1024) {
        int v = (base + t < n) ? deg[base + t] : 0;
        s[t] = v;
        __syncthreads();
        for (int off = 1; off < 1024; off <<= 1) {
            int add = (t >= off) ? s[t - off] : 0;
            __syncthreads();
            s[t] += add;
            __syncthreads();
        }
        int c0 = carry;
        int ex = c0 + s[t] - v;
        if (base + t < n) { rs[base + t] = ex; cur[base + t] = ex; }
        __syncthreads();
        if (t == 0) carry = c0 + s[1023];
        __syncthreads();
    }
    if (t == 0) rs[n] = carry;
}

__global__ void k_fill(const int* __restrict__ ei, int* __restrict__ cur,
                       int* __restrict__ cs) {
    int i = blockIdx.x * blockDim.x + threadIdx.x;
    if (i < NEDGE) {
        int d = ei[NEDGE + i];
        int p = atomicAdd(&cur[d], 1);
        cs[p] = ei[i];
    }
}

// ---------------- segment-sum + bf16 split of agg ----------------
__global__ void k_agg(const float* __restrict__ m, const int* __restrict__ rs,
                      const int* __restrict__ cs,
                      __nv_bfloat16* __restrict__ ahi, __nv_bfloat16* __restrict__ alo) {
    int w = (blockIdx.x * blockDim.x + threadIdx.x) >> 5;
    int lane = threadIdx.x & 31;
    if (w >= N_NODES) return;
    int s = rs[w], e = rs[w + 1];
    float a[7] = {0, 0, 0, 0, 0, 0, 0};
    int i = s;
    for (; i + 1 < e; i += 2) {
        const float* r0 = m + (long long)cs[i]     * HDIM;
        const float* r1 = m + (long long)cs[i + 1] * HDIM;
        a[0] += r0[lane]       + r1[lane];
        a[1] += r0[lane +  32] + r1[lane +  32];
        a[2] += r0[lane +  64] + r1[lane +  64];
        a[3] += r0[lane +  96] + r1[lane +  96];
        a[4] += r0[lane + 128] + r1[lane + 128];
        a[5] += r0[lane + 160] + r1[lane + 160];
        if (lane < 8) a[6] += r0[lane + 192] + r1[lane + 192];
    }
    if (i < e) {
        const float* r0 = m + (long long)cs[i] * HDIM;
        a[0] += r0[lane];       a[1] += r0[lane + 32];  a[2] += r0[lane + 64];
        a[3] += r0[lane + 96];  a[4] += r0[lane + 128]; a[5] += r0[lane + 160];
        if (lane < 8) a[6] += r0[lane + 192];
    }
    long long o = (long long)w * KPAD + lane;
#pragma unroll
    for (int q = 0; q < 6; q++) {
        __nv_bfloat16 h = __float2bfloat16(a[q]);
        ahi[o + q * 32] = h;
        alo[o + q * 32] = __float2bfloat16(a[q] - __bfloat162float(h));
    }
    if (lane < 8) {
        __nv_bfloat16 h = __float2bfloat16(a[6]);
        ahi[o + 192] = h;
        alo[o + 192] = __float2bfloat16(a[6] - __bfloat162float(h));
    }
}

// ---------------- GRU gates (+ bias fold + bf16 split of new h) ----------------
__global__ void k_gates(const float* __restrict__ gi, const float* __restrict__ gh,
                        const float* __restrict__ bih, const float* __restrict__ bhh,
                        const float* __restrict__ hsrc, float* __restrict__ hdst,
                        __nv_bfloat16* __restrict__ hhi, __nv_bfloat16* __restrict__ hlo) {
    int idx = blockIdx.x * blockDim.x + threadIdx.x;
    if (idx >= N_NODES * HDIM) return;
    int n = idx / HDIM, c = idx - n * HDIM;
    const float* giN = gi + (long long)n * 600;
    const float* ghN = gh + (long long)n * 600;
    float r  = 1.f / (1.f + expf(-(giN[c] + bih[c] + ghN[c] + bhh[c])));
    float z  = 1.f / (1.f + expf(-(giN[200 + c] + bih[200 + c] + ghN[200 + c] + bhh[200 + c])));
    float nn = tanhf(giN[400 + c] + bih[400 + c] + r * (ghN[400 + c] + bhh[400 + c]));
    float h = (1.f - z) * nn + z * hsrc[idx];
    hdst[idx] = h;
    __nv_bfloat16 hb = __float2bfloat16(h);
    long long o = (long long)n * KPAD + c;
    hhi[o] = hb;
    hlo[o] = __float2bfloat16(h - __bfloat162float(hb));
}

// ---------------- misc data movement ----------------
__global__ void k_hp(const float* __restrict__ h, float* __restrict__ hp) {
    int idx = blockIdx.x * blockDim.x + threadIdx.x;
    if (idx >= BATCH * 207 * HDIM) return;
    int b = idx / (207 * HDIM);
    int rem = idx - b * 207 * HDIM;
    int r = rem / HDIM, c = rem - r * HDIM;
    hp[idx] = (r == 0 || r == 206) ? 0.f
              : h[((long long)b * NPER + (r - 1)) * HDIM + c];
}

__global__ void k_wt(const float* __restrict__ w, float* __restrict__ wt,
                     int CO, int CI, int KK) {
    int idx = blockIdx.x * blockDim.x + threadIdx.x;
    if (idx >= CO * CI * KK) return;
    int co = idx / (CI * KK);
    int rem = idx - co * CI * KK;
    int ci = rem / KK, k = rem - ci * KK;
    wt[(long long)co * CI * KK + k * CI + ci] = w[idx];
}

// ---------------- fused FC head ----------------
__global__ void k_fc(const float* __restrict__ feats,
                     const float* __restrict__ w1, const float* __restrict__ b1,
                     const float* __restrict__ w2, const float* __restrict__ b2,
                     const float* __restrict__ w3, const float* __restrict__ b3,
                     float* __restrict__ out) {
    int b = blockIdx.x;
    int tid = threadIdx.x;
    int lane = tid & 31, wrp = tid >> 5;
    __shared__ float sf[800];
    __shared__ float s1[256];
    __shared__ float s2[128];
    for (int i = tid; i < 800; i += 256) sf[i] = feats[b * 800 + i];
    __syncthreads();
    for (int jj = 0; jj < 32; jj++) {
        int j = wrp * 32 + jj;
        float a = 0.f;
        for (int i = lane; i < 800; i += 32) a += sf[i] * w1[(long long)j * 800 + i];
        for (int o = 16; o; o >>= 1) a += __shfl_down_sync(0xffffffffu, a, o);
        if (lane == 0) s1[j] = fmaxf(a + b1[j], 0.f);
    }
    __syncthreads();
    if (tid < 128) {
        float a = b2[tid];
        for (int i = 0; i < 256; i++) a += s1[i] * w2[tid * 256 + i];
        s2[tid] = fmaxf(a, 0.f);
    }
    __syncthreads();
    if (tid < 2) {
        float a = b3[tid];
        for (int i = 0; i < 128; i++) a += s2[i] * w3[tid * 128 + i];
        out[b * 2 + tid] = a;
    }
}

// ---------------- launcher ----------------
extern "C" void kernel_launch(void* const* d_in, const int* in_sizes, int n_in,
                              void* d_out, int out_size) {
    const float* x     = (const float*)d_in[0];
    const int*   ei    = (const int*)  d_in[1];
    const int*   ids   = (const int*)  d_in[2];
    const float* etab  = (const float*)d_in[3];
    const float* ggcw  = (const float*)d_in[4];
    const float* wih   = (const float*)d_in[5];
    const float* whh   = (const float*)d_in[6];
    const float* bih   = (const float*)d_in[7];
    const float* bhh   = (const float*)d_in[8];
    const float* c0w   = (const float*)d_in[9];
    const float* c0b   = (const float*)d_in[10];
    const float* c1w   = (const float*)d_in[11];
    const float* c1b   = (const float*)d_in[12];
    const float* c2w   = (const float*)d_in[13];
    const float* c2b   = (const float*)d_in[14];
    const float* c3w   = (const float*)d_in[15];
    const float* c3b   = (const float*)d_in[16];
    const float* f1w   = (const float*)d_in[17];
    const float* f1b   = (const float*)d_in[18];
    const float* f2w   = (const float*)d_in[19];
    const float* f2b   = (const float*)d_in[20];
    const float* f3w   = (const float*)d_in[21];
    const float* f3b   = (const float*)d_in[22];
    float* out = (float*)d_out;

    float *h0, *h1, *mm, *gi, *gh, *hp, *w0t, *feats;
    int *deg, *rs, *cur, *cs;
    __half *e16, *w1h, *w2h, *w3h;
    __nv_bfloat16 *hhi, *hlo, *ahi, *alo, *wg, *wi, *wh;
    cudaGetSymbolAddress((void**)&h0,   g_h0);
    cudaGetSymbolAddress((void**)&h1,   g_h1);
    cudaGetSymbolAddress((void**)&mm,   g_m);
    cudaGetSymbolAddress((void**)&gi,   g_gi);
    cudaGetSymbolAddress((void**)&gh,   g_gh);
    cudaGetSymbolAddress((void**)&hp,   g_hp);
    cudaGetSymbolAddress((void**)&w0t,  g_w0t);
    cudaGetSymbolAddress((void**)&feats,g_feats);
    cudaGetSymbolAddress((void**)&deg,  g_deg);
    cudaGetSymbolAddress((void**)&rs,   g_rs);
    cudaGetSymbolAddress((void**)&cur,  g_cur);
    cudaGetSymbolAddress((void**)&cs,   g_csrc);
    cudaGetSymbolAddress((void**)&e16,  g_e16);
    cudaGetSymbolAddress((void**)&w1h,  g_w1h);
    cudaGetSymbolAddress((void**)&w2h,  g_w2h);
    cudaGetSymbolAddress((void**)&w3h,  g_w3h);
    cudaGetSymbolAddress((void**)&hhi,  g_hhi);
    cudaGetSymbolAddress((void**)&hlo,  g_hlo);
    cudaGetSymbolAddress((void**)&ahi,  g_ahi);
    cudaGetSymbolAddress((void**)&alo,  g_alo);
    cudaGetSymbolAddress((void**)&wg,   g_wg);
    cudaGetSymbolAddress((void**)&wi,   g_wi);
    cudaGetSymbolAddress((void**)&wh,   g_wh);

    const int CONV_SMEM = 36864 + 59904 + 832 + 832;   // 98432 B
    const int GGC_SMEM  = 36864 + 59904;               // 96768 B
    cudaFuncSetAttribute(conv3h_k,   cudaFuncAttributeMaxDynamicSharedMemorySize, CONV_SMEM);
    cudaFuncSetAttribute(ggc_hmma_k, cudaFuncAttributeMaxDynamicSharedMemorySize, GGC_SMEM);
    cudaFuncSetAttribute(ggc_mh_k,   cudaFuncAttributeMaxDynamicSharedMemorySize, GGC_SMEM);

    // side stream + events (created once; host resources, no device allocs)
    static cudaStream_t s2 = nullptr;
    static cudaEvent_t ev1 = nullptr, ev2 = nullptr;
    if (!s2) {
        cudaStreamCreateWithFlags(&s2, cudaStreamNonBlocking);
        cudaEventCreateWithFlags(&ev1, cudaEventDisableTiming);
        cudaEventCreateWithFlags(&ev2, cudaEventDisableTiming);
    }

    // ---- default stream: feats zero, then fork conv branch ----
    cudaMemsetAsync(feats, 0, BATCH * 800 * sizeof(float));
    cudaEventRecord(ev1, 0);
    cudaStreamWaitEvent(s2, ev1, 0);

    // ---- side stream: conv1/2/3 branch (independent of GGC) ----
    k_embed16<<<BATCH * SEQ + 8, 192, 0, s2>>>(ids, etab, e16);
    k_wsplit16<<<(200 * 768 * 3 + 255) / 256, 256, 0, s2>>>(c1w, w1h, 3);
    k_wsplit16<<<(200 * 768 * 4 + 255) / 256, 256, 0, s2>>>(c2w, w2h, 4);
    k_wsplit16<<<(200 * 768 * 5 + 255) / 256, 256, 0, s2>>>(c3w, w3h, 5);
    {
        Conv3Args ca;
        ca.wb[0] = w1h; ca.wb[1] = w2h; ca.wb[2] = w3h;
        ca.bias[0] = c1b; ca.bias[1] = c2b; ca.bias[2] = c3b;
        conv3h_k<<<dim3(3, 4, BATCH), 256, CONV_SMEM, s2>>>(e16, ca, feats);
    }
    cudaEventRecord(ev2, s2);

    // ---- default stream: CSR + GGC prep ----
    cudaMemsetAsync(deg, 0, N_NODES * sizeof(int));
    k_hist<<<(NEDGE + 255) / 256, 256>>>(ei, deg);
    k_scan<<<1, 1024>>>(deg, rs, cur, N_NODES);
    k_fill<<<(NEDGE + 255) / 256, 256>>>(ei, cur, cs);
    cudaMemcpyAsync(h0, x, (size_t)N_NODES * HDIM * sizeof(float),
                    cudaMemcpyDeviceToDevice);
    k_xsplit<<<(N_NODES * KPAD + 255) / 256, 256>>>(x, hhi, hlo);
    k_wggc<<<(NLAYERS * 208 * 768 + 255) / 256, 256>>>(ggcw, wg);
    k_wgru<<<(624 * 768 + 255) / 256, 256>>>(wih, wi);
    k_wgru<<<(624 * 768 + 255) / 256, 256>>>(whh, wh);
    k_wt<<<(200 * 200 * 3 + 255) / 256, 256>>>(c0w, w0t, 200, 200, 3);

    // ---- gated graph conv: 6 layers (HMMA bf16x3) ----
    float* hc = h0;
    float* hn = h1;
    for (int l = 0; l < NLAYERS; l++) {
        // fused: m = h @ ggc_w[l]  and  gh = h @ whh^T  (same A)
        ggc_mh_k<<<dim3(4, NPER), 256, GGC_SMEM>>>(hhi, hlo,
                                                   wg + (long long)l * 208 * 768, wh,
                                                   mm, gh);
        // agg = segment_sum(m[src], dst), split to bf16
        k_agg<<<(N_NODES + 7) / 8, 256>>>(mm, rs, cs, ahi, alo);
        // gi = agg @ wih^T
        ggc_hmma_k<<<dim3(3, NPER), 256, GGC_SMEM>>>(ahi, alo, wi, gi, 600, 600);
        // GRU update (+bias fold) and re-split h
        k_gates<<<(N_NODES * HDIM + 255) / 256, 256>>>(gi, gh, bih, bhh, hc, hn, hhi, hlo);
        float* t = hc; hc = hn; hn = t;
    }

    // ---- conv0 (fp32 SIMT, fused bias+ReLU+max; feats cols 0..199) ----
    k_hp<<<(BATCH * 207 * HDIM + 255) / 256, 256>>>(hc, hp);
    sgemm_k<true, 1><<<dim3(4, 2, BATCH), 256>>>(hp, 200, 207LL * 200, w0t, c0b, feats,
                                                 205, 200, 600, 0, 800, 0);

    // ---- join conv branch, then FC head ----
    cudaStreamWaitEvent(0, ev2, 0);
    k_fc<<<BATCH, 256>>>(feats, f1w, f1b, f2w, f2b, f3w, f3b, out);
}

// round 12
// speedup vs baseline: 3.5755x; 1.2562x over previous
#include <cuda_runtime.h>
#include <cuda_bf16.h>
#include <cuda_fp16.h>
#include <cstdint>

// ---------------- problem constants ----------------
#define N_NODES 26240      // B * N_PER = 128 * 205 (exactly 205 blocks of 128)
#define HDIM    200
#define NEDGE   209920
#define BATCH   128
#define NPER    205
#define EMBD    768
#define SEQ     512
#define NLAYERS 6
#define KPAD    256        // padded K per bf16x3 pass (GGC)

// ---------------- static device scratch ----------------
__device__ float g_h0[N_NODES * HDIM];
__device__ float g_h1[N_NODES * HDIM];
__device__ float g_m [N_NODES * HDIM];
__device__ float g_gi[N_NODES * 3 * HDIM];
__device__ float g_gh[N_NODES * 3 * HDIM];
__device__ float g_hp [BATCH * 207 * HDIM];             // zero-padded conv0 input
__device__ float g_w0t[200 * 600];
__device__ float g_feats[BATCH * 800];
__device__ int   g_deg[N_NODES];
__device__ int   g_rs [N_NODES + 1];
__device__ int   g_cur[N_NODES];
__device__ int   g_csrc[NEDGE];

// GGC bf16 split operands, K-padded to 256 (pads stay zero after init)
__device__ __align__(16) __nv_bfloat16 g_hhi[(size_t)N_NODES * KPAD];
__device__ __align__(16) __nv_bfloat16 g_hlo[(size_t)N_NODES * KPAD];
__device__ __align__(16) __nv_bfloat16 g_ahi[(size_t)N_NODES * KPAD];
__device__ __align__(16) __nv_bfloat16 g_alo[(size_t)N_NODES * KPAD];
// GGC weights expanded: [Npad][768] = [Whi(0:256) | Wlo(256:512) | Whi(512:768)]
__device__ __align__(16) __nv_bfloat16 g_wg[NLAYERS * 208 * 768];   // ggc_w[l]^T
__device__ __align__(16) __nv_bfloat16 g_wi[624 * 768];             // wih
__device__ __align__(16) __nv_bfloat16 g_wh[624 * 768];             // whh

// fp16 embeddings, time-major [b][t][c], +8 zero rows for tap overrun
__device__ __align__(16) __half g_e16[((size_t)BATCH * SEQ + 8) * EMBD];
// fp16 conv weights: [200][K], tap-major K (single pass)
__device__ __align__(16) __half g_w1h[200 * 2304];
__device__ __align__(16) __half g_w2h[200 * 3072];
__device__ __align__(16) __half g_w3h[200 * 3840];

// ---------------- packed fp32x2 helpers (sm_100+) ----------------
#define FMA2(d, a, b) asm("fma.rn.f32x2 %0, %1, %2, %0;" : "+l"(d) : "l"(a), "l"(b))

__device__ __forceinline__ unsigned long long pack2(float x, float y) {
    unsigned long long r;
    asm("mov.b64 %0, {%1, %2};" : "=l"(r) : "r"(__float_as_uint(x)), "r"(__float_as_uint(y)));
    return r;
}

// ---------------- warp-level MMAs (compute_100-safe PTX) ----------------
#define MMA_BF16(d, a, b0, b1) asm volatile(                           \
    "mma.sync.aligned.m16n8k16.row.col.f32.bf16.bf16.f32 "             \
    "{%0,%1,%2,%3}, {%4,%5,%6,%7}, {%8,%9}, {%0,%1,%2,%3};"            \
    : "+f"((d)[0]), "+f"((d)[1]), "+f"((d)[2]), "+f"((d)[3])           \
    : "r"((a)[0]), "r"((a)[1]), "r"((a)[2]), "r"((a)[3]),              \
      "r"(b0), "r"(b1))

#define MMA_F16(d, a, b0, b1) asm volatile(                            \
    "mma.sync.aligned.m16n8k16.row.col.f32.f16.f16.f32 "               \
    "{%0,%1,%2,%3}, {%4,%5,%6,%7}, {%8,%9}, {%0,%1,%2,%3};"            \
    : "+f"((d)[0]), "+f"((d)[1]), "+f"((d)[2]), "+f"((d)[3])           \
    : "r"((a)[0]), "r"((a)[1]), "r"((a)[2]), "r"((a)[3]),              \
      "r"(b0), "r"(b1))

// ---------------- cp.async helpers (sm_80+ PTX) ----------------
#define CP16(dst, src) asm volatile("cp.async.ca.shared.global [%0], [%1], 16;" \
                                    :: "r"(dst), "l"(src))
#define CP_COMMIT() asm volatile("cp.async.commit_group;" ::: "memory")
#define CP_WAIT0()  asm volatile("cp.async.wait_group 0;" ::: "memory")

__device__ __forceinline__ uint32_t s2u(const void* p) {
    return (uint32_t)__cvta_generic_to_shared(p);
}

// ---------------- GGC GEMM: gi = agg @ wih^T (bf16x3) ----------------
// grid (3 n-tiles, 205 m-tiles). 256 threads = 8 warps (4m x 2n). K3 = 768.
__global__ void __launch_bounds__(256, 1) ggc_hmma_k(
    const __nv_bfloat16* __restrict__ Ahi,
    const __nv_bfloat16* __restrict__ Alo,
    const __nv_bfloat16* __restrict__ B,
    float* __restrict__ C, int N, int ldc)
{
    extern __shared__ __align__(16) char dsm[];
    constexpr int ASTR = 72, BSTR = 72;
    __nv_bfloat16* As = (__nv_bfloat16*)dsm;                 // [2][128][72]
    __nv_bfloat16* Bs = (__nv_bfloat16*)(dsm + 36864);       // [2][208][72]

    const int tid = threadIdx.x;
    const int lane = tid & 31, wid = tid >> 5;
    const int wm = wid & 3, wn = wid >> 2;
    const int g = lane >> 2, t2 = (lane & 3) * 2;
    const int m0 = blockIdx.y * 128;
    const int n0 = blockIdx.x * 208;
    const uint32_t asb = s2u(As), bsb = s2u(Bs);

    auto copy_tile = [&](int kt, int buf) {
        const int p = kt >> 2;
        const int koff = (kt & 3) * 64;
        const __nv_bfloat16* src = (p < 2) ? Ahi : Alo;
        const uint32_t ab = asb + buf * 128 * ASTR * 2;
        const uint32_t bb = bsb + buf * 208 * BSTR * 2;
#pragma unroll
        for (int i = 0; i < 4; i++) {
            int u = tid + i * 256;
            int row = u >> 3, ch = u & 7;
            CP16(ab + (row * ASTR + ch * 8) * 2,
                 src + (long long)(m0 + row) * KPAD + koff + ch * 8);
        }
        const int kg = kt * 64;
#pragma unroll
        for (int i = 0; i < 7; i++) {
            int u = tid + i * 256;
            if (u < 1664) {
                int row = u >> 3, ch = u & 7;
                CP16(bb + (row * BSTR + ch * 8) * 2,
                     B + (long long)(n0 + row) * 768 + kg + ch * 8);
            }
        }
    };

    float acc[2][13][4];
#pragma unroll
    for (int i = 0; i < 2; i++)
#pragma unroll
        for (int j = 0; j < 13; j++)
#pragma unroll
            for (int q = 0; q < 4; q++) acc[i][j][q] = 0.f;

    copy_tile(0, 0); CP_COMMIT(); CP_WAIT0();
    __syncthreads();

#pragma unroll 1
    for (int kt = 0; kt < 12; kt++) {
        const int buf = kt & 1;
        const bool more = (kt + 1 < 12);
        if (more) { copy_tile(kt + 1, buf ^ 1); CP_COMMIT(); }

        const __nv_bfloat16* Ab = As + buf * 128 * ASTR;
        const __nv_bfloat16* Bb = Bs + buf * 208 * BSTR;
#pragma unroll
        for (int ks = 0; ks < 4; ks++) {
            const int ko = ks * 16;
            uint32_t a[2][4];
#pragma unroll
            for (int i = 0; i < 2; i++) {
                const int r = wm * 32 + i * 16 + g;
                a[i][0] = *(const uint32_t*)(Ab + (r)     * ASTR + ko + t2);
                a[i][1] = *(const uint32_t*)(Ab + (r + 8) * ASTR + ko + t2);
                a[i][2] = *(const uint32_t*)(Ab + (r)     * ASTR + ko + t2 + 8);
                a[i][3] = *(const uint32_t*)(Ab + (r + 8) * ASTR + ko + t2 + 8);
            }
            uint32_t bf[13][2];
#pragma unroll
            for (int j = 0; j < 13; j++) {
                const int n = wn * 104 + j * 8 + g;
                bf[j][0] = *(const uint32_t*)(Bb + n * BSTR + ko + t2);
                bf[j][1] = *(const uint32_t*)(Bb + n * BSTR + ko + t2 + 8);
            }
#pragma unroll
            for (int j = 0; j < 13; j++) {
                MMA_BF16(acc[0][j], a[0], bf[j][0], bf[j][1]);
                MMA_BF16(acc[1][j], a[1], bf[j][0], bf[j][1]);
            }
        }
        if (more) CP_WAIT0();
        __syncthreads();
    }

#pragma unroll
    for (int i = 0; i < 2; i++) {
        const int r = m0 + wm * 32 + i * 16 + g;
#pragma unroll
        for (int j = 0; j < 13; j++) {
            const int col = n0 + wn * 104 + j * 8 + t2;
            if (col < N) {
                C[(long long)r * ldc + col]       = acc[i][j][0];
                C[(long long)(r + 8) * ldc + col] = acc[i][j][2];
            }
            if (col + 1 < N) {
                C[(long long)r * ldc + col + 1]       = acc[i][j][1];
                C[(long long)(r + 8) * ldc + col + 1] = acc[i][j][3];
            }
        }
    }
}

// ---------------- fused m + gh GEMM (same A = h, bf16x3) ----------------
// grid (4, 205): bx==0 -> m = h @ ggc_w[l] (N=200); bx in 1..3 -> gh slice.
__global__ void __launch_bounds__(256, 1) ggc_mh_k(
    const __nv_bfloat16* __restrict__ Ahi,
    const __nv_bfloat16* __restrict__ Alo,
    const __nv_bfloat16* __restrict__ wgl,    // [208][768] layer slice
    const __nv_bfloat16* __restrict__ wh,     // [624][768]
    float* __restrict__ Cm,
    float* __restrict__ Cg)
{
    extern __shared__ __align__(16) char dsm[];
    constexpr int ASTR = 72, BSTR = 72;
    __nv_bfloat16* As = (__nv_bfloat16*)dsm;
    __nv_bfloat16* Bs = (__nv_bfloat16*)(dsm + 36864);

    const int tid = threadIdx.x;
    const int lane = tid & 31, wid = tid >> 5;
    const int wm = wid & 3, wn = wid >> 2;
    const int g = lane >> 2, t2 = (lane & 3) * 2;
    const int m0 = blockIdx.y * 128;
    const int bx = blockIdx.x;
    const uint32_t asb = s2u(As), bsb = s2u(Bs);

    const __nv_bfloat16* B = (bx == 0) ? wgl : (wh + (long long)(bx - 1) * 208 * 768);
    float* C      = (bx == 0) ? Cm  : Cg;
    const int ldc = (bx == 0) ? 200 : 600;
    const int N   = (bx == 0) ? 200 : 600;
    const int cb  = (bx == 0) ? 0   : (bx - 1) * 208;

    auto copy_tile = [&](int kt, int buf) {
        const int p = kt >> 2;
        const int koff = (kt & 3) * 64;
        const __nv_bfloat16* src = (p < 2) ? Ahi : Alo;
        const uint32_t ab = asb + buf * 128 * ASTR * 2;
        const uint32_t bb = bsb + buf * 208 * BSTR * 2;
#pragma unroll
        for (int i = 0; i < 4; i++) {
            int u = tid + i * 256;
            int row = u >> 3, ch = u & 7;
            CP16(ab + (row * ASTR + ch * 8) * 2,
                 src + (long long)(m0 + row) * KPAD + koff + ch * 8);
        }
        const int kg = kt * 64;
#pragma unroll
        for (int i = 0; i < 7; i++) {
            int u = tid + i * 256;
            if (u < 1664) {
                int row = u >> 3, ch = u & 7;
                CP16(bb + (row * BSTR + ch * 8) * 2,
                     B + (long long)row * 768 + kg + ch * 8);
            }
        }
    };

    float acc[2][13][4];
#pragma unroll
    for (int i = 0; i < 2; i++)
#pragma unroll
        for (int j = 0; j < 13; j++)
#pragma unroll
            for (int q = 0; q < 4; q++) acc[i][j][q] = 0.f;

    copy_tile(0, 0); CP_COMMIT(); CP_WAIT0();
    __syncthreads();

#pragma unroll 1
    for (int kt = 0; kt < 12; kt++) {
        const int buf = kt & 1;
        const bool more = (kt + 1 < 12);
        if (more) { copy_tile(kt + 1, buf ^ 1); CP_COMMIT(); }

        const __nv_bfloat16* Ab = As + buf * 128 * ASTR;
        const __nv_bfloat16* Bb = Bs + buf * 208 * BSTR;
#pragma unroll
        for (int ks = 0; ks < 4; ks++) {
            const int ko = ks * 16;
            uint32_t a[2][4];
#pragma unroll
            for (int i = 0; i < 2; i++) {
                const int r = wm * 32 + i * 16 + g;
                a[i][0] = *(const uint32_t*)(Ab + (r)     * ASTR + ko + t2);
                a[i][1] = *(const uint32_t*)(Ab + (r + 8) * ASTR + ko + t2);
                a[i][2] = *(const uint32_t*)(Ab + (r)     * ASTR + ko + t2 + 8);
                a[i][3] = *(const uint32_t*)(Ab + (r + 8) * ASTR + ko + t2 + 8);
            }
            uint32_t bf[13][2];
#pragma unroll
            for (int j = 0; j < 13; j++) {
                const int n = wn * 104 + j * 8 + g;
                bf[j][0] = *(const uint32_t*)(Bb + n * BSTR + ko + t2);
                bf[j][1] = *(const uint32_t*)(Bb + n * BSTR + ko + t2 + 8);
            }
#pragma unroll
            for (int j = 0; j < 13; j++) {
                MMA_BF16(acc[0][j], a[0], bf[j][0], bf[j][1]);
                MMA_BF16(acc[1][j], a[1], bf[j][0], bf[j][1]);
            }
        }
        if (more) CP_WAIT0();
        __syncthreads();
    }

#pragma unroll
    for (int i = 0; i < 2; i++) {
        const int r = m0 + wm * 32 + i * 16 + g;
#pragma unroll
        for (int j = 0; j < 13; j++) {
            const int col = cb + wn * 104 + j * 8 + t2;
            if (col < N) {
                C[(long long)r * ldc + col]       = acc[i][j][0];
                C[(long long)(r + 8) * ldc + col] = acc[i][j][2];
            }
            if (col + 1 < N) {
                C[(long long)r * ldc + col + 1]       = acc[i][j][1];
                C[(long long)(r + 8) * ldc + col + 1] = acc[i][j][3];
            }
        }
    }
}

// ---------------- fused conv1/2/3: pure fp16 conv-as-GEMM (single pass) ----------------
// D = fp16(E) @ fp16(W)^T; K in {2304, 3072, 3840}.
struct Conv3Args {
    const __half* wb[3];
    const float* bias[3];
};
// grid (3 convs, 4 m-tiles, 128 batches)
__global__ void __launch_bounds__(256, 1) conv3h_k(
    const __half* __restrict__ e16,
    Conv3Args args,
    float* __restrict__ feats)
{
    extern __shared__ __align__(16) char dsm[];
    constexpr int ASTR = 72, BSTR = 72;
    __half* As = (__half*)dsm;
    __half* Bs = (__half*)(dsm + 36864);
    float* smax  = (float*)(dsm + 36864 + 59904);
    float* sbias = smax + 208;

    const int cid = blockIdx.x;
    const int M   = (cid == 0) ? 510 : (cid == 1) ? 509 : 508;
    const int K   = (cid == 0) ? 2304 : (cid == 1) ? 3072 : 3840;   // 768 * taps
    const int featOff = 200 + cid * 200;
    const __half* wb = args.wb[cid];
    const float* bias = args.bias[cid];

    const int tid = threadIdx.x;
    const int lane = tid & 31, wid = tid >> 5;
    const int wm = wid & 3, wn = wid >> 2;
    const int g = lane >> 2, t2 = (lane & 3) * 2;
    const int b = blockIdx.z, m0 = blockIdx.y * 128;
    const int T = K / 64;              // total 64-tiles (= taps*12)
    const uint32_t asb = s2u(As), bsb = s2u(Bs);

    if (tid < 208) { smax[tid] = 0.f; sbias[tid] = (tid < 200) ? bias[tid] : 0.f; }

    auto copy_tile = [&](int kt, int buf) {
        int kk = kt / 12;
        int c0 = (kt - kk * 12) * 64;
        long long abase = ((long long)(b * SEQ + m0 + kk)) * EMBD + c0;
        const uint32_t ab = asb + buf * 128 * ASTR * 2;
        const uint32_t bb = bsb + buf * 208 * BSTR * 2;
#pragma unroll
        for (int i = 0; i < 4; i++) {
            int u = tid + i * 256;
            int row = u >> 3, ch = u & 7;
            CP16(ab + (row * ASTR + ch * 8) * 2,
                 e16 + abase + (long long)row * EMBD + ch * 8);
        }
        int kg = kt * 64;
#pragma unroll
        for (int i = 0; i < 7; i++) {
            int u = tid + i * 256;
            if (u < 1600) {
                int row = u >> 3, ch = u & 7;
                CP16(bb + (row * BSTR + ch * 8) * 2,
                     wb + (long long)row * K + kg + ch * 8);
            }
        }
    };

    float acc[2][13][4];
#pragma unroll
    for (int i = 0; i < 2; i++)
#pragma unroll
        for (int j = 0; j < 13; j++)
#pragma unroll
            for (int q = 0; q < 4; q++) acc[i][j][q] = 0.f;

    copy_tile(0, 0); CP_COMMIT(); CP_WAIT0();
    __syncthreads();

#pragma unroll 1
    for (int kt = 0; kt < T; kt++) {
        const int buf = kt & 1;
        const bool more = (kt + 1 < T);
        if (more) { copy_tile(kt + 1, buf ^ 1); CP_COMMIT(); }

        const __half* Ab = As + buf * 128 * ASTR;
        const __half* Bb = Bs + buf * 208 * BSTR;
#pragma unroll
        for (int ks = 0; ks < 4; ks++) {
            const int ko = ks * 16;
            uint32_t a[2][4];
#pragma unroll
            for (int i = 0; i < 2; i++) {
                const int r = wm * 32 + i * 16 + g;
                a[i][0] = *(const uint32_t*)(Ab + (r)     * ASTR + ko + t2);
                a[i][1] = *(const uint32_t*)(Ab + (r + 8) * ASTR + ko + t2);
                a[i][2] = *(const uint32_t*)(Ab + (r)     * ASTR + ko + t2 + 8);
                a[i][3] = *(const uint32_t*)(Ab + (r + 8) * ASTR + ko + t2 + 8);
            }
            uint32_t bf[13][2];
#pragma unroll
            for (int j = 0; j < 13; j++) {
                const int n = wn * 104 + j * 8 + g;
                bf[j][0] = *(const uint32_t*)(Bb + n * BSTR + ko + t2);
                bf[j][1] = *(const uint32_t*)(Bb + n * BSTR + ko + t2 + 8);
            }
#pragma unroll
            for (int j = 0; j < 13; j++) {
                MMA_F16(acc[0][j], a[0], bf[j][0], bf[j][1]);
                MMA_F16(acc[1][j], a[1], bf[j][0], bf[j][1]);
            }
        }
        if (more) CP_WAIT0();
        __syncthreads();
    }

    const int valid = (M - m0 < 128) ? (M - m0) : 128;
#pragma unroll
    for (int j = 0; j < 13; j++) {
        float v0 = -1e30f, v1 = -1e30f;
#pragma unroll
        for (int i = 0; i < 2; i++) {
            const int r0 = wm * 32 + i * 16 + g;
            if (r0 < valid)     { v0 = fmaxf(v0, acc[i][j][0]); v1 = fmaxf(v1, acc[i][j][1]); }
            if (r0 + 8 < valid) { v0 = fmaxf(v0, acc[i][j][2]); v1 = fmaxf(v1, acc[i][j][3]); }
        }
#pragma unroll
        for (int o = 4; o <= 16; o <<= 1) {
            v0 = fmaxf(v0, __shfl_xor_sync(~0u, v0, o));
            v1 = fmaxf(v1, __shfl_xor_sync(~0u, v1, o));
        }
        if (g == 0) {
            const int col = wn * 104 + j * 8 + t2;
            if (col < 200) {
                float r = fmaxf(v0 + sbias[col], 0.f);
                atomicMax((unsigned int*)&smax[col], __float_as_uint(r));
            }
            if (col + 1 < 200) {
                float r = fmaxf(v1 + sbias[col + 1], 0.f);
                atomicMax((unsigned int*)&smax[col + 1], __float_as_uint(r));
            }
        }
    }
    __syncthreads();
    if (tid < 200)
        atomicMax((unsigned int*)&feats[(long long)b * 800 + featOff + tid],
                  __float_as_uint(smax[tid]));
}

// ---------------- fp16 embed (single array) ----------------
__global__ void k_embed16(const int* __restrict__ ids, const float* __restrict__ tbl,
                          __half* __restrict__ e16) {
    int row = blockIdx.x;
    int t = threadIdx.x;                   // 192 threads, one float4 each
    long long o = (long long)row * EMBD;
    if (row >= BATCH * SEQ) {
        if (t < 96) {
            ((uint2*)(e16 + o))[t * 2]     = make_uint2(0, 0);
            ((uint2*)(e16 + o))[t * 2 + 1] = make_uint2(0, 0);
        }
        return;
    }
    long long id = ids[row];
    float4 v = ((const float4*)(tbl + id * EMBD))[t];
    __half2 h01 = __floats2half2_rn(v.x, v.y);
    __half2 h23 = __floats2half2_rn(v.z, v.w);
    uint2 hv;
    hv.x = *(uint32_t*)&h01; hv.y = *(uint32_t*)&h23;
    ((uint2*)(e16 + o))[t] = hv;
}

// w: [200][768][KK] fp32 -> wb: [200][K] fp16, tap-major K
__global__ void k_w16(const float* __restrict__ w, __half* __restrict__ wb, int KK) {
    int K = 768 * KK;
    int idx = blockIdx.x * blockDim.x + threadIdx.x;
    if (idx >= 200 * K) return;
    int co = idx / K, r = idx - co * K;
    int kk = r / 768, ci = r - kk * 768;
    wb[idx] = __float2half(w[(co * 768 + ci) * KK + kk]);
}

// ---------------- GGC bf16 split precompute ----------------
__global__ void k_wggc(const float* __restrict__ w, __nv_bfloat16* __restrict__ out) {
    int idx = blockIdx.x * blockDim.x + threadIdx.x;
    if (idx >= NLAYERS * 208 * 768) return;
    int l = idx / (208 * 768);
    int rem = idx - l * 208 * 768;
    int n = rem / 768, col = rem - n * 768;
    int p = col >> 8, kk = col & 255;
    float x = (n < 200 && kk < 200) ? w[(long long)l * 40000 + kk * 200 + n] : 0.f;
    __nv_bfloat16 h = __float2bfloat16(x);
    out[idx] = (p == 1) ? __float2bfloat16(x - __bfloat162float(h)) : h;
}

__global__ void k_wgru(const float* __restrict__ w, __nv_bfloat16* __restrict__ out) {
    int idx = blockIdx.x * blockDim.x + threadIdx.x;
    if (idx >= 624 * 768) return;
    int n = idx / 768, col = idx - n * 768;
    int p = col >> 8, kk = col & 255;
    float x = (n < 600 && kk < 200) ? w[n * 200 + kk] : 0.f;
    __nv_bfloat16 h = __float2bfloat16(x);
    out[idx] = (p == 1) ? __float2bfloat16(x - __bfloat162float(h)) : h;
}

__global__ void k_xsplit(const float* __restrict__ xin,
                         __nv_bfloat16* __restrict__ hi, __nv_bfloat16* __restrict__ lo) {
    int idx = blockIdx.x * blockDim.x + threadIdx.x;
    if (idx >= N_NODES * KPAD) return;
    int n = idx >> 8, c = idx & 255;
    float x = (c < 200) ? xin[n * HDIM + c] : 0.f;
    __nv_bfloat16 h = __float2bfloat16(x);
    hi[idx] = h;
    lo[idx] = __float2bfloat16(x - __bfloat162float(h));
}

// ---------------- fp32 SIMT GEMM (conv0 only) ----------------
template<bool TB, int EPI>
__global__ void __launch_bounds__(256, 2) sgemm_k(
    const float* __restrict__ A, int lda, long long aStride,
    const float* __restrict__ B,
    const float* __restrict__ bias,
    float* __restrict__ C,
    int M, int N, int K,
    int ldc, int featLd, int featOff)
{
    constexpr int BM = 128, BN = 64, BK = 8;
    __shared__ __align__(16) float As[2][BK][132];
    __shared__ __align__(16) float Bs[2][BK][68];
    __shared__ float red[16][68];

    const int tid = threadIdx.x;
    const int tx = tid & 15, ty = tid >> 4;
    const int m0 = blockIdx.y * BM;
    const int n0 = blockIdx.x * BN;
    const float* Ab = A + (long long)blockIdx.z * aStride;

    const int arow = tid >> 1, akq = (tid & 1) * 4;
    const int bk   = tid >> 5, bn2 = (tid & 31) * 2;
    const int bn   = tid >> 2, bkq = (tid & 3) * 2;

    unsigned long long acc[4][4];
#pragma unroll
    for (int i = 0; i < 4; i++)
#pragma unroll
        for (int j = 0; j < 4; j++) acc[i][j] = 0ULL;

    const int KT = K / BK;

    float4 aR = make_float4(0.f, 0.f, 0.f, 0.f);
    float2 bR = make_float2(0.f, 0.f);
    {
        int row = m0 + arow;
        if (row < M) aR = *(const float4*)(Ab + (long long)row * lda + akq);
        if (!TB) { if (n0 + bn2 < N) bR = *(const float2*)(B + (long long)bk * N + n0 + bn2); }
        else     { if (n0 + bn  < N) bR = *(const float2*)(B + (long long)(n0 + bn) * K + bkq); }
    }
    As[0][akq + 0][arow] = aR.x; As[0][akq + 1][arow] = aR.y;
    As[0][akq + 2][arow] = aR.z; As[0][akq + 3][arow] = aR.w;
    if (!TB) { Bs[0][bk][bn2] = bR.x; Bs[0][bk][bn2 + 1] = bR.y; }
    else     { Bs[0][bkq][bn] = bR.x; Bs[0][bkq + 1][bn] = bR.y; }
    __syncthreads();

    for (int kt = 0; kt < KT; kt++) {
        const int cur = kt & 1;
        const int k0n = (kt + 1) * BK;
        if (kt + 1 < KT) {
            int row = m0 + arow;
            aR = make_float4(0.f, 0.f, 0.f, 0.f);
            bR = make_float2(0.f, 0.f);
            if (row < M) aR = *(const float4*)(Ab + (long long)row * lda + k0n + akq);
            if (!TB) { if (n0 + bn2 < N) bR = *(const float2*)(B + (long long)(k0n + bk) * N + n0 + bn2); }
            else     { if (n0 + bn  < N) bR = *(const float2*)(B + (long long)(n0 + bn) * K + k0n + bkq); }
        }
#pragma unroll
        for (int k = 0; k < BK; k++) {
            const float* ap_ = &As[cur][k][ty * 8];
            ulonglong2 a0 = *(const ulonglong2*)ap_;
            ulonglong2 a1 = *(const ulonglong2*)(ap_ + 4);
            float4 bv = *(const float4*)&Bs[cur][k][tx * 4];
            unsigned long long ap[4] = { a0.x, a0.y, a1.x, a1.y };
            unsigned long long bb[4] = { pack2(bv.x, bv.x), pack2(bv.y, bv.y),
                                         pack2(bv.z, bv.z), pack2(bv.w, bv.w) };
#pragma unroll
            for (int mp = 0; mp < 4; mp++)
#pragma unroll
                for (int j = 0; j < 4; j++)
                    FMA2(acc[mp][j], ap[mp], bb[j]);
        }
        if (kt + 1 < KT) {
            const int nb = cur ^ 1;
            As[nb][akq + 0][arow] = aR.x; As[nb][akq + 1][arow] = aR.y;
            As[nb][akq + 2][arow] = aR.z; As[nb][akq + 3][arow] = aR.w;
            if (!TB) { Bs[nb][bk][bn2] = bR.x; Bs[nb][bk][bn2 + 1] = bR.y; }
            else     { Bs[nb][bkq][bn] = bR.x; Bs[nb][bkq + 1][bn] = bR.y; }
        }
        __syncthreads();
    }

    if (EPI == 0) {
#pragma unroll
        for (int j = 0; j < 4; j++) {
            int col = n0 + tx * 4 + j;
            if (col >= N) continue;
            float bv = bias ? bias[col] : 0.f;
#pragma unroll
            for (int mp = 0; mp < 4; mp++) {
                union { unsigned long long u; float2 f; } cv; cv.u = acc[mp][j];
                int r = m0 + ty * 8 + mp * 2;
                if (r     < M) C[(long long)r * ldc + col]       = cv.f.x + bv;
                if (r + 1 < M) C[(long long)(r + 1) * ldc + col] = cv.f.y + bv;
            }
        }
    } else {
        float cmax[4] = { 0.f, 0.f, 0.f, 0.f };
#pragma unroll
        for (int j = 0; j < 4; j++) {
            int col = n0 + tx * 4 + j;
            float bv = (col < N) ? bias[col] : 0.f;
#pragma unroll
            for (int mp = 0; mp < 4; mp++) {
                union { unsigned long long u; float2 f; } cv; cv.u = acc[mp][j];
                int r = m0 + ty * 8 + mp * 2;
                if (r     < M) cmax[j] = fmaxf(cmax[j], cv.f.x + bv);
                if (r + 1 < M) cmax[j] = fmaxf(cmax[j], cv.f.y + bv);
            }
        }
#pragma unroll
        for (int j = 0; j < 4; j++) red[ty][tx * 4 + j] = cmax[j];
        __syncthreads();
        if (ty == 0) {
#pragma unroll
            for (int j = 0; j < 4; j++) {
                int col = n0 + tx * 4 + j;
                if (col >= N) continue;
                float mx = 0.f;
                for (int t2 = 0; t2 < 16; t2++) mx = fmaxf(mx, red[t2][tx * 4 + j]);
                atomicMax((unsigned int*)&C[(long long)blockIdx.z * featLd + featOff + col],
                          __float_as_uint(mx));
            }
        }
    }
}

// ---------------- CSR build ----------------
__global__ void k_hist(const int* __restrict__ ei, int* __restrict__ deg) {
    int i = blockIdx.x * blockDim.x + threadIdx.x;
    if (i < NEDGE) atomicAdd(&deg[ei[NEDGE + i]], 1);
}

__global__ void k_scan(const int* __restrict__ deg, int* __restrict__ rs,
                       int* __restrict__ cur, int n) {
    __shared__ int s[1024];
    __shared__ int carry;
    int t = threadIdx.x;
    if (t == 0) carry = 0;
    __syncthreads();
    for (int base = 0; base < n; base += 1024) {
        int v = (base + t < n) ? deg[base + t] : 0;
        s[t] = v;
        __syncthreads();
        for (int off = 1; off < 1024; off <<= 1) {
            int add = (t >= off) ? s[t - off] : 0;
            __syncthreads();
            s[t] += add;
            __syncthreads();
        }
        int c0 = carry;
        int ex = c0 + s[t] - v;
        if (base + t < n) { rs[base + t] = ex; cur[base + t] = ex; }
        __syncthreads();
        if (t == 0) carry = c0 + s[1023];
        __syncthreads();
    }
    if (t == 0) rs[n] = carry;
}

__global__ void k_fill(const int* __restrict__ ei, int* __restrict__ cur,
                       int* __restrict__ cs) {
    int i = blockIdx.x * blockDim.x + threadIdx.x;
    if (i < NEDGE) {
        int d = ei[NEDGE + i];
        int p = atomicAdd(&cur[d], 1);
        cs[p] = ei[i];
    }
}

// ---------------- segment-sum + bf16 split of agg ----------------
__global__ void k_agg(const float* __restrict__ m, const int* __restrict__ rs,
                      const int* __restrict__ cs,
                      __nv_bfloat16* __restrict__ ahi, __nv_bfloat16* __restrict__ alo) {
    int w = (blockIdx.x * blockDim.x + threadIdx.x) >> 5;
    int lane = threadIdx.x & 31;
    if (w >= N_NODES) return;
    int s = rs[w], e = rs[w + 1];
    float a[7] = {0, 0, 0, 0, 0, 0, 0};
    int i = s;
    for (; i + 1 < e; i += 2) {
        const float* r0 = m + (long long)cs[i]     * HDIM;
        const float* r1 = m + (long long)cs[i + 1] * HDIM;
        a[0] += r0[lane]       + r1[lane];
        a[1] += r0[lane +  32] + r1[lane +  32];
        a[2] += r0[lane +  64] + r1[lane +  64];
        a[3] += r0[lane +  96] + r1[lane +  96];
        a[4] += r0[lane + 128] + r1[lane + 128];
        a[5] += r0[lane + 160] + r1[lane + 160];
        if (lane < 8) a[6] += r0[lane + 192] + r1[lane + 192];
    }
    if (i < e) {
        const float* r0 = m + (long long)cs[i] * HDIM;
        a[0] += r0[lane];       a[1] += r0[lane + 32];  a[2] += r0[lane + 64];
        a[3] += r0[lane + 96];  a[4] += r0[lane + 128]; a[5] += r0[lane + 160];
        if (lane < 8) a[6] += r0[lane + 192];
    }
    long long o = (long long)w * KPAD + lane;
#pragma unroll
    for (int q = 0; q < 6; q++) {
        __nv_bfloat16 h = __float2bfloat16(a[q]);
        ahi[o + q * 32] = h;
        alo[o + q * 32] = __float2bfloat16(a[q] - __bfloat162float(h));
    }
    if (lane < 8) {
        __nv_bfloat16 h = __float2bfloat16(a[6]);
        ahi[o + 192] = h;
        alo[o + 192] = __float2bfloat16(a[6] - __bfloat162float(h));
    }
}

// ---------------- GRU gates (+ bias fold + bf16 split of new h) ----------------
__global__ void k_gates(const float* __restrict__ gi, const float* __restrict__ gh,
                        const float* __restrict__ bih, const float* __restrict__ bhh,
                        const float* __restrict__ hsrc, float* __restrict__ hdst,
                        __nv_bfloat16* __restrict__ hhi, __nv_bfloat16* __restrict__ hlo) {
    int idx = blockIdx.x * blockDim.x + threadIdx.x;
    if (idx >= N_NODES * HDIM) return;
    int n = idx / HDIM, c = idx - n * HDIM;
    const float* giN = gi + (long long)n * 600;
    const float* ghN = gh + (long long)n * 600;
    float r  = 1.f / (1.f + expf(-(giN[c] + bih[c] + ghN[c] + bhh[c])));
    float z  = 1.f / (1.f + expf(-(giN[200 + c] + bih[200 + c] + ghN[200 + c] + bhh[200 + c])));
    float nn = tanhf(giN[400 + c] + bih[400 + c] + r * (ghN[400 + c] + bhh[400 + c]));
    float h = (1.f - z) * nn + z * hsrc[idx];
    hdst[idx] = h;
    __nv_bfloat16 hb = __float2bfloat16(h);
    long long o = (long long)n * KPAD + c;
    hhi[o] = hb;
    hlo[o] = __float2bfloat16(h - __bfloat162float(hb));
}

// ---------------- misc data movement ----------------
__global__ void k_hp(const float* __restrict__ h, float* __restrict__ hp) {
    int idx = blockIdx.x * blockDim.x + threadIdx.x;
    if (idx >= BATCH * 207 * HDIM) return;
    int b = idx / (207 * HDIM);
    int rem = idx - b * 207 * HDIM;
    int r = rem / HDIM, c = rem - r * HDIM;
    hp[idx] = (r == 0 || r == 206) ? 0.f
              : h[((long long)b * NPER + (r - 1)) * HDIM + c];
}

__global__ void k_wt(const float* __restrict__ w, float* __restrict__ wt,
                     int CO, int CI, int KK) {
    int idx = blockIdx.x * blockDim.x + threadIdx.x;
    if (idx >= CO * CI * KK) return;
    int co = idx / (CI * KK);
    int rem = idx - co * CI * KK;
    int ci = rem / KK, k = rem - ci * KK;
    wt[(long long)co * CI * KK + k * CI + ci] = w[idx];
}

// ---------------- fused FC head ----------------
__global__ void k_fc(const float* __restrict__ feats,
                     const float* __restrict__ w1, const float* __restrict__ b1,
                     const float* __restrict__ w2, const float* __restrict__ b2,
                     const float* __restrict__ w3, const float* __restrict__ b3,
                     float* __restrict__ out) {
    int b = blockIdx.x;
    int tid = threadIdx.x;
    int lane = tid & 31, wrp = tid >> 5;
    __shared__ float sf[800];
    __shared__ float s1[256];
    __shared__ float s2[128];
    for (int i = tid; i < 800; i += 256) sf[i] = feats[b * 800 + i];
    __syncthreads();
    for (int jj = 0; jj < 32; jj++) {
        int j = wrp * 32 + jj;
        float a = 0.f;
        for (int i = lane; i < 800; i += 32) a += sf[i] * w1[(long long)j * 800 + i];
        for (int o = 16; o; o >>= 1) a += __shfl_down_sync(0xffffffffu, a, o);
        if (lane == 0) s1[j] = fmaxf(a + b1[j], 0.f);
    }
    __syncthreads();
    if (tid < 128) {
        float a = b2[tid];
        for (int i = 0; i < 256; i++) a += s1[i] * w2[tid * 256 + i];
        s2[tid] = fmaxf(a, 0.f);
    }
    __syncthreads();
    if (tid < 2) {
        float a = b3[tid];
        for (int i = 0; i < 128; i++) a += s2[i] * w3[tid * 128 + i];
        out[b * 2 + tid] = a;
    }
}

// ---------------- launcher ----------------
extern "C" void kernel_launch(void* const* d_in, const int* in_sizes, int n_in,
                              void* d_out, int out_size) {
    const float* x     = (const float*)d_in[0];
    const int*   ei    = (const int*)  d_in[1];
    const int*   ids   = (const int*)  d_in[2];
    const float* etab  = (const float*)d_in[3];
    const float* ggcw  = (const float*)d_in[4];
    const float* wih   = (const float*)d_in[5];
    const float* whh   = (const float*)d_in[6];
    const float* bih   = (const float*)d_in[7];
    const float* bhh   = (const float*)d_in[8];
    const float* c0w   = (const float*)d_in[9];
    const float* c0b   = (const float*)d_in[10];
    const float* c1w   = (const float*)d_in[11];
    const float* c1b   = (const float*)d_in[12];
    const float* c2w   = (const float*)d_in[13];
    const float* c2b   = (const float*)d_in[14];
    const float* c3w   = (const float*)d_in[15];
    const float* c3b   = (const float*)d_in[16];
    const float* f1w   = (const float*)d_in[17];
    const float* f1b   = (const float*)d_in[18];
    const float* f2w   = (const float*)d_in[19];
    const float* f2b   = (const float*)d_in[20];
    const float* f3w   = (const float*)d_in[21];
    const float* f3b   = (const float*)d_in[22];
    float* out = (float*)d_out;

    float *h0, *h1, *mm, *gi, *gh, *hp, *w0t, *feats;
    int *deg, *rs, *cur, *cs;
    __half *e16, *w1h, *w2h, *w3h;
    __nv_bfloat16 *hhi, *hlo, *ahi, *alo, *wg, *wi, *wh;
    cudaGetSymbolAddress((void**)&h0,   g_h0);
    cudaGetSymbolAddress((void**)&h1,   g_h1);
    cudaGetSymbolAddress((void**)&mm,   g_m);
    cudaGetSymbolAddress((void**)&gi,   g_gi);
    cudaGetSymbolAddress((void**)&gh,   g_gh);
    cudaGetSymbolAddress((void**)&hp,   g_hp);
    cudaGetSymbolAddress((void**)&w0t,  g_w0t);
    cudaGetSymbolAddress((void**)&feats,g_feats);
    cudaGetSymbolAddress((void**)&deg,  g_deg);
    cudaGetSymbolAddress((void**)&rs,   g_rs);
    cudaGetSymbolAddress((void**)&cur,  g_cur);
    cudaGetSymbolAddress((void**)&cs,   g_csrc);
    cudaGetSymbolAddress((void**)&e16,  g_e16);
    cudaGetSymbolAddress((void**)&w1h,  g_w1h);
    cudaGetSymbolAddress((void**)&w2h,  g_w2h);
    cudaGetSymbolAddress((void**)&w3h,  g_w3h);
    cudaGetSymbolAddress((void**)&hhi,  g_hhi);
    cudaGetSymbolAddress((void**)&hlo,  g_hlo);
    cudaGetSymbolAddress((void**)&ahi,  g_ahi);
    cudaGetSymbolAddress((void**)&alo,  g_alo);
    cudaGetSymbolAddress((void**)&wg,   g_wg);
    cudaGetSymbolAddress((void**)&wi,   g_wi);
    cudaGetSymbolAddress((void**)&wh,   g_wh);

    const int CONV_SMEM = 36864 + 59904 + 832 + 832;   // 98432 B
    const int GGC_SMEM  = 36864 + 59904;               // 96768 B
    cudaFuncSetAttribute(conv3h_k,   cudaFuncAttributeMaxDynamicSharedMemorySize, CONV_SMEM);
    cudaFuncSetAttribute(ggc_hmma_k, cudaFuncAttributeMaxDynamicSharedMemorySize, GGC_SMEM);
    cudaFuncSetAttribute(ggc_mh_k,   cudaFuncAttributeMaxDynamicSharedMemorySize, GGC_SMEM);

    // side stream + events (created once; host resources, no device allocs)
    static cudaStream_t s2 = nullptr;
    static cudaEvent_t ev1 = nullptr, ev2 = nullptr;
    if (!s2) {
        cudaStreamCreateWithFlags(&s2, cudaStreamNonBlocking);
        cudaEventCreateWithFlags(&ev1, cudaEventDisableTiming);
        cudaEventCreateWithFlags(&ev2, cudaEventDisableTiming);
    }

    // ---- default stream: feats zero, then fork conv branch ----
    cudaMemsetAsync(feats, 0, BATCH * 800 * sizeof(float));
    cudaEventRecord(ev1, 0);
    cudaStreamWaitEvent(s2, ev1, 0);

    // ---- side stream: conv1/2/3 branch (independent of GGC) ----
    k_embed16<<<BATCH * SEQ + 8, 192, 0, s2>>>(ids, etab, e16);
    k_w16<<<(200 * 768 * 3 + 255) / 256, 256, 0, s2>>>(c1w, w1h, 3);
    k_w16<<<(200 * 768 * 4 + 255) / 256, 256, 0, s2>>>(c2w, w2h, 4);
    k_w16<<<(200 * 768 * 5 + 255) / 256, 256, 0, s2>>>(c3w, w3h, 5);
    {
        Conv3Args ca;
        ca.wb[0] = w1h; ca.wb[1] = w2h; ca.wb[2] = w3h;
        ca.bias[0] = c1b; ca.bias[1] = c2b; ca.bias[2] = c3b;
        conv3h_k<<<dim3(3, 4, BATCH), 256, CONV_SMEM, s2>>>(e16, ca, feats);
    }
    cudaEventRecord(ev2, s2);

    // ---- default stream: CSR + GGC prep ----
    cudaMemsetAsync(deg, 0, N_NODES * sizeof(int));
    k_hist<<<(NEDGE + 255) / 256, 256>>>(ei, deg);
    k_scan<<<1, 1024>>>(deg, rs, cur, N_NODES);
    k_fill<<<(NEDGE + 255) / 256, 256>>>(ei, cur, cs);
    cudaMemcpyAsync(h0, x, (size_t)N_NODES * HDIM * sizeof(float),
                    cudaMemcpyDeviceToDevice);
    k_xsplit<<<(N_NODES * KPAD + 255) / 256, 256>>>(x, hhi, hlo);
    k_wggc<<<(NLAYERS * 208 * 768 + 255) / 256, 256>>>(ggcw, wg);
    k_wgru<<<(624 * 768 + 255) / 256, 256>>>(wih, wi);
    k_wgru<<<(624 * 768 + 255) / 256, 256>>>(whh, wh);
    k_wt<<<(200 * 200 * 3 + 255) / 256, 256>>>(c0w, w0t, 200, 200, 3);

    // ---- gated graph conv: 6 layers (HMMA bf16x3) ----
    float* hc = h0;
    float* hn = h1;
    for (int l = 0; l < NLAYERS; l++) {
        // fused: m = h @ ggc_w[l]  and  gh = h @ whh^T  (same A)
        ggc_mh_k<<<dim3(4, NPER), 256, GGC_SMEM>>>(hhi, hlo,
                                                   wg + (long long)l * 208 * 768, wh,
                                                   mm, gh);
        // agg = segment_sum(m[src], dst), split to bf16
        k_agg<<<(N_NODES + 7) / 8, 256>>>(mm, rs, cs, ahi, alo);
        // gi = agg @ wih^T
        ggc_hmma_k<<<dim3(3, NPER), 256, GGC_SMEM>>>(ahi, alo, wi, gi, 600, 600);
        // GRU update (+bias fold) and re-split h
        k_gates<<<(N_NODES * HDIM + 255) / 256, 256>>>(gi, gh, bih, bhh, hc, hn, hhi, hlo);
        float* t = hc; hc = hn; hn = t;
    }

    // ---- conv0 (fp32 SIMT, fused bias+ReLU+max; feats cols 0..199) ----
    k_hp<<<(BATCH * 207 * HDIM + 255) / 256, 256>>>(hc, hp);
    sgemm_k<true, 1><<<dim3(4, 2, BATCH), 256>>>(hp, 200, 207LL * 200, w0t, c0b, feats,
                                                 205, 200, 600, 0, 800, 0);

    // ---- join conv branch, then FC head ----
    cudaStreamWaitEvent(0, ev2, 0);
    k_fc<<<BATCH, 256>>>(feats, f1w, f1b, f2w, f2b, f3w, f3b, out);
}

// round 13
// speedup vs baseline: 4.8168x; 1.3472x over previous
#include <cuda_runtime.h>
#include <cuda_bf16.h>
#include <cuda_fp16.h>
#include <cstdint>

// ---------------- problem constants ----------------
#define N_NODES 26240      // B * N_PER = 128 * 205 (exactly 205 blocks of 128)
#define HDIM    200
#define NEDGE   209920
#define BATCH   128
#define NPER    205
#define EMBD    768
#define SEQ     512
#define NLAYERS 6
#define KPAD    256        // padded K (GGC, fp16 single pass)

// ---------------- static device scratch ----------------
__device__ float g_h0[N_NODES * HDIM];
__device__ float g_h1[N_NODES * HDIM];
__device__ float g_m [N_NODES * HDIM];
__device__ float g_gi[N_NODES * 3 * HDIM];
__device__ float g_gh[N_NODES * 3 * HDIM];
__device__ float g_hp [BATCH * 207 * HDIM];             // zero-padded conv0 input
__device__ float g_w0t[200 * 600];
__device__ float g_feats[BATCH * 800];
__device__ int   g_deg[N_NODES];
__device__ int   g_rs [N_NODES + 1];
__device__ int   g_cur[N_NODES];
__device__ int   g_csrc[NEDGE];

// GGC fp16 operands, K-padded to 256 (pads stay zero after init)
__device__ __align__(16) __half g_h16[(size_t)N_NODES * KPAD];
__device__ __align__(16) __half g_a16[(size_t)N_NODES * KPAD];
// GGC fp16 weights: [Npad][256] K-padded
__device__ __align__(16) __half g_wg16[NLAYERS * 208 * KPAD];   // ggc_w[l]^T
__device__ __align__(16) __half g_wi16[624 * KPAD];             // wih
__device__ __align__(16) __half g_wh16[624 * KPAD];             // whh

// fp16 embeddings, time-major [b][t][c], +8 zero rows for tap overrun
__device__ __align__(16) __half g_e16[((size_t)BATCH * SEQ + 8) * EMBD];
// fp16 conv weights: [200][K], tap-major K (single pass)
__device__ __align__(16) __half g_w1h[200 * 2304];
__device__ __align__(16) __half g_w2h[200 * 3072];
__device__ __align__(16) __half g_w3h[200 * 3840];

// ---------------- packed fp32x2 helpers (sm_100+) ----------------
#define FMA2(d, a, b) asm("fma.rn.f32x2 %0, %1, %2, %0;" : "+l"(d) : "l"(a), "l"(b))

__device__ __forceinline__ unsigned long long pack2(float x, float y) {
    unsigned long long r;
    asm("mov.b64 %0, {%1, %2};" : "=l"(r) : "r"(__float_as_uint(x)), "r"(__float_as_uint(y)));
    return r;
}

// ---------------- warp-level MMAs (compute_100-safe PTX) ----------------
#define MMA_F16(d, a, b0, b1) asm volatile(                            \
    "mma.sync.aligned.m16n8k16.row.col.f32.f16.f16.f32 "               \
    "{%0,%1,%2,%3}, {%4,%5,%6,%7}, {%8,%9}, {%0,%1,%2,%3};"            \
    : "+f"((d)[0]), "+f"((d)[1]), "+f"((d)[2]), "+f"((d)[3])           \
    : "r"((a)[0]), "r"((a)[1]), "r"((a)[2]), "r"((a)[3]),              \
      "r"(b0), "r"(b1))

// ---------------- cp.async helpers (sm_80+ PTX) ----------------
#define CP16(dst, src) asm volatile("cp.async.ca.shared.global [%0], [%1], 16;" \
                                    :: "r"(dst), "l"(src))
#define CP_COMMIT() asm volatile("cp.async.commit_group;" ::: "memory")
#define CP_WAIT0()  asm volatile("cp.async.wait_group 0;" ::: "memory")

__device__ __forceinline__ uint32_t s2u(const void* p) {
    return (uint32_t)__cvta_generic_to_shared(p);
}

// ---------------- GGC GEMM: gi = agg @ wih^T (fp16 single pass) ----------------
// grid (3 n-tiles, 205 m-tiles). 256 threads = 8 warps (4m x 2n). K = 256 -> 4 tiles.
__global__ void __launch_bounds__(256, 1) ggc_hmma_k(
    const __half* __restrict__ A,
    const __half* __restrict__ B,
    float* __restrict__ C, int N, int ldc)
{
    extern __shared__ __align__(16) char dsm[];
    constexpr int ASTR = 72, BSTR = 72;
    __half* As = (__half*)dsm;                 // [2][128][72]
    __half* Bs = (__half*)(dsm + 36864);       // [2][208][72]

    const int tid = threadIdx.x;
    const int lane = tid & 31, wid = tid >> 5;
    const int wm = wid & 3, wn = wid >> 2;
    const int g = lane >> 2, t2 = (lane & 3) * 2;
    const int m0 = blockIdx.y * 128;
    const int n0 = blockIdx.x * 208;
    const uint32_t asb = s2u(As), bsb = s2u(Bs);

    auto copy_tile = [&](int kt, int buf) {
        const int kg = kt * 64;
        const uint32_t ab = asb + buf * 128 * ASTR * 2;
        const uint32_t bb = bsb + buf * 208 * BSTR * 2;
#pragma unroll
        for (int i = 0; i < 4; i++) {
            int u = tid + i * 256;
            int row = u >> 3, ch = u & 7;
            CP16(ab + (row * ASTR + ch * 8) * 2,
                 A + (long long)(m0 + row) * KPAD + kg + ch * 8);
        }
#pragma unroll
        for (int i = 0; i < 7; i++) {
            int u = tid + i * 256;
            if (u < 1664) {
                int row = u >> 3, ch = u & 7;
                CP16(bb + (row * BSTR + ch * 8) * 2,
                     B + (long long)(n0 + row) * KPAD + kg + ch * 8);
            }
        }
    };

    float acc[2][13][4];
#pragma unroll
    for (int i = 0; i < 2; i++)
#pragma unroll
        for (int j = 0; j < 13; j++)
#pragma unroll
            for (int q = 0; q < 4; q++) acc[i][j][q] = 0.f;

    copy_tile(0, 0); CP_COMMIT(); CP_WAIT0();
    __syncthreads();

#pragma unroll 1
    for (int kt = 0; kt < 4; kt++) {
        const int buf = kt & 1;
        const bool more = (kt + 1 < 4);
        if (more) { copy_tile(kt + 1, buf ^ 1); CP_COMMIT(); }

        const __half* Ab = As + buf * 128 * ASTR;
        const __half* Bb = Bs + buf * 208 * BSTR;
#pragma unroll
        for (int ks = 0; ks < 4; ks++) {
            const int ko = ks * 16;
            uint32_t a[2][4];
#pragma unroll
            for (int i = 0; i < 2; i++) {
                const int r = wm * 32 + i * 16 + g;
                a[i][0] = *(const uint32_t*)(Ab + (r)     * ASTR + ko + t2);
                a[i][1] = *(const uint32_t*)(Ab + (r + 8) * ASTR + ko + t2);
                a[i][2] = *(const uint32_t*)(Ab + (r)     * ASTR + ko + t2 + 8);
                a[i][3] = *(const uint32_t*)(Ab + (r + 8) * ASTR + ko + t2 + 8);
            }
            uint32_t bf[13][2];
#pragma unroll
            for (int j = 0; j < 13; j++) {
                const int n = wn * 104 + j * 8 + g;
                bf[j][0] = *(const uint32_t*)(Bb + n * BSTR + ko + t2);
                bf[j][1] = *(const uint32_t*)(Bb + n * BSTR + ko + t2 + 8);
            }
#pragma unroll
            for (int j = 0; j < 13; j++) {
                MMA_F16(acc[0][j], a[0], bf[j][0], bf[j][1]);
                MMA_F16(acc[1][j], a[1], bf[j][0], bf[j][1]);
            }
        }
        if (more) CP_WAIT0();
        __syncthreads();
    }

#pragma unroll
    for (int i = 0; i < 2; i++) {
        const int r = m0 + wm * 32 + i * 16 + g;
#pragma unroll
        for (int j = 0; j < 13; j++) {
            const int col = n0 + wn * 104 + j * 8 + t2;
            if (col < N) {
                C[(long long)r * ldc + col]       = acc[i][j][0];
                C[(long long)(r + 8) * ldc + col] = acc[i][j][2];
            }
            if (col + 1 < N) {
                C[(long long)r * ldc + col + 1]       = acc[i][j][1];
                C[(long long)(r + 8) * ldc + col + 1] = acc[i][j][3];
            }
        }
    }
}

// ---------------- fused m + gh GEMM (same A = h, fp16) ----------------
// grid (4, 205): bx==0 -> m = h @ ggc_w[l] (N=200); bx in 1..3 -> gh slice.
__global__ void __launch_bounds__(256, 1) ggc_mh_k(
    const __half* __restrict__ A,
    const __half* __restrict__ wgl,    // [208][256] layer slice
    const __half* __restrict__ wh,     // [624][256]
    float* __restrict__ Cm,
    float* __restrict__ Cg)
{
    extern __shared__ __align__(16) char dsm[];
    constexpr int ASTR = 72, BSTR = 72;
    __half* As = (__half*)dsm;
    __half* Bs = (__half*)(dsm + 36864);

    const int tid = threadIdx.x;
    const int lane = tid & 31, wid = tid >> 5;
    const int wm = wid & 3, wn = wid >> 2;
    const int g = lane >> 2, t2 = (lane & 3) * 2;
    const int m0 = blockIdx.y * 128;
    const int bx = blockIdx.x;
    const uint32_t asb = s2u(As), bsb = s2u(Bs);

    const __half* B = (bx == 0) ? wgl : (wh + (long long)(bx - 1) * 208 * KPAD);
    float* C      = (bx == 0) ? Cm  : Cg;
    const int ldc = (bx == 0) ? 200 : 600;
    const int N   = (bx == 0) ? 200 : 600;
    const int cb  = (bx == 0) ? 0   : (bx - 1) * 208;

    auto copy_tile = [&](int kt, int buf) {
        const int kg = kt * 64;
        const uint32_t ab = asb + buf * 128 * ASTR * 2;
        const uint32_t bb = bsb + buf * 208 * BSTR * 2;
#pragma unroll
        for (int i = 0; i < 4; i++) {
            int u = tid + i * 256;
            int row = u >> 3, ch = u & 7;
            CP16(ab + (row * ASTR + ch * 8) * 2,
                 A + (long long)(m0 + row) * KPAD + kg + ch * 8);
        }
#pragma unroll
        for (int i = 0; i < 7; i++) {
            int u = tid + i * 256;
            if (u < 1664) {
                int row = u >> 3, ch = u & 7;
                CP16(bb + (row * BSTR + ch * 8) * 2,
                     B + (long long)row * KPAD + kg + ch * 8);
            }
        }
    };

    float acc[2][13][4];
#pragma unroll
    for (int i = 0; i < 2; i++)
#pragma unroll
        for (int j = 0; j < 13; j++)
#pragma unroll
            for (int q = 0; q < 4; q++) acc[i][j][q] = 0.f;

    copy_tile(0, 0); CP_COMMIT(); CP_WAIT0();
    __syncthreads();

#pragma unroll 1
    for (int kt = 0; kt < 4; kt++) {
        const int buf = kt & 1;
        const bool more = (kt + 1 < 4);
        if (more) { copy_tile(kt + 1, buf ^ 1); CP_COMMIT(); }

        const __half* Ab = As + buf * 128 * ASTR;
        const __half* Bb = Bs + buf * 208 * BSTR;
#pragma unroll
        for (int ks = 0; ks < 4; ks++) {
            const int ko = ks * 16;
            uint32_t a[2][4];
#pragma unroll
            for (int i = 0; i < 2; i++) {
                const int r = wm * 32 + i * 16 + g;
                a[i][0] = *(const uint32_t*)(Ab + (r)     * ASTR + ko + t2);
                a[i][1] = *(const uint32_t*)(Ab + (r + 8) * ASTR + ko + t2);
                a[i][2] = *(const uint32_t*)(Ab + (r)     * ASTR + ko + t2 + 8);
                a[i][3] = *(const uint32_t*)(Ab + (r + 8) * ASTR + ko + t2 + 8);
            }
            uint32_t bf[13][2];
#pragma unroll
            for (int j = 0; j < 13; j++) {
                const int n = wn * 104 + j * 8 + g;
                bf[j][0] = *(const uint32_t*)(Bb + n * BSTR + ko + t2);
                bf[j][1] = *(const uint32_t*)(Bb + n * BSTR + ko + t2 + 8);
            }
#pragma unroll
            for (int j = 0; j < 13; j++) {
                MMA_F16(acc[0][j], a[0], bf[j][0], bf[j][1]);
                MMA_F16(acc[1][j], a[1], bf[j][0], bf[j][1]);
            }
        }
        if (more) CP_WAIT0();
        __syncthreads();
    }

#pragma unroll
    for (int i = 0; i < 2; i++) {
        const int r = m0 + wm * 32 + i * 16 + g;
#pragma unroll
        for (int j = 0; j < 13; j++) {
            const int col = cb + wn * 104 + j * 8 + t2;
            if (col < N) {
                C[(long long)r * ldc + col]       = acc[i][j][0];
                C[(long long)(r + 8) * ldc + col] = acc[i][j][2];
            }
            if (col + 1 < N) {
                C[(long long)r * ldc + col + 1]       = acc[i][j][1];
                C[(long long)(r + 8) * ldc + col + 1] = acc[i][j][3];
            }
        }
    }
}

// ---------------- fused conv1/2/3: pure fp16 conv-as-GEMM (single pass) ----------------
struct Conv3Args {
    const __half* wb[3];
    const float* bias[3];
};
// grid (3 convs, 4 m-tiles, 128 batches)
__global__ void __launch_bounds__(256, 1) conv3h_k(
    const __half* __restrict__ e16,
    Conv3Args args,
    float* __restrict__ feats)
{
    extern __shared__ __align__(16) char dsm[];
    constexpr int ASTR = 72, BSTR = 72;
    __half* As = (__half*)dsm;
    __half* Bs = (__half*)(dsm + 36864);
    float* smax  = (float*)(dsm + 36864 + 59904);
    float* sbias = smax + 208;

    const int cid = blockIdx.x;
    const int M   = (cid == 0) ? 510 : (cid == 1) ? 509 : 508;
    const int K   = (cid == 0) ? 2304 : (cid == 1) ? 3072 : 3840;   // 768 * taps
    const int featOff = 200 + cid * 200;
    const __half* wb = args.wb[cid];
    const float* bias = args.bias[cid];

    const int tid = threadIdx.x;
    const int lane = tid & 31, wid = tid >> 5;
    const int wm = wid & 3, wn = wid >> 2;
    const int g = lane >> 2, t2 = (lane & 3) * 2;
    const int b = blockIdx.z, m0 = blockIdx.y * 128;
    const int T = K / 64;
    const uint32_t asb = s2u(As), bsb = s2u(Bs);

    if (tid < 208) { smax[tid] = 0.f; sbias[tid] = (tid < 200) ? bias[tid] : 0.f; }

    auto copy_tile = [&](int kt, int buf) {
        int kk = kt / 12;
        int c0 = (kt - kk * 12) * 64;
        long long abase = ((long long)(b * SEQ + m0 + kk)) * EMBD + c0;
        const uint32_t ab = asb + buf * 128 * ASTR * 2;
        const uint32_t bb = bsb + buf * 208 * BSTR * 2;
#pragma unroll
        for (int i = 0; i < 4; i++) {
            int u = tid + i * 256;
            int row = u >> 3, ch = u & 7;
            CP16(ab + (row * ASTR + ch * 8) * 2,
                 e16 + abase + (long long)row * EMBD + ch * 8);
        }
        int kg = kt * 64;
#pragma unroll
        for (int i = 0; i < 7; i++) {
            int u = tid + i * 256;
            if (u < 1600) {
                int row = u >> 3, ch = u & 7;
                CP16(bb + (row * BSTR + ch * 8) * 2,
                     wb + (long long)row * K + kg + ch * 8);
            }
        }
    };

    float acc[2][13][4];
#pragma unroll
    for (int i = 0; i < 2; i++)
#pragma unroll
        for (int j = 0; j < 13; j++)
#pragma unroll
            for (int q = 0; q < 4; q++) acc[i][j][q] = 0.f;

    copy_tile(0, 0); CP_COMMIT(); CP_WAIT0();
    __syncthreads();

#pragma unroll 1
    for (int kt = 0; kt < T; kt++) {
        const int buf = kt & 1;
        const bool more = (kt + 1 < T);
        if (more) { copy_tile(kt + 1, buf ^ 1); CP_COMMIT(); }

        const __half* Ab = As + buf * 128 * ASTR;
        const __half* Bb = Bs + buf * 208 * BSTR;
#pragma unroll
        for (int ks = 0; ks < 4; ks++) {
            const int ko = ks * 16;
            uint32_t a[2][4];
#pragma unroll
            for (int i = 0; i < 2; i++) {
                const int r = wm * 32 + i * 16 + g;
                a[i][0] = *(const uint32_t*)(Ab + (r)     * ASTR + ko + t2);
                a[i][1] = *(const uint32_t*)(Ab + (r + 8) * ASTR + ko + t2);
                a[i][2] = *(const uint32_t*)(Ab + (r)     * ASTR + ko + t2 + 8);
                a[i][3] = *(const uint32_t*)(Ab + (r + 8) * ASTR + ko + t2 + 8);
            }
            uint32_t bf[13][2];
#pragma unroll
            for (int j = 0; j < 13; j++) {
                const int n = wn * 104 + j * 8 + g;
                bf[j][0] = *(const uint32_t*)(Bb + n * BSTR + ko + t2);
                bf[j][1] = *(const uint32_t*)(Bb + n * BSTR + ko + t2 + 8);
            }
#pragma unroll
            for (int j = 0; j < 13; j++) {
                MMA_F16(acc[0][j], a[0], bf[j][0], bf[j][1]);
                MMA_F16(acc[1][j], a[1], bf[j][0], bf[j][1]);
            }
        }
        if (more) CP_WAIT0();
        __syncthreads();
    }

    const int valid = (M - m0 < 128) ? (M - m0) : 128;
#pragma unroll
    for (int j = 0; j < 13; j++) {
        float v0 = -1e30f, v1 = -1e30f;
#pragma unroll
        for (int i = 0; i < 2; i++) {
            const int r0 = wm * 32 + i * 16 + g;
            if (r0 < valid)     { v0 = fmaxf(v0, acc[i][j][0]); v1 = fmaxf(v1, acc[i][j][1]); }
            if (r0 + 8 < valid) { v0 = fmaxf(v0, acc[i][j][2]); v1 = fmaxf(v1, acc[i][j][3]); }
        }
#pragma unroll
        for (int o = 4; o <= 16; o <<= 1) {
            v0 = fmaxf(v0, __shfl_xor_sync(~0u, v0, o));
            v1 = fmaxf(v1, __shfl_xor_sync(~0u, v1, o));
        }
        if (g == 0) {
            const int col = wn * 104 + j * 8 + t2;
            if (col < 200) {
                float r = fmaxf(v0 + sbias[col], 0.f);
                atomicMax((unsigned int*)&smax[col], __float_as_uint(r));
            }
            if (col + 1 < 200) {
                float r = fmaxf(v1 + sbias[col + 1], 0.f);
                atomicMax((unsigned int*)&smax[col + 1], __float_as_uint(r));
            }
        }
    }
    __syncthreads();
    if (tid < 200)
        atomicMax((unsigned int*)&feats[(long long)b * 800 + featOff + tid],
                  __float_as_uint(smax[tid]));
}

// ---------------- fp16 embed (single array) ----------------
__global__ void k_embed16(const int* __restrict__ ids, const float* __restrict__ tbl,
                          __half* __restrict__ e16) {
    int row = blockIdx.x;
    int t = threadIdx.x;                   // 192 threads, one float4 each
    long long o = (long long)row * EMBD;
    if (row >= BATCH * SEQ) {
        if (t < 96) {
            ((uint2*)(e16 + o))[t * 2]     = make_uint2(0, 0);
            ((uint2*)(e16 + o))[t * 2 + 1] = make_uint2(0, 0);
        }
        return;
    }
    long long id = ids[row];
    float4 v = ((const float4*)(tbl + id * EMBD))[t];
    __half2 h01 = __floats2half2_rn(v.x, v.y);
    __half2 h23 = __floats2half2_rn(v.z, v.w);
    uint2 hv;
    hv.x = *(uint32_t*)&h01; hv.y = *(uint32_t*)&h23;
    ((uint2*)(e16 + o))[t] = hv;
}

// w: [200][768][KK] fp32 -> wb: [200][K] fp16, tap-major K
__global__ void k_w16(const float* __restrict__ w, __half* __restrict__ wb, int KK) {
    int K = 768 * KK;
    int idx = blockIdx.x * blockDim.x + threadIdx.x;
    if (idx >= 200 * K) return;
    int co = idx / K, r = idx - co * K;
    int kk = r / 768, ci = r - kk * 768;
    wb[idx] = __float2half(w[(co * 768 + ci) * KK + kk]);
}

// ---------------- GGC fp16 precompute ----------------
// ggc_w[l][k][n] -> [l][208 rows (n)][256 cols (k)], zero pad
__global__ void k_wggc16(const float* __restrict__ w, __half* __restrict__ out) {
    int idx = blockIdx.x * blockDim.x + threadIdx.x;
    if (idx >= NLAYERS * 208 * KPAD) return;
    int l = idx / (208 * KPAD);
    int rem = idx - l * 208 * KPAD;
    int n = rem / KPAD, kk = rem - n * KPAD;
    float x = (n < 200 && kk < 200) ? w[(long long)l * 40000 + kk * 200 + n] : 0.f;
    out[idx] = __float2half(x);
}

// wih/whh [600][200] -> [624][256], zero pad
__global__ void k_wgru16(const float* __restrict__ w, __half* __restrict__ out) {
    int idx = blockIdx.x * blockDim.x + threadIdx.x;
    if (idx >= 624 * KPAD) return;
    int n = idx / KPAD, kk = idx - n * KPAD;
    float x = (n < 600 && kk < 200) ? w[n * 200 + kk] : 0.f;
    out[idx] = __float2half(x);
}

// x [26240][200] fp32 -> h16 [26240][256] fp16 (pads zeroed here, forever)
__global__ void k_x16(const float* __restrict__ xin, __half* __restrict__ h16) {
    int idx = blockIdx.x * blockDim.x + threadIdx.x;
    if (idx >= N_NODES * KPAD) return;
    int n = idx >> 8, c = idx & 255;
    h16[idx] = __float2half((c < 200) ? xin[n * HDIM + c] : 0.f);
}

// ---------------- fp32 SIMT GEMM (conv0 only) ----------------
template<bool TB, int EPI>
__global__ void __launch_bounds__(256, 2) sgemm_k(
    const float* __restrict__ A, int lda, long long aStride,
    const float* __restrict__ B,
    const float* __restrict__ bias,
    float* __restrict__ C,
    int M, int N, int K,
    int ldc, int featLd, int featOff)
{
    constexpr int BM = 128, BN = 64, BK = 8;
    __shared__ __align__(16) float As[2][BK][132];
    __shared__ __align__(16) float Bs[2][BK][68];
    __shared__ float red[16][68];

    const int tid = threadIdx.x;
    const int tx = tid & 15, ty = tid >> 4;
    const int m0 = blockIdx.y * BM;
    const int n0 = blockIdx.x * BN;
    const float* Ab = A + (long long)blockIdx.z * aStride;

    const int arow = tid >> 1, akq = (tid & 1) * 4;
    const int bk   = tid >> 5, bn2 = (tid & 31) * 2;
    const int bn   = tid >> 2, bkq = (tid & 3) * 2;

    unsigned long long acc[4][4];
#pragma unroll
    for (int i = 0; i < 4; i++)
#pragma unroll
        for (int j = 0; j < 4; j++) acc[i][j] = 0ULL;

    const int KT = K / BK;

    float4 aR = make_float4(0.f, 0.f, 0.f, 0.f);
    float2 bR = make_float2(0.f, 0.f);
    {
        int row = m0 + arow;
        if (row < M) aR = *(const float4*)(Ab + (long long)row * lda + akq);
        if (!TB) { if (n0 + bn2 < N) bR = *(const float2*)(B + (long long)bk * N + n0 + bn2); }
        else     { if (n0 + bn  < N) bR = *(const float2*)(B + (long long)(n0 + bn) * K + bkq); }
    }
    As[0][akq + 0][arow] = aR.x; As[0][akq + 1][arow] = aR.y;
    As[0][akq + 2][arow] = aR.z; As[0][akq + 3][arow] = aR.w;
    if (!TB) { Bs[0][bk][bn2] = bR.x; Bs[0][bk][bn2 + 1] = bR.y; }
    else     { Bs[0][bkq][bn] = bR.x; Bs[0][bkq + 1][bn] = bR.y; }
    __syncthreads();

    for (int kt = 0; kt < KT; kt++) {
        const int cur = kt & 1;
        const int k0n = (kt + 1) * BK;
        if (kt + 1 < KT) {
            int row = m0 + arow;
            aR = make_float4(0.f, 0.f, 0.f, 0.f);
            bR = make_float2(0.f, 0.f);
            if (row < M) aR = *(const float4*)(Ab + (long long)row * lda + k0n + akq);
            if (!TB) { if (n0 + bn2 < N) bR = *(const float2*)(B + (long long)(k0n + bk) * N + n0 + bn2); }
            else     { if (n0 + bn  < N) bR = *(const float2*)(B + (long long)(n0 + bn) * K + k0n + bkq); }
        }
#pragma unroll
        for (int k = 0; k < BK; k++) {
            const float* ap_ = &As[cur][k][ty * 8];
            ulonglong2 a0 = *(const ulonglong2*)ap_;
            ulonglong2 a1 = *(const ulonglong2*)(ap_ + 4);
            float4 bv = *(const float4*)&Bs[cur][k][tx * 4];
            unsigned long long ap[4] = { a0.x, a0.y, a1.x, a1.y };
            unsigned long long bb[4] = { pack2(bv.x, bv.x), pack2(bv.y, bv.y),
                                         pack2(bv.z, bv.z), pack2(bv.w, bv.w) };
#pragma unroll
            for (int mp = 0; mp < 4; mp++)
#pragma unroll
                for (int j = 0; j < 4; j++)
                    FMA2(acc[mp][j], ap[mp], bb[j]);
        }
        if (kt + 1 < KT) {
            const int nb = cur ^ 1;
            As[nb][akq + 0][arow] = aR.x; As[nb][akq + 1][arow] = aR.y;
            As[nb][akq + 2][arow] = aR.z; As[nb][akq + 3][arow] = aR.w;
            if (!TB) { Bs[nb][bk][bn2] = bR.x; Bs[nb][bk][bn2 + 1] = bR.y; }
            else     { Bs[nb][bkq][bn] = bR.x; Bs[nb][bkq + 1][bn] = bR.y; }
        }
        __syncthreads();
    }

    if (EPI == 0) {
#pragma unroll
        for (int j = 0; j < 4; j++) {
            int col = n0 + tx * 4 + j;
            if (col >= N) continue;
            float bv = bias ? bias[col] : 0.f;
#pragma unroll
            for (int mp = 0; mp < 4; mp++) {
                union { unsigned long long u; float2 f; } cv; cv.u = acc[mp][j];
                int r = m0 + ty * 8 + mp * 2;
                if (r     < M) C[(long long)r * ldc + col]       = cv.f.x + bv;
                if (r + 1 < M) C[(long long)(r + 1) * ldc + col] = cv.f.y + bv;
            }
        }
    } else {
        float cmax[4] = { 0.f, 0.f, 0.f, 0.f };
#pragma unroll
        for (int j = 0; j < 4; j++) {
            int col = n0 + tx * 4 + j;
            float bv = (col < N) ? bias[col] : 0.f;
#pragma unroll
            for (int mp = 0; mp < 4; mp++) {
                union { unsigned long long u; float2 f; } cv; cv.u = acc[mp][j];
                int r = m0 + ty * 8 + mp * 2;
                if (r     < M) cmax[j] = fmaxf(cmax[j], cv.f.x + bv);
                if (r + 1 < M) cmax[j] = fmaxf(cmax[j], cv.f.y + bv);
            }
        }
#pragma unroll
        for (int j = 0; j < 4; j++) red[ty][tx * 4 + j] = cmax[j];
        __syncthreads();
        if (ty == 0) {
#pragma unroll
            for (int j = 0; j < 4; j++) {
                int col = n0 + tx * 4 + j;
                if (col >= N) continue;
                float mx = 0.f;
                for (int t2 = 0; t2 < 16; t2++) mx = fmaxf(mx, red[t2][tx * 4 + j]);
                atomicMax((unsigned int*)&C[(long long)blockIdx.z * featLd + featOff + col],
                          __float_as_uint(mx));
            }
        }
    }
}

// ---------------- CSR build ----------------
__global__ void k_hist(const int* __restrict__ ei, int* __restrict__ deg) {
    int i = blockIdx.x * blockDim.x + threadIdx.x;
    if (i < NEDGE) atomicAdd(&deg[ei[NEDGE + i]], 1);
}

__global__ void k_scan(const int* __restrict__ deg, int* __restrict__ rs,
                       int* __restrict__ cur, int n) {
    __shared__ int s[1024];
    __shared__ int carry;
    int t = threadIdx.x;
    if (t == 0) carry = 0;
    __syncthreads();
    for (int base = 0; base < n; base += 1024) {
        int v = (base + t < n) ? deg[base + t] : 0;
        s[t] = v;
        __syncthreads();
        for (int off = 1; off < 1024; off <<= 1) {
            int add = (t >= off) ? s[t - off] : 0;
            __syncthreads();
            s[t] += add;
            __syncthreads();
        }
        int c0 = carry;
        int ex = c0 + s[t] - v;
        if (base + t < n) { rs[base + t] = ex; cur[base + t] = ex; }
        __syncthreads();
        if (t == 0) carry = c0 + s[1023];
        __syncthreads();
    }
    if (t == 0) rs[n] = carry;
}

__global__ void k_fill(const int* __restrict__ ei, int* __restrict__ cur,
                       int* __restrict__ cs) {
    int i = blockIdx.x * blockDim.x + threadIdx.x;
    if (i < NEDGE) {
        int d = ei[NEDGE + i];
        int p = atomicAdd(&cur[d], 1);
        cs[p] = ei[i];
    }
}

// ---------------- segment-sum + fp16 write of agg ----------------
__global__ void k_agg(const float* __restrict__ m, const int* __restrict__ rs,
                      const int* __restrict__ cs, __half* __restrict__ a16) {
    int w = (blockIdx.x * blockDim.x + threadIdx.x) >> 5;
    int lane = threadIdx.x & 31;
    if (w >= N_NODES) return;
    int s = rs[w], e = rs[w + 1];
    float a[7] = {0, 0, 0, 0, 0, 0, 0};
    int i = s;
    for (; i + 1 < e; i += 2) {
        const float* r0 = m + (long long)cs[i]     * HDIM;
        const float* r1 = m + (long long)cs[i + 1] * HDIM;
        a[0] += r0[lane]       + r1[lane];
        a[1] += r0[lane +  32] + r1[lane +  32];
        a[2] += r0[lane +  64] + r1[lane +  64];
        a[3] += r0[lane +  96] + r1[lane +  96];
        a[4] += r0[lane + 128] + r1[lane + 128];
        a[5] += r0[lane + 160] + r1[lane + 160];
        if (lane < 8) a[6] += r0[lane + 192] + r1[lane + 192];
    }
    if (i < e) {
        const float* r0 = m + (long long)cs[i] * HDIM;
        a[0] += r0[lane];       a[1] += r0[lane + 32];  a[2] += r0[lane + 64];
        a[3] += r0[lane + 96];  a[4] += r0[lane + 128]; a[5] += r0[lane + 160];
        if (lane < 8) a[6] += r0[lane + 192];
    }
    long long o = (long long)w * KPAD + lane;
#pragma unroll
    for (int q = 0; q < 6; q++) a16[o + q * 32] = __float2half(a[q]);
    if (lane < 8) a16[o + 192] = __float2half(a[6]);
}

// ---------------- GRU gates (+ bias fold + fp16 write of new h) ----------------
__global__ void k_gates(const float* __restrict__ gi, const float* __restrict__ gh,
                        const float* __restrict__ bih, const float* __restrict__ bhh,
                        const float* __restrict__ hsrc, float* __restrict__ hdst,
                        __half* __restrict__ h16) {
    int idx = blockIdx.x * blockDim.x + threadIdx.x;
    if (idx >= N_NODES * HDIM) return;
    int n = idx / HDIM, c = idx - n * HDIM;
    const float* giN = gi + (long long)n * 600;
    const float* ghN = gh + (long long)n * 600;
    float r  = 1.f / (1.f + expf(-(giN[c] + bih[c] + ghN[c] + bhh[c])));
    float z  = 1.f / (1.f + expf(-(giN[200 + c] + bih[200 + c] + ghN[200 + c] + bhh[200 + c])));
    float nn = tanhf(giN[400 + c] + bih[400 + c] + r * (ghN[400 + c] + bhh[400 + c]));
    float h = (1.f - z) * nn + z * hsrc[idx];
    hdst[idx] = h;
    h16[(long long)n * KPAD + c] = __float2half(h);
}

// ---------------- misc data movement ----------------
__global__ void k_hp(const float* __restrict__ h, float* __restrict__ hp) {
    int idx = blockIdx.x * blockDim.x + threadIdx.x;
    if (idx >= BATCH * 207 * HDIM) return;
    int b = idx / (207 * HDIM);
    int rem = idx - b * 207 * HDIM;
    int r = rem / HDIM, c = rem - r * HDIM;
    hp[idx] = (r == 0 || r == 206) ? 0.f
              : h[((long long)b * NPER + (r - 1)) * HDIM + c];
}

__global__ void k_wt(const float* __restrict__ w, float* __restrict__ wt,
                     int CO, int CI, int KK) {
    int idx = blockIdx.x * blockDim.x + threadIdx.x;
    if (idx >= CO * CI * KK) return;
    int co = idx / (CI * KK);
    int rem = idx - co * CI * KK;
    int ci = rem / KK, k = rem - ci * KK;
    wt[(long long)co * CI * KK + k * CI + ci] = w[idx];
}

// ---------------- fused FC head ----------------
__global__ void k_fc(const float* __restrict__ feats,
                     const float* __restrict__ w1, const float* __restrict__ b1,
                     const float* __restrict__ w2, const float* __restrict__ b2,
                     const float* __restrict__ w3, const float* __restrict__ b3,
                     float* __restrict__ out) {
    int b = blockIdx.x;
    int tid = threadIdx.x;
    int lane = tid & 31, wrp = tid >> 5;
    __shared__ float sf[800];
    __shared__ float s1[256];
    __shared__ float s2[128];
    for (int i = tid; i < 800; i += 256) sf[i] = feats[b * 800 + i];
    __syncthreads();
    for (int jj = 0; jj < 32; jj++) {
        int j = wrp * 32 + jj;
        float a = 0.f;
        for (int i = lane; i < 800; i += 32) a += sf[i] * w1[(long long)j * 800 + i];
        for (int o = 16; o; o >>= 1) a += __shfl_down_sync(0xffffffffu, a, o);
        if (lane == 0) s1[j] = fmaxf(a + b1[j], 0.f);
    }
    __syncthreads();
    if (tid < 128) {
        float a = b2[tid];
        for (int i = 0; i < 256; i++) a += s1[i] * w2[tid * 256 + i];
        s2[tid] = fmaxf(a, 0.f);
    }
    __syncthreads();
    if (tid < 2) {
        float a = b3[tid];
        for (int i = 0; i < 128; i++) a += s2[i] * w3[tid * 128 + i];
        out[b * 2 + tid] = a;
    }
}

// ---------------- launcher ----------------
extern "C" void kernel_launch(void* const* d_in, const int* in_sizes, int n_in,
                              void* d_out, int out_size) {
    const float* x     = (const float*)d_in[0];
    const int*   ei    = (const int*)  d_in[1];
    const int*   ids   = (const int*)  d_in[2];
    const float* etab  = (const float*)d_in[3];
    const float* ggcw  = (const float*)d_in[4];
    const float* wih   = (const float*)d_in[5];
    const float* whh   = (const float*)d_in[6];
    const float* bih   = (const float*)d_in[7];
    const float* bhh   = (const float*)d_in[8];
    const float* c0w   = (const float*)d_in[9];
    const float* c0b   = (const float*)d_in[10];
    const float* c1w   = (const float*)d_in[11];
    const float* c1b   = (const float*)d_in[12];
    const float* c2w   = (const float*)d_in[13];
    const float* c2b   = (const float*)d_in[14];
    const float* c3w   = (const float*)d_in[15];
    const float* c3b   = (const float*)d_in[16];
    const float* f1w   = (const float*)d_in[17];
    const float* f1b   = (const float*)d_in[18];
    const float* f2w   = (const float*)d_in[19];
    const float* f2b   = (const float*)d_in[20];
    const float* f3w   = (const float*)d_in[21];
    const float* f3b   = (const float*)d_in[22];
    float* out = (float*)d_out;

    float *h0, *h1, *mm, *gi, *gh, *hp, *w0t, *feats;
    int *deg, *rs, *cur, *cs;
    __half *e16, *w1h, *w2h, *w3h;
    __half *h16, *a16, *wg16, *wi16, *wh16;
    cudaGetSymbolAddress((void**)&h0,   g_h0);
    cudaGetSymbolAddress((void**)&h1,   g_h1);
    cudaGetSymbolAddress((void**)&mm,   g_m);
    cudaGetSymbolAddress((void**)&gi,   g_gi);
    cudaGetSymbolAddress((void**)&gh,   g_gh);
    cudaGetSymbolAddress((void**)&hp,   g_hp);
    cudaGetSymbolAddress((void**)&w0t,  g_w0t);
    cudaGetSymbolAddress((void**)&feats,g_feats);
    cudaGetSymbolAddress((void**)&deg,  g_deg);
    cudaGetSymbolAddress((void**)&rs,   g_rs);
    cudaGetSymbolAddress((void**)&cur,  g_cur);
    cudaGetSymbolAddress((void**)&cs,   g_csrc);
    cudaGetSymbolAddress((void**)&e16,  g_e16);
    cudaGetSymbolAddress((void**)&w1h,  g_w1h);
    cudaGetSymbolAddress((void**)&w2h,  g_w2h);
    cudaGetSymbolAddress((void**)&w3h,  g_w3h);
    cudaGetSymbolAddress((void**)&h16,  g_h16);
    cudaGetSymbolAddress((void**)&a16,  g_a16);
    cudaGetSymbolAddress((void**)&wg16, g_wg16);
    cudaGetSymbolAddress((void**)&wi16, g_wi16);
    cudaGetSymbolAddress((void**)&wh16, g_wh16);

    const int CONV_SMEM = 36864 + 59904 + 832 + 832;   // 98432 B
    const int GGC_SMEM  = 36864 + 59904;               // 96768 B
    cudaFuncSetAttribute(conv3h_k,   cudaFuncAttributeMaxDynamicSharedMemorySize, CONV_SMEM);
    cudaFuncSetAttribute(ggc_hmma_k, cudaFuncAttributeMaxDynamicSharedMemorySize, GGC_SMEM);
    cudaFuncSetAttribute(ggc_mh_k,   cudaFuncAttributeMaxDynamicSharedMemorySize, GGC_SMEM);

    // side stream + events (created once; host resources, no device allocs)
    static cudaStream_t s2 = nullptr;
    static cudaEvent_t ev1 = nullptr, ev2 = nullptr;
    if (!s2) {
        cudaStreamCreateWithFlags(&s2, cudaStreamNonBlocking);
        cudaEventCreateWithFlags(&ev1, cudaEventDisableTiming);
        cudaEventCreateWithFlags(&ev2, cudaEventDisableTiming);
    }

    // ---- default stream: feats zero, then fork conv branch ----
    cudaMemsetAsync(feats, 0, BATCH * 800 * sizeof(float));
    cudaEventRecord(ev1, 0);
    cudaStreamWaitEvent(s2, ev1, 0);

    // ---- side stream: conv1/2/3 branch (independent of GGC) ----
    k_embed16<<<BATCH * SEQ + 8, 192, 0, s2>>>(ids, etab, e16);
    k_w16<<<(200 * 768 * 3 + 255) / 256, 256, 0, s2>>>(c1w, w1h, 3);
    k_w16<<<(200 * 768 * 4 + 255) / 256, 256, 0, s2>>>(c2w, w2h, 4);
    k_w16<<<(200 * 768 * 5 + 255) / 256, 256, 0, s2>>>(c3w, w3h, 5);
    {
        Conv3Args ca;
        ca.wb[0] = w1h; ca.wb[1] = w2h; ca.wb[2] = w3h;
        ca.bias[0] = c1b; ca.bias[1] = c2b; ca.bias[2] = c3b;
        conv3h_k<<<dim3(3, 4, BATCH), 256, CONV_SMEM, s2>>>(e16, ca, feats);
    }
    cudaEventRecord(ev2, s2);

    // ---- default stream: CSR + GGC prep ----
    cudaMemsetAsync(deg, 0, N_NODES * sizeof(int));
    k_hist<<<(NEDGE + 255) / 256, 256>>>(ei, deg);
    k_scan<<<1, 1024>>>(deg, rs, cur, N_NODES);
    k_fill<<<(NEDGE + 255) / 256, 256>>>(ei, cur, cs);
    cudaMemcpyAsync(h0, x, (size_t)N_NODES * HDIM * sizeof(float),
                    cudaMemcpyDeviceToDevice);
    k_x16<<<(N_NODES * KPAD + 255) / 256, 256>>>(x, h16);
    k_wggc16<<<(NLAYERS * 208 * KPAD + 255) / 256, 256>>>(ggcw, wg16);
    k_wgru16<<<(624 * KPAD + 255) / 256, 256>>>(wih, wi16);
    k_wgru16<<<(624 * KPAD + 255) / 256, 256>>>(whh, wh16);
    k_wt<<<(200 * 200 * 3 + 255) / 256, 256>>>(c0w, w0t, 200, 200, 3);

    // ---- gated graph conv: 6 layers (fp16 HMMA) ----
    float* hc = h0;
    float* hn = h1;
    for (int l = 0; l < NLAYERS; l++) {
        // fused: m = h @ ggc_w[l]  and  gh = h @ whh^T  (same A)
        ggc_mh_k<<<dim3(4, NPER), 256, GGC_SMEM>>>(h16,
                                                   wg16 + (long long)l * 208 * KPAD, wh16,
                                                   mm, gh);
        // agg = segment_sum(m[src], dst), write fp16
        k_agg<<<(N_NODES + 7) / 8, 256>>>(mm, rs, cs, a16);
        // gi = agg @ wih^T
        ggc_hmma_k<<<dim3(3, NPER), 256, GGC_SMEM>>>(a16, wi16, gi, 600, 600);
        // GRU update (+bias fold) and fp16 re-write of h
        k_gates<<<(N_NODES * HDIM + 255) / 256, 256>>>(gi, gh, bih, bhh, hc, hn, h16);
        float* t = hc; hc = hn; hn = t;
    }

    // ---- conv0 (fp32 SIMT, fused bias+ReLU+max; feats cols 0..199) ----
    k_hp<<<(BATCH * 207 * HDIM + 255) / 256, 256>>>(hc, hp);
    sgemm_k<true, 1><<<dim3(4, 2, BATCH), 256>>>(hp, 200, 207LL * 200, w0t, c0b, feats,
                                                 205, 200, 600, 0, 800, 0);

    // ---- join conv branch, then FC head ----
    cudaStreamWaitEvent(0, ev2, 0);
    k_fc<<<BATCH, 256>>>(feats, f1w, f1b, f2w, f2b, f3w, f3b, out);
}

// round 14
// speedup vs baseline: 5.3565x; 1.1121x over previous
#include <cuda_runtime.h>
#include <cuda_fp16.h>
#include <cstdint>

// ---------------- problem constants ----------------
#define N_NODES 26240      // B * N_PER = 128 * 205 (exactly 205 blocks of 128)
#define HDIM    200
#define NEDGE   209920
#define BATCH   128
#define NPER    205
#define EMBD    768
#define SEQ     512
#define NLAYERS 6
#define KPAD    208        // padded K (GGC, fp16 single pass; 3x64 + 1x16 tiles)

// ---------------- static device scratch ----------------
__device__ float g_h0[N_NODES * HDIM];
__device__ float g_h1[N_NODES * HDIM];
__device__ float g_m [N_NODES * HDIM];
__device__ float g_gi[N_NODES * 3 * HDIM];
__device__ float g_gh[N_NODES * 3 * HDIM];
__device__ float g_feats[BATCH * 800];
__device__ int   g_deg[N_NODES];
__device__ int   g_rs [N_NODES + 1];
__device__ int   g_cur[N_NODES];
__device__ int   g_csrc[NEDGE];

// GGC fp16 operands, K-padded to 208 (pads zero from module init, never written)
__device__ __align__(16) __half g_h16[(size_t)N_NODES * KPAD];
__device__ __align__(16) __half g_a16[(size_t)N_NODES * KPAD];
// GGC fp16 weights: [Npad][208]
__device__ __align__(16) __half g_wg16[NLAYERS * 208 * KPAD];   // ggc_w[l]^T
__device__ __align__(16) __half g_wi16[624 * KPAD];             // wih
__device__ __align__(16) __half g_wh16[624 * KPAD];             // whh

// fp16 embeddings, time-major [b][t][c], +8 zero rows for tap overrun
__device__ __align__(16) __half g_e16[((size_t)BATCH * SEQ + 8) * EMBD];
// fp16 conv weights: [200][K], tap-major K (single pass)
__device__ __align__(16) __half g_w1h[200 * 2304];
__device__ __align__(16) __half g_w2h[200 * 3072];
__device__ __align__(16) __half g_w3h[200 * 3840];
// conv0: fp16 padded h input [BATCH][260][256] and weights [208][768]
__device__ __align__(16) __half g_hp16[(size_t)BATCH * 260 * 256];
__device__ __align__(16) __half g_w0h[208 * 768];

// ---------------- warp-level MMA (compute_100-safe PTX) ----------------
#define MMA_F16(d, a, b0, b1) asm volatile(                            \
    "mma.sync.aligned.m16n8k16.row.col.f32.f16.f16.f32 "               \
    "{%0,%1,%2,%3}, {%4,%5,%6,%7}, {%8,%9}, {%0,%1,%2,%3};"            \
    : "+f"((d)[0]), "+f"((d)[1]), "+f"((d)[2]), "+f"((d)[3])           \
    : "r"((a)[0]), "r"((a)[1]), "r"((a)[2]), "r"((a)[3]),              \
      "r"(b0), "r"(b1))

// ---------------- cp.async helpers (sm_80+ PTX) ----------------
#define CP16(dst, src) asm volatile("cp.async.ca.shared.global [%0], [%1], 16;" \
                                    :: "r"(dst), "l"(src))
#define CP_COMMIT() asm volatile("cp.async.commit_group;" ::: "memory")
#define CP_WAIT0()  asm volatile("cp.async.wait_group 0;" ::: "memory")

__device__ __forceinline__ uint32_t s2u(const void* p) {
    return (uint32_t)__cvta_generic_to_shared(p);
}

// ---------------- GGC GEMM: gi = agg @ wih^T (fp16, K=208: 3x64 + 1x16) --------
// grid (3 n-tiles, 205 m-tiles). 256 threads = 8 warps (4m x 2n).
__global__ void __launch_bounds__(256, 1) ggc_hmma_k(
    const __half* __restrict__ A,
    const __half* __restrict__ B,
    float* __restrict__ C, int N, int ldc)
{
    extern __shared__ __align__(16) char dsm[];
    constexpr int ASTR = 72, BSTR = 72;
    __half* As = (__half*)dsm;                 // [2][128][72]
    __half* Bs = (__half*)(dsm + 36864);       // [2][208][72]

    const int tid = threadIdx.x;
    const int lane = tid & 31, wid = tid >> 5;
    const int wm = wid & 3, wn = wid >> 2;
    const int g = lane >> 2, t2 = (lane & 3) * 2;
    const int m0 = blockIdx.y * 128;
    const int n0 = blockIdx.x * 208;
    const uint32_t asb = s2u(As), bsb = s2u(Bs);

    auto copy_tile = [&](int kt, int buf) {
        const int kg = kt * 64;
        const uint32_t ab = asb + buf * 128 * ASTR * 2;
        const uint32_t bb = bsb + buf * 208 * BSTR * 2;
        if (kt < 3) {
#pragma unroll
            for (int i = 0; i < 4; i++) {
                int u = tid + i * 256;
                int row = u >> 3, ch = u & 7;
                CP16(ab + (row * ASTR + ch * 8) * 2,
                     A + (long long)(m0 + row) * KPAD + kg + ch * 8);
            }
#pragma unroll
            for (int i = 0; i < 7; i++) {
                int u = tid + i * 256;
                if (u < 1664) {
                    int row = u >> 3, ch = u & 7;
                    CP16(bb + (row * BSTR + ch * 8) * 2,
                         B + (long long)(n0 + row) * KPAD + kg + ch * 8);
                }
            }
        } else {   // 16-wide tail tile, cols 192..207
            {
                int row = tid >> 1, ch = tid & 1;
                CP16(ab + (row * ASTR + ch * 8) * 2,
                     A + (long long)(m0 + row) * KPAD + kg + ch * 8);
            }
#pragma unroll
            for (int i = 0; i < 2; i++) {
                int u = tid + i * 256;
                if (u < 416) {
                    int row = u >> 1, ch = u & 1;
                    CP16(bb + (row * BSTR + ch * 8) * 2,
                         B + (long long)(n0 + row) * KPAD + kg + ch * 8);
                }
            }
        }
    };

    float acc[2][13][4];
#pragma unroll
    for (int i = 0; i < 2; i++)
#pragma unroll
        for (int j = 0; j < 13; j++)
#pragma unroll
            for (int q = 0; q < 4; q++) acc[i][j][q] = 0.f;

    copy_tile(0, 0); CP_COMMIT(); CP_WAIT0();
    __syncthreads();

#pragma unroll 1
    for (int kt = 0; kt < 4; kt++) {
        const int buf = kt & 1;
        const bool more = (kt + 1 < 4);
        if (more) { copy_tile(kt + 1, buf ^ 1); CP_COMMIT(); }

        const __half* Ab = As + buf * 128 * ASTR;
        const __half* Bb = Bs + buf * 208 * BSTR;
        const int ksteps = (kt == 3) ? 1 : 4;
#pragma unroll 1
        for (int ks = 0; ks < ksteps; ks++) {
            const int ko = ks * 16;
            uint32_t a[2][4];
#pragma unroll
            for (int i = 0; i < 2; i++) {
                const int r = wm * 32 + i * 16 + g;
                a[i][0] = *(const uint32_t*)(Ab + (r)     * ASTR + ko + t2);
                a[i][1] = *(const uint32_t*)(Ab + (r + 8) * ASTR + ko + t2);
                a[i][2] = *(const uint32_t*)(Ab + (r)     * ASTR + ko + t2 + 8);
                a[i][3] = *(const uint32_t*)(Ab + (r + 8) * ASTR + ko + t2 + 8);
            }
            uint32_t bf[13][2];
#pragma unroll
            for (int j = 0; j < 13; j++) {
                const int n = wn * 104 + j * 8 + g;
                bf[j][0] = *(const uint32_t*)(Bb + n * BSTR + ko + t2);
                bf[j][1] = *(const uint32_t*)(Bb + n * BSTR + ko + t2 + 8);
            }
#pragma unroll
            for (int j = 0; j < 13; j++) {
                MMA_F16(acc[0][j], a[0], bf[j][0], bf[j][1]);
                MMA_F16(acc[1][j], a[1], bf[j][0], bf[j][1]);
            }
        }
        if (more) CP_WAIT0();
        __syncthreads();
    }

#pragma unroll
    for (int i = 0; i < 2; i++) {
        const int r = m0 + wm * 32 + i * 16 + g;
#pragma unroll
        for (int j = 0; j < 13; j++) {
            const int col = n0 + wn * 104 + j * 8 + t2;
            if (col < N) {
                C[(long long)r * ldc + col]       = acc[i][j][0];
                C[(long long)(r + 8) * ldc + col] = acc[i][j][2];
            }
            if (col + 1 < N) {
                C[(long long)r * ldc + col + 1]       = acc[i][j][1];
                C[(long long)(r + 8) * ldc + col + 1] = acc[i][j][3];
            }
        }
    }
}

// ---------------- fused m + gh GEMM (same A = h, fp16, K=208) ----------------
// grid (4, 205): bx==0 -> m = h @ ggc_w[l] (N=200); bx in 1..3 -> gh slice.
__global__ void __launch_bounds__(256, 1) ggc_mh_k(
    const __half* __restrict__ A,
    const __half* __restrict__ wgl,    // [208][208] layer slice
    const __half* __restrict__ wh,     // [624][208]
    float* __restrict__ Cm,
    float* __restrict__ Cg)
{
    extern __shared__ __align__(16) char dsm[];
    constexpr int ASTR = 72, BSTR = 72;
    __half* As = (__half*)dsm;
    __half* Bs = (__half*)(dsm + 36864);

    const int tid = threadIdx.x;
    const int lane = tid & 31, wid = tid >> 5;
    const int wm = wid & 3, wn = wid >> 2;
    const int g = lane >> 2, t2 = (lane & 3) * 2;
    const int m0 = blockIdx.y * 128;
    const int bx = blockIdx.x;
    const uint32_t asb = s2u(As), bsb = s2u(Bs);

    const __half* B = (bx == 0) ? wgl : (wh + (long long)(bx - 1) * 208 * KPAD);
    float* C      = (bx == 0) ? Cm  : Cg;
    const int ldc = (bx == 0) ? 200 : 600;
    const int N   = (bx == 0) ? 200 : 600;
    const int cb  = (bx == 0) ? 0   : (bx - 1) * 208;

    auto copy_tile = [&](int kt, int buf) {
        const int kg = kt * 64;
        const uint32_t ab = asb + buf * 128 * ASTR * 2;
        const uint32_t bb = bsb + buf * 208 * BSTR * 2;
        if (kt < 3) {
#pragma unroll
            for (int i = 0; i < 4; i++) {
                int u = tid + i * 256;
                int row = u >> 3, ch = u & 7;
                CP16(ab + (row * ASTR + ch * 8) * 2,
                     A + (long long)(m0 + row) * KPAD + kg + ch * 8);
            }
#pragma unroll
            for (int i = 0; i < 7; i++) {
                int u = tid + i * 256;
                if (u < 1664) {
                    int row = u >> 3, ch = u & 7;
                    CP16(bb + (row * BSTR + ch * 8) * 2,
                         B + (long long)row * KPAD + kg + ch * 8);
                }
            }
        } else {
            {
                int row = tid >> 1, ch = tid & 1;
                CP16(ab + (row * ASTR + ch * 8) * 2,
                     A + (long long)(m0 + row) * KPAD + kg + ch * 8);
            }
#pragma unroll
            for (int i = 0; i < 2; i++) {
                int u = tid + i * 256;
                if (u < 416) {
                    int row = u >> 1, ch = u & 1;
                    CP16(bb + (row * BSTR + ch * 8) * 2,
                         B + (long long)row * KPAD + kg + ch * 8);
                }
            }
        }
    };

    float acc[2][13][4];
#pragma unroll
    for (int i = 0; i < 2; i++)
#pragma unroll
        for (int j = 0; j < 13; j++)
#pragma unroll
            for (int q = 0; q < 4; q++) acc[i][j][q] = 0.f;

    copy_tile(0, 0); CP_COMMIT(); CP_WAIT0();
    __syncthreads();

#pragma unroll 1
    for (int kt = 0; kt < 4; kt++) {
        const int buf = kt & 1;
        const bool more = (kt + 1 < 4);
        if (more) { copy_tile(kt + 1, buf ^ 1); CP_COMMIT(); }

        const __half* Ab = As + buf * 128 * ASTR;
        const __half* Bb = Bs + buf * 208 * BSTR;
        const int ksteps = (kt == 3) ? 1 : 4;
#pragma unroll 1
        for (int ks = 0; ks < ksteps; ks++) {
            const int ko = ks * 16;
            uint32_t a[2][4];
#pragma unroll
            for (int i = 0; i < 2; i++) {
                const int r = wm * 32 + i * 16 + g;
                a[i][0] = *(const uint32_t*)(Ab + (r)     * ASTR + ko + t2);
                a[i][1] = *(const uint32_t*)(Ab + (r + 8) * ASTR + ko + t2);
                a[i][2] = *(const uint32_t*)(Ab + (r)     * ASTR + ko + t2 + 8);
                a[i][3] = *(const uint32_t*)(Ab + (r + 8) * ASTR + ko + t2 + 8);
            }
            uint32_t bf[13][2];
#pragma unroll
            for (int j = 0; j < 13; j++) {
                const int n = wn * 104 + j * 8 + g;
                bf[j][0] = *(const uint32_t*)(Bb + n * BSTR + ko + t2);
                bf[j][1] = *(const uint32_t*)(Bb + n * BSTR + ko + t2 + 8);
            }
#pragma unroll
            for (int j = 0; j < 13; j++) {
                MMA_F16(acc[0][j], a[0], bf[j][0], bf[j][1]);
                MMA_F16(acc[1][j], a[1], bf[j][0], bf[j][1]);
            }
        }
        if (more) CP_WAIT0();
        __syncthreads();
    }

#pragma unroll
    for (int i = 0; i < 2; i++) {
        const int r = m0 + wm * 32 + i * 16 + g;
#pragma unroll
        for (int j = 0; j < 13; j++) {
            const int col = cb + wn * 104 + j * 8 + t2;
            if (col < N) {
                C[(long long)r * ldc + col]       = acc[i][j][0];
                C[(long long)(r + 8) * ldc + col] = acc[i][j][2];
            }
            if (col + 1 < N) {
                C[(long long)r * ldc + col + 1]       = acc[i][j][1];
                C[(long long)(r + 8) * ldc + col + 1] = acc[i][j][3];
            }
        }
    }
}

// ---------------- fused conv1/2/3: pure fp16 conv-as-GEMM ----------------
struct Conv3Args {
    const __half* wb[3];
    const float* bias[3];
};
// grid (3 convs, 4 m-tiles, 128 batches)
__global__ void __launch_bounds__(256, 1) conv3h_k(
    const __half* __restrict__ e16,
    Conv3Args args,
    float* __restrict__ feats)
{
    extern __shared__ __align__(16) char dsm[];
    constexpr int ASTR = 72, BSTR = 72;
    __half* As = (__half*)dsm;
    __half* Bs = (__half*)(dsm + 36864);
    float* smax  = (float*)(dsm + 36864 + 59904);
    float* sbias = smax + 208;

    const int cid = blockIdx.x;
    const int M   = (cid == 0) ? 510 : (cid == 1) ? 509 : 508;
    const int K   = (cid == 0) ? 2304 : (cid == 1) ? 3072 : 3840;   // 768 * taps
    const int featOff = 200 + cid * 200;
    const __half* wb = args.wb[cid];
    const float* bias = args.bias[cid];

    const int tid = threadIdx.x;
    const int lane = tid & 31, wid = tid >> 5;
    const int wm = wid & 3, wn = wid >> 2;
    const int g = lane >> 2, t2 = (lane & 3) * 2;
    const int b = blockIdx.z, m0 = blockIdx.y * 128;
    const int T = K / 64;
    const uint32_t asb = s2u(As), bsb = s2u(Bs);

    if (tid < 208) { smax[tid] = 0.f; sbias[tid] = (tid < 200) ? bias[tid] : 0.f; }

    auto copy_tile = [&](int kt, int buf) {
        int kk = kt / 12;
        int c0 = (kt - kk * 12) * 64;
        long long abase = ((long long)(b * SEQ + m0 + kk)) * EMBD + c0;
        const uint32_t ab = asb + buf * 128 * ASTR * 2;
        const uint32_t bb = bsb + buf * 208 * BSTR * 2;
#pragma unroll
        for (int i = 0; i < 4; i++) {
            int u = tid + i * 256;
            int row = u >> 3, ch = u & 7;
            CP16(ab + (row * ASTR + ch * 8) * 2,
                 e16 + abase + (long long)row * EMBD + ch * 8);
        }
        int kg = kt * 64;
#pragma unroll
        for (int i = 0; i < 7; i++) {
            int u = tid + i * 256;
            if (u < 1600) {
                int row = u >> 3, ch = u & 7;
                CP16(bb + (row * BSTR + ch * 8) * 2,
                     wb + (long long)row * K + kg + ch * 8);
            }
        }
    };

    float acc[2][13][4];
#pragma unroll
    for (int i = 0; i < 2; i++)
#pragma unroll
        for (int j = 0; j < 13; j++)
#pragma unroll
            for (int q = 0; q < 4; q++) acc[i][j][q] = 0.f;

    copy_tile(0, 0); CP_COMMIT(); CP_WAIT0();
    __syncthreads();

#pragma unroll 1
    for (int kt = 0; kt < T; kt++) {
        const int buf = kt & 1;
        const bool more = (kt + 1 < T);
        if (more) { copy_tile(kt + 1, buf ^ 1); CP_COMMIT(); }

        const __half* Ab = As + buf * 128 * ASTR;
        const __half* Bb = Bs + buf * 208 * BSTR;
#pragma unroll
        for (int ks = 0; ks < 4; ks++) {
            const int ko = ks * 16;
            uint32_t a[2][4];
#pragma unroll
            for (int i = 0; i < 2; i++) {
                const int r = wm * 32 + i * 16 + g;
                a[i][0] = *(const uint32_t*)(Ab + (r)     * ASTR + ko + t2);
                a[i][1] = *(const uint32_t*)(Ab + (r + 8) * ASTR + ko + t2);
                a[i][2] = *(const uint32_t*)(Ab + (r)     * ASTR + ko + t2 + 8);
                a[i][3] = *(const uint32_t*)(Ab + (r + 8) * ASTR + ko + t2 + 8);
            }
            uint32_t bf[13][2];
#pragma unroll
            for (int j = 0; j < 13; j++) {
                const int n = wn * 104 + j * 8 + g;
                bf[j][0] = *(const uint32_t*)(Bb + n * BSTR + ko + t2);
                bf[j][1] = *(const uint32_t*)(Bb + n * BSTR + ko + t2 + 8);
            }
#pragma unroll
            for (int j = 0; j < 13; j++) {
                MMA_F16(acc[0][j], a[0], bf[j][0], bf[j][1]);
                MMA_F16(acc[1][j], a[1], bf[j][0], bf[j][1]);
            }
        }
        if (more) CP_WAIT0();
        __syncthreads();
    }

    const int valid = (M - m0 < 128) ? (M - m0) : 128;
#pragma unroll
    for (int j = 0; j < 13; j++) {
        float v0 = -1e30f, v1 = -1e30f;
#pragma unroll
        for (int i = 0; i < 2; i++) {
            const int r0 = wm * 32 + i * 16 + g;
            if (r0 < valid)     { v0 = fmaxf(v0, acc[i][j][0]); v1 = fmaxf(v1, acc[i][j][1]); }
            if (r0 + 8 < valid) { v0 = fmaxf(v0, acc[i][j][2]); v1 = fmaxf(v1, acc[i][j][3]); }
        }
#pragma unroll
        for (int o = 4; o <= 16; o <<= 1) {
            v0 = fmaxf(v0, __shfl_xor_sync(~0u, v0, o));
            v1 = fmaxf(v1, __shfl_xor_sync(~0u, v1, o));
        }
        if (g == 0) {
            const int col = wn * 104 + j * 8 + t2;
            if (col < 200) {
                float r = fmaxf(v0 + sbias[col], 0.f);
                atomicMax((unsigned int*)&smax[col], __float_as_uint(r));
            }
            if (col + 1 < 200) {
                float r = fmaxf(v1 + sbias[col + 1], 0.f);
                atomicMax((unsigned int*)&smax[col + 1], __float_as_uint(r));
            }
        }
    }
    __syncthreads();
    if (tid < 200)
        atomicMax((unsigned int*)&feats[(long long)b * 800 + featOff + tid],
                  __float_as_uint(smax[tid]));
}

// ---------------- conv0: fp16 conv-as-GEMM over padded h ----------------
// A = hp16 [BATCH][260][256] (tap decomposition, per-tap KPAD 256 -> K3 = 768).
// grid (1, 2 m-tiles, 128 batches). M = 205, N = 200, feats cols 0..199.
__global__ void __launch_bounds__(256, 1) conv0h_k(
    const __half* __restrict__ hp16,
    const __half* __restrict__ w0h,     // [208][768] (rows 200..207 zero)
    const float* __restrict__ bias,
    float* __restrict__ feats)
{
    extern __shared__ __align__(16) char dsm[];
    constexpr int ASTR = 72, BSTR = 72;
    __half* As = (__half*)dsm;
    __half* Bs = (__half*)(dsm + 36864);
    float* smax  = (float*)(dsm + 36864 + 59904);
    float* sbias = smax + 208;

    const int tid = threadIdx.x;
    const int lane = tid & 31, wid = tid >> 5;
    const int wm = wid & 3, wn = wid >> 2;
    const int g = lane >> 2, t2 = (lane & 3) * 2;
    const int b = blockIdx.z, m0 = blockIdx.y * 128;
    const uint32_t asb = s2u(As), bsb = s2u(Bs);

    if (tid < 208) { smax[tid] = 0.f; sbias[tid] = (tid < 200) ? bias[tid] : 0.f; }

    auto copy_tile = [&](int kt, int buf) {
        int kk = kt >> 2;                    // tap 0..2
        int c0 = (kt & 3) * 64;
        long long abase = ((long long)b * 260 + m0 + kk) * 256 + c0;
        const uint32_t ab = asb + buf * 128 * ASTR * 2;
        const uint32_t bb = bsb + buf * 208 * BSTR * 2;
#pragma unroll
        for (int i = 0; i < 4; i++) {
            int u = tid + i * 256;
            int row = u >> 3, ch = u & 7;
            CP16(ab + (row * ASTR + ch * 8) * 2,
                 hp16 + abase + (long long)row * 256 + ch * 8);
        }
        int kg = kt * 64;
#pragma unroll
        for (int i = 0; i < 7; i++) {
            int u = tid + i * 256;
            if (u < 1664) {
                int row = u >> 3, ch = u & 7;
                CP16(bb + (row * BSTR + ch * 8) * 2,
                     w0h + (long long)row * 768 + kg + ch * 8);
            }
        }
    };

    float acc[2][13][4];
#pragma unroll
    for (int i = 0; i < 2; i++)
#pragma unroll
        for (int j = 0; j < 13; j++)
#pragma unroll
            for (int q = 0; q < 4; q++) acc[i][j][q] = 0.f;

    copy_tile(0, 0); CP_COMMIT(); CP_WAIT0();
    __syncthreads();

#pragma unroll 1
    for (int kt = 0; kt < 12; kt++) {
        const int buf = kt & 1;
        const bool more = (kt + 1 < 12);
        if (more) { copy_tile(kt + 1, buf ^ 1); CP_COMMIT(); }

        const __half* Ab = As + buf * 128 * ASTR;
        const __half* Bb = Bs + buf * 208 * BSTR;
#pragma unroll
        for (int ks = 0; ks < 4; ks++) {
            const int ko = ks * 16;
            uint32_t a[2][4];
#pragma unroll
            for (int i = 0; i < 2; i++) {
                const int r = wm * 32 + i * 16 + g;
                a[i][0] = *(const uint32_t*)(Ab + (r)     * ASTR + ko + t2);
                a[i][1] = *(const uint32_t*)(Ab + (r + 8) * ASTR + ko + t2);
                a[i][2] = *(const uint32_t*)(Ab + (r)     * ASTR + ko + t2 + 8);
                a[i][3] = *(const uint32_t*)(Ab + (r + 8) * ASTR + ko + t2 + 8);
            }
            uint32_t bf[13][2];
#pragma unroll
            for (int j = 0; j < 13; j++) {
                const int n = wn * 104 + j * 8 + g;
                bf[j][0] = *(const uint32_t*)(Bb + n * BSTR + ko + t2);
                bf[j][1] = *(const uint32_t*)(Bb + n * BSTR + ko + t2 + 8);
            }
#pragma unroll
            for (int j = 0; j < 13; j++) {
                MMA_F16(acc[0][j], a[0], bf[j][0], bf[j][1]);
                MMA_F16(acc[1][j], a[1], bf[j][0], bf[j][1]);
            }
        }
        if (more) CP_WAIT0();
        __syncthreads();
    }

    const int valid = (205 - m0 < 128) ? (205 - m0) : 128;
#pragma unroll
    for (int j = 0; j < 13; j++) {
        float v0 = -1e30f, v1 = -1e30f;
#pragma unroll
        for (int i = 0; i < 2; i++) {
            const int r0 = wm * 32 + i * 16 + g;
            if (r0 < valid)     { v0 = fmaxf(v0, acc[i][j][0]); v1 = fmaxf(v1, acc[i][j][1]); }
            if (r0 + 8 < valid) { v0 = fmaxf(v0, acc[i][j][2]); v1 = fmaxf(v1, acc[i][j][3]); }
        }
#pragma unroll
        for (int o = 4; o <= 16; o <<= 1) {
            v0 = fmaxf(v0, __shfl_xor_sync(~0u, v0, o));
            v1 = fmaxf(v1, __shfl_xor_sync(~0u, v1, o));
        }
        if (g == 0) {
            const int col = wn * 104 + j * 8 + t2;
            if (col < 200) {
                float r = fmaxf(v0 + sbias[col], 0.f);
                atomicMax((unsigned int*)&smax[col], __float_as_uint(r));
            }
            if (col + 1 < 200) {
                float r = fmaxf(v1 + sbias[col + 1], 0.f);
                atomicMax((unsigned int*)&smax[col + 1], __float_as_uint(r));
            }
        }
    }
    __syncthreads();
    if (tid < 200)
        atomicMax((unsigned int*)&feats[(long long)b * 800 + tid],
                  __float_as_uint(smax[tid]));
}

// ---------------- fp16 embed (single array) ----------------
__global__ void k_embed16(const int* __restrict__ ids, const float* __restrict__ tbl,
                          __half* __restrict__ e16) {
    int row = blockIdx.x;
    int t = threadIdx.x;                   // 192 threads, one float4 each
    long long o = (long long)row * EMBD;
    if (row >= BATCH * SEQ) {
        if (t < 96) {
            ((uint2*)(e16 + o))[t * 2]     = make_uint2(0, 0);
            ((uint2*)(e16 + o))[t * 2 + 1] = make_uint2(0, 0);
        }
        return;
    }
    long long id = ids[row];
    float4 v = ((const float4*)(tbl + id * EMBD))[t];
    __half2 h01 = __floats2half2_rn(v.x, v.y);
    __half2 h23 = __floats2half2_rn(v.z, v.w);
    uint2 hv;
    hv.x = *(uint32_t*)&h01; hv.y = *(uint32_t*)&h23;
    ((uint2*)(e16 + o))[t] = hv;
}

// w: [200][768][KK] fp32 -> wb: [200][K] fp16, tap-major K
__global__ void k_w16(const float* __restrict__ w, __half* __restrict__ wb, int KK) {
    int K = 768 * KK;
    int idx = blockIdx.x * blockDim.x + threadIdx.x;
    if (idx >= 200 * K) return;
    int co = idx / K, r = idx - co * K;
    int kk = r / 768, ci = r - kk * 768;
    wb[idx] = __float2half(w[(co * 768 + ci) * KK + kk]);
}

// conv0 weights: c0w [200][200][3] -> w0h [208][768] (col = kk*256 + ci)
__global__ void k_w0h(const float* __restrict__ w, __half* __restrict__ out) {
    int idx = blockIdx.x * blockDim.x + threadIdx.x;
    if (idx >= 200 * 600) return;
    int co = idx / 600, r = idx - co * 600;
    int kk = r / 200, ci = r - kk * 200;
    out[(long long)co * 768 + kk * 256 + ci] =
        __float2half(w[(co * 200 + ci) * 3 + kk]);
}

// ---------------- GGC fp16 precompute ----------------
__global__ void k_wggc16(const float* __restrict__ w, __half* __restrict__ out) {
    int idx = blockIdx.x * blockDim.x + threadIdx.x;
    if (idx >= NLAYERS * 208 * KPAD) return;
    int l = idx / (208 * KPAD);
    int rem = idx - l * 208 * KPAD;
    int n = rem / KPAD, kk = rem - n * KPAD;
    float x = (n < 200 && kk < 200) ? w[(long long)l * 40000 + kk * 200 + n] : 0.f;
    out[idx] = __float2half(x);
}

__global__ void k_wgru16(const float* __restrict__ w, __half* __restrict__ out) {
    int idx = blockIdx.x * blockDim.x + threadIdx.x;
    if (idx >= 624 * KPAD) return;
    int n = idx / KPAD, kk = idx - n * KPAD;
    float x = (n < 600 && kk < 200) ? w[n * 200 + kk] : 0.f;
    out[idx] = __float2half(x);
}

// x [26240][200] fp32 -> h16 [26240][208] fp16 (pads zeroed here, forever)
__global__ void k_x16(const float* __restrict__ xin, __half* __restrict__ h16) {
    int idx = blockIdx.x * blockDim.x + threadIdx.x;
    if (idx >= N_NODES * KPAD) return;
    int n = idx / KPAD, c = idx - n * KPAD;
    h16[idx] = __float2half((c < 200) ? xin[n * HDIM + c] : 0.f);
}

// ---------------- CSR build ----------------
__global__ void k_hist(const int* __restrict__ ei, int* __restrict__ deg) {
    int i = blockIdx.x * blockDim.x + threadIdx.x;
    if (i < NEDGE) atomicAdd(&deg[ei[NEDGE + i]], 1);
}

__global__ void k_scan(const int* __restrict__ deg, int* __restrict__ rs,
                       int* __restrict__ cur, int n) {
    __shared__ int s[1024];
    __shared__ int carry;
    int t = threadIdx.x;
    if (t == 0) carry = 0;
    __syncthreads();
    for (int base = 0; base < n; base += 1024) {
        int v = (base + t < n) ? deg[base + t] : 0;
        s[t] = v;
        __syncthreads();
        for (int off = 1; off < 1024; off <<= 1) {
            int add = (t >= off) ? s[t - off] : 0;
            __syncthreads();
            s[t] += add;
            __syncthreads();
        }
        int c0 = carry;
        int ex = c0 + s[t] - v;
        if (base + t < n) { rs[base + t] = ex; cur[base + t] = ex; }
        __syncthreads();
        if (t == 0) carry = c0 + s[1023];
        __syncthreads();
    }
    if (t == 0) rs[n] = carry;
}

__global__ void k_fill(const int* __restrict__ ei, int* __restrict__ cur,
                       int* __restrict__ cs) {
    int i = blockIdx.x * blockDim.x + threadIdx.x;
    if (i < NEDGE) {
        int d = ei[NEDGE + i];
        int p = atomicAdd(&cur[d], 1);
        cs[p] = ei[i];
    }
}

// ---------------- segment-sum + fp16 write of agg ----------------
__global__ void k_agg(const float* __restrict__ m, const int* __restrict__ rs,
                      const int* __restrict__ cs, __half* __restrict__ a16) {
    int w = (blockIdx.x * blockDim.x + threadIdx.x) >> 5;
    int lane = threadIdx.x & 31;
    if (w >= N_NODES) return;
    int s = rs[w], e = rs[w + 1];
    float a[7] = {0, 0, 0, 0, 0, 0, 0};
    int i = s;
    for (; i + 1 < e; i += 2) {
        const float* r0 = m + (long long)cs[i]     * HDIM;
        const float* r1 = m + (long long)cs[i + 1] * HDIM;
        a[0] += r0[lane]       + r1[lane];
        a[1] += r0[lane +  32] + r1[lane +  32];
        a[2] += r0[lane +  64] + r1[lane +  64];
        a[3] += r0[lane +  96] + r1[lane +  96];
        a[4] += r0[lane + 128] + r1[lane + 128];
        a[5] += r0[lane + 160] + r1[lane + 160];
        if (lane < 8) a[6] += r0[lane + 192] + r1[lane + 192];
    }
    if (i < e) {
        const float* r0 = m + (long long)cs[i] * HDIM;
        a[0] += r0[lane];       a[1] += r0[lane + 32];  a[2] += r0[lane + 64];
        a[3] += r0[lane + 96];  a[4] += r0[lane + 128]; a[5] += r0[lane + 160];
        if (lane < 8) a[6] += r0[lane + 192];
    }
    long long o = (long long)w * KPAD + lane;
#pragma unroll
    for (int q = 0; q < 6; q++) a16[o + q * 32] = __float2half(a[q]);
    if (lane < 8) a16[o + 192] = __float2half(a[6]);
}

// ---------------- GRU gates (+ bias fold + fp16 write of new h) ----------------
__global__ void k_gates(const float* __restrict__ gi, const float* __restrict__ gh,
                        const float* __restrict__ bih, const float* __restrict__ bhh,
                        const float* __restrict__ hsrc, float* __restrict__ hdst,
                        __half* __restrict__ h16) {
    int idx = blockIdx.x * blockDim.x + threadIdx.x;
    if (idx >= N_NODES * HDIM) return;
    int n = idx / HDIM, c = idx - n * HDIM;
    const float* giN = gi + (long long)n * 600;
    const float* ghN = gh + (long long)n * 600;
    float r  = 1.f / (1.f + expf(-(giN[c] + bih[c] + ghN[c] + bhh[c])));
    float z  = 1.f / (1.f + expf(-(giN[200 + c] + bih[200 + c] + ghN[200 + c] + bhh[200 + c])));
    float nn = tanhf(giN[400 + c] + bih[400 + c] + r * (ghN[400 + c] + bhh[400 + c]));
    float h = (1.f - z) * nn + z * hsrc[idx];
    hdst[idx] = h;
    h16[(long long)n * KPAD + c] = __float2half(h);
}

// ---------------- conv0 input build (fp16, zero-padded) ----------------
__global__ void k_hp16(const float* __restrict__ h, __half* __restrict__ hp) {
    int idx = blockIdx.x * blockDim.x + threadIdx.x;
    if (idx >= BATCH * 207 * 200) return;
    int b = idx / (207 * 200);
    int rem = idx - b * 207 * 200;
    int r = rem / 200, c = rem - r * 200;
    float v = (r == 0 || r == 206) ? 0.f
              : h[((long long)b * NPER + (r - 1)) * HDIM + c];
    hp[((long long)b * 260 + r) * 256 + c] = __float2half(v);
}

// ---------------- fused FC head ----------------
__global__ void k_fc(const float* __restrict__ feats,
                     const float* __restrict__ w1, const float* __restrict__ b1,
                     const float* __restrict__ w2, const float* __restrict__ b2,
                     const float* __restrict__ w3, const float* __restrict__ b3,
                     float* __restrict__ out) {
    int b = blockIdx.x;
    int tid = threadIdx.x;
    int lane = tid & 31, wrp = tid >> 5;
    __shared__ float sf[800];
    __shared__ float s1[256];
    __shared__ float s2[128];
    for (int i = tid; i < 800; i += 256) sf[i] = feats[b * 800 + i];
    __syncthreads();
    for (int jj = 0; jj < 32; jj++) {
        int j = wrp * 32 + jj;
        float a = 0.f;
        for (int i = lane; i < 800; i += 32) a += sf[i] * w1[(long long)j * 800 + i];
        for (int o = 16; o; o >>= 1) a += __shfl_down_sync(0xffffffffu, a, o);
        if (lane == 0) s1[j] = fmaxf(a + b1[j], 0.f);
    }
    __syncthreads();
    if (tid < 128) {
        float a = b2[tid];
        for (int i = 0; i < 256; i++) a += s1[i] * w2[tid * 256 + i];
        s2[tid] = fmaxf(a, 0.f);
    }
    __syncthreads();
    if (tid < 2) {
        float a = b3[tid];
        for (int i = 0; i < 128; i++) a += s2[i] * w3[tid * 128 + i];
        out[b * 2 + tid] = a;
    }
}

// ---------------- launcher ----------------
extern "C" void kernel_launch(void* const* d_in, const int* in_sizes, int n_in,
                              void* d_out, int out_size) {
    const float* x     = (const float*)d_in[0];
    const int*   ei    = (const int*)  d_in[1];
    const int*   ids   = (const int*)  d_in[2];
    const float* etab  = (const float*)d_in[3];
    const float* ggcw  = (const float*)d_in[4];
    const float* wih   = (const float*)d_in[5];
    const float* whh   = (const float*)d_in[6];
    const float* bih   = (const float*)d_in[7];
    const float* bhh   = (const float*)d_in[8];
    const float* c0w   = (const float*)d_in[9];
    const float* c0b   = (const float*)d_in[10];
    const float* c1w   = (const float*)d_in[11];
    const float* c1b   = (const float*)d_in[12];
    const float* c2w   = (const float*)d_in[13];
    const float* c2b   = (const float*)d_in[14];
    const float* c3w   = (const float*)d_in[15];
    const float* c3b   = (const float*)d_in[16];
    const float* f1w   = (const float*)d_in[17];
    const float* f1b   = (const float*)d_in[18];
    const float* f2w   = (const float*)d_in[19];
    const float* f2b   = (const float*)d_in[20];
    const float* f3w   = (const float*)d_in[21];
    const float* f3b   = (const float*)d_in[22];
    float* out = (float*)d_out;

    float *h0, *h1, *mm, *gi, *gh, *feats;
    int *deg, *rs, *cur, *cs;
    __half *e16, *w1h, *w2h, *w3h, *hp16, *w0h;
    __half *h16, *a16, *wg16, *wi16, *wh16;
    cudaGetSymbolAddress((void**)&h0,   g_h0);
    cudaGetSymbolAddress((void**)&h1,   g_h1);
    cudaGetSymbolAddress((void**)&mm,   g_m);
    cudaGetSymbolAddress((void**)&gi,   g_gi);
    cudaGetSymbolAddress((void**)&gh,   g_gh);
    cudaGetSymbolAddress((void**)&feats,g_feats);
    cudaGetSymbolAddress((void**)&deg,  g_deg);
    cudaGetSymbolAddress((void**)&rs,   g_rs);
    cudaGetSymbolAddress((void**)&cur,  g_cur);
    cudaGetSymbolAddress((void**)&cs,   g_csrc);
    cudaGetSymbolAddress((void**)&e16,  g_e16);
    cudaGetSymbolAddress((void**)&w1h,  g_w1h);
    cudaGetSymbolAddress((void**)&w2h,  g_w2h);
    cudaGetSymbolAddress((void**)&w3h,  g_w3h);
    cudaGetSymbolAddress((void**)&hp16, g_hp16);
    cudaGetSymbolAddress((void**)&w0h,  g_w0h);
    cudaGetSymbolAddress((void**)&h16,  g_h16);
    cudaGetSymbolAddress((void**)&a16,  g_a16);
    cudaGetSymbolAddress((void**)&wg16, g_wg16);
    cudaGetSymbolAddress((void**)&wi16, g_wi16);
    cudaGetSymbolAddress((void**)&wh16, g_wh16);

    const int CONV_SMEM = 36864 + 59904 + 832 + 832;   // 98432 B
    const int GGC_SMEM  = 36864 + 59904;               // 96768 B
    cudaFuncSetAttribute(conv3h_k,   cudaFuncAttributeMaxDynamicSharedMemorySize, CONV_SMEM);
    cudaFuncSetAttribute(conv0h_k,   cudaFuncAttributeMaxDynamicSharedMemorySize, CONV_SMEM);
    cudaFuncSetAttribute(ggc_hmma_k, cudaFuncAttributeMaxDynamicSharedMemorySize, GGC_SMEM);
    cudaFuncSetAttribute(ggc_mh_k,   cudaFuncAttributeMaxDynamicSharedMemorySize, GGC_SMEM);

    // side stream + events (created once; host resources, no device allocs)
    static cudaStream_t s2 = nullptr;
    static cudaEvent_t ev1 = nullptr, ev2 = nullptr;
    if (!s2) {
        cudaStreamCreateWithFlags(&s2, cudaStreamNonBlocking);
        cudaEventCreateWithFlags(&ev1, cudaEventDisableTiming);
        cudaEventCreateWithFlags(&ev2, cudaEventDisableTiming);
    }

    // ---- default stream: feats zero, then fork conv branch ----
    cudaMemsetAsync(feats, 0, BATCH * 800 * sizeof(float));
    cudaEventRecord(ev1, 0);
    cudaStreamWaitEvent(s2, ev1, 0);

    // ---- side stream: conv1/2/3 branch (independent of GGC) ----
    k_embed16<<<BATCH * SEQ + 8, 192, 0, s2>>>(ids, etab, e16);
    k_w16<<<(200 * 768 * 3 + 255) / 256, 256, 0, s2>>>(c1w, w1h, 3);
    k_w16<<<(200 * 768 * 4 + 255) / 256, 256, 0, s2>>>(c2w, w2h, 4);
    k_w16<<<(200 * 768 * 5 + 255) / 256, 256, 0, s2>>>(c3w, w3h, 5);
    {
        Conv3Args ca;
        ca.wb[0] = w1h; ca.wb[1] = w2h; ca.wb[2] = w3h;
        ca.bias[0] = c1b; ca.bias[1] = c2b; ca.bias[2] = c3b;
        conv3h_k<<<dim3(3, 4, BATCH), 256, CONV_SMEM, s2>>>(e16, ca, feats);
    }
    cudaEventRecord(ev2, s2);

    // ---- default stream: CSR + GGC prep ----
    cudaMemsetAsync(deg, 0, N_NODES * sizeof(int));
    k_hist<<<(NEDGE + 255) / 256, 256>>>(ei, deg);
    k_scan<<<1, 1024>>>(deg, rs, cur, N_NODES);
    k_fill<<<(NEDGE + 255) / 256, 256>>>(ei, cur, cs);
    cudaMemcpyAsync(h0, x, (size_t)N_NODES * HDIM * sizeof(float),
                    cudaMemcpyDeviceToDevice);
    k_x16<<<(N_NODES * KPAD + 255) / 256, 256>>>(x, h16);
    k_wggc16<<<(NLAYERS * 208 * KPAD + 255) / 256, 256>>>(ggcw, wg16);
    k_wgru16<<<(624 * KPAD + 255) / 256, 256>>>(wih, wi16);
    k_wgru16<<<(624 * KPAD + 255) / 256, 256>>>(whh, wh16);
    k_w0h<<<(200 * 600 + 255) / 256, 256>>>(c0w, w0h);

    // ---- gated graph conv: 6 layers (fp16 HMMA, K = 208) ----
    float* hc = h0;
    float* hn = h1;
    for (int l = 0; l < NLAYERS; l++) {
        // fused: m = h @ ggc_w[l]  and  gh = h @ whh^T  (same A)
        ggc_mh_k<<<dim3(4, NPER), 256, GGC_SMEM>>>(h16,
                                                   wg16 + (long long)l * 208 * KPAD, wh16,
                                                   mm, gh);
        // agg = segment_sum(m[src], dst), write fp16
        k_agg<<<(N_NODES + 7) / 8, 256>>>(mm, rs, cs, a16);
        // gi = agg @ wih^T
        ggc_hmma_k<<<dim3(3, NPER), 256, GGC_SMEM>>>(a16, wi16, gi, 600, 600);
        // GRU update (+bias fold) and fp16 re-write of h
        k_gates<<<(N_NODES * HDIM + 255) / 256, 256>>>(gi, gh, bih, bhh, hc, hn, h16);
        float* t = hc; hc = hn; hn = t;
    }

    // ---- conv0 (fp16 HMMA, fused bias+ReLU+max; feats cols 0..199) ----
    k_hp16<<<(BATCH * 207 * 200 + 255) / 256, 256>>>(hc, hp16);
    conv0h_k<<<dim3(1, 2, BATCH), 256, CONV_SMEM>>>(hp16, w0h, c0b, feats);

    // ---- join conv branch, then FC head ----
    cudaStreamWaitEvent(0, ev2, 0);
    k_fc<<<BATCH, 256>>>(feats, f1w, f1b, f2w, f2b, f3w, f3b, out);
}

// round 15
// speedup vs baseline: 5.6988x; 1.0639x over previous
#include <cuda_runtime.h>
#include <cuda_fp16.h>
#include <cstdint>

// ---------------- problem constants ----------------
#define N_NODES 26240      // B * N_PER = 128 * 205 (exactly 205 blocks of 128)
#define HDIM    200
#define NEDGE   209920
#define BATCH   128
#define NPER    205
#define EMBD    768
#define SEQ     512
#define NLAYERS 6
#define KPAD    208        // padded K (fp16 single pass; 3x64 + 1x16 tiles)

// ---------------- static device scratch ----------------
__device__ float g_h0[N_NODES * HDIM];
__device__ float g_h1[N_NODES * HDIM];
__device__ float g_gi[N_NODES * 3 * HDIM];
__device__ float g_gh[N_NODES * 3 * HDIM];
__device__ float g_feats[BATCH * 800];
__device__ int   g_deg[N_NODES];
__device__ int   g_rs [N_NODES + 1];
__device__ int   g_cur[N_NODES];
__device__ int   g_csrc[NEDGE];

// GGC fp16 operands, K-padded to 208 (pads zero from module init, never written)
__device__ __align__(16) __half g_h16[(size_t)N_NODES * KPAD];
__device__ __align__(16) __half g_a16[(size_t)N_NODES * KPAD];
// GGC fp16 weights
__device__ __align__(16) __half g_wi16[640 * KPAD];             // wih, rows 600..639 zero
__device__ __align__(16) __half g_wh16[640 * KPAD];             // whh, rows 600..639 zero
__device__ __align__(16) __half g_wgd16[NLAYERS * 208 * KPAD];  // ggc_w[l] direct cast
__device__ __align__(16) __half g_wc16[NLAYERS * 640 * KPAD];   // Wcomb_l = wih @ W_l^T

// fp16 embeddings, time-major [b][t][c], +8 zero rows for tap overrun
__device__ __align__(16) __half g_e16[((size_t)BATCH * SEQ + 8) * EMBD];
// fp16 conv weights: [200][K], tap-major K (single pass)
__device__ __align__(16) __half g_w1h[200 * 2304];
__device__ __align__(16) __half g_w2h[200 * 3072];
__device__ __align__(16) __half g_w3h[200 * 3840];
// conv0: fp16 padded h input [BATCH][260][256] and weights [208][768]
__device__ __align__(16) __half g_hp16[(size_t)BATCH * 260 * 256];
__device__ __align__(16) __half g_w0h[208 * 768];

// ---------------- warp-level MMA (compute_100-safe PTX) ----------------
#define MMA_F16(d, a, b0, b1) asm volatile(                            \
    "mma.sync.aligned.m16n8k16.row.col.f32.f16.f16.f32 "               \
    "{%0,%1,%2,%3}, {%4,%5,%6,%7}, {%8,%9}, {%0,%1,%2,%3};"            \
    : "+f"((d)[0]), "+f"((d)[1]), "+f"((d)[2]), "+f"((d)[3])           \
    : "r"((a)[0]), "r"((a)[1]), "r"((a)[2]), "r"((a)[3]),              \
      "r"(b0), "r"(b1))

// ---------------- cp.async helpers (sm_80+ PTX) ----------------
#define CP16(dst, src) asm volatile("cp.async.ca.shared.global [%0], [%1], 16;" \
                                    :: "r"(dst), "l"(src))
#define CP_COMMIT() asm volatile("cp.async.commit_group;" ::: "memory")
#define CP_WAIT0()  asm volatile("cp.async.wait_group 0;" ::: "memory")

__device__ __forceinline__ uint32_t s2u(const void* p) {
    return (uint32_t)__cvta_generic_to_shared(p);
}

// ---------------- shared copy helpers for K=208 (3x64 + 1x16) -----------------
// A: 128 rows stride KPAD; B: 208 rows stride KPAD.
__device__ __forceinline__ void cp_k208(const __half* A, const __half* B,
                                        uint32_t ab, uint32_t bb,
                                        int tid, int kt) {
    const int kg = kt * 64;
    constexpr int ASTR = 72, BSTR = 72;
    if (kt < 3) {
#pragma unroll
        for (int i = 0; i < 4; i++) {
            int u = tid + i * 256;
            int row = u >> 3, ch = u & 7;
            CP16(ab + (row * ASTR + ch * 8) * 2,
                 A + (long long)row * KPAD + kg + ch * 8);
        }
#pragma unroll
        for (int i = 0; i < 7; i++) {
            int u = tid + i * 256;
            if (u < 1664) {
                int row = u >> 3, ch = u & 7;
                CP16(bb + (row * BSTR + ch * 8) * 2,
                     B + (long long)row * KPAD + kg + ch * 8);
            }
        }
    } else {   // 16-wide tail, cols 192..207
        {
            int row = tid >> 1, ch = tid & 1;
            CP16(ab + (row * ASTR + ch * 8) * 2,
                 A + (long long)row * KPAD + kg + ch * 8);
        }
#pragma unroll
        for (int i = 0; i < 2; i++) {
            int u = tid + i * 256;
            if (u < 416) {
                int row = u >> 1, ch = u & 1;
                CP16(bb + (row * BSTR + ch * 8) * 2,
                     B + (long long)row * KPAD + kg + ch * 8);
            }
        }
    }
}

// ---------------- fused gh + gi GEMM ----------------
// grid (6, 205): bx<3 -> gh = h16 @ whh^T slice; bx>=3 -> gi = a16 @ Wcomb^T slice.
__global__ void __launch_bounds__(256, 1) ggc2_k(
    const __half* __restrict__ h16,
    const __half* __restrict__ a16,
    const __half* __restrict__ wh,     // [640][208]
    const __half* __restrict__ wc,     // [640][208] layer slice
    float* __restrict__ Cgh,
    float* __restrict__ Cgi)
{
    extern __shared__ __align__(16) char dsm[];
    constexpr int ASTR = 72, BSTR = 72;
    __half* As = (__half*)dsm;
    __half* Bs = (__half*)(dsm + 36864);

    const int tid = threadIdx.x;
    const int lane = tid & 31, wid = tid >> 5;
    const int wm = wid & 3, wn = wid >> 2;
    const int g = lane >> 2, t2 = (lane & 3) * 2;
    const int m0 = blockIdx.y * 128;
    const int bx = blockIdx.x;
    const uint32_t asb = s2u(As), bsb = s2u(Bs);

    const bool isGi = (bx >= 3);
    const int nb = isGi ? (bx - 3) : bx;
    const __half* A = (isGi ? a16 : h16) + (long long)m0 * KPAD;
    const __half* B = (isGi ? wc : wh) + (long long)nb * 208 * KPAD;
    float* C = isGi ? Cgi : Cgh;
    const int cb = nb * 208;

    float acc[2][13][4];
#pragma unroll
    for (int i = 0; i < 2; i++)
#pragma unroll
        for (int j = 0; j < 13; j++)
#pragma unroll
            for (int q = 0; q < 4; q++) acc[i][j][q] = 0.f;

    cp_k208(A, B, asb, bsb, tid, 0); CP_COMMIT(); CP_WAIT0();
    __syncthreads();

#pragma unroll 1
    for (int kt = 0; kt < 4; kt++) {
        const int buf = kt & 1;
        const bool more = (kt + 1 < 4);
        if (more) {
            cp_k208(A, B, asb + (buf ^ 1) * 128 * ASTR * 2,
                    bsb + (buf ^ 1) * 208 * BSTR * 2, tid, kt + 1);
            CP_COMMIT();
        }
        const __half* Ab = As + buf * 128 * ASTR;
        const __half* Bb = Bs + buf * 208 * BSTR;
        const int ksteps = (kt == 3) ? 1 : 4;
#pragma unroll 1
        for (int ks = 0; ks < ksteps; ks++) {
            const int ko = ks * 16;
            uint32_t a[2][4];
#pragma unroll
            for (int i = 0; i < 2; i++) {
                const int r = wm * 32 + i * 16 + g;
                a[i][0] = *(const uint32_t*)(Ab + (r)     * ASTR + ko + t2);
                a[i][1] = *(const uint32_t*)(Ab + (r + 8) * ASTR + ko + t2);
                a[i][2] = *(const uint32_t*)(Ab + (r)     * ASTR + ko + t2 + 8);
                a[i][3] = *(const uint32_t*)(Ab + (r + 8) * ASTR + ko + t2 + 8);
            }
            uint32_t bf[13][2];
#pragma unroll
            for (int j = 0; j < 13; j++) {
                const int n = wn * 104 + j * 8 + g;
                bf[j][0] = *(const uint32_t*)(Bb + n * BSTR + ko + t2);
                bf[j][1] = *(const uint32_t*)(Bb + n * BSTR + ko + t2 + 8);
            }
#pragma unroll
            for (int j = 0; j < 13; j++) {
                MMA_F16(acc[0][j], a[0], bf[j][0], bf[j][1]);
                MMA_F16(acc[1][j], a[1], bf[j][0], bf[j][1]);
            }
        }
        if (more) CP_WAIT0();
        __syncthreads();
    }

#pragma unroll
    for (int i = 0; i < 2; i++) {
        const int r = m0 + wm * 32 + i * 16 + g;
#pragma unroll
        for (int j = 0; j < 13; j++) {
            const int col = cb + wn * 104 + j * 8 + t2;
            if (col < 600) {
                C[(long long)r * 600 + col]       = acc[i][j][0];
                C[(long long)(r + 8) * 600 + col] = acc[i][j][2];
            }
            if (col + 1 < 600) {
                C[(long long)r * 600 + col + 1]       = acc[i][j][1];
                C[(long long)(r + 8) * 600 + col + 1] = acc[i][j][3];
            }
        }
    }
}

// ---------------- Wcomb = wih @ W_l^T (fp16 out) ----------------
// grid (1, 5 m-tiles, 6 layers). C[l][j:640][k1:208] fp16.
__global__ void __launch_bounds__(256, 1) wcomb_k(
    const __half* __restrict__ wi,      // [640][208]
    const __half* __restrict__ wgd,     // [L][208][208]
    __half* __restrict__ wc)            // [L][640][208]
{
    extern __shared__ __align__(16) char dsm[];
    constexpr int ASTR = 72, BSTR = 72;
    __half* As = (__half*)dsm;
    __half* Bs = (__half*)(dsm + 36864);

    const int tid = threadIdx.x;
    const int lane = tid & 31, wid = tid >> 5;
    const int wm = wid & 3, wn = wid >> 2;
    const int g = lane >> 2, t2 = (lane & 3) * 2;
    const int m0 = blockIdx.y * 128;
    const int l = blockIdx.z;
    const uint32_t asb = s2u(As), bsb = s2u(Bs);

    const __half* A = wi + (long long)m0 * KPAD;
    const __half* B = wgd + (long long)l * 208 * KPAD;
    __half* C = wc + (long long)l * 640 * KPAD;

    float acc[2][13][4];
#pragma unroll
    for (int i = 0; i < 2; i++)
#pragma unroll
        for (int j = 0; j < 13; j++)
#pragma unroll
            for (int q = 0; q < 4; q++) acc[i][j][q] = 0.f;

    cp_k208(A, B, asb, bsb, tid, 0); CP_COMMIT(); CP_WAIT0();
    __syncthreads();

#pragma unroll 1
    for (int kt = 0; kt < 4; kt++) {
        const int buf = kt & 1;
        const bool more = (kt + 1 < 4);
        if (more) {
            cp_k208(A, B, asb + (buf ^ 1) * 128 * ASTR * 2,
                    bsb + (buf ^ 1) * 208 * BSTR * 2, tid, kt + 1);
            CP_COMMIT();
        }
        const __half* Ab = As + buf * 128 * ASTR;
        const __half* Bb = Bs + buf * 208 * BSTR;
        const int ksteps = (kt == 3) ? 1 : 4;
#pragma unroll 1
        for (int ks = 0; ks < ksteps; ks++) {
            const int ko = ks * 16;
            uint32_t a[2][4];
#pragma unroll
            for (int i = 0; i < 2; i++) {
                const int r = wm * 32 + i * 16 + g;
                a[i][0] = *(const uint32_t*)(Ab + (r)     * ASTR + ko + t2);
                a[i][1] = *(const uint32_t*)(Ab + (r + 8) * ASTR + ko + t2);
                a[i][2] = *(const uint32_t*)(Ab + (r)     * ASTR + ko + t2 + 8);
                a[i][3] = *(const uint32_t*)(Ab + (r + 8) * ASTR + ko + t2 + 8);
            }
            uint32_t bf[13][2];
#pragma unroll
            for (int j = 0; j < 13; j++) {
                const int n = wn * 104 + j * 8 + g;
                bf[j][0] = *(const uint32_t*)(Bb + n * BSTR + ko + t2);
                bf[j][1] = *(const uint32_t*)(Bb + n * BSTR + ko + t2 + 8);
            }
#pragma unroll
            for (int j = 0; j < 13; j++) {
                MMA_F16(acc[0][j], a[0], bf[j][0], bf[j][1]);
                MMA_F16(acc[1][j], a[1], bf[j][0], bf[j][1]);
            }
        }
        if (more) CP_WAIT0();
        __syncthreads();
    }

#pragma unroll
    for (int i = 0; i < 2; i++) {
        const int r = m0 + wm * 32 + i * 16 + g;
#pragma unroll
        for (int j = 0; j < 13; j++) {
            const int col = wn * 104 + j * 8 + t2;
            if (col < 208) {
                C[(long long)r * KPAD + col]       = __float2half(acc[i][j][0]);
                C[(long long)(r + 8) * KPAD + col] = __float2half(acc[i][j][2]);
            }
            if (col + 1 < 208) {
                C[(long long)r * KPAD + col + 1]       = __float2half(acc[i][j][1]);
                C[(long long)(r + 8) * KPAD + col + 1] = __float2half(acc[i][j][3]);
            }
        }
    }
}

// ---------------- fused conv1/2/3: pure fp16 conv-as-GEMM ----------------
struct Conv3Args {
    const __half* wb[3];
    const float* bias[3];
};
// grid (3 convs, 4 m-tiles, 128 batches)
__global__ void __launch_bounds__(256, 1) conv3h_k(
    const __half* __restrict__ e16,
    Conv3Args args,
    float* __restrict__ feats)
{
    extern __shared__ __align__(16) char dsm[];
    constexpr int ASTR = 72, BSTR = 72;
    __half* As = (__half*)dsm;
    __half* Bs = (__half*)(dsm + 36864);
    float* smax  = (float*)(dsm + 36864 + 59904);
    float* sbias = smax + 208;

    const int cid = blockIdx.x;
    const int M   = (cid == 0) ? 510 : (cid == 1) ? 509 : 508;
    const int K   = (cid == 0) ? 2304 : (cid == 1) ? 3072 : 3840;
    const int featOff = 200 + cid * 200;
    const __half* wb = args.wb[cid];
    const float* bias = args.bias[cid];

    const int tid = threadIdx.x;
    const int lane = tid & 31, wid = tid >> 5;
    const int wm = wid & 3, wn = wid >> 2;
    const int g = lane >> 2, t2 = (lane & 3) * 2;
    const int b = blockIdx.z, m0 = blockIdx.y * 128;
    const int T = K / 64;
    const uint32_t asb = s2u(As), bsb = s2u(Bs);

    if (tid < 208) { smax[tid] = 0.f; sbias[tid] = (tid < 200) ? bias[tid] : 0.f; }

    auto copy_tile = [&](int kt, int buf) {
        int kk = kt / 12;
        int c0 = (kt - kk * 12) * 64;
        long long abase = ((long long)(b * SEQ + m0 + kk)) * EMBD + c0;
        const uint32_t ab = asb + buf * 128 * ASTR * 2;
        const uint32_t bb = bsb + buf * 208 * BSTR * 2;
#pragma unroll
        for (int i = 0; i < 4; i++) {
            int u = tid + i * 256;
            int row = u >> 3, ch = u & 7;
            CP16(ab + (row * ASTR + ch * 8) * 2,
                 e16 + abase + (long long)row * EMBD + ch * 8);
        }
        int kg = kt * 64;
#pragma unroll
        for (int i = 0; i < 7; i++) {
            int u = tid + i * 256;
            if (u < 1600) {
                int row = u >> 3, ch = u & 7;
                CP16(bb + (row * BSTR + ch * 8) * 2,
                     wb + (long long)row * K + kg + ch * 8);
            }
        }
    };

    float acc[2][13][4];
#pragma unroll
    for (int i = 0; i < 2; i++)
#pragma unroll
        for (int j = 0; j < 13; j++)
#pragma unroll
            for (int q = 0; q < 4; q++) acc[i][j][q] = 0.f;

    copy_tile(0, 0); CP_COMMIT(); CP_WAIT0();
    __syncthreads();

#pragma unroll 1
    for (int kt = 0; kt < T; kt++) {
        const int buf = kt & 1;
        const bool more = (kt + 1 < T);
        if (more) { copy_tile(kt + 1, buf ^ 1); CP_COMMIT(); }

        const __half* Ab = As + buf * 128 * ASTR;
        const __half* Bb = Bs + buf * 208 * BSTR;
#pragma unroll
        for (int ks = 0; ks < 4; ks++) {
            const int ko = ks * 16;
            uint32_t a[2][4];
#pragma unroll
            for (int i = 0; i < 2; i++) {
                const int r = wm * 32 + i * 16 + g;
                a[i][0] = *(const uint32_t*)(Ab + (r)     * ASTR + ko + t2);
                a[i][1] = *(const uint32_t*)(Ab + (r + 8) * ASTR + ko + t2);
                a[i][2] = *(const uint32_t*)(Ab + (r)     * ASTR + ko + t2 + 8);
                a[i][3] = *(const uint32_t*)(Ab + (r + 8) * ASTR + ko + t2 + 8);
            }
            uint32_t bf[13][2];
#pragma unroll
            for (int j = 0; j < 13; j++) {
                const int n = wn * 104 + j * 8 + g;
                bf[j][0] = *(const uint32_t*)(Bb + n * BSTR + ko + t2);
                bf[j][1] = *(const uint32_t*)(Bb + n * BSTR + ko + t2 + 8);
            }
#pragma unroll
            for (int j = 0; j < 13; j++) {
                MMA_F16(acc[0][j], a[0], bf[j][0], bf[j][1]);
                MMA_F16(acc[1][j], a[1], bf[j][0], bf[j][1]);
            }
        }
        if (more) CP_WAIT0();
        __syncthreads();
    }

    const int valid = (M - m0 < 128) ? (M - m0) : 128;
#pragma unroll
    for (int j = 0; j < 13; j++) {
        float v0 = -1e30f, v1 = -1e30f;
#pragma unroll
        for (int i = 0; i < 2; i++) {
            const int r0 = wm * 32 + i * 16 + g;
            if (r0 < valid)     { v0 = fmaxf(v0, acc[i][j][0]); v1 = fmaxf(v1, acc[i][j][1]); }
            if (r0 + 8 < valid) { v0 = fmaxf(v0, acc[i][j][2]); v1 = fmaxf(v1, acc[i][j][3]); }
        }
#pragma unroll
        for (int o = 4; o <= 16; o <<= 1) {
            v0 = fmaxf(v0, __shfl_xor_sync(~0u, v0, o));
            v1 = fmaxf(v1, __shfl_xor_sync(~0u, v1, o));
        }
        if (g == 0) {
            const int col = wn * 104 + j * 8 + t2;
            if (col < 200) {
                float r = fmaxf(v0 + sbias[col], 0.f);
                atomicMax((unsigned int*)&smax[col], __float_as_uint(r));
            }
            if (col + 1 < 200) {
                float r = fmaxf(v1 + sbias[col + 1], 0.f);
                atomicMax((unsigned int*)&smax[col + 1], __float_as_uint(r));
            }
        }
    }
    __syncthreads();
    if (tid < 200)
        atomicMax((unsigned int*)&feats[(long long)b * 800 + featOff + tid],
                  __float_as_uint(smax[tid]));
}

// ---------------- conv0: fp16 conv-as-GEMM over padded h ----------------
// grid (1, 2 m-tiles, 128 batches). M = 205, N = 200, feats cols 0..199.
__global__ void __launch_bounds__(256, 1) conv0h_k(
    const __half* __restrict__ hp16,
    const __half* __restrict__ w0h,     // [208][768] (rows 200..207 zero)
    const float* __restrict__ bias,
    float* __restrict__ feats)
{
    extern __shared__ __align__(16) char dsm[];
    constexpr int ASTR = 72, BSTR = 72;
    __half* As = (__half*)dsm;
    __half* Bs = (__half*)(dsm + 36864);
    float* smax  = (float*)(dsm + 36864 + 59904);
    float* sbias = smax + 208;

    const int tid = threadIdx.x;
    const int lane = tid & 31, wid = tid >> 5;
    const int wm = wid & 3, wn = wid >> 2;
    const int g = lane >> 2, t2 = (lane & 3) * 2;
    const int b = blockIdx.z, m0 = blockIdx.y * 128;
    const uint32_t asb = s2u(As), bsb = s2u(Bs);

    if (tid < 208) { smax[tid] = 0.f; sbias[tid] = (tid < 200) ? bias[tid] : 0.f; }

    auto copy_tile = [&](int kt, int buf) {
        int kk = kt >> 2;
        int c0 = (kt & 3) * 64;
        long long abase = ((long long)b * 260 + m0 + kk) * 256 + c0;
        const uint32_t ab = asb + buf * 128 * ASTR * 2;
        const uint32_t bb = bsb + buf * 208 * BSTR * 2;
#pragma unroll
        for (int i = 0; i < 4; i++) {
            int u = tid + i * 256;
            int row = u >> 3, ch = u & 7;
            CP16(ab + (row * ASTR + ch * 8) * 2,
                 hp16 + abase + (long long)row * 256 + ch * 8);
        }
        int kg = kt * 64;
#pragma unroll
        for (int i = 0; i < 7; i++) {
            int u = tid + i * 256;
            if (u < 1664) {
                int row = u >> 3, ch = u & 7;
                CP16(bb + (row * BSTR + ch * 8) * 2,
                     w0h + (long long)row * 768 + kg + ch * 8);
            }
        }
    };

    float acc[2][13][4];
#pragma unroll
    for (int i = 0; i < 2; i++)
#pragma unroll
        for (int j = 0; j < 13; j++)
#pragma unroll
            for (int q = 0; q < 4; q++) acc[i][j][q] = 0.f;

    copy_tile(0, 0); CP_COMMIT(); CP_WAIT0();
    __syncthreads();

#pragma unroll 1
    for (int kt = 0; kt < 12; kt++) {
        const int buf = kt & 1;
        const bool more = (kt + 1 < 12);
        if (more) { copy_tile(kt + 1, buf ^ 1); CP_COMMIT(); }

        const __half* Ab = As + buf * 128 * ASTR;
        const __half* Bb = Bs + buf * 208 * BSTR;
#pragma unroll
        for (int ks = 0; ks < 4; ks++) {
            const int ko = ks * 16;
            uint32_t a[2][4];
#pragma unroll
            for (int i = 0; i < 2; i++) {
                const int r = wm * 32 + i * 16 + g;
                a[i][0] = *(const uint32_t*)(Ab + (r)     * ASTR + ko + t2);
                a[i][1] = *(const uint32_t*)(Ab + (r + 8) * ASTR + ko + t2);
                a[i][2] = *(const uint32_t*)(Ab + (r)     * ASTR + ko + t2 + 8);
                a[i][3] = *(const uint32_t*)(Ab + (r + 8) * ASTR + ko + t2 + 8);
            }
            uint32_t bf[13][2];
#pragma unroll
            for (int j = 0; j < 13; j++) {
                const int n = wn * 104 + j * 8 + g;
                bf[j][0] = *(const uint32_t*)(Bb + n * BSTR + ko + t2);
                bf[j][1] = *(const uint32_t*)(Bb + n * BSTR + ko + t2 + 8);
            }
#pragma unroll
            for (int j = 0; j < 13; j++) {
                MMA_F16(acc[0][j], a[0], bf[j][0], bf[j][1]);
                MMA_F16(acc[1][j], a[1], bf[j][0], bf[j][1]);
            }
        }
        if (more) CP_WAIT0();
        __syncthreads();
    }

    const int valid = (205 - m0 < 128) ? (205 - m0) : 128;
#pragma unroll
    for (int j = 0; j < 13; j++) {
        float v0 = -1e30f, v1 = -1e30f;
#pragma unroll
        for (int i = 0; i < 2; i++) {
            const int r0 = wm * 32 + i * 16 + g;
            if (r0 < valid)     { v0 = fmaxf(v0, acc[i][j][0]); v1 = fmaxf(v1, acc[i][j][1]); }
            if (r0 + 8 < valid) { v0 = fmaxf(v0, acc[i][j][2]); v1 = fmaxf(v1, acc[i][j][3]); }
        }
#pragma unroll
        for (int o = 4; o <= 16; o <<= 1) {
            v0 = fmaxf(v0, __shfl_xor_sync(~0u, v0, o));
            v1 = fmaxf(v1, __shfl_xor_sync(~0u, v1, o));
        }
        if (g == 0) {
            const int col = wn * 104 + j * 8 + t2;
            if (col < 200) {
                float r = fmaxf(v0 + sbias[col], 0.f);
                atomicMax((unsigned int*)&smax[col], __float_as_uint(r));
            }
            if (col + 1 < 200) {
                float r = fmaxf(v1 + sbias[col + 1], 0.f);
                atomicMax((unsigned int*)&smax[col + 1], __float_as_uint(r));
            }
        }
    }
    __syncthreads();
    if (tid < 200)
        atomicMax((unsigned int*)&feats[(long long)b * 800 + tid],
                  __float_as_uint(smax[tid]));
}

// ---------------- fp16 embed ----------------
__global__ void k_embed16(const int* __restrict__ ids, const float* __restrict__ tbl,
                          __half* __restrict__ e16) {
    int row = blockIdx.x;
    int t = threadIdx.x;
    long long o = (long long)row * EMBD;
    if (row >= BATCH * SEQ) {
        if (t < 96) {
            ((uint2*)(e16 + o))[t * 2]     = make_uint2(0, 0);
            ((uint2*)(e16 + o))[t * 2 + 1] = make_uint2(0, 0);
        }
        return;
    }
    long long id = ids[row];
    float4 v = ((const float4*)(tbl + id * EMBD))[t];
    __half2 h01 = __floats2half2_rn(v.x, v.y);
    __half2 h23 = __floats2half2_rn(v.z, v.w);
    uint2 hv;
    hv.x = *(uint32_t*)&h01; hv.y = *(uint32_t*)&h23;
    ((uint2*)(e16 + o))[t] = hv;
}

// w: [200][768][KK] fp32 -> wb: [200][K] fp16, tap-major K
__global__ void k_w16(const float* __restrict__ w, __half* __restrict__ wb, int KK) {
    int K = 768 * KK;
    int idx = blockIdx.x * blockDim.x + threadIdx.x;
    if (idx >= 200 * K) return;
    int co = idx / K, r = idx - co * K;
    int kk = r / 768, ci = r - kk * 768;
    wb[idx] = __float2half(w[(co * 768 + ci) * KK + kk]);
}

// conv0 weights: c0w [200][200][3] -> w0h [208][768] (col = kk*256 + ci)
__global__ void k_w0h(const float* __restrict__ w, __half* __restrict__ out) {
    int idx = blockIdx.x * blockDim.x + threadIdx.x;
    if (idx >= 200 * 600) return;
    int co = idx / 600, r = idx - co * 600;
    int kk = r / 200, ci = r - kk * 200;
    out[(long long)co * 768 + kk * 256 + ci] =
        __float2half(w[(co * 200 + ci) * 3 + kk]);
}

// ggc_w direct cast: [L][208 rows k1][208 cols k2]
__global__ void k_wgd16(const float* __restrict__ w, __half* __restrict__ out) {
    int idx = blockIdx.x * blockDim.x + threadIdx.x;
    if (idx >= NLAYERS * 208 * KPAD) return;
    int l = idx / (208 * KPAD);
    int rem = idx - l * 208 * KPAD;
    int k1 = rem / KPAD, k2 = rem - k1 * KPAD;
    float x = (k1 < 200 && k2 < 200) ? w[(long long)l * 40000 + k1 * 200 + k2] : 0.f;
    out[idx] = __float2half(x);
}

// wih/whh [600][200] -> [640][208], zero pad
__global__ void k_wgru16(const float* __restrict__ w, __half* __restrict__ out) {
    int idx = blockIdx.x * blockDim.x + threadIdx.x;
    if (idx >= 640 * KPAD) return;
    int n = idx / KPAD, kk = idx - n * KPAD;
    float x = (n < 600 && kk < 200) ? w[n * 200 + kk] : 0.f;
    out[idx] = __float2half(x);
}

// x [26240][200] fp32 -> h16 [26240][208] fp16 (pads zeroed here, forever)
__global__ void k_x16(const float* __restrict__ xin, __half* __restrict__ h16) {
    int idx = blockIdx.x * blockDim.x + threadIdx.x;
    if (idx >= N_NODES * KPAD) return;
    int n = idx / KPAD, c = idx - n * KPAD;
    h16[idx] = __float2half((c < 200) ? xin[n * HDIM + c] : 0.f);
}

// ---------------- CSR build ----------------
__global__ void k_hist(const int* __restrict__ ei, int* __restrict__ deg) {
    int i = blockIdx.x * blockDim.x + threadIdx.x;
    if (i < NEDGE) atomicAdd(&deg[ei[NEDGE + i]], 1);
}

__global__ void k_scan(const int* __restrict__ deg, int* __restrict__ rs,
                       int* __restrict__ cur, int n) {
    __shared__ int s[1024];
    __shared__ int carry;
    int t = threadIdx.x;
    if (t == 0) carry = 0;
    __syncthreads();
    for (int base = 0; base < n; base += 1024) {
        int v = (base + t < n) ? deg[base + t] : 0;
        s[t] = v;
        __syncthreads();
        for (int off = 1; off < 1024; off <<= 1) {
            int add = (t >= off) ? s[t - off] : 0;
            __syncthreads();
            s[t] += add;
            __syncthreads();
        }
        int c0 = carry;
        int ex = c0 + s[t] - v;
        if (base + t < n) { rs[base + t] = ex; cur[base + t] = ex; }
        __syncthreads();
        if (t == 0) carry = c0 + s[1023];
        __syncthreads();
    }
    if (t == 0) rs[n] = carry;
}

__global__ void k_fill(const int* __restrict__ ei, int* __restrict__ cur,
                       int* __restrict__ cs) {
    int i = blockIdx.x * blockDim.x + threadIdx.x;
    if (i < NEDGE) {
        int d = ei[NEDGE + i];
        int p = atomicAdd(&cur[d], 1);
        cs[p] = ei[i];
    }
}

// ---------------- segment-sum of h (fp32 source) + fp16 write --------------
__global__ void k_agg(const float* __restrict__ h, const int* __restrict__ rs,
                      const int* __restrict__ cs, __half* __restrict__ a16) {
    int w = (blockIdx.x * blockDim.x + threadIdx.x) >> 5;
    int lane = threadIdx.x & 31;
    if (w >= N_NODES) return;
    int s = rs[w], e = rs[w + 1];
    float a[7] = {0, 0, 0, 0, 0, 0, 0};
    int i = s;
    for (; i + 1 < e; i += 2) {
        const float* r0 = h + (long long)cs[i]     * HDIM;
        const float* r1 = h + (long long)cs[i + 1] * HDIM;
        a[0] += r0[lane]       + r1[lane];
        a[1] += r0[lane +  32] + r1[lane +  32];
        a[2] += r0[lane +  64] + r1[lane +  64];
        a[3] += r0[lane +  96] + r1[lane +  96];
        a[4] += r0[lane + 128] + r1[lane + 128];
        a[5] += r0[lane + 160] + r1[lane + 160];
        if (lane < 8) a[6] += r0[lane + 192] + r1[lane + 192];
    }
    if (i < e) {
        const float* r0 = h + (long long)cs[i] * HDIM;
        a[0] += r0[lane];       a[1] += r0[lane + 32];  a[2] += r0[lane + 64];
        a[3] += r0[lane + 96];  a[4] += r0[lane + 128]; a[5] += r0[lane + 160];
        if (lane < 8) a[6] += r0[lane + 192];
    }
    long long o = (long long)w * KPAD + lane;
#pragma unroll
    for (int q = 0; q < 6; q++) a16[o + q * 32] = __float2half(a[q]);
    if (lane < 8) a16[o + 192] = __float2half(a[6]);
}

// ---------------- GRU gates (+ bias fold + fp16 h; optional hp16 write) ----------
__global__ void k_gates(const float* __restrict__ gi, const float* __restrict__ gh,
                        const float* __restrict__ bih, const float* __restrict__ bhh,
                        const float* __restrict__ hsrc, float* __restrict__ hdst,
                        __half* __restrict__ h16, __half* __restrict__ hp) {
    int idx = blockIdx.x * blockDim.x + threadIdx.x;
    if (idx >= N_NODES * HDIM) return;
    int n = idx / HDIM, c = idx - n * HDIM;
    const float* giN = gi + (long long)n * 600;
    const float* ghN = gh + (long long)n * 600;
    float r  = 1.f / (1.f + expf(-(giN[c] + bih[c] + ghN[c] + bhh[c])));
    float z  = 1.f / (1.f + expf(-(giN[200 + c] + bih[200 + c] + ghN[200 + c] + bhh[200 + c])));
    float nn = tanhf(giN[400 + c] + bih[400 + c] + r * (ghN[400 + c] + bhh[400 + c]));
    float h = (1.f - z) * nn + z * hsrc[idx];
    hdst[idx] = h;
    __half hf = __float2half(h);
    h16[(long long)n * KPAD + c] = hf;
    if (hp) {
        int b = n / NPER, rr = n - b * NPER;
        hp[((long long)b * 260 + rr + 1) * 256 + c] = hf;
    }
}

// ---------------- fused FC head ----------------
__global__ void k_fc(const float* __restrict__ feats,
                     const float* __restrict__ w1, const float* __restrict__ b1,
                     const float* __restrict__ w2, const float* __restrict__ b2,
                     const float* __restrict__ w3, const float* __restrict__ b3,
                     float* __restrict__ out) {
    int b = blockIdx.x;
    int tid = threadIdx.x;
    int lane = tid & 31, wrp = tid >> 5;
    __shared__ float sf[800];
    __shared__ float s1[256];
    __shared__ float s2[128];
    for (int i = tid; i < 800; i += 256) sf[i] = feats[b * 800 + i];
    __syncthreads();
    for (int jj = 0; jj < 32; jj++) {
        int j = wrp * 32 + jj;
        float a = 0.f;
        for (int i = lane; i < 800; i += 32) a += sf[i] * w1[(long long)j * 800 + i];
        for (int o = 16; o; o >>= 1) a += __shfl_down_sync(0xffffffffu, a, o);
        if (lane == 0) s1[j] = fmaxf(a + b1[j], 0.f);
    }
    __syncthreads();
    if (tid < 128) {
        float a = b2[tid];
        for (int i = 0; i < 256; i++) a += s1[i] * w2[tid * 256 + i];
        s2[tid] = fmaxf(a, 0.f);
    }
    __syncthreads();
    if (tid < 2) {
        float a = b3[tid];
        for (int i = 0; i < 128; i++) a += s2[i] * w3[tid * 128 + i];
        out[b * 2 + tid] = a;
    }
}

// ---------------- launcher ----------------
extern "C" void kernel_launch(void* const* d_in, const int* in_sizes, int n_in,
                              void* d_out, int out_size) {
    const float* x     = (const float*)d_in[0];
    const int*   ei    = (const int*)  d_in[1];
    const int*   ids   = (const int*)  d_in[2];
    const float* etab  = (const float*)d_in[3];
    const float* ggcw  = (const float*)d_in[4];
    const float* wih   = (const float*)d_in[5];
    const float* whh   = (const float*)d_in[6];
    const float* bih   = (const float*)d_in[7];
    const float* bhh   = (const float*)d_in[8];
    const float* c0w   = (const float*)d_in[9];
    const float* c0b   = (const float*)d_in[10];
    const float* c1w   = (const float*)d_in[11];
    const float* c1b   = (const float*)d_in[12];
    const float* c2w   = (const float*)d_in[13];
    const float* c2b   = (const float*)d_in[14];
    const float* c3w   = (const float*)d_in[15];
    const float* c3b   = (const float*)d_in[16];
    const float* f1w   = (const float*)d_in[17];
    const float* f1b   = (const float*)d_in[18];
    const float* f2w   = (const float*)d_in[19];
    const float* f2b   = (const float*)d_in[20];
    const float* f3w   = (const float*)d_in[21];
    const float* f3b   = (const float*)d_in[22];
    float* out = (float*)d_out;

    float *h0, *h1, *gi, *gh, *feats;
    int *deg, *rs, *cur, *cs;
    __half *e16, *w1h, *w2h, *w3h, *hp16, *w0h;
    __half *h16, *a16, *wi16, *wh16, *wgd16, *wc16;
    cudaGetSymbolAddress((void**)&h0,   g_h0);
    cudaGetSymbolAddress((void**)&h1,   g_h1);
    cudaGetSymbolAddress((void**)&gi,   g_gi);
    cudaGetSymbolAddress((void**)&gh,   g_gh);
    cudaGetSymbolAddress((void**)&feats,g_feats);
    cudaGetSymbolAddress((void**)&deg,  g_deg);
    cudaGetSymbolAddress((void**)&rs,   g_rs);
    cudaGetSymbolAddress((void**)&cur,  g_cur);
    cudaGetSymbolAddress((void**)&cs,   g_csrc);
    cudaGetSymbolAddress((void**)&e16,  g_e16);
    cudaGetSymbolAddress((void**)&w1h,  g_w1h);
    cudaGetSymbolAddress((void**)&w2h,  g_w2h);
    cudaGetSymbolAddress((void**)&w3h,  g_w3h);
    cudaGetSymbolAddress((void**)&hp16, g_hp16);
    cudaGetSymbolAddress((void**)&w0h,  g_w0h);
    cudaGetSymbolAddress((void**)&h16,  g_h16);
    cudaGetSymbolAddress((void**)&a16,  g_a16);
    cudaGetSymbolAddress((void**)&wi16, g_wi16);
    cudaGetSymbolAddress((void**)&wh16, g_wh16);
    cudaGetSymbolAddress((void**)&wgd16,g_wgd16);
    cudaGetSymbolAddress((void**)&wc16, g_wc16);

    const int CONV_SMEM = 36864 + 59904 + 832 + 832;   // 98432 B
    const int GGC_SMEM  = 36864 + 59904;               // 96768 B
    cudaFuncSetAttribute(conv3h_k, cudaFuncAttributeMaxDynamicSharedMemorySize, CONV_SMEM);
    cudaFuncSetAttribute(conv0h_k, cudaFuncAttributeMaxDynamicSharedMemorySize, CONV_SMEM);
    cudaFuncSetAttribute(ggc2_k,   cudaFuncAttributeMaxDynamicSharedMemorySize, GGC_SMEM);
    cudaFuncSetAttribute(wcomb_k,  cudaFuncAttributeMaxDynamicSharedMemorySize, GGC_SMEM);

    // side stream + events (created once; host resources, no device allocs)
    static cudaStream_t s2 = nullptr;
    static cudaEvent_t ev1 = nullptr, ev2 = nullptr;
    if (!s2) {
        cudaStreamCreateWithFlags(&s2, cudaStreamNonBlocking);
        cudaEventCreateWithFlags(&ev1, cudaEventDisableTiming);
        cudaEventCreateWithFlags(&ev2, cudaEventDisableTiming);
    }

    // ---- default stream: feats zero, then fork conv branch ----
    cudaMemsetAsync(feats, 0, BATCH * 800 * sizeof(float));
    cudaEventRecord(ev1, 0);
    cudaStreamWaitEvent(s2, ev1, 0);

    // ---- side stream: conv1/2/3 branch (independent of GGC) ----
    k_embed16<<<BATCH * SEQ + 8, 192, 0, s2>>>(ids, etab, e16);
    k_w16<<<(200 * 768 * 3 + 255) / 256, 256, 0, s2>>>(c1w, w1h, 3);
    k_w16<<<(200 * 768 * 4 + 255) / 256, 256, 0, s2>>>(c2w, w2h, 4);
    k_w16<<<(200 * 768 * 5 + 255) / 256, 256, 0, s2>>>(c3w, w3h, 5);
    {
        Conv3Args ca;
        ca.wb[0] = w1h; ca.wb[1] = w2h; ca.wb[2] = w3h;
        ca.bias[0] = c1b; ca.bias[1] = c2b; ca.bias[2] = c3b;
        conv3h_k<<<dim3(3, 4, BATCH), 256, CONV_SMEM, s2>>>(e16, ca, feats);
    }
    cudaEventRecord(ev2, s2);

    // ---- default stream: CSR + GGC prep ----
    cudaMemsetAsync(deg, 0, N_NODES * sizeof(int));
    k_hist<<<(NEDGE + 255) / 256, 256>>>(ei, deg);
    k_scan<<<1, 1024>>>(deg, rs, cur, N_NODES);
    k_fill<<<(NEDGE + 255) / 256, 256>>>(ei, cur, cs);
    cudaMemcpyAsync(h0, x, (size_t)N_NODES * HDIM * sizeof(float),
                    cudaMemcpyDeviceToDevice);
    k_x16<<<(N_NODES * KPAD + 255) / 256, 256>>>(x, h16);
    k_wgd16<<<(NLAYERS * 208 * KPAD + 255) / 256, 256>>>(ggcw, wgd16);
    k_wgru16<<<(640 * KPAD + 255) / 256, 256>>>(wih, wi16);
    k_wgru16<<<(640 * KPAD + 255) / 256, 256>>>(whh, wh16);
    k_w0h<<<(200 * 600 + 255) / 256, 256>>>(c0w, w0h);
    // Wcomb_l = wih @ W_l^T for all 6 layers (30 CTAs)
    wcomb_k<<<dim3(1, 5, NLAYERS), 256, GGC_SMEM>>>(wi16, wgd16, wc16);

    // ---- gated graph conv: 6 layers (fp16 HMMA, composed weights) ----
    float* hc = h0;
    float* hn = h1;
    for (int l = 0; l < NLAYERS; l++) {
        // hsum = segsum(h) -> fp16
        k_agg<<<(N_NODES + 7) / 8, 256>>>(hc, rs, cs, a16);
        // fused: gh = h16 @ whh^T and gi = a16 @ Wcomb_l^T
        ggc2_k<<<dim3(6, NPER), 256, GGC_SMEM>>>(h16, a16, wh16,
                                                 wc16 + (long long)l * 640 * KPAD,
                                                 gh, gi);
        // GRU update; last layer also writes conv0 input hp16
        k_gates<<<(N_NODES * HDIM + 255) / 256, 256>>>(
            gi, gh, bih, bhh, hc, hn, h16,
            (l == NLAYERS - 1) ? hp16 : (__half*)nullptr);
        float* t = hc; hc = hn; hn = t;
    }

    // ---- conv0 (fp16 HMMA, fused bias+ReLU+max; feats cols 0..199) ----
    conv0h_k<<<dim3(1, 2, BATCH), 256, CONV_SMEM>>>(hp16, w0h, c0b, feats);

    // ---- join conv branch, then FC head ----
    cudaStreamWaitEvent(0, ev2, 0);
    k_fc<<<BATCH, 256>>>(feats, f1w, f1b, f2w, f2b, f3w, f3b, out);
}

// round 16
// speedup vs baseline: 5.7352x; 1.0064x over previous
#include <cuda_runtime.h>
#include <cuda_fp16.h>
#include <cstdint>

// ---------------- problem constants ----------------
#define N_NODES 26240      // B * N_PER = 128 * 205 (exactly 205 blocks of 128)
#define HDIM    200
#define NEDGE   209920
#define BATCH   128
#define NPER    205
#define EMBD    768
#define SEQ     512
#define NLAYERS 6
#define KPAD    208        // padded K (fp16 single pass; 3x64 + 1x16 tiles)

// ---------------- static device scratch ----------------
__device__ float g_h0[N_NODES * HDIM];
__device__ float g_h1[N_NODES * HDIM];
__device__ float g_gi[N_NODES * 3 * HDIM];
__device__ float g_gh[N_NODES * 3 * HDIM];
__device__ float g_feats[BATCH * 800];
__device__ int   g_deg[N_NODES];
__device__ int   g_rs [N_NODES + 1];
__device__ int   g_cur[N_NODES];
__device__ int   g_csrc[NEDGE];

// GGC fp16 operands, K-padded to 208 (pads zero from module init, never written)
__device__ __align__(16) __half g_h16[(size_t)N_NODES * KPAD];
__device__ __align__(16) __half g_a16[(size_t)N_NODES * KPAD];
// GGC fp16 weights
__device__ __align__(16) __half g_wi16[640 * KPAD];             // wih, rows 600..639 zero
__device__ __align__(16) __half g_wh16[640 * KPAD];             // whh, rows 600..639 zero
__device__ __align__(16) __half g_wgd16[NLAYERS * 208 * KPAD];  // ggc_w[l] direct cast
__device__ __align__(16) __half g_wc16[NLAYERS * 640 * KPAD];   // Wcomb_l = wih @ W_l^T

// fp16 embeddings, time-major [b][t][c], +8 zero rows for tap overrun
__device__ __align__(16) __half g_e16[((size_t)BATCH * SEQ + 8) * EMBD];
// fp16 conv weights: [200][K], tap-major K (single pass)
__device__ __align__(16) __half g_w1h[200 * 2304];
__device__ __align__(16) __half g_w2h[200 * 3072];
__device__ __align__(16) __half g_w3h[200 * 3840];
// conv0: fp16 padded h input [BATCH][260][256] and weights [208][768]
__device__ __align__(16) __half g_hp16[(size_t)BATCH * 260 * 256];
__device__ __align__(16) __half g_w0h[208 * 768];

// ---------------- warp-level MMA (compute_100-safe PTX) ----------------
#define MMA_F16(d, a, b0, b1) asm volatile(                            \
    "mma.sync.aligned.m16n8k16.row.col.f32.f16.f16.f32 "               \
    "{%0,%1,%2,%3}, {%4,%5,%6,%7}, {%8,%9}, {%0,%1,%2,%3};"            \
    : "+f"((d)[0]), "+f"((d)[1]), "+f"((d)[2]), "+f"((d)[3])           \
    : "r"((a)[0]), "r"((a)[1]), "r"((a)[2]), "r"((a)[3]),              \
      "r"(b0), "r"(b1))

// ---------------- cp.async helpers (sm_80+ PTX) ----------------
#define CP16(dst, src) asm volatile("cp.async.ca.shared.global [%0], [%1], 16;" \
                                    :: "r"(dst), "l"(src))
#define CP_COMMIT() asm volatile("cp.async.commit_group;" ::: "memory")
#define CP_WAIT0()  asm volatile("cp.async.wait_group 0;" ::: "memory")

__device__ __forceinline__ uint32_t s2u(const void* p) {
    return (uint32_t)__cvta_generic_to_shared(p);
}

// ---------------- shared copy helper for K=208 (3x64 + 1x16) -----------------
__device__ __forceinline__ void cp_k208(const __half* A, const __half* B,
                                        uint32_t ab, uint32_t bb,
                                        int tid, int kt) {
    const int kg = kt * 64;
    constexpr int ASTR = 72, BSTR = 72;
    if (kt < 3) {
#pragma unroll
        for (int i = 0; i < 4; i++) {
            int u = tid + i * 256;
            int row = u >> 3, ch = u & 7;
            CP16(ab + (row * ASTR + ch * 8) * 2,
                 A + (long long)row * KPAD + kg + ch * 8);
        }
#pragma unroll
        for (int i = 0; i < 7; i++) {
            int u = tid + i * 256;
            if (u < 1664) {
                int row = u >> 3, ch = u & 7;
                CP16(bb + (row * BSTR + ch * 8) * 2,
                     B + (long long)row * KPAD + kg + ch * 8);
            }
        }
    } else {   // 16-wide tail, cols 192..207
        {
            int row = tid >> 1, ch = tid & 1;
            CP16(ab + (row * ASTR + ch * 8) * 2,
                 A + (long long)row * KPAD + kg + ch * 8);
        }
#pragma unroll
        for (int i = 0; i < 2; i++) {
            int u = tid + i * 256;
            if (u < 416) {
                int row = u >> 1, ch = u & 1;
                CP16(bb + (row * BSTR + ch * 8) * 2,
                     B + (long long)row * KPAD + kg + ch * 8);
            }
        }
    }
}

// ---------------- GGC GEMM: C = A @ Bfull^T slice (fp16, K=208) ----------------
// grid (3 n-tiles, 205 m-tiles). Bfull is [640][208]; slice nb covers cols nb*208.
__global__ void __launch_bounds__(256, 1) ggcN_k(
    const __half* __restrict__ Ag,
    const __half* __restrict__ Bfull,
    float* __restrict__ C)
{
    extern __shared__ __align__(16) char dsm[];
    constexpr int ASTR = 72, BSTR = 72;
    __half* As = (__half*)dsm;
    __half* Bs = (__half*)(dsm + 36864);

    const int tid = threadIdx.x;
    const int lane = tid & 31, wid = tid >> 5;
    const int wm = wid & 3, wn = wid >> 2;
    const int g = lane >> 2, t2 = (lane & 3) * 2;
    const int m0 = blockIdx.y * 128;
    const int nb = blockIdx.x;
    const uint32_t asb = s2u(As), bsb = s2u(Bs);

    const __half* A = Ag + (long long)m0 * KPAD;
    const __half* B = Bfull + (long long)nb * 208 * KPAD;
    const int cb = nb * 208;

    float acc[2][13][4];
#pragma unroll
    for (int i = 0; i < 2; i++)
#pragma unroll
        for (int j = 0; j < 13; j++)
#pragma unroll
            for (int q = 0; q < 4; q++) acc[i][j][q] = 0.f;

    cp_k208(A, B, asb, bsb, tid, 0); CP_COMMIT(); CP_WAIT0();
    __syncthreads();

#pragma unroll 1
    for (int kt = 0; kt < 4; kt++) {
        const int buf = kt & 1;
        const bool more = (kt + 1 < 4);
        if (more) {
            cp_k208(A, B, asb + (buf ^ 1) * 128 * ASTR * 2,
                    bsb + (buf ^ 1) * 208 * BSTR * 2, tid, kt + 1);
            CP_COMMIT();
        }
        const __half* Ab = As + buf * 128 * ASTR;
        const __half* Bb = Bs + buf * 208 * BSTR;
        const int ksteps = (kt == 3) ? 1 : 4;
#pragma unroll 1
        for (int ks = 0; ks < ksteps; ks++) {
            const int ko = ks * 16;
            uint32_t a[2][4];
#pragma unroll
            for (int i = 0; i < 2; i++) {
                const int r = wm * 32 + i * 16 + g;
                a[i][0] = *(const uint32_t*)(Ab + (r)     * ASTR + ko + t2);
                a[i][1] = *(const uint32_t*)(Ab + (r + 8) * ASTR + ko + t2);
                a[i][2] = *(const uint32_t*)(Ab + (r)     * ASTR + ko + t2 + 8);
                a[i][3] = *(const uint32_t*)(Ab + (r + 8) * ASTR + ko + t2 + 8);
            }
            uint32_t bf[13][2];
#pragma unroll
            for (int j = 0; j < 13; j++) {
                const int n = wn * 104 + j * 8 + g;
                bf[j][0] = *(const uint32_t*)(Bb + n * BSTR + ko + t2);
                bf[j][1] = *(const uint32_t*)(Bb + n * BSTR + ko + t2 + 8);
            }
#pragma unroll
            for (int j = 0; j < 13; j++) {
                MMA_F16(acc[0][j], a[0], bf[j][0], bf[j][1]);
                MMA_F16(acc[1][j], a[1], bf[j][0], bf[j][1]);
            }
        }
        if (more) CP_WAIT0();
        __syncthreads();
    }

#pragma unroll
    for (int i = 0; i < 2; i++) {
        const int r = m0 + wm * 32 + i * 16 + g;
#pragma unroll
        for (int j = 0; j < 13; j++) {
            const int col = cb + wn * 104 + j * 8 + t2;
            if (col < 600) {
                C[(long long)r * 600 + col]       = acc[i][j][0];
                C[(long long)(r + 8) * 600 + col] = acc[i][j][2];
            }
            if (col + 1 < 600) {
                C[(long long)r * 600 + col + 1]       = acc[i][j][1];
                C[(long long)(r + 8) * 600 + col + 1] = acc[i][j][3];
            }
        }
    }
}

// ---------------- Wcomb = wih @ W_l^T (fp16 out) ----------------
// grid (1, 5 m-tiles, 6 layers). C[l][j:640][k1:208] fp16.
__global__ void __launch_bounds__(256, 1) wcomb_k(
    const __half* __restrict__ wi,      // [640][208]
    const __half* __restrict__ wgd,     // [L][208][208]
    __half* __restrict__ wc)            // [L][640][208]
{
    extern __shared__ __align__(16) char dsm[];
    constexpr int ASTR = 72, BSTR = 72;
    __half* As = (__half*)dsm;
    __half* Bs = (__half*)(dsm + 36864);

    const int tid = threadIdx.x;
    const int lane = tid & 31, wid = tid >> 5;
    const int wm = wid & 3, wn = wid >> 2;
    const int g = lane >> 2, t2 = (lane & 3) * 2;
    const int m0 = blockIdx.y * 128;
    const int l = blockIdx.z;
    const uint32_t asb = s2u(As), bsb = s2u(Bs);

    const __half* A = wi + (long long)m0 * KPAD;
    const __half* B = wgd + (long long)l * 208 * KPAD;
    __half* C = wc + (long long)l * 640 * KPAD;

    float acc[2][13][4];
#pragma unroll
    for (int i = 0; i < 2; i++)
#pragma unroll
        for (int j = 0; j < 13; j++)
#pragma unroll
            for (int q = 0; q < 4; q++) acc[i][j][q] = 0.f;

    cp_k208(A, B, asb, bsb, tid, 0); CP_COMMIT(); CP_WAIT0();
    __syncthreads();

#pragma unroll 1
    for (int kt = 0; kt < 4; kt++) {
        const int buf = kt & 1;
        const bool more = (kt + 1 < 4);
        if (more) {
            cp_k208(A, B, asb + (buf ^ 1) * 128 * ASTR * 2,
                    bsb + (buf ^ 1) * 208 * BSTR * 2, tid, kt + 1);
            CP_COMMIT();
        }
        const __half* Ab = As + buf * 128 * ASTR;
        const __half* Bb = Bs + buf * 208 * BSTR;
        const int ksteps = (kt == 3) ? 1 : 4;
#pragma unroll 1
        for (int ks = 0; ks < ksteps; ks++) {
            const int ko = ks * 16;
            uint32_t a[2][4];
#pragma unroll
            for (int i = 0; i < 2; i++) {
                const int r = wm * 32 + i * 16 + g;
                a[i][0] = *(const uint32_t*)(Ab + (r)     * ASTR + ko + t2);
                a[i][1] = *(const uint32_t*)(Ab + (r + 8) * ASTR + ko + t2);
                a[i][2] = *(const uint32_t*)(Ab + (r)     * ASTR + ko + t2 + 8);
                a[i][3] = *(const uint32_t*)(Ab + (r + 8) * ASTR + ko + t2 + 8);
            }
            uint32_t bf[13][2];
#pragma unroll
            for (int j = 0; j < 13; j++) {
                const int n = wn * 104 + j * 8 + g;
                bf[j][0] = *(const uint32_t*)(Bb + n * BSTR + ko + t2);
                bf[j][1] = *(const uint32_t*)(Bb + n * BSTR + ko + t2 + 8);
            }
#pragma unroll
            for (int j = 0; j < 13; j++) {
                MMA_F16(acc[0][j], a[0], bf[j][0], bf[j][1]);
                MMA_F16(acc[1][j], a[1], bf[j][0], bf[j][1]);
            }
        }
        if (more) CP_WAIT0();
        __syncthreads();
    }

#pragma unroll
    for (int i = 0; i < 2; i++) {
        const int r = m0 + wm * 32 + i * 16 + g;
#pragma unroll
        for (int j = 0; j < 13; j++) {
            const int col = wn * 104 + j * 8 + t2;
            if (col < 208) {
                C[(long long)r * KPAD + col]       = __float2half(acc[i][j][0]);
                C[(long long)(r + 8) * KPAD + col] = __float2half(acc[i][j][2]);
            }
            if (col + 1 < 208) {
                C[(long long)r * KPAD + col + 1]       = __float2half(acc[i][j][1]);
                C[(long long)(r + 8) * KPAD + col + 1] = __float2half(acc[i][j][3]);
            }
        }
    }
}

// ---------------- fused conv1/2/3: pure fp16 conv-as-GEMM ----------------
struct Conv3Args {
    const __half* wb[3];
    const float* bias[3];
};
// grid (3 convs, 4 m-tiles, 128 batches)
__global__ void __launch_bounds__(256, 1) conv3h_k(
    const __half* __restrict__ e16,
    Conv3Args args,
    float* __restrict__ feats)
{
    extern __shared__ __align__(16) char dsm[];
    constexpr int ASTR = 72, BSTR = 72;
    __half* As = (__half*)dsm;
    __half* Bs = (__half*)(dsm + 36864);
    float* smax  = (float*)(dsm + 36864 + 59904);
    float* sbias = smax + 208;

    const int cid = blockIdx.x;
    const int M   = (cid == 0) ? 510 : (cid == 1) ? 509 : 508;
    const int K   = (cid == 0) ? 2304 : (cid == 1) ? 3072 : 3840;
    const int featOff = 200 + cid * 200;
    const __half* wb = args.wb[cid];
    const float* bias = args.bias[cid];

    const int tid = threadIdx.x;
    const int lane = tid & 31, wid = tid >> 5;
    const int wm = wid & 3, wn = wid >> 2;
    const int g = lane >> 2, t2 = (lane & 3) * 2;
    const int b = blockIdx.z, m0 = blockIdx.y * 128;
    const int T = K / 64;
    const uint32_t asb = s2u(As), bsb = s2u(Bs);

    if (tid < 208) { smax[tid] = 0.f; sbias[tid] = (tid < 200) ? bias[tid] : 0.f; }

    auto copy_tile = [&](int kt, int buf) {
        int kk = kt / 12;
        int c0 = (kt - kk * 12) * 64;
        long long abase = ((long long)(b * SEQ + m0 + kk)) * EMBD + c0;
        const uint32_t ab = asb + buf * 128 * ASTR * 2;
        const uint32_t bb = bsb + buf * 208 * BSTR * 2;
#pragma unroll
        for (int i = 0; i < 4; i++) {
            int u = tid + i * 256;
            int row = u >> 3, ch = u & 7;
            CP16(ab + (row * ASTR + ch * 8) * 2,
                 e16 + abase + (long long)row * EMBD + ch * 8);
        }
        int kg = kt * 64;
#pragma unroll
        for (int i = 0; i < 7; i++) {
            int u = tid + i * 256;
            if (u < 1600) {
                int row = u >> 3, ch = u & 7;
                CP16(bb + (row * BSTR + ch * 8) * 2,
                     wb + (long long)row * K + kg + ch * 8);
            }
        }
    };

    float acc[2][13][4];
#pragma unroll
    for (int i = 0; i < 2; i++)
#pragma unroll
        for (int j = 0; j < 13; j++)
#pragma unroll
            for (int q = 0; q < 4; q++) acc[i][j][q] = 0.f;

    copy_tile(0, 0); CP_COMMIT(); CP_WAIT0();
    __syncthreads();

#pragma unroll 1
    for (int kt = 0; kt < T; kt++) {
        const int buf = kt & 1;
        const bool more = (kt + 1 < T);
        if (more) { copy_tile(kt + 1, buf ^ 1); CP_COMMIT(); }

        const __half* Ab = As + buf * 128 * ASTR;
        const __half* Bb = Bs + buf * 208 * BSTR;
#pragma unroll
        for (int ks = 0; ks < 4; ks++) {
            const int ko = ks * 16;
            uint32_t a[2][4];
#pragma unroll
            for (int i = 0; i < 2; i++) {
                const int r = wm * 32 + i * 16 + g;
                a[i][0] = *(const uint32_t*)(Ab + (r)     * ASTR + ko + t2);
                a[i][1] = *(const uint32_t*)(Ab + (r + 8) * ASTR + ko + t2);
                a[i][2] = *(const uint32_t*)(Ab + (r)     * ASTR + ko + t2 + 8);
                a[i][3] = *(const uint32_t*)(Ab + (r + 8) * ASTR + ko + t2 + 8);
            }
            uint32_t bf[13][2];
#pragma unroll
            for (int j = 0; j < 13; j++) {
                const int n = wn * 104 + j * 8 + g;
                bf[j][0] = *(const uint32_t*)(Bb + n * BSTR + ko + t2);
                bf[j][1] = *(const uint32_t*)(Bb + n * BSTR + ko + t2 + 8);
            }
#pragma unroll
            for (int j = 0; j < 13; j++) {
                MMA_F16(acc[0][j], a[0], bf[j][0], bf[j][1]);
                MMA_F16(acc[1][j], a[1], bf[j][0], bf[j][1]);
            }
        }
        if (more) CP_WAIT0();
        __syncthreads();
    }

    const int valid = (M - m0 < 128) ? (M - m0) : 128;
#pragma unroll
    for (int j = 0; j < 13; j++) {
        float v0 = -1e30f, v1 = -1e30f;
#pragma unroll
        for (int i = 0; i < 2; i++) {
            const int r0 = wm * 32 + i * 16 + g;
            if (r0 < valid)     { v0 = fmaxf(v0, acc[i][j][0]); v1 = fmaxf(v1, acc[i][j][1]); }
            if (r0 + 8 < valid) { v0 = fmaxf(v0, acc[i][j][2]); v1 = fmaxf(v1, acc[i][j][3]); }
        }
#pragma unroll
        for (int o = 4; o <= 16; o <<= 1) {
            v0 = fmaxf(v0, __shfl_xor_sync(~0u, v0, o));
            v1 = fmaxf(v1, __shfl_xor_sync(~0u, v1, o));
        }
        if (g == 0) {
            const int col = wn * 104 + j * 8 + t2;
            if (col < 200) {
                float r = fmaxf(v0 + sbias[col], 0.f);
                atomicMax((unsigned int*)&smax[col], __float_as_uint(r));
            }
            if (col + 1 < 200) {
                float r = fmaxf(v1 + sbias[col + 1], 0.f);
                atomicMax((unsigned int*)&smax[col + 1], __float_as_uint(r));
            }
        }
    }
    __syncthreads();
    if (tid < 200)
        atomicMax((unsigned int*)&feats[(long long)b * 800 + featOff + tid],
                  __float_as_uint(smax[tid]));
}

// ---------------- conv0: fp16 conv-as-GEMM over padded h ----------------
// grid (1, 2 m-tiles, 128 batches). M = 205, N = 200, feats cols 0..199.
__global__ void __launch_bounds__(256, 1) conv0h_k(
    const __half* __restrict__ hp16,
    const __half* __restrict__ w0h,     // [208][768] (rows 200..207 zero)
    const float* __restrict__ bias,
    float* __restrict__ feats)
{
    extern __shared__ __align__(16) char dsm[];
    constexpr int ASTR = 72, BSTR = 72;
    __half* As = (__half*)dsm;
    __half* Bs = (__half*)(dsm + 36864);
    float* smax  = (float*)(dsm + 36864 + 59904);
    float* sbias = smax + 208;

    const int tid = threadIdx.x;
    const int lane = tid & 31, wid = tid >> 5;
    const int wm = wid & 3, wn = wid >> 2;
    const int g = lane >> 2, t2 = (lane & 3) * 2;
    const int b = blockIdx.z, m0 = blockIdx.y * 128;
    const uint32_t asb = s2u(As), bsb = s2u(Bs);

    if (tid < 208) { smax[tid] = 0.f; sbias[tid] = (tid < 200) ? bias[tid] : 0.f; }

    auto copy_tile = [&](int kt, int buf) {
        int kk = kt >> 2;
        int c0 = (kt & 3) * 64;
        long long abase = ((long long)b * 260 + m0 + kk) * 256 + c0;
        const uint32_t ab = asb + buf * 128 * ASTR * 2;
        const uint32_t bb = bsb + buf * 208 * BSTR * 2;
#pragma unroll
        for (int i = 0; i < 4; i++) {
            int u = tid + i * 256;
            int row = u >> 3, ch = u & 7;
            CP16(ab + (row * ASTR + ch * 8) * 2,
                 hp16 + abase + (long long)row * 256 + ch * 8);
        }
        int kg = kt * 64;
#pragma unroll
        for (int i = 0; i < 7; i++) {
            int u = tid + i * 256;
            if (u < 1664) {
                int row = u >> 3, ch = u & 7;
                CP16(bb + (row * BSTR + ch * 8) * 2,
                     w0h + (long long)row * 768 + kg + ch * 8);
            }
        }
    };

    float acc[2][13][4];
#pragma unroll
    for (int i = 0; i < 2; i++)
#pragma unroll
        for (int j = 0; j < 13; j++)
#pragma unroll
            for (int q = 0; q < 4; q++) acc[i][j][q] = 0.f;

    copy_tile(0, 0); CP_COMMIT(); CP_WAIT0();
    __syncthreads();

#pragma unroll 1
    for (int kt = 0; kt < 12; kt++) {
        const int buf = kt & 1;
        const bool more = (kt + 1 < 12);
        if (more) { copy_tile(kt + 1, buf ^ 1); CP_COMMIT(); }

        const __half* Ab = As + buf * 128 * ASTR;
        const __half* Bb = Bs + buf * 208 * BSTR;
#pragma unroll
        for (int ks = 0; ks < 4; ks++) {
            const int ko = ks * 16;
            uint32_t a[2][4];
#pragma unroll
            for (int i = 0; i < 2; i++) {
                const int r = wm * 32 + i * 16 + g;
                a[i][0] = *(const uint32_t*)(Ab + (r)     * ASTR + ko + t2);
                a[i][1] = *(const uint32_t*)(Ab + (r + 8) * ASTR + ko + t2);
                a[i][2] = *(const uint32_t*)(Ab + (r)     * ASTR + ko + t2 + 8);
                a[i][3] = *(const uint32_t*)(Ab + (r + 8) * ASTR + ko + t2 + 8);
            }
            uint32_t bf[13][2];
#pragma unroll
            for (int j = 0; j < 13; j++) {
                const int n = wn * 104 + j * 8 + g;
                bf[j][0] = *(const uint32_t*)(Bb + n * BSTR + ko + t2);
                bf[j][1] = *(const uint32_t*)(Bb + n * BSTR + ko + t2 + 8);
            }
#pragma unroll
            for (int j = 0; j < 13; j++) {
                MMA_F16(acc[0][j], a[0], bf[j][0], bf[j][1]);
                MMA_F16(acc[1][j], a[1], bf[j][0], bf[j][1]);
            }
        }
        if (more) CP_WAIT0();
        __syncthreads();
    }

    const int valid = (205 - m0 < 128) ? (205 - m0) : 128;
#pragma unroll
    for (int j = 0; j < 13; j++) {
        float v0 = -1e30f, v1 = -1e30f;
#pragma unroll
        for (int i = 0; i < 2; i++) {
            const int r0 = wm * 32 + i * 16 + g;
            if (r0 < valid)     { v0 = fmaxf(v0, acc[i][j][0]); v1 = fmaxf(v1, acc[i][j][1]); }
            if (r0 + 8 < valid) { v0 = fmaxf(v0, acc[i][j][2]); v1 = fmaxf(v1, acc[i][j][3]); }
        }
#pragma unroll
        for (int o = 4; o <= 16; o <<= 1) {
            v0 = fmaxf(v0, __shfl_xor_sync(~0u, v0, o));
            v1 = fmaxf(v1, __shfl_xor_sync(~0u, v1, o));
        }
        if (g == 0) {
            const int col = wn * 104 + j * 8 + t2;
            if (col < 200) {
                float r = fmaxf(v0 + sbias[col], 0.f);
                atomicMax((unsigned int*)&smax[col], __float_as_uint(r));
            }
            if (col + 1 < 200) {
                float r = fmaxf(v1 + sbias[col + 1], 0.f);
                atomicMax((unsigned int*)&smax[col + 1], __float_as_uint(r));
            }
        }
    }
    __syncthreads();
    if (tid < 200)
        atomicMax((unsigned int*)&feats[(long long)b * 800 + tid],
                  __float_as_uint(smax[tid]));
}

// ---------------- fp16 embed ----------------
__global__ void k_embed16(const int* __restrict__ ids, const float* __restrict__ tbl,
                          __half* __restrict__ e16) {
    int row = blockIdx.x;
    int t = threadIdx.x;
    long long o = (long long)row * EMBD;
    if (row >= BATCH * SEQ) {
        if (t < 96) {
            ((uint2*)(e16 + o))[t * 2]     = make_uint2(0, 0);
            ((uint2*)(e16 + o))[t * 2 + 1] = make_uint2(0, 0);
        }
        return;
    }
    long long id = ids[row];
    float4 v = ((const float4*)(tbl + id * EMBD))[t];
    __half2 h01 = __floats2half2_rn(v.x, v.y);
    __half2 h23 = __floats2half2_rn(v.z, v.w);
    uint2 hv;
    hv.x = *(uint32_t*)&h01; hv.y = *(uint32_t*)&h23;
    ((uint2*)(e16 + o))[t] = hv;
}

// w: [200][768][KK] fp32 -> wb: [200][K] fp16, tap-major K
__global__ void k_w16(const float* __restrict__ w, __half* __restrict__ wb, int KK) {
    int K = 768 * KK;
    int idx = blockIdx.x * blockDim.x + threadIdx.x;
    if (idx >= 200 * K) return;
    int co = idx / K, r = idx - co * K;
    int kk = r / 768, ci = r - kk * 768;
    wb[idx] = __float2half(w[(co * 768 + ci) * KK + kk]);
}

// conv0 weights: c0w [200][200][3] -> w0h [208][768] (col = kk*256 + ci)
__global__ void k_w0h(const float* __restrict__ w, __half* __restrict__ out) {
    int idx = blockIdx.x * blockDim.x + threadIdx.x;
    if (idx >= 200 * 600) return;
    int co = idx / 600, r = idx - co * 600;
    int kk = r / 200, ci = r - kk * 200;
    out[(long long)co * 768 + kk * 256 + ci] =
        __float2half(w[(co * 200 + ci) * 3 + kk]);
}

// ggc_w direct cast: [L][208 rows k1][208 cols k2]
__global__ void k_wgd16(const float* __restrict__ w, __half* __restrict__ out) {
    int idx = blockIdx.x * blockDim.x + threadIdx.x;
    if (idx >= NLAYERS * 208 * KPAD) return;
    int l = idx / (208 * KPAD);
    int rem = idx - l * 208 * KPAD;
    int k1 = rem / KPAD, k2 = rem - k1 * KPAD;
    float x = (k1 < 200 && k2 < 200) ? w[(long long)l * 40000 + k1 * 200 + k2] : 0.f;
    out[idx] = __float2half(x);
}

// wih/whh [600][200] -> [640][208], zero pad
__global__ void k_wgru16(const float* __restrict__ w, __half* __restrict__ out) {
    int idx = blockIdx.x * blockDim.x + threadIdx.x;
    if (idx >= 640 * KPAD) return;
    int n = idx / KPAD, kk = idx - n * KPAD;
    float x = (n < 600 && kk < 200) ? w[n * 200 + kk] : 0.f;
    out[idx] = __float2half(x);
}

// x [26240][200] fp32 -> h16 [26240][208] fp16 (pads zeroed here, forever)
__global__ void k_x16(const float* __restrict__ xin, __half* __restrict__ h16) {
    int idx = blockIdx.x * blockDim.x + threadIdx.x;
    if (idx >= N_NODES * KPAD) return;
    int n = idx / KPAD, c = idx - n * KPAD;
    h16[idx] = __float2half((c < 200) ? xin[n * HDIM + c] : 0.f);
}

// ---------------- CSR build ----------------
__global__ void k_hist(const int* __restrict__ ei, int* __restrict__ deg) {
    int i = blockIdx.x * blockDim.x + threadIdx.x;
    if (i < NEDGE) atomicAdd(&deg[ei[NEDGE + i]], 1);
}

__global__ void k_scan(const int* __restrict__ deg, int* __restrict__ rs,
                       int* __restrict__ cur, int n) {
    __shared__ int s[1024];
    __shared__ int carry;
    int t = threadIdx.x;
    if (t == 0) carry = 0;
    __syncthreads();
    for (int base = 0; base < n; base += 1024) {
        int v = (base + t < n) ? deg[base + t] : 0;
        s[t] = v;
        __syncthreads();
        for (int off = 1; off < 1024; off <<= 1) {
            int add = (t >= off) ? s[t - off] : 0;
            __syncthreads();
            s[t] += add;
            __syncthreads();
        }
        int c0 = carry;
        int ex = c0 + s[t] - v;
        if (base + t < n) { rs[base + t] = ex; cur[base + t] = ex; }
        __syncthreads();
        if (t == 0) carry = c0 + s[1023];
        __syncthreads();
    }
    if (t == 0) rs[n] = carry;
}

__global__ void k_fill(const int* __restrict__ ei, int* __restrict__ cur,
                       int* __restrict__ cs) {
    int i = blockIdx.x * blockDim.x + threadIdx.x;
    if (i < NEDGE) {
        int d = ei[NEDGE + i];
        int p = atomicAdd(&cur[d], 1);
        cs[p] = ei[i];
    }
}

// ---------------- segment-sum of h (fp32 source) + fp16 write --------------
__global__ void k_agg(const float* __restrict__ h, const int* __restrict__ rs,
                      const int* __restrict__ cs, __half* __restrict__ a16) {
    int w = (blockIdx.x * blockDim.x + threadIdx.x) >> 5;
    int lane = threadIdx.x & 31;
    if (w >= N_NODES) return;
    int s = rs[w], e = rs[w + 1];
    float a[7] = {0, 0, 0, 0, 0, 0, 0};
    int i = s;
    for (; i + 1 < e; i += 2) {
        const float* r0 = h + (long long)cs[i]     * HDIM;
        const float* r1 = h + (long long)cs[i + 1] * HDIM;
        a[0] += r0[lane]       + r1[lane];
        a[1] += r0[lane +  32] + r1[lane +  32];
        a[2] += r0[lane +  64] + r1[lane +  64];
        a[3] += r0[lane +  96] + r1[lane +  96];
        a[4] += r0[lane + 128] + r1[lane + 128];
        a[5] += r0[lane + 160] + r1[lane + 160];
        if (lane < 8) a[6] += r0[lane + 192] + r1[lane + 192];
    }
    if (i < e) {
        const float* r0 = h + (long long)cs[i] * HDIM;
        a[0] += r0[lane];       a[1] += r0[lane + 32];  a[2] += r0[lane + 64];
        a[3] += r0[lane + 96];  a[4] += r0[lane + 128]; a[5] += r0[lane + 160];
        if (lane < 8) a[6] += r0[lane + 192];
    }
    long long o = (long long)w * KPAD + lane;
#pragma unroll
    for (int q = 0; q < 6; q++) a16[o + q * 32] = __float2half(a[q]);
    if (lane < 8) a16[o + 192] = __float2half(a[6]);
}

// ---------------- GRU gates (+ bias fold + fp16 h; optional hp16 write) ----------
__global__ void k_gates(const float* __restrict__ gi, const float* __restrict__ gh,
                        const float* __restrict__ bih, const float* __restrict__ bhh,
                        const float* __restrict__ hsrc, float* __restrict__ hdst,
                        __half* __restrict__ h16, __half* __restrict__ hp) {
    int idx = blockIdx.x * blockDim.x + threadIdx.x;
    if (idx >= N_NODES * HDIM) return;
    int n = idx / HDIM, c = idx - n * HDIM;
    const float* giN = gi + (long long)n * 600;
    const float* ghN = gh + (long long)n * 600;
    float r  = 1.f / (1.f + expf(-(giN[c] + bih[c] + ghN[c] + bhh[c])));
    float z  = 1.f / (1.f + expf(-(giN[200 + c] + bih[200 + c] + ghN[200 + c] + bhh[200 + c])));
    float nn = tanhf(giN[400 + c] + bih[400 + c] + r * (ghN[400 + c] + bhh[400 + c]));
    float h = (1.f - z) * nn + z * hsrc[idx];
    hdst[idx] = h;
    __half hf = __float2half(h);
    h16[(long long)n * KPAD + c] = hf;
    if (hp) {
        int b = n / NPER, rr = n - b * NPER;
        hp[((long long)b * 260 + rr + 1) * 256 + c] = hf;
    }
}

// ---------------- fused FC head ----------------
__global__ void k_fc(const float* __restrict__ feats,
                     const float* __restrict__ w1, const float* __restrict__ b1,
                     const float* __restrict__ w2, const float* __restrict__ b2,
                     const float* __restrict__ w3, const float* __restrict__ b3,
                     float* __restrict__ out) {
    int b = blockIdx.x;
    int tid = threadIdx.x;
    int lane = tid & 31, wrp = tid >> 5;
    __shared__ float sf[800];
    __shared__ float s1[256];
    __shared__ float s2[128];
    for (int i = tid; i < 800; i += 256) sf[i] = feats[b * 800 + i];
    __syncthreads();
    for (int jj = 0; jj < 32; jj++) {
        int j = wrp * 32 + jj;
        float a = 0.f;
        for (int i = lane; i < 800; i += 32) a += sf[i] * w1[(long long)j * 800 + i];
        for (int o = 16; o; o >>= 1) a += __shfl_down_sync(0xffffffffu, a, o);
        if (lane == 0) s1[j] = fmaxf(a + b1[j], 0.f);
    }
    __syncthreads();
    if (tid < 128) {
        float a = b2[tid];
        for (int i = 0; i < 256; i++) a += s1[i] * w2[tid * 256 + i];
        s2[tid] = fmaxf(a, 0.f);
    }
    __syncthreads();
    if (tid < 2) {
        float a = b3[tid];
        for (int i = 0; i < 128; i++) a += s2[i] * w3[tid * 128 + i];
        out[b * 2 + tid] = a;
    }
}

// ---------------- launcher ----------------
extern "C" void kernel_launch(void* const* d_in, const int* in_sizes, int n_in,
                              void* d_out, int out_size) {
    const float* x     = (const float*)d_in[0];
    const int*   ei    = (const int*)  d_in[1];
    const int*   ids   = (const int*)  d_in[2];
    const float* etab  = (const float*)d_in[3];
    const float* ggcw  = (const float*)d_in[4];
    const float* wih   = (const float*)d_in[5];
    const float* whh   = (const float*)d_in[6];
    const float* bih   = (const float*)d_in[7];
    const float* bhh   = (const float*)d_in[8];
    const float* c0w   = (const float*)d_in[9];
    const float* c0b   = (const float*)d_in[10];
    const float* c1w   = (const float*)d_in[11];
    const float* c1b   = (const float*)d_in[12];
    const float* c2w   = (const float*)d_in[13];
    const float* c2b   = (const float*)d_in[14];
    const float* c3w   = (const float*)d_in[15];
    const float* c3b   = (const float*)d_in[16];
    const float* f1w   = (const float*)d_in[17];
    const float* f1b   = (const float*)d_in[18];
    const float* f2w   = (const float*)d_in[19];
    const float* f2b   = (const float*)d_in[20];
    const float* f3w   = (const float*)d_in[21];
    const float* f3b   = (const float*)d_in[22];
    float* out = (float*)d_out;

    float *h0, *h1, *gi, *gh, *feats;
    int *deg, *rs, *cur, *cs;
    __half *e16, *w1h, *w2h, *w3h, *hp16, *w0h;
    __half *h16, *a16, *wi16, *wh16, *wgd16, *wc16;
    cudaGetSymbolAddress((void**)&h0,   g_h0);
    cudaGetSymbolAddress((void**)&h1,   g_h1);
    cudaGetSymbolAddress((void**)&gi,   g_gi);
    cudaGetSymbolAddress((void**)&gh,   g_gh);
    cudaGetSymbolAddress((void**)&feats,g_feats);
    cudaGetSymbolAddress((void**)&deg,  g_deg);
    cudaGetSymbolAddress((void**)&rs,   g_rs);
    cudaGetSymbolAddress((void**)&cur,  g_cur);
    cudaGetSymbolAddress((void**)&cs,   g_csrc);
    cudaGetSymbolAddress((void**)&e16,  g_e16);
    cudaGetSymbolAddress((void**)&w1h,  g_w1h);
    cudaGetSymbolAddress((void**)&w2h,  g_w2h);
    cudaGetSymbolAddress((void**)&w3h,  g_w3h);
    cudaGetSymbolAddress((void**)&hp16, g_hp16);
    cudaGetSymbolAddress((void**)&w0h,  g_w0h);
    cudaGetSymbolAddress((void**)&h16,  g_h16);
    cudaGetSymbolAddress((void**)&a16,  g_a16);
    cudaGetSymbolAddress((void**)&wi16, g_wi16);
    cudaGetSymbolAddress((void**)&wh16, g_wh16);
    cudaGetSymbolAddress((void**)&wgd16,g_wgd16);
    cudaGetSymbolAddress((void**)&wc16, g_wc16);

    const int CONV_SMEM = 36864 + 59904 + 832 + 832;   // 98432 B
    const int GGC_SMEM  = 36864 + 59904;               // 96768 B
    cudaFuncSetAttribute(conv3h_k, cudaFuncAttributeMaxDynamicSharedMemorySize, CONV_SMEM);
    cudaFuncSetAttribute(conv0h_k, cudaFuncAttributeMaxDynamicSharedMemorySize, CONV_SMEM);
    cudaFuncSetAttribute(ggcN_k,   cudaFuncAttributeMaxDynamicSharedMemorySize, GGC_SMEM);
    cudaFuncSetAttribute(wcomb_k,  cudaFuncAttributeMaxDynamicSharedMemorySize, GGC_SMEM);

    // streams + events (created once; host resources, no device allocs)
    static cudaStream_t s2 = nullptr, s3 = nullptr;
    static cudaEvent_t ev1 = nullptr, ev2 = nullptr, evCSR = nullptr;
    static cudaEvent_t evG = nullptr, evB = nullptr;
    if (!s2) {
        cudaStreamCreateWithFlags(&s2, cudaStreamNonBlocking);
        cudaStreamCreateWithFlags(&s3, cudaStreamNonBlocking);
        cudaEventCreateWithFlags(&ev1,   cudaEventDisableTiming);
        cudaEventCreateWithFlags(&ev2,   cudaEventDisableTiming);
        cudaEventCreateWithFlags(&evCSR, cudaEventDisableTiming);
        cudaEventCreateWithFlags(&evG,   cudaEventDisableTiming);
        cudaEventCreateWithFlags(&evB,   cudaEventDisableTiming);
    }

    // ---- default stream: feats zero, then fork conv branch ----
    cudaMemsetAsync(feats, 0, BATCH * 800 * sizeof(float));
    cudaEventRecord(ev1, 0);
    cudaStreamWaitEvent(s2, ev1, 0);
    cudaStreamWaitEvent(s3, ev1, 0);

    // ---- side stream s2: conv1/2/3 branch (independent of GGC) ----
    k_embed16<<<BATCH * SEQ + 8, 192, 0, s2>>>(ids, etab, e16);
    k_w16<<<(200 * 768 * 3 + 255) / 256, 256, 0, s2>>>(c1w, w1h, 3);
    k_w16<<<(200 * 768 * 4 + 255) / 256, 256, 0, s2>>>(c2w, w2h, 4);
    k_w16<<<(200 * 768 * 5 + 255) / 256, 256, 0, s2>>>(c3w, w3h, 5);
    {
        Conv3Args ca;
        ca.wb[0] = w1h; ca.wb[1] = w2h; ca.wb[2] = w3h;
        ca.bias[0] = c1b; ca.bias[1] = c2b; ca.bias[2] = c3b;
        conv3h_k<<<dim3(3, 4, BATCH), 256, CONV_SMEM, s2>>>(e16, ca, feats);
    }
    cudaEventRecord(ev2, s2);

    // ---- side stream s3: CSR build (needed only by first k_agg) ----
    cudaMemsetAsync(deg, 0, N_NODES * sizeof(int), s3);
    k_hist<<<(NEDGE + 255) / 256, 256, 0, s3>>>(ei, deg);
    k_scan<<<1, 1024, 0, s3>>>(deg, rs, cur, N_NODES);
    k_fill<<<(NEDGE + 255) / 256, 256, 0, s3>>>(ei, cur, cs);
    cudaEventRecord(evCSR, s3);

    // ---- default stream: GGC weight prep (overlaps CSR) ----
    cudaMemcpyAsync(h0, x, (size_t)N_NODES * HDIM * sizeof(float),
                    cudaMemcpyDeviceToDevice);
    k_x16<<<(N_NODES * KPAD + 255) / 256, 256>>>(x, h16);
    k_wgd16<<<(NLAYERS * 208 * KPAD + 255) / 256, 256>>>(ggcw, wgd16);
    k_wgru16<<<(640 * KPAD + 255) / 256, 256>>>(wih, wi16);
    k_wgru16<<<(640 * KPAD + 255) / 256, 256>>>(whh, wh16);
    k_w0h<<<(200 * 600 + 255) / 256, 256>>>(c0w, w0h);
    wcomb_k<<<dim3(1, 5, NLAYERS), 256, GGC_SMEM>>>(wi16, wgd16, wc16);
    cudaStreamWaitEvent(0, evCSR, 0);

    // ---- gated graph conv: 6 layers; gh on s3 overlaps k_agg+gi on main ----
    float* hc = h0;
    float* hn = h1;
    for (int l = 0; l < NLAYERS; l++) {
        // h16 (and wh16 on l==0) ready on main -> gh on s3
        cudaEventRecord(evG, 0);
        cudaStreamWaitEvent(s3, evG, 0);
        ggcN_k<<<dim3(3, NPER), 256, GGC_SMEM, s3>>>(h16, wh16, gh);
        cudaEventRecord(evB, s3);
        // main: hsum = segsum(h) -> fp16, then gi = a16 @ Wcomb_l^T
        k_agg<<<(N_NODES + 7) / 8, 256>>>(hc, rs, cs, a16);
        ggcN_k<<<dim3(3, NPER), 256, GGC_SMEM>>>(a16,
                                                 wc16 + (long long)l * 640 * KPAD, gi);
        // join gh, then GRU update (last layer also writes conv0 input hp16)
        cudaStreamWaitEvent(0, evB, 0);
        k_gates<<<(N_NODES * HDIM + 255) / 256, 256>>>(
            gi, gh, bih, bhh, hc, hn, h16,
            (l == NLAYERS - 1) ? hp16 : (__half*)nullptr);
        float* t = hc; hc = hn; hn = t;
    }

    // ---- conv0 (fp16 HMMA, fused bias+ReLU+max; feats cols 0..199) ----
    conv0h_k<<<dim3(1, 2, BATCH), 256, CONV_SMEM>>>(hp16, w0h, c0b, feats);

    // ---- join conv branch, then FC head ----
    cudaStreamWaitEvent(0, ev2, 0);
    k_fc<<<BATCH, 256>>>(feats, f1w, f1b, f2w, f2b, f3w, f3b, out);
}